// round 1
// baseline (speedup 1.0000x reference)
#include <cuda_runtime.h>
#include <cuda_bf16.h>
#include <math.h>

// Problem constants
#define BATCH 4
#define SEQT 1024
#define EMB 1024
#define NHEAD 16
#define HDIM 64          // EMB / NHEAD
#define E3 (3 * EMB)     // 3072
#define MTOK (BATCH * SEQT)  // 4096

// Scratch (allocation-free rule: __device__ globals)
__device__ float g_qkv[(size_t)MTOK * E3];     // [4096, 3072]  q|k|v
__device__ float g_ao [(size_t)MTOK * EMB];    // [4096, 1024]  attention output in [B,T,E]

// ---------------------------------------------------------------------------
// SGEMM: C[M,N] = A[M,K] @ B[N,K]^T + bias[N]
// BM=BN=128, BK=16, 256 threads, 8x8 per thread
// ---------------------------------------------------------------------------
#define GBM 128
#define GBN 128
#define GBK 16

__global__ __launch_bounds__(256)
void sgemm_bias_kernel(const float* __restrict__ A,
                       const float* __restrict__ B,
                       const float* __restrict__ bias,
                       float* __restrict__ C,
                       int M, int N, int K)
{
    __shared__ float As[GBK][GBM];
    __shared__ float Bs[GBK][GBN];

    const int tid = threadIdx.x;
    const int tx  = tid & 15;   // 0..15
    const int ty  = tid >> 4;   // 0..15
    const int rowBase = blockIdx.y * GBM;
    const int colBase = blockIdx.x * GBN;

    float acc[8][8];
#pragma unroll
    for (int i = 0; i < 8; i++)
#pragma unroll
        for (int j = 0; j < 8; j++) acc[i][j] = 0.f;

    for (int kt = 0; kt < K; kt += GBK) {
        // Stage A,B tiles (512 float4 each; 2 per thread per matrix)
#pragma unroll
        for (int it = 0; it < 2; it++) {
            int f  = tid + it * 256;
            int r  = f >> 2;        // 0..127
            int c4 = f & 3;         // 0..3
            float4 av = *reinterpret_cast<const float4*>(
                &A[(size_t)(rowBase + r) * K + kt + c4 * 4]);
            As[c4 * 4 + 0][r] = av.x;
            As[c4 * 4 + 1][r] = av.y;
            As[c4 * 4 + 2][r] = av.z;
            As[c4 * 4 + 3][r] = av.w;
            float4 bv = *reinterpret_cast<const float4*>(
                &B[(size_t)(colBase + r) * K + kt + c4 * 4]);
            Bs[c4 * 4 + 0][r] = bv.x;
            Bs[c4 * 4 + 1][r] = bv.y;
            Bs[c4 * 4 + 2][r] = bv.z;
            Bs[c4 * 4 + 3][r] = bv.w;
        }
        __syncthreads();

#pragma unroll
        for (int kk = 0; kk < GBK; kk++) {
            float a[8], b[8];
#pragma unroll
            for (int i = 0; i < 8; i++) a[i] = As[kk][ty * 8 + i];
#pragma unroll
            for (int j = 0; j < 8; j++) b[j] = Bs[kk][tx * 8 + j];
#pragma unroll
            for (int i = 0; i < 8; i++)
#pragma unroll
                for (int j = 0; j < 8; j++) acc[i][j] = fmaf(a[i], b[j], acc[i][j]);
        }
        __syncthreads();
    }

    // Epilogue: + bias, vectorized stores
#pragma unroll
    for (int i = 0; i < 8; i++) {
        int row = rowBase + ty * 8 + i;
#pragma unroll
        for (int j = 0; j < 8; j += 4) {
            int col = colBase + tx * 8 + j;
            float4 o;
            o.x = acc[i][j + 0] + bias[col + 0];
            o.y = acc[i][j + 1] + bias[col + 1];
            o.z = acc[i][j + 2] + bias[col + 2];
            o.w = acc[i][j + 3] + bias[col + 3];
            *reinterpret_cast<float4*>(&C[(size_t)row * N + col]) = o;
        }
    }
}

// ---------------------------------------------------------------------------
// Attention: flash-style, thread-per-query-row.
// grid: (T/128, B*H), block: 128 threads. Thread r owns query row (qbase+r).
// Streams 16-key tiles: K/V staged in smem (broadcast float4 reads),
// bias staged in padded smem (conflict-free).
// Output written to g_ao in [B,T,E] layout ([bt, h*64+d]).
// ---------------------------------------------------------------------------
#define ABN 16   // keys per tile

__global__ __launch_bounds__(128)
void attn_kernel(const float* __restrict__ qkv,
                 const float* __restrict__ attn_bias,
                 const unsigned char* __restrict__ kmask,
                 float* __restrict__ out)
{
    const int bh = blockIdx.y;            // 0..63
    const int b  = bh >> 4;
    const int h  = bh & 15;
    const int qbase = blockIdx.x * 128;
    const int r  = threadIdx.x;           // query row within tile
    const int tid = threadIdx.x;

    __shared__ float Ks[ABN][HDIM];
    __shared__ float Vs[ABN][HDIM];
    __shared__ float Bi[128][ABN + 1];    // padded: conflict-free Bi[r][j]
    __shared__ unsigned char Ms[ABN];

    const float scale = 0.125f;           // D^-0.5, D=64

    // Load my q row into registers, pre-scaled
    float qv[HDIM];
    {
        const float* qp = qkv + (size_t)(b * SEQT + qbase + r) * E3 + h * HDIM;
#pragma unroll
        for (int i = 0; i < 16; i++) {
            float4 t = reinterpret_cast<const float4*>(qp)[i];
            qv[4 * i + 0] = t.x * scale;
            qv[4 * i + 1] = t.y * scale;
            qv[4 * i + 2] = t.z * scale;
            qv[4 * i + 3] = t.w * scale;
        }
    }

    float acc[HDIM];
#pragma unroll
    for (int d = 0; d < HDIM; d++) acc[d] = 0.f;
    float m_i = -3.0e38f;
    float l_i = 0.f;

    const float* kbasep = qkv + (size_t)b * SEQT * E3 + EMB     + h * HDIM;
    const float* vbasep = qkv + (size_t)b * SEQT * E3 + 2 * EMB + h * HDIM;
    const float* biasp  = attn_bias + (size_t)bh * SEQT * SEQT;

    for (int kb = 0; kb < SEQT; kb += ABN) {
        // --- stage K and V tiles: 16 rows x 64 floats = 256 float4 each ---
#pragma unroll
        for (int it = 0; it < 2; it++) {
            int f   = tid + it * 128;     // 0..255
            int row = f >> 4;             // 0..15
            int c   = f & 15;             // 0..15 (float4 within row)
            float4 kv4 = *reinterpret_cast<const float4*>(
                kbasep + (size_t)(kb + row) * E3 + c * 4);
            *reinterpret_cast<float4*>(&Ks[row][c * 4]) = kv4;
            float4 vv4 = *reinterpret_cast<const float4*>(
                vbasep + (size_t)(kb + row) * E3 + c * 4);
            *reinterpret_cast<float4*>(&Vs[row][c * 4]) = vv4;
        }
        // --- stage bias tile: 128 rows x 16 cols, float4 gmem loads ---
#pragma unroll
        for (int it = 0; it < 4; it++) {
            int f   = tid + it * 128;     // 0..511
            int row = f >> 2;             // 0..127
            int c4  = f & 3;              // 0..3
            float4 bb = *reinterpret_cast<const float4*>(
                biasp + (size_t)(qbase + row) * SEQT + kb + c4 * 4);
            Bi[row][c4 * 4 + 0] = bb.x;
            Bi[row][c4 * 4 + 1] = bb.y;
            Bi[row][c4 * 4 + 2] = bb.z;
            Bi[row][c4 * 4 + 3] = bb.w;
        }
        if (tid < ABN) Ms[tid] = kmask[b * SEQT + kb + tid];
        __syncthreads();

        // --- scores for my row ---
        float s[ABN];
        float mnew = m_i;
#pragma unroll
        for (int j = 0; j < ABN; j++) {
            const float4* kr = reinterpret_cast<const float4*>(Ks[j]);
            float dot = 0.f;
#pragma unroll
            for (int d4 = 0; d4 < 16; d4++) {
                float4 kk = kr[d4];   // broadcast across warp
                dot = fmaf(qv[4 * d4 + 0], kk.x, dot);
                dot = fmaf(qv[4 * d4 + 1], kk.y, dot);
                dot = fmaf(qv[4 * d4 + 2], kk.z, dot);
                dot = fmaf(qv[4 * d4 + 3], kk.w, dot);
            }
            if (Ms[j]) dot = -3.0e38f;
            float sj = dot + Bi[r][j];
            s[j] = sj;
            mnew = fmaxf(mnew, sj);
        }

        // --- online softmax rescale (all state thread-local) ---
        float corr = __expf(m_i - mnew);   // first iter: exp(-inf)=0
        l_i *= corr;
#pragma unroll
        for (int d = 0; d < HDIM; d++) acc[d] *= corr;

#pragma unroll
        for (int j = 0; j < ABN; j++) {
            float p = __expf(s[j] - mnew);
            l_i += p;
            const float4* vr = reinterpret_cast<const float4*>(Vs[j]);
#pragma unroll
            for (int d4 = 0; d4 < 16; d4++) {
                float4 vv = vr[d4];   // broadcast
                acc[4 * d4 + 0] = fmaf(p, vv.x, acc[4 * d4 + 0]);
                acc[4 * d4 + 1] = fmaf(p, vv.y, acc[4 * d4 + 1]);
                acc[4 * d4 + 2] = fmaf(p, vv.z, acc[4 * d4 + 2]);
                acc[4 * d4 + 3] = fmaf(p, vv.w, acc[4 * d4 + 3]);
            }
        }
        m_i = mnew;
        __syncthreads();
    }

    // --- write my row, normalized, in [B,T,E] layout ---
    float inv = 1.f / l_i;
    float* op = out + (size_t)(b * SEQT + qbase + r) * EMB + h * HDIM;
#pragma unroll
    for (int d4 = 0; d4 < 16; d4++) {
        float4 o;
        o.x = acc[4 * d4 + 0] * inv;
        o.y = acc[4 * d4 + 1] * inv;
        o.z = acc[4 * d4 + 2] * inv;
        o.w = acc[4 * d4 + 3] * inv;
        *reinterpret_cast<float4*>(op + 4 * d4) = o;
    }
}

// ---------------------------------------------------------------------------
// Launch
// ---------------------------------------------------------------------------
extern "C" void kernel_launch(void* const* d_in, const int* in_sizes, int n_in,
                              void* d_out, int out_size)
{
    const float*         query = (const float*)d_in[0];          // [4,1024,1024]
    const float*         abias = (const float*)d_in[1];          // [64,1024,1024]
    const unsigned char* kmask = (const unsigned char*)d_in[2];  // [4,1024] bool
    const float*         in_w  = (const float*)d_in[3];          // [3072,1024]
    const float*         in_b  = (const float*)d_in[4];          // [3072]
    const float*         out_w = (const float*)d_in[5];          // [1024,1024]
    const float*         out_b = (const float*)d_in[6];          // [1024]
    float*               out   = (float*)d_out;                  // [4,1024,1024]

    float* qkv = nullptr;
    float* ao  = nullptr;
    cudaGetSymbolAddress((void**)&qkv, g_qkv);
    cudaGetSymbolAddress((void**)&ao,  g_ao);

    // 1) QKV projection: [4096,3072] = query @ in_w^T + in_b
    {
        dim3 grid(E3 / GBN, MTOK / GBM);   // 24 x 32
        sgemm_bias_kernel<<<grid, 256>>>(query, in_w, in_b, qkv, MTOK, E3, EMB);
    }
    // 2) Attention
    {
        dim3 grid(SEQT / 128, BATCH * NHEAD);  // 8 x 64
        attn_kernel<<<grid, 128>>>(qkv, abias, kmask, ao);
    }
    // 3) Output projection: [4096,1024] = ao @ out_w^T + out_b
    {
        dim3 grid(EMB / GBN, MTOK / GBM);  // 8 x 32
        sgemm_bias_kernel<<<grid, 256>>>(ao, out_w, out_b, out, MTOK, EMB, EMB);
    }
}

// round 3
// speedup vs baseline: 1.4518x; 1.4518x over previous
#include <cuda_runtime.h>
#include <cuda_bf16.h>
#include <cstdint>
#include <math.h>

// Problem constants
#define BATCH 4
#define SEQT 1024
#define EMB 1024
#define NHEAD 16
#define HDIM 64
#define E3 (3 * EMB)
#define MTOK (BATCH * SEQT)

// Scratch
__device__ float g_qkv[(size_t)MTOK * E3];
__device__ float g_ao [(size_t)MTOK * EMB];

// ---------------------------------------------------------------------------
// mma.sync helpers (sm_80 PTX -- legal on compute_103 baseline)
// ---------------------------------------------------------------------------
__device__ __forceinline__ uint32_t smem_u32(const void* p) {
    uint32_t a;
    asm("{ .reg .u64 t; cvta.to.shared.u64 t, %1; cvt.u32.u64 %0, t; }"
        : "=r"(a) : "l"(p));
    return a;
}

#define LDM4(r0, r1, r2, r3, addr) \
    asm volatile("ldmatrix.sync.aligned.m8n8.x4.shared.b16 {%0,%1,%2,%3}, [%4];" \
                 : "=r"(r0), "=r"(r1), "=r"(r2), "=r"(r3) : "r"(addr))

#define MMA16816(d, a, b0, b1) \
    asm volatile("mma.sync.aligned.m16n8k16.row.col.f32.bf16.bf16.f32 " \
                 "{%0,%1,%2,%3},{%4,%5,%6,%7},{%8,%9},{%0,%1,%2,%3};" \
                 : "+f"((d)[0]), "+f"((d)[1]), "+f"((d)[2]), "+f"((d)[3]) \
                 : "r"((a)[0]), "r"((a)[1]), "r"((a)[2]), "r"((a)[3]), \
                   "r"(b0), "r"(b1))

__device__ __forceinline__ void split_bf16(float x, __nv_bfloat16& h, __nv_bfloat16& l) {
    h = __float2bfloat16_rn(x);
    l = __float2bfloat16_rn(x - __bfloat162float(h));
}

__device__ __forceinline__ uint32_t pack2(__nv_bfloat16 a, __nv_bfloat16 b) {
    __nv_bfloat162 t(a, b);
    return *reinterpret_cast<uint32_t*>(&t);
}

// ---------------------------------------------------------------------------
// bf16x3 GEMM: C[M,N] = A[M,K] @ B[N,K]^T + bias[N]
// CTA 128x128, BK=32 fp32, 256 thr, warp grid 4(m) x 2(n), warp tile 32x64.
// SMEM: padded rows of 32 bf16 + 8 pad (80B stride -> conflict-free ldmatrix).
// Double buffered; next chunk prefetched into registers during MMA.
// ---------------------------------------------------------------------------
#define GBK 32
#define RSTR 40            // halves per smem row (80 bytes)
#define TILE_B 10240u      // 128 rows * 80 B
#define BUF_B  40960u      // Ah|Al|Bh|Bl
#define GEMM_SMEM (2 * 40960 + 128)

__global__ __launch_bounds__(256)
void gemm_bf16x3_kernel(const float* __restrict__ A,
                        const float* __restrict__ B,
                        const float* __restrict__ bias,
                        float* __restrict__ C,
                        int N, int K)
{
    extern __shared__ char dsm[];
    const uint32_t sbase = (smem_u32(dsm) + 127u) & ~127u;

    const int tid  = threadIdx.x;
    const int lane = tid & 31;
    const int wm   = (tid >> 5) & 3;    // 0..3  (m warp)
    const int wn   = tid >> 7;          // 0..1  (n warp)
    const int rowBase = blockIdx.y * 128;
    const int colBase = blockIdx.x * 128;

    float acc[2][8][4];
#pragma unroll
    for (int i = 0; i < 2; i++)
#pragma unroll
        for (int j = 0; j < 8; j++)
#pragma unroll
            for (int q = 0; q < 4; q++) acc[i][j][q] = 0.f;

    // gmem chunk prefetch (A: 128x32, B: 128x32; 4 float4 each per thread)
    const int lr = tid >> 3;           // 0..31  (row step 32 over 4 iters)
    const int lc = tid & 7;            // float4 col
    float4 ra[4], rb[4];

    auto prefetch = [&](int kt) {
#pragma unroll
        for (int i = 0; i < 4; i++) {
            int r = lr + i * 32;
            ra[i] = *reinterpret_cast<const float4*>(A + (size_t)(rowBase + r) * K + kt + lc * 4);
            rb[i] = *reinterpret_cast<const float4*>(B + (size_t)(colBase + r) * K + kt + lc * 4);
        }
    };

    auto store_smem = [&](int buf) {
        const uint32_t bo = sbase + (uint32_t)buf * BUF_B;
#pragma unroll
        for (int i = 0; i < 4; i++) {
            int r = lr + i * 32;
            uint32_t off = (uint32_t)(r * 80 + lc * 8);
            __nv_bfloat16 hx, lx, hy, ly, hz, lz, hw, lw;
            split_bf16(ra[i].x, hx, lx); split_bf16(ra[i].y, hy, ly);
            split_bf16(ra[i].z, hz, lz); split_bf16(ra[i].w, hw, lw);
            uint2 hv = make_uint2(pack2(hx, hy), pack2(hz, hw));
            uint2 lv = make_uint2(pack2(lx, ly), pack2(lz, lw));
            *reinterpret_cast<uint2*>(dsm + (bo - smem_u32(dsm)) + off)            = hv;
            *reinterpret_cast<uint2*>(dsm + (bo - smem_u32(dsm)) + TILE_B + off)   = lv;
            split_bf16(rb[i].x, hx, lx); split_bf16(rb[i].y, hy, ly);
            split_bf16(rb[i].z, hz, lz); split_bf16(rb[i].w, hw, lw);
            hv = make_uint2(pack2(hx, hy), pack2(hz, hw));
            lv = make_uint2(pack2(lx, ly), pack2(lz, lw));
            *reinterpret_cast<uint2*>(dsm + (bo - smem_u32(dsm)) + 2 * TILE_B + off) = hv;
            *reinterpret_cast<uint2*>(dsm + (bo - smem_u32(dsm)) + 3 * TILE_B + off) = lv;
        }
    };

    // ldmatrix source addresses (byte offsets within a tile)
    // A: row = wm*32 + mi*16 + (lane&15), halves col = ks*16 + (lane>>4)*8
    const uint32_t aRow = (uint32_t)(wm * 32 + (lane & 15));
    const uint32_t aColH = (uint32_t)((lane >> 4) * 8);
    // B: row = wn*64 + ni*16 + (lane&7) + ((lane>>4)<<3), col = ks*16 + ((lane>>3)&1)*8
    const uint32_t bRow = (uint32_t)(wn * 64 + (lane & 7) + ((lane >> 4) << 3));
    const uint32_t bColH = (uint32_t)(((lane >> 3) & 1) * 8);

    prefetch(0);
    store_smem(0);
    __syncthreads();

    const int NIT = K / GBK;
    for (int it = 0; it < NIT; ++it) {
        const int cur = it & 1;
        if (it + 1 < NIT) prefetch((it + 1) * GBK);

        const uint32_t tb = sbase + (uint32_t)cur * BUF_B;
#pragma unroll
        for (int ks = 0; ks < 2; ks++) {
            uint32_t ah[2][4], al[2][4], bh[4][4], bl[4][4];
#pragma unroll
            for (int mi = 0; mi < 2; mi++) {
                uint32_t addr = tb + (aRow + mi * 16) * 80 + (aColH + ks * 16) * 2;
                LDM4(ah[mi][0], ah[mi][1], ah[mi][2], ah[mi][3], addr);
                LDM4(al[mi][0], al[mi][1], al[mi][2], al[mi][3], addr + TILE_B);
            }
#pragma unroll
            for (int ni = 0; ni < 4; ni++) {
                uint32_t addr = tb + 2 * TILE_B + (bRow + ni * 16) * 80 + (bColH + ks * 16) * 2;
                LDM4(bh[ni][0], bh[ni][1], bh[ni][2], bh[ni][3], addr);
                LDM4(bl[ni][0], bl[ni][1], bl[ni][2], bl[ni][3], addr + TILE_B);
            }
#pragma unroll
            for (int mi = 0; mi < 2; mi++)
#pragma unroll
                for (int n8 = 0; n8 < 8; n8++) {
                    const int ni = n8 >> 1, hh = (n8 & 1) * 2;
                    MMA16816(acc[mi][n8], ah[mi], bh[ni][hh], bh[ni][hh + 1]);
                    MMA16816(acc[mi][n8], ah[mi], bl[ni][hh], bl[ni][hh + 1]);
                    MMA16816(acc[mi][n8], al[mi], bh[ni][hh], bh[ni][hh + 1]);
                }
        }

        if (it + 1 < NIT) store_smem(1 - cur);
        __syncthreads();
    }

    // Epilogue: D layout of m16n8k16 -> direct fp32 stores + bias
    const int r0 = rowBase + wm * 32 + (lane >> 2);
    const int c0 = colBase + wn * 64 + (lane & 3) * 2;
#pragma unroll
    for (int mi = 0; mi < 2; mi++)
#pragma unroll
        for (int n8 = 0; n8 < 8; n8++) {
            const int row = r0 + mi * 16;
            const int col = c0 + n8 * 8;
            const float2 bv = *reinterpret_cast<const float2*>(bias + col);
            float2 o0 = make_float2(acc[mi][n8][0] + bv.x, acc[mi][n8][1] + bv.y);
            float2 o1 = make_float2(acc[mi][n8][2] + bv.x, acc[mi][n8][3] + bv.y);
            *reinterpret_cast<float2*>(C + (size_t)row * N + col)       = o0;
            *reinterpret_cast<float2*>(C + (size_t)(row + 8) * N + col) = o1;
        }
}

// ---------------------------------------------------------------------------
// Attention (unchanged): flash-style, thread-per-query-row.
// ---------------------------------------------------------------------------
#define ABN 16

__global__ __launch_bounds__(128)
void attn_kernel(const float* __restrict__ qkv,
                 const float* __restrict__ attn_bias,
                 const unsigned char* __restrict__ kmask,
                 float* __restrict__ out)
{
    const int bh = blockIdx.y;
    const int b  = bh >> 4;
    const int h  = bh & 15;
    const int qbase = blockIdx.x * 128;
    const int r  = threadIdx.x;
    const int tid = threadIdx.x;

    __shared__ float Ks[ABN][HDIM];
    __shared__ float Vs[ABN][HDIM];
    __shared__ float Bi[128][ABN + 1];
    __shared__ unsigned char Ms[ABN];

    const float scale = 0.125f;

    float qv[HDIM];
    {
        const float* qp = qkv + (size_t)(b * SEQT + qbase + r) * E3 + h * HDIM;
#pragma unroll
        for (int i = 0; i < 16; i++) {
            float4 t = reinterpret_cast<const float4*>(qp)[i];
            qv[4 * i + 0] = t.x * scale;
            qv[4 * i + 1] = t.y * scale;
            qv[4 * i + 2] = t.z * scale;
            qv[4 * i + 3] = t.w * scale;
        }
    }

    float acc[HDIM];
#pragma unroll
    for (int d = 0; d < HDIM; d++) acc[d] = 0.f;
    float m_i = -3.0e38f;
    float l_i = 0.f;

    const float* kbasep = qkv + (size_t)b * SEQT * E3 + EMB     + h * HDIM;
    const float* vbasep = qkv + (size_t)b * SEQT * E3 + 2 * EMB + h * HDIM;
    const float* biasp  = attn_bias + (size_t)bh * SEQT * SEQT;

    for (int kb = 0; kb < SEQT; kb += ABN) {
#pragma unroll
        for (int it = 0; it < 2; it++) {
            int f   = tid + it * 128;
            int row = f >> 4;
            int c   = f & 15;
            float4 kv4 = *reinterpret_cast<const float4*>(
                kbasep + (size_t)(kb + row) * E3 + c * 4);
            *reinterpret_cast<float4*>(&Ks[row][c * 4]) = kv4;
            float4 vv4 = *reinterpret_cast<const float4*>(
                vbasep + (size_t)(kb + row) * E3 + c * 4);
            *reinterpret_cast<float4*>(&Vs[row][c * 4]) = vv4;
        }
#pragma unroll
        for (int it = 0; it < 4; it++) {
            int f   = tid + it * 128;
            int row = f >> 2;
            int c4  = f & 3;
            float4 bb = *reinterpret_cast<const float4*>(
                biasp + (size_t)(qbase + row) * SEQT + kb + c4 * 4);
            Bi[row][c4 * 4 + 0] = bb.x;
            Bi[row][c4 * 4 + 1] = bb.y;
            Bi[row][c4 * 4 + 2] = bb.z;
            Bi[row][c4 * 4 + 3] = bb.w;
        }
        if (tid < ABN) Ms[tid] = kmask[b * SEQT + kb + tid];
        __syncthreads();

        float s[ABN];
        float mnew = m_i;
#pragma unroll
        for (int j = 0; j < ABN; j++) {
            const float4* kr = reinterpret_cast<const float4*>(Ks[j]);
            float dot = 0.f;
#pragma unroll
            for (int d4 = 0; d4 < 16; d4++) {
                float4 kk = kr[d4];
                dot = fmaf(qv[4 * d4 + 0], kk.x, dot);
                dot = fmaf(qv[4 * d4 + 1], kk.y, dot);
                dot = fmaf(qv[4 * d4 + 2], kk.z, dot);
                dot = fmaf(qv[4 * d4 + 3], kk.w, dot);
            }
            if (Ms[j]) dot = -3.0e38f;
            float sj = dot + Bi[r][j];
            s[j] = sj;
            mnew = fmaxf(mnew, sj);
        }

        float corr = __expf(m_i - mnew);
        l_i *= corr;
#pragma unroll
        for (int d = 0; d < HDIM; d++) acc[d] *= corr;

#pragma unroll
        for (int j = 0; j < ABN; j++) {
            float pj = __expf(s[j] - mnew);
            l_i += pj;
            const float4* vr = reinterpret_cast<const float4*>(Vs[j]);
#pragma unroll
            for (int d4 = 0; d4 < 16; d4++) {
                float4 vv = vr[d4];
                acc[4 * d4 + 0] = fmaf(pj, vv.x, acc[4 * d4 + 0]);
                acc[4 * d4 + 1] = fmaf(pj, vv.y, acc[4 * d4 + 1]);
                acc[4 * d4 + 2] = fmaf(pj, vv.z, acc[4 * d4 + 2]);
                acc[4 * d4 + 3] = fmaf(pj, vv.w, acc[4 * d4 + 3]);
            }
        }
        m_i = mnew;
        __syncthreads();
    }

    float inv = 1.f / l_i;
    float* op = out + (size_t)(b * SEQT + qbase + r) * EMB + h * HDIM;
#pragma unroll
    for (int d4 = 0; d4 < 16; d4++) {
        float4 o;
        o.x = acc[4 * d4 + 0] * inv;
        o.y = acc[4 * d4 + 1] * inv;
        o.z = acc[4 * d4 + 2] * inv;
        o.w = acc[4 * d4 + 3] * inv;
        *reinterpret_cast<float4*>(op + 4 * d4) = o;
    }
}

// ---------------------------------------------------------------------------
// Launch
// ---------------------------------------------------------------------------
extern "C" void kernel_launch(void* const* d_in, const int* in_sizes, int n_in,
                              void* d_out, int out_size)
{
    const float*         query = (const float*)d_in[0];
    const float*         abias = (const float*)d_in[1];
    const unsigned char* kmask = (const unsigned char*)d_in[2];
    const float*         in_w  = (const float*)d_in[3];
    const float*         in_b  = (const float*)d_in[4];
    const float*         out_w = (const float*)d_in[5];
    const float*         out_b = (const float*)d_in[6];
    float*               out   = (float*)d_out;

    float* qkv = nullptr;
    float* ao  = nullptr;
    cudaGetSymbolAddress((void**)&qkv, g_qkv);
    cudaGetSymbolAddress((void**)&ao,  g_ao);

    static bool attr_done = false;
    if (!attr_done) {
        cudaFuncSetAttribute(gemm_bf16x3_kernel,
                             cudaFuncAttributeMaxDynamicSharedMemorySize, GEMM_SMEM);
        attr_done = true;
    }

    // 1) QKV projection: [4096,3072] = query @ in_w^T + in_b   (bf16x3 mma.sync)
    {
        dim3 grid(E3 / 128, MTOK / 128);   // 24 x 32
        gemm_bf16x3_kernel<<<grid, 256, GEMM_SMEM>>>(query, in_w, in_b, qkv, E3, EMB);
    }
    // 2) Attention
    {
        dim3 grid(SEQT / 128, BATCH * NHEAD);
        attn_kernel<<<grid, 128>>>(qkv, abias, kmask, ao);
    }
    // 3) Output projection: [4096,1024] = ao @ out_w^T + out_b (bf16x3 mma.sync)
    {
        dim3 grid(EMB / 128, MTOK / 128);  // 8 x 32
        gemm_bf16x3_kernel<<<grid, 256, GEMM_SMEM>>>(ao, out_w, out_b, out, EMB, EMB);
    }
}

// round 4
// speedup vs baseline: 2.4962x; 1.7194x over previous
#include <cuda_runtime.h>
#include <cuda_bf16.h>
#include <cstdint>
#include <math.h>

#define BATCH 4
#define SEQT 1024
#define EMB 1024
#define NHEAD 16
#define HDIM 64
#define E3 (3 * EMB)
#define MTOK (BATCH * SEQT)
#define BH (BATCH * NHEAD)

// Scratch
__device__ float g_qkv[(size_t)MTOK * E3];
__device__ float g_ao [(size_t)MTOK * EMB];
// bf16 hi/lo split arrays for attention
__device__ __nv_bfloat16 g_qh[(size_t)BH * SEQT * HDIM];
__device__ __nv_bfloat16 g_ql[(size_t)BH * SEQT * HDIM];
__device__ __nv_bfloat16 g_kh[(size_t)BH * SEQT * HDIM];
__device__ __nv_bfloat16 g_kl[(size_t)BH * SEQT * HDIM];
__device__ __nv_bfloat16 g_vth[(size_t)BH * HDIM * SEQT];  // V^T [bh][d][t]
__device__ __nv_bfloat16 g_vtl[(size_t)BH * HDIM * SEQT];

// ---------------------------------------------------------------------------
// helpers
// ---------------------------------------------------------------------------
__device__ __forceinline__ uint32_t smem_u32(const void* p) {
    uint32_t a;
    asm("{ .reg .u64 t; cvta.to.shared.u64 t, %1; cvt.u32.u64 %0, t; }"
        : "=r"(a) : "l"(p));
    return a;
}

#define LDM4(r0, r1, r2, r3, addr) \
    asm volatile("ldmatrix.sync.aligned.m8n8.x4.shared.b16 {%0,%1,%2,%3}, [%4];" \
                 : "=r"(r0), "=r"(r1), "=r"(r2), "=r"(r3) : "r"(addr))

#define MMA16816(d, a, b0, b1) \
    asm volatile("mma.sync.aligned.m16n8k16.row.col.f32.bf16.bf16.f32 " \
                 "{%0,%1,%2,%3},{%4,%5,%6,%7},{%8,%9},{%0,%1,%2,%3};" \
                 : "+f"((d)[0]), "+f"((d)[1]), "+f"((d)[2]), "+f"((d)[3]) \
                 : "r"((a)[0]), "r"((a)[1]), "r"((a)[2]), "r"((a)[3]), \
                   "r"(b0), "r"(b1))

#define CPASYNC16(sdst, gsrc) \
    asm volatile("cp.async.cg.shared.global [%0], [%1], 16;" \
                 :: "r"(sdst), "l"(gsrc) : "memory")
#define CPCOMMIT() asm volatile("cp.async.commit_group;" ::: "memory")
#define CPWAIT0()  asm volatile("cp.async.wait_group 0;" ::: "memory")

__device__ __forceinline__ void split_bf16(float x, __nv_bfloat16& h, __nv_bfloat16& l) {
    h = __float2bfloat16_rn(x);
    l = __float2bfloat16_rn(x - __bfloat162float(h));
}
__device__ __forceinline__ uint32_t pack2(__nv_bfloat16 a, __nv_bfloat16 b) {
    __nv_bfloat162 t(a, b);
    return *reinterpret_cast<uint32_t*>(&t);
}

// ---------------------------------------------------------------------------
// bf16x3 GEMM (unchanged from round 3): C[M,N] = A[M,K] @ B[N,K]^T + bias[N]
// ---------------------------------------------------------------------------
#define GBK 32
#define TILE_B 10240u
#define BUF_B  40960u
#define GEMM_SMEM (2 * 40960 + 128)

__global__ __launch_bounds__(256)
void gemm_bf16x3_kernel(const float* __restrict__ A,
                        const float* __restrict__ B,
                        const float* __restrict__ bias,
                        float* __restrict__ C,
                        int N, int K)
{
    extern __shared__ char dsm[];
    const uint32_t sbase = (smem_u32(dsm) + 127u) & ~127u;

    const int tid  = threadIdx.x;
    const int lane = tid & 31;
    const int wm   = (tid >> 5) & 3;
    const int wn   = tid >> 7;
    const int rowBase = blockIdx.y * 128;
    const int colBase = blockIdx.x * 128;

    float acc[2][8][4];
#pragma unroll
    for (int i = 0; i < 2; i++)
#pragma unroll
        for (int j = 0; j < 8; j++)
#pragma unroll
            for (int q = 0; q < 4; q++) acc[i][j][q] = 0.f;

    const int lr = tid >> 3;
    const int lc = tid & 7;
    float4 ra[4], rb[4];

    auto prefetch = [&](int kt) {
#pragma unroll
        for (int i = 0; i < 4; i++) {
            int r = lr + i * 32;
            ra[i] = *reinterpret_cast<const float4*>(A + (size_t)(rowBase + r) * K + kt + lc * 4);
            rb[i] = *reinterpret_cast<const float4*>(B + (size_t)(colBase + r) * K + kt + lc * 4);
        }
    };

    auto store_smem = [&](int buf) {
        const uint32_t bo = sbase + (uint32_t)buf * BUF_B;
#pragma unroll
        for (int i = 0; i < 4; i++) {
            int r = lr + i * 32;
            uint32_t off = (uint32_t)(r * 80 + lc * 8);
            __nv_bfloat16 hx, lx, hy, ly, hz, lz, hw, lw;
            split_bf16(ra[i].x, hx, lx); split_bf16(ra[i].y, hy, ly);
            split_bf16(ra[i].z, hz, lz); split_bf16(ra[i].w, hw, lw);
            uint2 hv = make_uint2(pack2(hx, hy), pack2(hz, hw));
            uint2 lv = make_uint2(pack2(lx, ly), pack2(lz, lw));
            *reinterpret_cast<uint2*>(dsm + (bo - smem_u32(dsm)) + off)            = hv;
            *reinterpret_cast<uint2*>(dsm + (bo - smem_u32(dsm)) + TILE_B + off)   = lv;
            split_bf16(rb[i].x, hx, lx); split_bf16(rb[i].y, hy, ly);
            split_bf16(rb[i].z, hz, lz); split_bf16(rb[i].w, hw, lw);
            hv = make_uint2(pack2(hx, hy), pack2(hz, hw));
            lv = make_uint2(pack2(lx, ly), pack2(lz, lw));
            *reinterpret_cast<uint2*>(dsm + (bo - smem_u32(dsm)) + 2 * TILE_B + off) = hv;
            *reinterpret_cast<uint2*>(dsm + (bo - smem_u32(dsm)) + 3 * TILE_B + off) = lv;
        }
    };

    const uint32_t aRow = (uint32_t)(wm * 32 + (lane & 15));
    const uint32_t aColH = (uint32_t)((lane >> 4) * 8);
    const uint32_t bRow = (uint32_t)(wn * 64 + (lane & 7) + ((lane >> 4) << 3));
    const uint32_t bColH = (uint32_t)(((lane >> 3) & 1) * 8);

    prefetch(0);
    store_smem(0);
    __syncthreads();

    const int NIT = K / GBK;
    for (int it = 0; it < NIT; ++it) {
        const int cur = it & 1;
        if (it + 1 < NIT) prefetch((it + 1) * GBK);

        const uint32_t tb = sbase + (uint32_t)cur * BUF_B;
#pragma unroll
        for (int ks = 0; ks < 2; ks++) {
            uint32_t ah[2][4], al[2][4], bh[4][4], bl[4][4];
#pragma unroll
            for (int mi = 0; mi < 2; mi++) {
                uint32_t addr = tb + (aRow + mi * 16) * 80 + (aColH + ks * 16) * 2;
                LDM4(ah[mi][0], ah[mi][1], ah[mi][2], ah[mi][3], addr);
                LDM4(al[mi][0], al[mi][1], al[mi][2], al[mi][3], addr + TILE_B);
            }
#pragma unroll
            for (int ni = 0; ni < 4; ni++) {
                uint32_t addr = tb + 2 * TILE_B + (bRow + ni * 16) * 80 + (bColH + ks * 16) * 2;
                LDM4(bh[ni][0], bh[ni][1], bh[ni][2], bh[ni][3], addr);
                LDM4(bl[ni][0], bl[ni][1], bl[ni][2], bl[ni][3], addr + TILE_B);
            }
#pragma unroll
            for (int mi = 0; mi < 2; mi++)
#pragma unroll
                for (int n8 = 0; n8 < 8; n8++) {
                    const int ni = n8 >> 1, hh = (n8 & 1) * 2;
                    MMA16816(acc[mi][n8], ah[mi], bh[ni][hh], bh[ni][hh + 1]);
                    MMA16816(acc[mi][n8], ah[mi], bl[ni][hh], bl[ni][hh + 1]);
                    MMA16816(acc[mi][n8], al[mi], bh[ni][hh], bh[ni][hh + 1]);
                }
        }

        if (it + 1 < NIT) store_smem(1 - cur);
        __syncthreads();
    }

    const int r0 = rowBase + wm * 32 + (lane >> 2);
    const int c0 = colBase + wn * 64 + (lane & 3) * 2;
#pragma unroll
    for (int mi = 0; mi < 2; mi++)
#pragma unroll
        for (int n8 = 0; n8 < 8; n8++) {
            const int row = r0 + mi * 16;
            const int col = c0 + n8 * 8;
            const float2 bv = *reinterpret_cast<const float2*>(bias + col);
            float2 o0 = make_float2(acc[mi][n8][0] + bv.x, acc[mi][n8][1] + bv.y);
            float2 o1 = make_float2(acc[mi][n8][2] + bv.x, acc[mi][n8][3] + bv.y);
            *reinterpret_cast<float2*>(C + (size_t)row * N + col)       = o0;
            *reinterpret_cast<float2*>(C + (size_t)(row + 8) * N + col) = o1;
        }
}

// ---------------------------------------------------------------------------
// Prepass: qkv fp32 -> bf16 hi/lo splits. Q scaled by 0.125. V transposed.
// grid (16, 64), block 256.
// ---------------------------------------------------------------------------
__global__ __launch_bounds__(256)
void prepass_kernel(const float* __restrict__ qkv)
{
    __shared__ float vs[64][65];
    const int bh = blockIdx.y;
    const int b  = bh >> 4;
    const int h  = bh & 15;
    const int t0 = blockIdx.x * 64;
    const int tid = threadIdx.x;

    const int r  = tid >> 2;
    const int dg = (tid & 3) * 16;

    const float* rowp = qkv + (size_t)(b * SEQT + t0 + r) * E3 + h * HDIM + dg;
    const size_t obase = ((size_t)bh * SEQT + t0 + r) * HDIM + dg;

    // Q (scaled)
    {
        uint32_t hw[8], lw[8];
#pragma unroll
        for (int j = 0; j < 8; j++) {
            float x0 = rowp[2 * j] * 0.125f, x1 = rowp[2 * j + 1] * 0.125f;
            __nv_bfloat16 h0, l0, h1, l1;
            split_bf16(x0, h0, l0); split_bf16(x1, h1, l1);
            hw[j] = pack2(h0, h1); lw[j] = pack2(l0, l1);
        }
        *reinterpret_cast<uint4*>(g_qh + obase)     = *reinterpret_cast<uint4*>(hw);
        *reinterpret_cast<uint4*>(g_qh + obase + 8) = *reinterpret_cast<uint4*>(hw + 4);
        *reinterpret_cast<uint4*>(g_ql + obase)     = *reinterpret_cast<uint4*>(lw);
        *reinterpret_cast<uint4*>(g_ql + obase + 8) = *reinterpret_cast<uint4*>(lw + 4);
    }
    // K
    {
        const float* kp = rowp + EMB;
        uint32_t hw[8], lw[8];
#pragma unroll
        for (int j = 0; j < 8; j++) {
            float x0 = kp[2 * j], x1 = kp[2 * j + 1];
            __nv_bfloat16 h0, l0, h1, l1;
            split_bf16(x0, h0, l0); split_bf16(x1, h1, l1);
            hw[j] = pack2(h0, h1); lw[j] = pack2(l0, l1);
        }
        *reinterpret_cast<uint4*>(g_kh + obase)     = *reinterpret_cast<uint4*>(hw);
        *reinterpret_cast<uint4*>(g_kh + obase + 8) = *reinterpret_cast<uint4*>(hw + 4);
        *reinterpret_cast<uint4*>(g_kl + obase)     = *reinterpret_cast<uint4*>(lw);
        *reinterpret_cast<uint4*>(g_kl + obase + 8) = *reinterpret_cast<uint4*>(lw + 4);
    }
    // V -> smem, then transposed write
    {
        const float* vp = rowp + 2 * EMB;
#pragma unroll
        for (int j = 0; j < 16; j++) vs[r][dg + j] = vp[j];
    }
    __syncthreads();
    {
        const int d  = tid >> 2;
        const int tg = (tid & 3) * 16;
        uint32_t hw[8], lw[8];
#pragma unroll
        for (int j = 0; j < 8; j++) {
            float x0 = vs[tg + 2 * j][d], x1 = vs[tg + 2 * j + 1][d];
            __nv_bfloat16 h0, l0, h1, l1;
            split_bf16(x0, h0, l0); split_bf16(x1, h1, l1);
            hw[j] = pack2(h0, h1); lw[j] = pack2(l0, l1);
        }
        const size_t vo = ((size_t)bh * HDIM + d) * SEQT + t0 + tg;
        *reinterpret_cast<uint4*>(g_vth + vo)     = *reinterpret_cast<uint4*>(hw);
        *reinterpret_cast<uint4*>(g_vth + vo + 8) = *reinterpret_cast<uint4*>(hw + 4);
        *reinterpret_cast<uint4*>(g_vtl + vo)     = *reinterpret_cast<uint4*>(lw);
        *reinterpret_cast<uint4*>(g_vtl + vo + 8) = *reinterpret_cast<uint4*>(lw + 4);
    }
}

// ---------------------------------------------------------------------------
// Tensorized flash attention (bf16x3 mma.sync), no-max softmax.
// grid (8, 64), block 256 (8 warps x 16 q rows). Key tile = 64.
// ---------------------------------------------------------------------------
#define AQH   0u
#define AQL   18432u
#define ABUF0 36864u
#define ABUF1 73728u
#define AMSK  110592u
#define ATTN_SMEM (110592 + 4096 + 128)
#define RS 144u   // smem row stride (bytes)

__global__ __launch_bounds__(256, 1)
void attn_mma_kernel(const float* __restrict__ attn_bias,
                     const unsigned char* __restrict__ kmask,
                     float* __restrict__ out)
{
    extern __shared__ char dsm[];
    char* sp = dsm + ((128 - (smem_u32(dsm) & 127)) & 127);
    const uint32_t sb = smem_u32(sp);

    const int bh = blockIdx.y;
    const int b  = bh >> 4;
    const int h  = bh & 15;
    const int qbase = blockIdx.x * 128;
    const int tid  = threadIdx.x;
    const int lane = tid & 31;
    const int w    = tid >> 5;

    // mask -> float addend
    for (int i = tid; i < SEQT; i += 256)
        *reinterpret_cast<float*>(sp + AMSK + i * 4) =
            kmask[b * SEQT + i] ? -3.0e38f : 0.f;

    // stage Q (hi/lo), 8 chunks per thread
#pragma unroll
    for (int i = 0; i < 8; i++) {
        int g = tid + i * 256;
        int arr = g >> 10, rem = g & 1023;
        int row = rem >> 3, cc = rem & 7;
        const __nv_bfloat16* src = (arr ? g_ql : g_qh) +
            ((size_t)bh * SEQT + qbase + row) * HDIM + cc * 8;
        uint32_t dst = sb + (arr ? AQL : AQH) + row * RS + cc * 16;
        CPASYNC16(dst, src);
    }

    auto load_kv = [&](int kb, uint32_t bufoff) {
#pragma unroll
        for (int i = 0; i < 8; i++) {
            int g = tid + i * 256;
            int arr = g >> 9, rem = g & 511;
            int row = rem >> 3, cc = rem & 7;
            const __nv_bfloat16* src;
            if (arr == 0)      src = g_kh  + ((size_t)bh * SEQT + kb + row) * HDIM + cc * 8;
            else if (arr == 1) src = g_kl  + ((size_t)bh * SEQT + kb + row) * HDIM + cc * 8;
            else if (arr == 2) src = g_vth + ((size_t)bh * HDIM + row) * SEQT + kb + cc * 8;
            else               src = g_vtl + ((size_t)bh * HDIM + row) * SEQT + kb + cc * 8;
            uint32_t dst = sb + bufoff + (uint32_t)arr * 9216u + row * RS + cc * 16;
            CPASYNC16(dst, src);
        }
    };

    load_kv(0, ABUF0);
    CPCOMMIT();
    CPWAIT0();
    __syncthreads();

    // Q fragments (held in registers)
    const uint32_t aRow  = (uint32_t)(w * 16 + (lane & 15));
    const uint32_t aColH = (uint32_t)((lane >> 4) * 8);
    uint32_t qfh[4][4], qfl[4][4];
#pragma unroll
    for (int kc = 0; kc < 4; kc++) {
        uint32_t addr = sb + AQH + aRow * RS + (aColH + kc * 16) * 2;
        LDM4(qfh[kc][0], qfh[kc][1], qfh[kc][2], qfh[kc][3], addr);
        LDM4(qfl[kc][0], qfl[kc][1], qfl[kc][2], qfl[kc][3], addr + (AQL - AQH));
    }

    float oacc[8][4];
#pragma unroll
    for (int i = 0; i < 8; i++)
#pragma unroll
        for (int j = 0; j < 4; j++) oacc[i][j] = 0.f;
    float rs0 = 0.f, rs1 = 0.f;

    const uint32_t bRowB = (uint32_t)((lane & 7) + ((lane >> 4) << 3));
    const uint32_t bColH = (uint32_t)(((lane >> 3) & 1) * 8);
    const float* biasp = attn_bias + (size_t)bh * SEQT * SEQT +
        (size_t)(qbase + w * 16 + (lane >> 2)) * SEQT + (lane & 3) * 2;

    for (int it = 0; it < 16; ++it) {
        const int kb = it * 64;
        const uint32_t buf = (it & 1) ? ABUF1 : ABUF0;
        if (it + 1 < 16) {
            load_kv((it + 1) * 64, (it & 1) ? ABUF0 : ABUF1);
            CPCOMMIT();
        }
        // bias loads (early issue)
        float2 bias0[8], bias1[8];
#pragma unroll
        for (int n8 = 0; n8 < 8; n8++) {
            bias0[n8] = *reinterpret_cast<const float2*>(biasp + kb + n8 * 8);
            bias1[n8] = *reinterpret_cast<const float2*>(biasp + 8 * SEQT + kb + n8 * 8);
        }

        // S = Q K^T (x3)
        float sacc[8][4];
#pragma unroll
        for (int i = 0; i < 8; i++)
#pragma unroll
            for (int j = 0; j < 4; j++) sacc[i][j] = 0.f;
#pragma unroll
        for (int kc = 0; kc < 4; kc++) {
            uint32_t kfh[4][4], kfl[4][4];
#pragma unroll
            for (int nt = 0; nt < 4; nt++) {
                uint32_t addr = sb + buf + (bRowB + nt * 16) * RS + (bColH + kc * 16) * 2;
                LDM4(kfh[nt][0], kfh[nt][1], kfh[nt][2], kfh[nt][3], addr);
                LDM4(kfl[nt][0], kfl[nt][1], kfl[nt][2], kfl[nt][3], addr + 9216);
            }
#pragma unroll
            for (int n8 = 0; n8 < 8; n8++) {
                const int nt = n8 >> 1, hh = (n8 & 1) * 2;
                MMA16816(sacc[n8], qfh[kc], kfh[nt][hh], kfh[nt][hh + 1]);
                MMA16816(sacc[n8], qfh[kc], kfl[nt][hh], kfl[nt][hh + 1]);
                MMA16816(sacc[n8], qfl[kc], kfh[nt][hh], kfh[nt][hh + 1]);
            }
        }

        // softmax numerators (no max-subtraction; scores are O(10))
        uint32_t pph[16], ppl[16];
#pragma unroll
        for (int n8 = 0; n8 < 8; n8++) {
            float2 mk = *reinterpret_cast<const float2*>(
                sp + AMSK + (kb + n8 * 8 + (lane & 3) * 2) * 4);
            float p0 = __expf(sacc[n8][0] + bias0[n8].x + mk.x);
            float p1 = __expf(sacc[n8][1] + bias0[n8].y + mk.y);
            float p2 = __expf(sacc[n8][2] + bias1[n8].x + mk.x);
            float p3 = __expf(sacc[n8][3] + bias1[n8].y + mk.y);
            rs0 += p0 + p1;
            rs1 += p2 + p3;
            __nv_bfloat16 h0, l0, h1, l1, h2, l2, h3, l3;
            split_bf16(p0, h0, l0); split_bf16(p1, h1, l1);
            split_bf16(p2, h2, l2); split_bf16(p3, h3, l3);
            pph[n8 * 2]     = pack2(h0, h1);
            pph[n8 * 2 + 1] = pack2(h2, h3);
            ppl[n8 * 2]     = pack2(l0, l1);
            ppl[n8 * 2 + 1] = pack2(l2, l3);
        }

        // O += P V (x3)
#pragma unroll
        for (int kc = 0; kc < 4; kc++) {
            uint32_t pah[4] = { pph[4 * kc], pph[4 * kc + 1], pph[4 * kc + 2], pph[4 * kc + 3] };
            uint32_t pal[4] = { ppl[4 * kc], ppl[4 * kc + 1], ppl[4 * kc + 2], ppl[4 * kc + 3] };
            uint32_t vfh[4][4], vfl[4][4];
#pragma unroll
            for (int nt = 0; nt < 4; nt++) {
                uint32_t addr = sb + buf + 18432u + (bRowB + nt * 16) * RS + (bColH + kc * 16) * 2;
                LDM4(vfh[nt][0], vfh[nt][1], vfh[nt][2], vfh[nt][3], addr);
                LDM4(vfl[nt][0], vfl[nt][1], vfl[nt][2], vfl[nt][3], addr + 9216);
            }
#pragma unroll
            for (int n8 = 0; n8 < 8; n8++) {
                const int nt = n8 >> 1, hh = (n8 & 1) * 2;
                MMA16816(oacc[n8], pah, vfh[nt][hh], vfh[nt][hh + 1]);
                MMA16816(oacc[n8], pah, vfl[nt][hh], vfl[nt][hh + 1]);
                MMA16816(oacc[n8], pal, vfh[nt][hh], vfh[nt][hh + 1]);
            }
        }

        CPWAIT0();
        __syncthreads();
    }

    // row-sum reduce across quad lanes
    rs0 += __shfl_xor_sync(0xffffffffu, rs0, 1);
    rs0 += __shfl_xor_sync(0xffffffffu, rs0, 2);
    rs1 += __shfl_xor_sync(0xffffffffu, rs1, 1);
    rs1 += __shfl_xor_sync(0xffffffffu, rs1, 2);
    const float inv0 = 1.f / rs0;
    const float inv1 = 1.f / rs1;

    const int row0 = qbase + w * 16 + (lane >> 2);
    const int col0 = h * HDIM + (lane & 3) * 2;
#pragma unroll
    for (int n8 = 0; n8 < 8; n8++) {
        float2 o0 = make_float2(oacc[n8][0] * inv0, oacc[n8][1] * inv0);
        float2 o1 = make_float2(oacc[n8][2] * inv1, oacc[n8][3] * inv1);
        *reinterpret_cast<float2*>(out + (size_t)(b * SEQT + row0) * EMB + col0 + n8 * 8)       = o0;
        *reinterpret_cast<float2*>(out + (size_t)(b * SEQT + row0 + 8) * EMB + col0 + n8 * 8)   = o1;
    }
}

// ---------------------------------------------------------------------------
// Launch
// ---------------------------------------------------------------------------
extern "C" void kernel_launch(void* const* d_in, const int* in_sizes, int n_in,
                              void* d_out, int out_size)
{
    const float*         query = (const float*)d_in[0];
    const float*         abias = (const float*)d_in[1];
    const unsigned char* kmask = (const unsigned char*)d_in[2];
    const float*         in_w  = (const float*)d_in[3];
    const float*         in_b  = (const float*)d_in[4];
    const float*         out_w = (const float*)d_in[5];
    const float*         out_b = (const float*)d_in[6];
    float*               out   = (float*)d_out;

    float* qkv = nullptr;
    float* ao  = nullptr;
    cudaGetSymbolAddress((void**)&qkv, g_qkv);
    cudaGetSymbolAddress((void**)&ao,  g_ao);

    cudaFuncSetAttribute(gemm_bf16x3_kernel,
                         cudaFuncAttributeMaxDynamicSharedMemorySize, GEMM_SMEM);
    cudaFuncSetAttribute(attn_mma_kernel,
                         cudaFuncAttributeMaxDynamicSharedMemorySize, ATTN_SMEM);

    // 1) QKV projection
    {
        dim3 grid(E3 / 128, MTOK / 128);
        gemm_bf16x3_kernel<<<grid, 256, GEMM_SMEM>>>(query, in_w, in_b, qkv, E3, EMB);
    }
    // 2) Prepass: split/transpose Q,K,V
    {
        dim3 grid(SEQT / 64, BH);
        prepass_kernel<<<grid, 256>>>(qkv);
    }
    // 3) Attention (tensorized)
    {
        dim3 grid(SEQT / 128, BH);
        attn_mma_kernel<<<grid, 256, ATTN_SMEM>>>(abias, kmask, ao);
    }
    // 4) Output projection
    {
        dim3 grid(EMB / 128, MTOK / 128);
        gemm_bf16x3_kernel<<<grid, 256, GEMM_SMEM>>>(ao, out_w, out_b, out, EMB, EMB);
    }
}

// round 5
// speedup vs baseline: 2.5138x; 1.0071x over previous
#include <cuda_runtime.h>
#include <cuda_bf16.h>
#include <cstdint>
#include <math.h>

#define BATCH 4
#define SEQT 1024
#define EMB 1024
#define NHEAD 16
#define HDIM 64
#define E3 (3 * EMB)
#define MTOK (BATCH * SEQT)
#define BH (BATCH * NHEAD)

// Scratch (bf16 hi/lo pre-split operands + attention arrays)
__device__ __nv_bfloat16 g_xh[(size_t)MTOK * EMB];   // query split
__device__ __nv_bfloat16 g_xl[(size_t)MTOK * EMB];
__device__ __nv_bfloat16 g_w1h[(size_t)E3 * EMB];    // in_w split
__device__ __nv_bfloat16 g_w1l[(size_t)E3 * EMB];
__device__ __nv_bfloat16 g_w2h[(size_t)EMB * EMB];   // out_w split
__device__ __nv_bfloat16 g_w2l[(size_t)EMB * EMB];
__device__ float         g_v  [(size_t)MTOK * EMB];  // V fp32 (pre-transpose)
__device__ __nv_bfloat16 g_aoh[(size_t)MTOK * EMB];  // attention out split
__device__ __nv_bfloat16 g_aol[(size_t)MTOK * EMB];
__device__ __nv_bfloat16 g_qh[(size_t)BH * SEQT * HDIM];
__device__ __nv_bfloat16 g_ql[(size_t)BH * SEQT * HDIM];
__device__ __nv_bfloat16 g_kh[(size_t)BH * SEQT * HDIM];
__device__ __nv_bfloat16 g_kl[(size_t)BH * SEQT * HDIM];
__device__ __nv_bfloat16 g_vth[(size_t)BH * HDIM * SEQT]; // V^T [bh][d][t]
__device__ __nv_bfloat16 g_vtl[(size_t)BH * HDIM * SEQT];

// ---------------------------------------------------------------------------
// helpers
// ---------------------------------------------------------------------------
__device__ __forceinline__ uint32_t smem_u32(const void* p) {
    uint32_t a;
    asm("{ .reg .u64 t; cvta.to.shared.u64 t, %1; cvt.u32.u64 %0, t; }"
        : "=r"(a) : "l"(p));
    return a;
}

#define LDM4(r0, r1, r2, r3, addr) \
    asm volatile("ldmatrix.sync.aligned.m8n8.x4.shared.b16 {%0,%1,%2,%3}, [%4];" \
                 : "=r"(r0), "=r"(r1), "=r"(r2), "=r"(r3) : "r"(addr))

#define MMA16816(d, a, b0, b1) \
    asm volatile("mma.sync.aligned.m16n8k16.row.col.f32.bf16.bf16.f32 " \
                 "{%0,%1,%2,%3},{%4,%5,%6,%7},{%8,%9},{%0,%1,%2,%3};" \
                 : "+f"((d)[0]), "+f"((d)[1]), "+f"((d)[2]), "+f"((d)[3]) \
                 : "r"((a)[0]), "r"((a)[1]), "r"((a)[2]), "r"((a)[3]), \
                   "r"(b0), "r"(b1))

#define CPASYNC16(sdst, gsrc) \
    asm volatile("cp.async.cg.shared.global [%0], [%1], 16;" \
                 :: "r"(sdst), "l"(gsrc) : "memory")
#define CPCOMMIT() asm volatile("cp.async.commit_group;" ::: "memory")
#define CPWAIT0()  asm volatile("cp.async.wait_group 0;" ::: "memory")
#define CPWAIT2()  asm volatile("cp.async.wait_group 2;" ::: "memory")

__device__ __forceinline__ void split_bf16(float x, __nv_bfloat16& h, __nv_bfloat16& l) {
    h = __float2bfloat16_rn(x);
    l = __float2bfloat16_rn(x - __bfloat162float(h));
}
__device__ __forceinline__ uint32_t pack2(__nv_bfloat16 a, __nv_bfloat16 b) {
    __nv_bfloat162 t(a, b);
    return *reinterpret_cast<uint32_t*>(&t);
}

// ---------------------------------------------------------------------------
// Elementwise fp32 -> bf16 hi/lo split
// ---------------------------------------------------------------------------
__global__ __launch_bounds__(256)
void split_kernel(const float* __restrict__ src,
                  __nv_bfloat16* __restrict__ dh,
                  __nv_bfloat16* __restrict__ dl, int n4)
{
    int i = blockIdx.x * 256 + threadIdx.x;
    if (i >= n4) return;
    float4 v = reinterpret_cast<const float4*>(src)[i];
    __nv_bfloat16 h0, l0, h1, l1, h2, l2, h3, l3;
    split_bf16(v.x, h0, l0); split_bf16(v.y, h1, l1);
    split_bf16(v.z, h2, l2); split_bf16(v.w, h3, l3);
    reinterpret_cast<uint2*>(dh)[i] = make_uint2(pack2(h0, h1), pack2(h2, h3));
    reinterpret_cast<uint2*>(dl)[i] = make_uint2(pack2(l0, l1), pack2(l2, l3));
}

// ---------------------------------------------------------------------------
// bf16x3 GEMM, pre-split operands, cp.async 4-stage pipeline.
// C[M,N] = (Ah+Al)[M,K] @ (Bh+Bl)[N,K]^T + bias[N]   (x3 terms)
// CTA 128x128, BK=32, 256 thr, warp grid 4(m) x 2(n), warp tile 32x64.
// EPI 0: fp32 C + bias.  EPI 1: QKV epilogue (q/k bf16-split writes, v fp32).
// ---------------------------------------------------------------------------
#define STG_B 40960u            // stage bytes: 4 tiles x (128 rows x 80B)
#define GEMM_SMEM (4 * 40960 + 128)

template<int EPI>
__global__ __launch_bounds__(256)
void gemm_pre_kernel(const __nv_bfloat16* __restrict__ Ah,
                     const __nv_bfloat16* __restrict__ Al,
                     const __nv_bfloat16* __restrict__ Bh,
                     const __nv_bfloat16* __restrict__ Bl,
                     const float* __restrict__ bias,
                     float* __restrict__ C,
                     int N, int K)
{
    extern __shared__ char dsm[];
    char* sp = dsm + ((128 - (smem_u32(dsm) & 127)) & 127);
    const uint32_t sb = smem_u32(sp);

    const int tid  = threadIdx.x;
    const int lane = tid & 31;
    const int wm   = (tid >> 5) & 3;
    const int wn   = tid >> 7;
    const int rowBase = blockIdx.y * 128;
    const int colBase = blockIdx.x * 128;

    float acc[2][8][4];
#pragma unroll
    for (int i = 0; i < 2; i++)
#pragma unroll
        for (int j = 0; j < 8; j++)
#pragma unroll
            for (int q = 0; q < 4; q++) acc[i][j][q] = 0.f;

    auto issue = [&](int it_, int stg) {
        const int kt = it_ * 32;
        const uint32_t so = sb + (uint32_t)stg * STG_B;
#pragma unroll
        for (int i = 0; i < 8; i++) {
            int g = tid + i * 256;
            int arr = g >> 9;            // 0=Ah 1=Al 2=Bh 3=Bl
            int rem = g & 511;
            int row = rem >> 2, c = rem & 3;
            const __nv_bfloat16* src;
            if (arr == 0)      src = Ah + (size_t)(rowBase + row) * K + kt + c * 8;
            else if (arr == 1) src = Al + (size_t)(rowBase + row) * K + kt + c * 8;
            else if (arr == 2) src = Bh + (size_t)(colBase + row) * K + kt + c * 8;
            else               src = Bl + (size_t)(colBase + row) * K + kt + c * 8;
            CPASYNC16(so + (uint32_t)arr * 10240u + row * 80 + c * 16, src);
        }
    };

    const uint32_t aRow  = (uint32_t)(wm * 32 + (lane & 15));
    const uint32_t aColH = (uint32_t)((lane >> 4) * 8);
    const uint32_t bRow  = (uint32_t)(wn * 64 + (lane & 7) + ((lane >> 4) << 3));
    const uint32_t bColH = (uint32_t)(((lane >> 3) & 1) * 8);

    const int NIT = K / 32;   // 32
    issue(0, 0); CPCOMMIT();
    issue(1, 1); CPCOMMIT();
    issue(2, 2); CPCOMMIT();

    for (int it = 0; it < NIT; ++it) {
        const int cur = it & 3;
        CPWAIT2();                 // stage `cur` complete (2 newer pending)
        __syncthreads();           // also: all warps done reading stage (it-1)&3
        if (it + 3 < NIT) issue(it + 3, (it + 3) & 3);
        CPCOMMIT();

        const uint32_t tb = sb + (uint32_t)cur * STG_B;
#pragma unroll
        for (int ks = 0; ks < 2; ks++) {
            uint32_t ah[2][4], al[2][4], bh[4][4], bl[4][4];
#pragma unroll
            for (int mi = 0; mi < 2; mi++) {
                uint32_t addr = tb + (aRow + mi * 16) * 80 + (aColH + ks * 16) * 2;
                LDM4(ah[mi][0], ah[mi][1], ah[mi][2], ah[mi][3], addr);
                LDM4(al[mi][0], al[mi][1], al[mi][2], al[mi][3], addr + 10240);
            }
#pragma unroll
            for (int nt = 0; nt < 4; nt++) {
                uint32_t addr = tb + 20480u + (bRow + nt * 16) * 80 + (bColH + ks * 16) * 2;
                LDM4(bh[nt][0], bh[nt][1], bh[nt][2], bh[nt][3], addr);
                LDM4(bl[nt][0], bl[nt][1], bl[nt][2], bl[nt][3], addr + 10240);
            }
#pragma unroll
            for (int mi = 0; mi < 2; mi++)
#pragma unroll
                for (int n8 = 0; n8 < 8; n8++) {
                    const int nt = n8 >> 1, hh = (n8 & 1) * 2;
                    MMA16816(acc[mi][n8], ah[mi], bh[nt][hh], bh[nt][hh + 1]);
                    MMA16816(acc[mi][n8], ah[mi], bl[nt][hh], bl[nt][hh + 1]);
                    MMA16816(acc[mi][n8], al[mi], bh[nt][hh], bh[nt][hh + 1]);
                }
        }
    }

    // Epilogue
    const int r0 = rowBase + wm * 32 + (lane >> 2);
    const int c0 = colBase + wn * 64 + (lane & 3) * 2;

    if (EPI == 0) {
#pragma unroll
        for (int mi = 0; mi < 2; mi++)
#pragma unroll
            for (int n8 = 0; n8 < 8; n8++) {
                const int row = r0 + mi * 16;
                const int col = c0 + n8 * 8;
                const float2 bv = *reinterpret_cast<const float2*>(bias + col);
                float2 o0 = make_float2(acc[mi][n8][0] + bv.x, acc[mi][n8][1] + bv.y);
                float2 o1 = make_float2(acc[mi][n8][2] + bv.x, acc[mi][n8][3] + bv.y);
                *reinterpret_cast<float2*>(C + (size_t)row * N + col)       = o0;
                *reinterpret_cast<float2*>(C + (size_t)(row + 8) * N + col) = o1;
            }
    } else {
        // QKV epilogue: cols [0,1024)=Q (scaled, split), [1024,2048)=K (split),
        // [2048,3072)=V (fp32 to g_v compact [tok][1024]).
        auto wr = [&](int row, int col, float x0, float x1) {
            const int sect = col >> 10;
            const int coli = col & 1023;
            const int bb = row >> 10, t = row & 1023;
            if (sect == 2) {
                *reinterpret_cast<float2*>(C + (size_t)row * 1024 + coli) =
                    make_float2(x0, x1);
            } else {
                const int hh = coli >> 6, d = coli & 63;
                const size_t idx = ((size_t)(bb * 16 + hh) * 1024 + t) * 64 + d;
                if (sect == 0) { x0 *= 0.125f; x1 *= 0.125f; }
                __nv_bfloat16 h0, l0, h1, l1;
                split_bf16(x0, h0, l0); split_bf16(x1, h1, l1);
                if (sect == 0) {
                    *reinterpret_cast<uint32_t*>(g_qh + idx) = pack2(h0, h1);
                    *reinterpret_cast<uint32_t*>(g_ql + idx) = pack2(l0, l1);
                } else {
                    *reinterpret_cast<uint32_t*>(g_kh + idx) = pack2(h0, h1);
                    *reinterpret_cast<uint32_t*>(g_kl + idx) = pack2(l0, l1);
                }
            }
        };
#pragma unroll
        for (int mi = 0; mi < 2; mi++)
#pragma unroll
            for (int n8 = 0; n8 < 8; n8++) {
                const int row = r0 + mi * 16;
                const int col = c0 + n8 * 8;
                const float2 bv = *reinterpret_cast<const float2*>(bias + col);
                wr(row,     col, acc[mi][n8][0] + bv.x, acc[mi][n8][1] + bv.y);
                wr(row + 8, col, acc[mi][n8][2] + bv.x, acc[mi][n8][3] + bv.y);
            }
    }
}

// ---------------------------------------------------------------------------
// V prepass: g_v fp32 [tok][h*64+d] -> transposed bf16 hi/lo [bh][d][t]
// grid (16, 64), block 256.
// ---------------------------------------------------------------------------
__global__ __launch_bounds__(256)
void vprep_kernel()
{
    __shared__ float vs[64][65];
    const int bh = blockIdx.y;
    const int b  = bh >> 4;
    const int h  = bh & 15;
    const int t0 = blockIdx.x * 64;
    const int tid = threadIdx.x;

    {
        const int r  = tid >> 2;
        const int dg = (tid & 3) * 16;
        const float* vp = g_v + (size_t)(b * SEQT + t0 + r) * EMB + h * HDIM + dg;
#pragma unroll
        for (int j = 0; j < 4; j++) {
            float4 t = reinterpret_cast<const float4*>(vp)[j];
            vs[r][dg + 4 * j + 0] = t.x; vs[r][dg + 4 * j + 1] = t.y;
            vs[r][dg + 4 * j + 2] = t.z; vs[r][dg + 4 * j + 3] = t.w;
        }
    }
    __syncthreads();
    {
        const int d  = tid >> 2;
        const int tg = (tid & 3) * 16;
        uint32_t hw[8], lw[8];
#pragma unroll
        for (int j = 0; j < 8; j++) {
            float x0 = vs[tg + 2 * j][d], x1 = vs[tg + 2 * j + 1][d];
            __nv_bfloat16 h0, l0, h1, l1;
            split_bf16(x0, h0, l0); split_bf16(x1, h1, l1);
            hw[j] = pack2(h0, h1); lw[j] = pack2(l0, l1);
        }
        const size_t vo = ((size_t)bh * HDIM + d) * SEQT + t0 + tg;
        *reinterpret_cast<uint4*>(g_vth + vo)     = *reinterpret_cast<uint4*>(hw);
        *reinterpret_cast<uint4*>(g_vth + vo + 8) = *reinterpret_cast<uint4*>(hw + 4);
        *reinterpret_cast<uint4*>(g_vtl + vo)     = *reinterpret_cast<uint4*>(lw);
        *reinterpret_cast<uint4*>(g_vtl + vo + 8) = *reinterpret_cast<uint4*>(lw + 4);
    }
}

// ---------------------------------------------------------------------------
// Tensorized flash attention (bf16x3 mma.sync), no-max softmax.
// grid (8, 64), block 256 (8 warps x 16 q rows). Key tile = 64.
// Epilogue writes bf16 hi/lo O directly (for the out-proj GEMM).
// ---------------------------------------------------------------------------
#define AQH   0u
#define AQL   18432u
#define ABUF0 36864u
#define ABUF1 73728u
#define AMSK  110592u
#define ATTN_SMEM (110592 + 4096 + 128)
#define RS 144u

__global__ __launch_bounds__(256, 1)
void attn_mma_kernel(const float* __restrict__ attn_bias,
                     const unsigned char* __restrict__ kmask)
{
    extern __shared__ char dsm[];
    char* sp = dsm + ((128 - (smem_u32(dsm) & 127)) & 127);
    const uint32_t sb = smem_u32(sp);

    const int bh = blockIdx.y;
    const int b  = bh >> 4;
    const int h  = bh & 15;
    const int qbase = blockIdx.x * 128;
    const int tid  = threadIdx.x;
    const int lane = tid & 31;
    const int w    = tid >> 5;

    for (int i = tid; i < SEQT; i += 256)
        *reinterpret_cast<float*>(sp + AMSK + i * 4) =
            kmask[b * SEQT + i] ? -3.0e38f : 0.f;

#pragma unroll
    for (int i = 0; i < 8; i++) {
        int g = tid + i * 256;
        int arr = g >> 10, rem = g & 1023;
        int row = rem >> 3, cc = rem & 7;
        const __nv_bfloat16* src = (arr ? g_ql : g_qh) +
            ((size_t)bh * SEQT + qbase + row) * HDIM + cc * 8;
        uint32_t dst = sb + (arr ? AQL : AQH) + row * RS + cc * 16;
        CPASYNC16(dst, src);
    }

    auto load_kv = [&](int kb, uint32_t bufoff) {
#pragma unroll
        for (int i = 0; i < 8; i++) {
            int g = tid + i * 256;
            int arr = g >> 9, rem = g & 511;
            int row = rem >> 3, cc = rem & 7;
            const __nv_bfloat16* src;
            if (arr == 0)      src = g_kh  + ((size_t)bh * SEQT + kb + row) * HDIM + cc * 8;
            else if (arr == 1) src = g_kl  + ((size_t)bh * SEQT + kb + row) * HDIM + cc * 8;
            else if (arr == 2) src = g_vth + ((size_t)bh * HDIM + row) * SEQT + kb + cc * 8;
            else               src = g_vtl + ((size_t)bh * HDIM + row) * SEQT + kb + cc * 8;
            uint32_t dst = sb + bufoff + (uint32_t)arr * 9216u + row * RS + cc * 16;
            CPASYNC16(dst, src);
        }
    };

    load_kv(0, ABUF0);
    CPCOMMIT();
    CPWAIT0();
    __syncthreads();

    const uint32_t aRow  = (uint32_t)(w * 16 + (lane & 15));
    const uint32_t aColH = (uint32_t)((lane >> 4) * 8);
    uint32_t qfh[4][4], qfl[4][4];
#pragma unroll
    for (int kc = 0; kc < 4; kc++) {
        uint32_t addr = sb + AQH + aRow * RS + (aColH + kc * 16) * 2;
        LDM4(qfh[kc][0], qfh[kc][1], qfh[kc][2], qfh[kc][3], addr);
        LDM4(qfl[kc][0], qfl[kc][1], qfl[kc][2], qfl[kc][3], addr + (AQL - AQH));
    }

    float oacc[8][4];
#pragma unroll
    for (int i = 0; i < 8; i++)
#pragma unroll
        for (int j = 0; j < 4; j++) oacc[i][j] = 0.f;
    float rs0 = 0.f, rs1 = 0.f;

    const uint32_t bRowB = (uint32_t)((lane & 7) + ((lane >> 4) << 3));
    const uint32_t bColH = (uint32_t)(((lane >> 3) & 1) * 8);
    const float* biasp = attn_bias + (size_t)bh * SEQT * SEQT +
        (size_t)(qbase + w * 16 + (lane >> 2)) * SEQT + (lane & 3) * 2;

    for (int it = 0; it < 16; ++it) {
        const int kb = it * 64;
        const uint32_t buf = (it & 1) ? ABUF1 : ABUF0;
        if (it + 1 < 16) {
            load_kv((it + 1) * 64, (it & 1) ? ABUF0 : ABUF1);
            CPCOMMIT();
        }
        float2 bias0[8], bias1[8];
#pragma unroll
        for (int n8 = 0; n8 < 8; n8++) {
            bias0[n8] = *reinterpret_cast<const float2*>(biasp + kb + n8 * 8);
            bias1[n8] = *reinterpret_cast<const float2*>(biasp + 8 * SEQT + kb + n8 * 8);
        }

        float sacc[8][4];
#pragma unroll
        for (int i = 0; i < 8; i++)
#pragma unroll
            for (int j = 0; j < 4; j++) sacc[i][j] = 0.f;
#pragma unroll
        for (int kc = 0; kc < 4; kc++) {
            uint32_t kfh[4][4], kfl[4][4];
#pragma unroll
            for (int nt = 0; nt < 4; nt++) {
                uint32_t addr = sb + buf + (bRowB + nt * 16) * RS + (bColH + kc * 16) * 2;
                LDM4(kfh[nt][0], kfh[nt][1], kfh[nt][2], kfh[nt][3], addr);
                LDM4(kfl[nt][0], kfl[nt][1], kfl[nt][2], kfl[nt][3], addr + 9216);
            }
#pragma unroll
            for (int n8 = 0; n8 < 8; n8++) {
                const int nt = n8 >> 1, hh = (n8 & 1) * 2;
                MMA16816(sacc[n8], qfh[kc], kfh[nt][hh], kfh[nt][hh + 1]);
                MMA16816(sacc[n8], qfh[kc], kfl[nt][hh], kfl[nt][hh + 1]);
                MMA16816(sacc[n8], qfl[kc], kfh[nt][hh], kfh[nt][hh + 1]);
            }
        }

        uint32_t pph[16], ppl[16];
#pragma unroll
        for (int n8 = 0; n8 < 8; n8++) {
            float2 mk = *reinterpret_cast<const float2*>(
                sp + AMSK + (kb + n8 * 8 + (lane & 3) * 2) * 4);
            float p0 = __expf(sacc[n8][0] + bias0[n8].x + mk.x);
            float p1 = __expf(sacc[n8][1] + bias0[n8].y + mk.y);
            float p2 = __expf(sacc[n8][2] + bias1[n8].x + mk.x);
            float p3 = __expf(sacc[n8][3] + bias1[n8].y + mk.y);
            rs0 += p0 + p1;
            rs1 += p2 + p3;
            __nv_bfloat16 h0, l0, h1, l1, h2, l2, h3, l3;
            split_bf16(p0, h0, l0); split_bf16(p1, h1, l1);
            split_bf16(p2, h2, l2); split_bf16(p3, h3, l3);
            pph[n8 * 2]     = pack2(h0, h1);
            pph[n8 * 2 + 1] = pack2(h2, h3);
            ppl[n8 * 2]     = pack2(l0, l1);
            ppl[n8 * 2 + 1] = pack2(l2, l3);
        }

#pragma unroll
        for (int kc = 0; kc < 4; kc++) {
            uint32_t pah[4] = { pph[4 * kc], pph[4 * kc + 1], pph[4 * kc + 2], pph[4 * kc + 3] };
            uint32_t pal[4] = { ppl[4 * kc], ppl[4 * kc + 1], ppl[4 * kc + 2], ppl[4 * kc + 3] };
            uint32_t vfh[4][4], vfl[4][4];
#pragma unroll
            for (int nt = 0; nt < 4; nt++) {
                uint32_t addr = sb + buf + 18432u + (bRowB + nt * 16) * RS + (bColH + kc * 16) * 2;
                LDM4(vfh[nt][0], vfh[nt][1], vfh[nt][2], vfh[nt][3], addr);
                LDM4(vfl[nt][0], vfl[nt][1], vfl[nt][2], vfl[nt][3], addr + 9216);
            }
#pragma unroll
            for (int n8 = 0; n8 < 8; n8++) {
                const int nt = n8 >> 1, hh = (n8 & 1) * 2;
                MMA16816(oacc[n8], pah, vfh[nt][hh], vfh[nt][hh + 1]);
                MMA16816(oacc[n8], pah, vfl[nt][hh], vfl[nt][hh + 1]);
                MMA16816(oacc[n8], pal, vfh[nt][hh], vfh[nt][hh + 1]);
            }
        }

        CPWAIT0();
        __syncthreads();
    }

    rs0 += __shfl_xor_sync(0xffffffffu, rs0, 1);
    rs0 += __shfl_xor_sync(0xffffffffu, rs0, 2);
    rs1 += __shfl_xor_sync(0xffffffffu, rs1, 1);
    rs1 += __shfl_xor_sync(0xffffffffu, rs1, 2);
    const float inv0 = 1.f / rs0;
    const float inv1 = 1.f / rs1;

    // write O as bf16 hi/lo (A operand of out-proj GEMM)
    const int row0 = qbase + w * 16 + (lane >> 2);
    const int col0 = h * HDIM + (lane & 3) * 2;
#pragma unroll
    for (int n8 = 0; n8 < 8; n8++) {
        float x0 = oacc[n8][0] * inv0, x1 = oacc[n8][1] * inv0;
        float y0 = oacc[n8][2] * inv1, y1 = oacc[n8][3] * inv1;
        __nv_bfloat16 h0, l0, h1, l1;
        size_t i0 = (size_t)(b * SEQT + row0) * EMB + col0 + n8 * 8;
        size_t i1 = (size_t)(b * SEQT + row0 + 8) * EMB + col0 + n8 * 8;
        split_bf16(x0, h0, l0); split_bf16(x1, h1, l1);
        *reinterpret_cast<uint32_t*>(g_aoh + i0) = pack2(h0, h1);
        *reinterpret_cast<uint32_t*>(g_aol + i0) = pack2(l0, l1);
        split_bf16(y0, h0, l0); split_bf16(y1, h1, l1);
        *reinterpret_cast<uint32_t*>(g_aoh + i1) = pack2(h0, h1);
        *reinterpret_cast<uint32_t*>(g_aol + i1) = pack2(l0, l1);
    }
}

// ---------------------------------------------------------------------------
// Launch
// ---------------------------------------------------------------------------
extern "C" void kernel_launch(void* const* d_in, const int* in_sizes, int n_in,
                              void* d_out, int out_size)
{
    const float*         query = (const float*)d_in[0];
    const float*         abias = (const float*)d_in[1];
    const unsigned char* kmask = (const unsigned char*)d_in[2];
    const float*         in_w  = (const float*)d_in[3];
    const float*         in_b  = (const float*)d_in[4];
    const float*         out_w = (const float*)d_in[5];
    const float*         out_b = (const float*)d_in[6];
    float*               out   = (float*)d_out;

    __nv_bfloat16 *xh, *xl, *w1h, *w1l, *w2h, *w2l, *aoh, *aol;
    float* v;
    cudaGetSymbolAddress((void**)&xh,  g_xh);
    cudaGetSymbolAddress((void**)&xl,  g_xl);
    cudaGetSymbolAddress((void**)&w1h, g_w1h);
    cudaGetSymbolAddress((void**)&w1l, g_w1l);
    cudaGetSymbolAddress((void**)&w2h, g_w2h);
    cudaGetSymbolAddress((void**)&w2l, g_w2l);
    cudaGetSymbolAddress((void**)&aoh, g_aoh);
    cudaGetSymbolAddress((void**)&aol, g_aol);
    cudaGetSymbolAddress((void**)&v,   g_v);

    cudaFuncSetAttribute(gemm_pre_kernel<0>,
                         cudaFuncAttributeMaxDynamicSharedMemorySize, GEMM_SMEM);
    cudaFuncSetAttribute(gemm_pre_kernel<1>,
                         cudaFuncAttributeMaxDynamicSharedMemorySize, GEMM_SMEM);
    cudaFuncSetAttribute(attn_mma_kernel,
                         cudaFuncAttributeMaxDynamicSharedMemorySize, ATTN_SMEM);

    // 0) pre-split operands
    split_kernel<<<(MTOK * EMB / 4 + 255) / 256, 256>>>(query, xh, xl, MTOK * EMB / 4);
    split_kernel<<<(E3 * EMB / 4 + 255) / 256, 256>>>(in_w, w1h, w1l, E3 * EMB / 4);
    split_kernel<<<(EMB * EMB / 4 + 255) / 256, 256>>>(out_w, w2h, w2l, EMB * EMB / 4);

    // 1) QKV projection + fused split/scale epilogue (v -> g_v fp32)
    {
        dim3 grid(E3 / 128, MTOK / 128);
        gemm_pre_kernel<1><<<grid, 256, GEMM_SMEM>>>(xh, xl, w1h, w1l, in_b, v, E3, EMB);
    }
    // 2) V transpose/split
    {
        dim3 grid(SEQT / 64, BH);
        vprep_kernel<<<grid, 256>>>();
    }
    // 3) Attention (writes g_aoh/g_aol)
    {
        dim3 grid(SEQT / 128, BH);
        attn_mma_kernel<<<grid, 256, ATTN_SMEM>>>(abias, kmask);
    }
    // 4) Output projection
    {
        dim3 grid(EMB / 128, MTOK / 128);
        gemm_pre_kernel<0><<<grid, 256, GEMM_SMEM>>>(aoh, aol, w2h, w2l, out_b, out, EMB, EMB);
    }
}

// round 6
// speedup vs baseline: 3.0078x; 1.1965x over previous
#include <cuda_runtime.h>
#include <cuda_bf16.h>
#include <cstdint>
#include <math.h>

#define BATCH 4
#define SEQT 1024
#define EMB 1024
#define NHEAD 16
#define HDIM 64
#define E3 (3 * EMB)
#define MTOK (BATCH * SEQT)
#define BH (BATCH * NHEAD)

// Scratch (bf16 hi/lo pre-split operands + attention arrays)
__device__ __nv_bfloat16 g_xh[(size_t)MTOK * EMB];
__device__ __nv_bfloat16 g_xl[(size_t)MTOK * EMB];
__device__ __nv_bfloat16 g_w1h[(size_t)E3 * EMB];
__device__ __nv_bfloat16 g_w1l[(size_t)E3 * EMB];
__device__ __nv_bfloat16 g_w2h[(size_t)EMB * EMB];
__device__ __nv_bfloat16 g_w2l[(size_t)EMB * EMB];
__device__ float         g_v  [(size_t)MTOK * EMB];
__device__ __nv_bfloat16 g_aoh[(size_t)MTOK * EMB];
__device__ __nv_bfloat16 g_aol[(size_t)MTOK * EMB];
__device__ __nv_bfloat16 g_qh[(size_t)BH * SEQT * HDIM];
__device__ __nv_bfloat16 g_ql[(size_t)BH * SEQT * HDIM];
__device__ __nv_bfloat16 g_kh[(size_t)BH * SEQT * HDIM];
__device__ __nv_bfloat16 g_kl[(size_t)BH * SEQT * HDIM];
__device__ __nv_bfloat16 g_vth[(size_t)BH * HDIM * SEQT];
__device__ __nv_bfloat16 g_vtl[(size_t)BH * HDIM * SEQT];

// ---------------------------------------------------------------------------
// helpers
// ---------------------------------------------------------------------------
__device__ __forceinline__ uint32_t smem_u32(const void* p) {
    uint32_t a;
    asm("{ .reg .u64 t; cvta.to.shared.u64 t, %1; cvt.u32.u64 %0, t; }"
        : "=r"(a) : "l"(p));
    return a;
}

#define LDM4(r0, r1, r2, r3, addr) \
    asm volatile("ldmatrix.sync.aligned.m8n8.x4.shared.b16 {%0,%1,%2,%3}, [%4];" \
                 : "=r"(r0), "=r"(r1), "=r"(r2), "=r"(r3) : "r"(addr))

#define MMA16816(d, a, b0, b1) \
    asm volatile("mma.sync.aligned.m16n8k16.row.col.f32.bf16.bf16.f32 " \
                 "{%0,%1,%2,%3},{%4,%5,%6,%7},{%8,%9},{%0,%1,%2,%3};" \
                 : "+f"((d)[0]), "+f"((d)[1]), "+f"((d)[2]), "+f"((d)[3]) \
                 : "r"((a)[0]), "r"((a)[1]), "r"((a)[2]), "r"((a)[3]), \
                   "r"(b0), "r"(b1))

#define CPASYNC16(sdst, gsrc) \
    asm volatile("cp.async.cg.shared.global [%0], [%1], 16;" \
                 :: "r"(sdst), "l"(gsrc) : "memory")
#define CPCOMMIT() asm volatile("cp.async.commit_group;" ::: "memory")
#define CPWAIT0()  asm volatile("cp.async.wait_group 0;" ::: "memory")
#define CPWAIT1()  asm volatile("cp.async.wait_group 1;" ::: "memory")

__device__ __forceinline__ void split_bf16(float x, __nv_bfloat16& h, __nv_bfloat16& l) {
    h = __float2bfloat16_rn(x);
    l = __float2bfloat16_rn(x - __bfloat162float(h));
}
__device__ __forceinline__ uint32_t pack2(__nv_bfloat16 a, __nv_bfloat16 b) {
    __nv_bfloat162 t(a, b);
    return *reinterpret_cast<uint32_t*>(&t);
}

// ---------------------------------------------------------------------------
// Elementwise fp32 -> bf16 hi/lo split
// ---------------------------------------------------------------------------
__global__ __launch_bounds__(256)
void split_kernel(const float* __restrict__ src,
                  __nv_bfloat16* __restrict__ dh,
                  __nv_bfloat16* __restrict__ dl, int n4)
{
    int i = blockIdx.x * 256 + threadIdx.x;
    if (i >= n4) return;
    float4 v = reinterpret_cast<const float4*>(src)[i];
    __nv_bfloat16 h0, l0, h1, l1, h2, l2, h3, l3;
    split_bf16(v.x, h0, l0); split_bf16(v.y, h1, l1);
    split_bf16(v.z, h2, l2); split_bf16(v.w, h3, l3);
    reinterpret_cast<uint2*>(dh)[i] = make_uint2(pack2(h0, h1), pack2(h2, h3));
    reinterpret_cast<uint2*>(dl)[i] = make_uint2(pack2(l0, l1), pack2(l2, l3));
}

// ---------------------------------------------------------------------------
// bf16x3 GEMM, pre-split operands, 3-stage cp.async, 2 CTAs/SM.
// SMEM tiles: compact 64B rows with XOR swizzle (c16 ^= (row>>1)&3).
// CTA 128x128, BK=32, 256 thr, warp grid 4(m) x 2(n), warp tile 32x64.
// Term-major MMA ordering (16 independent MMAs per term run).
// ---------------------------------------------------------------------------
#define STG_B 32768u            // stage: 4 tiles x (128 rows x 64B)
#define GEMM_SMEM (3 * 32768 + 128)

template<int EPI>
__global__ __launch_bounds__(256, 2)
void gemm_pre_kernel(const __nv_bfloat16* __restrict__ Ah,
                     const __nv_bfloat16* __restrict__ Al,
                     const __nv_bfloat16* __restrict__ Bh,
                     const __nv_bfloat16* __restrict__ Bl,
                     const float* __restrict__ bias,
                     float* __restrict__ C,
                     int N, int K)
{
    extern __shared__ char dsm[];
    char* sp = dsm + ((128 - (smem_u32(dsm) & 127)) & 127);
    const uint32_t sb = smem_u32(sp);

    const int tid  = threadIdx.x;
    const int lane = tid & 31;
    const int wm   = (tid >> 5) & 3;
    const int wn   = tid >> 7;
    const int rowBase = blockIdx.y * 128;
    const int colBase = blockIdx.x * 128;

    float acc[2][8][4];
#pragma unroll
    for (int i = 0; i < 2; i++)
#pragma unroll
        for (int j = 0; j < 8; j++)
#pragma unroll
            for (int q = 0; q < 4; q++) acc[i][j][q] = 0.f;

    // loader: 4 arrays x 128 rows x 4 cols16; swizzled 64B rows
    const int ldRow = (tid & 511) >> 2;   // reused via g below
    (void)ldRow;
    auto issue = [&](int it_, int stg) {
        const int kt = it_ * 32;
        const uint32_t so = sb + (uint32_t)stg * STG_B;
#pragma unroll
        for (int i = 0; i < 8; i++) {
            int g = tid + i * 256;
            int arr = g >> 9;            // 0=Ah 1=Al 2=Bh 3=Bl
            int rem = g & 511;
            int row = rem >> 2, c = rem & 3;
            int cs = c ^ ((row >> 1) & 3);
            const __nv_bfloat16* src;
            if (arr == 0)      src = Ah + (size_t)(rowBase + row) * K + kt + c * 8;
            else if (arr == 1) src = Al + (size_t)(rowBase + row) * K + kt + c * 8;
            else if (arr == 2) src = Bh + (size_t)(colBase + row) * K + kt + c * 8;
            else               src = Bl + (size_t)(colBase + row) * K + kt + c * 8;
            CPASYNC16(so + (uint32_t)arr * 8192u + (uint32_t)(row * 64 + cs * 16), src);
        }
    };

    const uint32_t aRow = (uint32_t)(wm * 32 + (lane & 15));
    const uint32_t aHi  = (uint32_t)(lane >> 4);           // col16 bit
    const uint32_t aSwz = (aRow >> 1) & 3;
    const uint32_t bRow = (uint32_t)(wn * 64 + (lane & 7) + ((lane >> 4) << 3));
    const uint32_t bHi  = (uint32_t)((lane >> 3) & 1);
    const uint32_t bSwz = (bRow >> 1) & 3;

    const int NIT = K / 32;   // 32
    issue(0, 0); CPCOMMIT();
    issue(1, 1); CPCOMMIT();

    for (int it = 0; it < NIT; ++it) {
        const int cur = it % 3;
        CPWAIT1();                 // stage `cur` complete (<=1 newer pending)
        __syncthreads();           // all warps done reading stage (it-1)%3
        if (it + 2 < NIT) issue(it + 2, (it + 2) % 3);
        CPCOMMIT();

        const uint32_t tb = sb + (uint32_t)cur * STG_B;
#pragma unroll
        for (int ks = 0; ks < 2; ks++) {
            uint32_t ah[2][4], al[2][4], bh[4][4], bl[4][4];
            const uint32_t caA = ((uint32_t)(ks * 2) + aHi) ^ aSwz;
            const uint32_t caB = ((uint32_t)(ks * 2) + bHi) ^ bSwz;
#pragma unroll
            for (int mi = 0; mi < 2; mi++) {
                uint32_t addr = tb + (aRow + mi * 16) * 64 + caA * 16;
                LDM4(ah[mi][0], ah[mi][1], ah[mi][2], ah[mi][3], addr);
                LDM4(al[mi][0], al[mi][1], al[mi][2], al[mi][3], addr + 8192);
            }
#pragma unroll
            for (int nt = 0; nt < 4; nt++) {
                uint32_t addr = tb + 16384u + (bRow + nt * 16) * 64 + caB * 16;
                LDM4(bh[nt][0], bh[nt][1], bh[nt][2], bh[nt][3], addr);
                LDM4(bl[nt][0], bl[nt][1], bl[nt][2], bl[nt][3], addr + 8192);
            }
            // term-major: 16 independent MMAs per run
#pragma unroll
            for (int mi = 0; mi < 2; mi++)
#pragma unroll
                for (int n8 = 0; n8 < 8; n8++) {
                    const int nt = n8 >> 1, hh = (n8 & 1) * 2;
                    MMA16816(acc[mi][n8], ah[mi], bh[nt][hh], bh[nt][hh + 1]);
                }
#pragma unroll
            for (int mi = 0; mi < 2; mi++)
#pragma unroll
                for (int n8 = 0; n8 < 8; n8++) {
                    const int nt = n8 >> 1, hh = (n8 & 1) * 2;
                    MMA16816(acc[mi][n8], ah[mi], bl[nt][hh], bl[nt][hh + 1]);
                }
#pragma unroll
            for (int mi = 0; mi < 2; mi++)
#pragma unroll
                for (int n8 = 0; n8 < 8; n8++) {
                    const int nt = n8 >> 1, hh = (n8 & 1) * 2;
                    MMA16816(acc[mi][n8], al[mi], bh[nt][hh], bh[nt][hh + 1]);
                }
        }
    }

    // Epilogue
    const int r0 = rowBase + wm * 32 + (lane >> 2);
    const int c0 = colBase + wn * 64 + (lane & 3) * 2;

    if (EPI == 0) {
#pragma unroll
        for (int mi = 0; mi < 2; mi++)
#pragma unroll
            for (int n8 = 0; n8 < 8; n8++) {
                const int row = r0 + mi * 16;
                const int col = c0 + n8 * 8;
                const float2 bv = *reinterpret_cast<const float2*>(bias + col);
                float2 o0 = make_float2(acc[mi][n8][0] + bv.x, acc[mi][n8][1] + bv.y);
                float2 o1 = make_float2(acc[mi][n8][2] + bv.x, acc[mi][n8][3] + bv.y);
                *reinterpret_cast<float2*>(C + (size_t)row * N + col)       = o0;
                *reinterpret_cast<float2*>(C + (size_t)(row + 8) * N + col) = o1;
            }
    } else {
        auto wr = [&](int row, int col, float x0, float x1) {
            const int sect = col >> 10;
            const int coli = col & 1023;
            const int bb = row >> 10, t = row & 1023;
            if (sect == 2) {
                *reinterpret_cast<float2*>(C + (size_t)row * 1024 + coli) =
                    make_float2(x0, x1);
            } else {
                const int hh = coli >> 6, d = coli & 63;
                const size_t idx = ((size_t)(bb * 16 + hh) * 1024 + t) * 64 + d;
                if (sect == 0) { x0 *= 0.125f; x1 *= 0.125f; }
                __nv_bfloat16 h0, l0, h1, l1;
                split_bf16(x0, h0, l0); split_bf16(x1, h1, l1);
                if (sect == 0) {
                    *reinterpret_cast<uint32_t*>(g_qh + idx) = pack2(h0, h1);
                    *reinterpret_cast<uint32_t*>(g_ql + idx) = pack2(l0, l1);
                } else {
                    *reinterpret_cast<uint32_t*>(g_kh + idx) = pack2(h0, h1);
                    *reinterpret_cast<uint32_t*>(g_kl + idx) = pack2(l0, l1);
                }
            }
        };
#pragma unroll
        for (int mi = 0; mi < 2; mi++)
#pragma unroll
            for (int n8 = 0; n8 < 8; n8++) {
                const int row = r0 + mi * 16;
                const int col = c0 + n8 * 8;
                const float2 bv = *reinterpret_cast<const float2*>(bias + col);
                wr(row,     col, acc[mi][n8][0] + bv.x, acc[mi][n8][1] + bv.y);
                wr(row + 8, col, acc[mi][n8][2] + bv.x, acc[mi][n8][3] + bv.y);
            }
    }
}

// ---------------------------------------------------------------------------
// V prepass: g_v fp32 -> transposed bf16 hi/lo [bh][d][t]
// ---------------------------------------------------------------------------
__global__ __launch_bounds__(256)
void vprep_kernel()
{
    __shared__ float vs[64][65];
    const int bh = blockIdx.y;
    const int b  = bh >> 4;
    const int h  = bh & 15;
    const int t0 = blockIdx.x * 64;
    const int tid = threadIdx.x;

    {
        const int r  = tid >> 2;
        const int dg = (tid & 3) * 16;
        const float* vp = g_v + (size_t)(b * SEQT + t0 + r) * EMB + h * HDIM + dg;
#pragma unroll
        for (int j = 0; j < 4; j++) {
            float4 t = reinterpret_cast<const float4*>(vp)[j];
            vs[r][dg + 4 * j + 0] = t.x; vs[r][dg + 4 * j + 1] = t.y;
            vs[r][dg + 4 * j + 2] = t.z; vs[r][dg + 4 * j + 3] = t.w;
        }
    }
    __syncthreads();
    {
        const int d  = tid >> 2;
        const int tg = (tid & 3) * 16;
        uint32_t hw[8], lw[8];
#pragma unroll
        for (int j = 0; j < 8; j++) {
            float x0 = vs[tg + 2 * j][d], x1 = vs[tg + 2 * j + 1][d];
            __nv_bfloat16 h0, l0, h1, l1;
            split_bf16(x0, h0, l0); split_bf16(x1, h1, l1);
            hw[j] = pack2(h0, h1); lw[j] = pack2(l0, l1);
        }
        const size_t vo = ((size_t)bh * HDIM + d) * SEQT + t0 + tg;
        *reinterpret_cast<uint4*>(g_vth + vo)     = *reinterpret_cast<uint4*>(hw);
        *reinterpret_cast<uint4*>(g_vth + vo + 8) = *reinterpret_cast<uint4*>(hw + 4);
        *reinterpret_cast<uint4*>(g_vtl + vo)     = *reinterpret_cast<uint4*>(lw);
        *reinterpret_cast<uint4*>(g_vtl + vo + 8) = *reinterpret_cast<uint4*>(lw + 4);
    }
}

// ---------------------------------------------------------------------------
// Tensorized flash attention (bf16x3 mma.sync), term-major MMA ordering.
// grid (8, 64), block 256. Key tile = 64. Output: bf16 hi/lo.
// ---------------------------------------------------------------------------
#define AQH   0u
#define AQL   18432u
#define ABUF0 36864u
#define ABUF1 73728u
#define AMSK  110592u
#define ATTN_SMEM (110592 + 4096 + 128)
#define RS 144u

__global__ __launch_bounds__(256, 1)
void attn_mma_kernel(const float* __restrict__ attn_bias,
                     const unsigned char* __restrict__ kmask)
{
    extern __shared__ char dsm[];
    char* sp = dsm + ((128 - (smem_u32(dsm) & 127)) & 127);
    const uint32_t sb = smem_u32(sp);

    const int bh = blockIdx.y;
    const int b  = bh >> 4;
    const int h  = bh & 15;
    const int qbase = blockIdx.x * 128;
    const int tid  = threadIdx.x;
    const int lane = tid & 31;
    const int w    = tid >> 5;

    for (int i = tid; i < SEQT; i += 256)
        *reinterpret_cast<float*>(sp + AMSK + i * 4) =
            kmask[b * SEQT + i] ? -3.0e38f : 0.f;

#pragma unroll
    for (int i = 0; i < 8; i++) {
        int g = tid + i * 256;
        int arr = g >> 10, rem = g & 1023;
        int row = rem >> 3, cc = rem & 7;
        const __nv_bfloat16* src = (arr ? g_ql : g_qh) +
            ((size_t)bh * SEQT + qbase + row) * HDIM + cc * 8;
        uint32_t dst = sb + (arr ? AQL : AQH) + row * RS + cc * 16;
        CPASYNC16(dst, src);
    }

    auto load_kv = [&](int kb, uint32_t bufoff) {
#pragma unroll
        for (int i = 0; i < 8; i++) {
            int g = tid + i * 256;
            int arr = g >> 9, rem = g & 511;
            int row = rem >> 3, cc = rem & 7;
            const __nv_bfloat16* src;
            if (arr == 0)      src = g_kh  + ((size_t)bh * SEQT + kb + row) * HDIM + cc * 8;
            else if (arr == 1) src = g_kl  + ((size_t)bh * SEQT + kb + row) * HDIM + cc * 8;
            else if (arr == 2) src = g_vth + ((size_t)bh * HDIM + row) * SEQT + kb + cc * 8;
            else               src = g_vtl + ((size_t)bh * HDIM + row) * SEQT + kb + cc * 8;
            uint32_t dst = sb + bufoff + (uint32_t)arr * 9216u + row * RS + cc * 16;
            CPASYNC16(dst, src);
        }
    };

    load_kv(0, ABUF0);
    CPCOMMIT();
    CPWAIT0();
    __syncthreads();

    const uint32_t aRow  = (uint32_t)(w * 16 + (lane & 15));
    const uint32_t aColH = (uint32_t)((lane >> 4) * 8);
    uint32_t qfh[4][4], qfl[4][4];
#pragma unroll
    for (int kc = 0; kc < 4; kc++) {
        uint32_t addr = sb + AQH + aRow * RS + (aColH + kc * 16) * 2;
        LDM4(qfh[kc][0], qfh[kc][1], qfh[kc][2], qfh[kc][3], addr);
        LDM4(qfl[kc][0], qfl[kc][1], qfl[kc][2], qfl[kc][3], addr + (AQL - AQH));
    }

    float oacc[8][4];
#pragma unroll
    for (int i = 0; i < 8; i++)
#pragma unroll
        for (int j = 0; j < 4; j++) oacc[i][j] = 0.f;
    float rs0 = 0.f, rs1 = 0.f;

    const uint32_t bRowB = (uint32_t)((lane & 7) + ((lane >> 4) << 3));
    const uint32_t bColH = (uint32_t)(((lane >> 3) & 1) * 8);
    const float* biasp = attn_bias + (size_t)bh * SEQT * SEQT +
        (size_t)(qbase + w * 16 + (lane >> 2)) * SEQT + (lane & 3) * 2;

    for (int it = 0; it < 16; ++it) {
        const int kb = it * 64;
        const uint32_t buf = (it & 1) ? ABUF1 : ABUF0;
        if (it + 1 < 16) {
            load_kv((it + 1) * 64, (it & 1) ? ABUF0 : ABUF1);
            CPCOMMIT();
        }
        float2 bias0[8], bias1[8];
#pragma unroll
        for (int n8 = 0; n8 < 8; n8++) {
            bias0[n8] = *reinterpret_cast<const float2*>(biasp + kb + n8 * 8);
            bias1[n8] = *reinterpret_cast<const float2*>(biasp + 8 * SEQT + kb + n8 * 8);
        }

        float sacc[8][4];
#pragma unroll
        for (int i = 0; i < 8; i++)
#pragma unroll
            for (int j = 0; j < 4; j++) sacc[i][j] = 0.f;
#pragma unroll
        for (int kc = 0; kc < 4; kc++) {
            uint32_t kfh[4][4], kfl[4][4];
#pragma unroll
            for (int nt = 0; nt < 4; nt++) {
                uint32_t addr = sb + buf + (bRowB + nt * 16) * RS + (bColH + kc * 16) * 2;
                LDM4(kfh[nt][0], kfh[nt][1], kfh[nt][2], kfh[nt][3], addr);
                LDM4(kfl[nt][0], kfl[nt][1], kfl[nt][2], kfl[nt][3], addr + 9216);
            }
            // term-major
#pragma unroll
            for (int n8 = 0; n8 < 8; n8++) {
                const int nt = n8 >> 1, hh = (n8 & 1) * 2;
                MMA16816(sacc[n8], qfh[kc], kfh[nt][hh], kfh[nt][hh + 1]);
            }
#pragma unroll
            for (int n8 = 0; n8 < 8; n8++) {
                const int nt = n8 >> 1, hh = (n8 & 1) * 2;
                MMA16816(sacc[n8], qfh[kc], kfl[nt][hh], kfl[nt][hh + 1]);
            }
#pragma unroll
            for (int n8 = 0; n8 < 8; n8++) {
                const int nt = n8 >> 1, hh = (n8 & 1) * 2;
                MMA16816(sacc[n8], qfl[kc], kfh[nt][hh], kfh[nt][hh + 1]);
            }
        }

        uint32_t pph[16], ppl[16];
#pragma unroll
        for (int n8 = 0; n8 < 8; n8++) {
            float2 mk = *reinterpret_cast<const float2*>(
                sp + AMSK + (kb + n8 * 8 + (lane & 3) * 2) * 4);
            float p0 = __expf(sacc[n8][0] + bias0[n8].x + mk.x);
            float p1 = __expf(sacc[n8][1] + bias0[n8].y + mk.y);
            float p2 = __expf(sacc[n8][2] + bias1[n8].x + mk.x);
            float p3 = __expf(sacc[n8][3] + bias1[n8].y + mk.y);
            rs0 += p0 + p1;
            rs1 += p2 + p3;
            __nv_bfloat16 h0, l0, h1, l1, h2, l2, h3, l3;
            split_bf16(p0, h0, l0); split_bf16(p1, h1, l1);
            split_bf16(p2, h2, l2); split_bf16(p3, h3, l3);
            pph[n8 * 2]     = pack2(h0, h1);
            pph[n8 * 2 + 1] = pack2(h2, h3);
            ppl[n8 * 2]     = pack2(l0, l1);
            ppl[n8 * 2 + 1] = pack2(l2, l3);
        }

#pragma unroll
        for (int kc = 0; kc < 4; kc++) {
            uint32_t pah[4] = { pph[4 * kc], pph[4 * kc + 1], pph[4 * kc + 2], pph[4 * kc + 3] };
            uint32_t pal[4] = { ppl[4 * kc], ppl[4 * kc + 1], ppl[4 * kc + 2], ppl[4 * kc + 3] };
            uint32_t vfh[4][4], vfl[4][4];
#pragma unroll
            for (int nt = 0; nt < 4; nt++) {
                uint32_t addr = sb + buf + 18432u + (bRowB + nt * 16) * RS + (bColH + kc * 16) * 2;
                LDM4(vfh[nt][0], vfh[nt][1], vfh[nt][2], vfh[nt][3], addr);
                LDM4(vfl[nt][0], vfl[nt][1], vfl[nt][2], vfl[nt][3], addr + 9216);
            }
            // term-major
#pragma unroll
            for (int n8 = 0; n8 < 8; n8++) {
                const int nt = n8 >> 1, hh = (n8 & 1) * 2;
                MMA16816(oacc[n8], pah, vfh[nt][hh], vfh[nt][hh + 1]);
            }
#pragma unroll
            for (int n8 = 0; n8 < 8; n8++) {
                const int nt = n8 >> 1, hh = (n8 & 1) * 2;
                MMA16816(oacc[n8], pah, vfl[nt][hh], vfl[nt][hh + 1]);
            }
#pragma unroll
            for (int n8 = 0; n8 < 8; n8++) {
                const int nt = n8 >> 1, hh = (n8 & 1) * 2;
                MMA16816(oacc[n8], pal, vfh[nt][hh], vfh[nt][hh + 1]);
            }
        }

        CPWAIT0();
        __syncthreads();
    }

    rs0 += __shfl_xor_sync(0xffffffffu, rs0, 1);
    rs0 += __shfl_xor_sync(0xffffffffu, rs0, 2);
    rs1 += __shfl_xor_sync(0xffffffffu, rs1, 1);
    rs1 += __shfl_xor_sync(0xffffffffu, rs1, 2);
    const float inv0 = 1.f / rs0;
    const float inv1 = 1.f / rs1;

    const int row0 = qbase + w * 16 + (lane >> 2);
    const int col0 = h * HDIM + (lane & 3) * 2;
#pragma unroll
    for (int n8 = 0; n8 < 8; n8++) {
        float x0 = oacc[n8][0] * inv0, x1 = oacc[n8][1] * inv0;
        float y0 = oacc[n8][2] * inv1, y1 = oacc[n8][3] * inv1;
        __nv_bfloat16 h0, l0, h1, l1;
        size_t i0 = (size_t)(b * SEQT + row0) * EMB + col0 + n8 * 8;
        size_t i1 = (size_t)(b * SEQT + row0 + 8) * EMB + col0 + n8 * 8;
        split_bf16(x0, h0, l0); split_bf16(x1, h1, l1);
        *reinterpret_cast<uint32_t*>(g_aoh + i0) = pack2(h0, h1);
        *reinterpret_cast<uint32_t*>(g_aol + i0) = pack2(l0, l1);
        split_bf16(y0, h0, l0); split_bf16(y1, h1, l1);
        *reinterpret_cast<uint32_t*>(g_aoh + i1) = pack2(h0, h1);
        *reinterpret_cast<uint32_t*>(g_aol + i1) = pack2(l0, l1);
    }
}

// ---------------------------------------------------------------------------
// Launch
// ---------------------------------------------------------------------------
extern "C" void kernel_launch(void* const* d_in, const int* in_sizes, int n_in,
                              void* d_out, int out_size)
{
    const float*         query = (const float*)d_in[0];
    const float*         abias = (const float*)d_in[1];
    const unsigned char* kmask = (const unsigned char*)d_in[2];
    const float*         in_w  = (const float*)d_in[3];
    const float*         in_b  = (const float*)d_in[4];
    const float*         out_w = (const float*)d_in[5];
    const float*         out_b = (const float*)d_in[6];
    float*               out   = (float*)d_out;

    __nv_bfloat16 *xh, *xl, *w1h, *w1l, *w2h, *w2l, *aoh, *aol;
    float* v;
    cudaGetSymbolAddress((void**)&xh,  g_xh);
    cudaGetSymbolAddress((void**)&xl,  g_xl);
    cudaGetSymbolAddress((void**)&w1h, g_w1h);
    cudaGetSymbolAddress((void**)&w1l, g_w1l);
    cudaGetSymbolAddress((void**)&w2h, g_w2h);
    cudaGetSymbolAddress((void**)&w2l, g_w2l);
    cudaGetSymbolAddress((void**)&aoh, g_aoh);
    cudaGetSymbolAddress((void**)&aol, g_aol);
    cudaGetSymbolAddress((void**)&v,   g_v);

    cudaFuncSetAttribute(gemm_pre_kernel<0>,
                         cudaFuncAttributeMaxDynamicSharedMemorySize, GEMM_SMEM);
    cudaFuncSetAttribute(gemm_pre_kernel<1>,
                         cudaFuncAttributeMaxDynamicSharedMemorySize, GEMM_SMEM);
    cudaFuncSetAttribute(attn_mma_kernel,
                         cudaFuncAttributeMaxDynamicSharedMemorySize, ATTN_SMEM);

    // 0) pre-split operands
    split_kernel<<<(MTOK * EMB / 4 + 255) / 256, 256>>>(query, xh, xl, MTOK * EMB / 4);
    split_kernel<<<(E3 * EMB / 4 + 255) / 256, 256>>>(in_w, w1h, w1l, E3 * EMB / 4);
    split_kernel<<<(EMB * EMB / 4 + 255) / 256, 256>>>(out_w, w2h, w2l, EMB * EMB / 4);

    // 1) QKV projection + fused split/scale epilogue
    {
        dim3 grid(E3 / 128, MTOK / 128);
        gemm_pre_kernel<1><<<grid, 256, GEMM_SMEM>>>(xh, xl, w1h, w1l, in_b, v, E3, EMB);
    }
    // 2) V transpose/split
    {
        dim3 grid(SEQT / 64, BH);
        vprep_kernel<<<grid, 256>>>();
    }
    // 3) Attention
    {
        dim3 grid(SEQT / 128, BH);
        attn_mma_kernel<<<grid, 256, ATTN_SMEM>>>(abias, kmask);
    }
    // 4) Output projection
    {
        dim3 grid(EMB / 128, MTOK / 128);
        gemm_pre_kernel<0><<<grid, 256, GEMM_SMEM>>>(aoh, aol, w2h, w2l, out_b, out, EMB, EMB);
    }
}

// round 7
// speedup vs baseline: 3.2269x; 1.0729x over previous
#include <cuda_runtime.h>
#include <cuda_bf16.h>
#include <cstdint>
#include <math.h>

#define BATCH 4
#define SEQT 1024
#define EMB 1024
#define NHEAD 16
#define HDIM 64
#define E3 (3 * EMB)
#define MTOK (BATCH * SEQT)
#define BH (BATCH * NHEAD)

// Scratch (bf16 hi/lo pre-split operands + attention arrays)
__device__ __nv_bfloat16 g_xh[(size_t)MTOK * EMB];
__device__ __nv_bfloat16 g_xl[(size_t)MTOK * EMB];
__device__ __nv_bfloat16 g_w1h[(size_t)E3 * EMB];
__device__ __nv_bfloat16 g_w1l[(size_t)E3 * EMB];
__device__ __nv_bfloat16 g_w2h[(size_t)EMB * EMB];
__device__ __nv_bfloat16 g_w2l[(size_t)EMB * EMB];
__device__ float         g_v  [(size_t)MTOK * EMB];
__device__ __nv_bfloat16 g_aoh[(size_t)MTOK * EMB];
__device__ __nv_bfloat16 g_aol[(size_t)MTOK * EMB];
__device__ __nv_bfloat16 g_qh[(size_t)BH * SEQT * HDIM];
__device__ __nv_bfloat16 g_ql[(size_t)BH * SEQT * HDIM];
__device__ __nv_bfloat16 g_kh[(size_t)BH * SEQT * HDIM];
__device__ __nv_bfloat16 g_kl[(size_t)BH * SEQT * HDIM];
__device__ __nv_bfloat16 g_vth[(size_t)BH * HDIM * SEQT];
__device__ __nv_bfloat16 g_vtl[(size_t)BH * HDIM * SEQT];

// ---------------------------------------------------------------------------
// helpers
// ---------------------------------------------------------------------------
__device__ __forceinline__ uint32_t smem_u32(const void* p) {
    uint32_t a;
    asm("{ .reg .u64 t; cvta.to.shared.u64 t, %1; cvt.u32.u64 %0, t; }"
        : "=r"(a) : "l"(p));
    return a;
}

#define LDM4(r0, r1, r2, r3, addr) \
    asm volatile("ldmatrix.sync.aligned.m8n8.x4.shared.b16 {%0,%1,%2,%3}, [%4];" \
                 : "=r"(r0), "=r"(r1), "=r"(r2), "=r"(r3) : "r"(addr))

#define MMA16816(d, a, b0, b1) \
    asm volatile("mma.sync.aligned.m16n8k16.row.col.f32.bf16.bf16.f32 " \
                 "{%0,%1,%2,%3},{%4,%5,%6,%7},{%8,%9},{%0,%1,%2,%3};" \
                 : "+f"((d)[0]), "+f"((d)[1]), "+f"((d)[2]), "+f"((d)[3]) \
                 : "r"((a)[0]), "r"((a)[1]), "r"((a)[2]), "r"((a)[3]), \
                   "r"(b0), "r"(b1))

#define CPASYNC16(sdst, gsrc) \
    asm volatile("cp.async.cg.shared.global [%0], [%1], 16;" \
                 :: "r"(sdst), "l"(gsrc) : "memory")
#define CPCOMMIT() asm volatile("cp.async.commit_group;" ::: "memory")
#define CPWAIT0()  asm volatile("cp.async.wait_group 0;" ::: "memory")
#define CPWAIT1()  asm volatile("cp.async.wait_group 1;" ::: "memory")

__device__ __forceinline__ void split_bf16(float x, __nv_bfloat16& h, __nv_bfloat16& l) {
    h = __float2bfloat16_rn(x);
    l = __float2bfloat16_rn(x - __bfloat162float(h));
}
__device__ __forceinline__ uint32_t pack2(__nv_bfloat16 a, __nv_bfloat16 b) {
    __nv_bfloat162 t(a, b);
    return *reinterpret_cast<uint32_t*>(&t);
}

// ---------------------------------------------------------------------------
// Elementwise fp32 -> bf16 hi/lo split
// ---------------------------------------------------------------------------
__global__ __launch_bounds__(256)
void split_kernel(const float* __restrict__ src,
                  __nv_bfloat16* __restrict__ dh,
                  __nv_bfloat16* __restrict__ dl, int n4)
{
    int i = blockIdx.x * 256 + threadIdx.x;
    if (i >= n4) return;
    float4 v = reinterpret_cast<const float4*>(src)[i];
    __nv_bfloat16 h0, l0, h1, l1, h2, l2, h3, l3;
    split_bf16(v.x, h0, l0); split_bf16(v.y, h1, l1);
    split_bf16(v.z, h2, l2); split_bf16(v.w, h3, l3);
    reinterpret_cast<uint2*>(dh)[i] = make_uint2(pack2(h0, h1), pack2(h2, h3));
    reinterpret_cast<uint2*>(dl)[i] = make_uint2(pack2(l0, l1), pack2(l2, l3));
}

// ---------------------------------------------------------------------------
// bf16x3 GEMM (unchanged from round 6)
// ---------------------------------------------------------------------------
#define STG_B 32768u
#define GEMM_SMEM (3 * 32768 + 128)

template<int EPI>
__global__ __launch_bounds__(256, 2)
void gemm_pre_kernel(const __nv_bfloat16* __restrict__ Ah,
                     const __nv_bfloat16* __restrict__ Al,
                     const __nv_bfloat16* __restrict__ Bh,
                     const __nv_bfloat16* __restrict__ Bl,
                     const float* __restrict__ bias,
                     float* __restrict__ C,
                     int N, int K)
{
    extern __shared__ char dsm[];
    char* sp = dsm + ((128 - (smem_u32(dsm) & 127)) & 127);
    const uint32_t sb = smem_u32(sp);

    const int tid  = threadIdx.x;
    const int lane = tid & 31;
    const int wm   = (tid >> 5) & 3;
    const int wn   = tid >> 7;
    const int rowBase = blockIdx.y * 128;
    const int colBase = blockIdx.x * 128;

    float acc[2][8][4];
#pragma unroll
    for (int i = 0; i < 2; i++)
#pragma unroll
        for (int j = 0; j < 8; j++)
#pragma unroll
            for (int q = 0; q < 4; q++) acc[i][j][q] = 0.f;

    auto issue = [&](int it_, int stg) {
        const int kt = it_ * 32;
        const uint32_t so = sb + (uint32_t)stg * STG_B;
#pragma unroll
        for (int i = 0; i < 8; i++) {
            int g = tid + i * 256;
            int arr = g >> 9;
            int rem = g & 511;
            int row = rem >> 2, c = rem & 3;
            int cs = c ^ ((row >> 1) & 3);
            const __nv_bfloat16* src;
            if (arr == 0)      src = Ah + (size_t)(rowBase + row) * K + kt + c * 8;
            else if (arr == 1) src = Al + (size_t)(rowBase + row) * K + kt + c * 8;
            else if (arr == 2) src = Bh + (size_t)(colBase + row) * K + kt + c * 8;
            else               src = Bl + (size_t)(colBase + row) * K + kt + c * 8;
            CPASYNC16(so + (uint32_t)arr * 8192u + (uint32_t)(row * 64 + cs * 16), src);
        }
    };

    const uint32_t aRow = (uint32_t)(wm * 32 + (lane & 15));
    const uint32_t aHi  = (uint32_t)(lane >> 4);
    const uint32_t aSwz = (aRow >> 1) & 3;
    const uint32_t bRow = (uint32_t)(wn * 64 + (lane & 7) + ((lane >> 4) << 3));
    const uint32_t bHi  = (uint32_t)((lane >> 3) & 1);
    const uint32_t bSwz = (bRow >> 1) & 3;

    const int NIT = K / 32;
    issue(0, 0); CPCOMMIT();
    issue(1, 1); CPCOMMIT();

    for (int it = 0; it < NIT; ++it) {
        const int cur = it % 3;
        CPWAIT1();
        __syncthreads();
        if (it + 2 < NIT) issue(it + 2, (it + 2) % 3);
        CPCOMMIT();

        const uint32_t tb = sb + (uint32_t)cur * STG_B;
#pragma unroll
        for (int ks = 0; ks < 2; ks++) {
            uint32_t ah[2][4], al[2][4], bh[4][4], bl[4][4];
            const uint32_t caA = ((uint32_t)(ks * 2) + aHi) ^ aSwz;
            const uint32_t caB = ((uint32_t)(ks * 2) + bHi) ^ bSwz;
#pragma unroll
            for (int mi = 0; mi < 2; mi++) {
                uint32_t addr = tb + (aRow + mi * 16) * 64 + caA * 16;
                LDM4(ah[mi][0], ah[mi][1], ah[mi][2], ah[mi][3], addr);
                LDM4(al[mi][0], al[mi][1], al[mi][2], al[mi][3], addr + 8192);
            }
#pragma unroll
            for (int nt = 0; nt < 4; nt++) {
                uint32_t addr = tb + 16384u + (bRow + nt * 16) * 64 + caB * 16;
                LDM4(bh[nt][0], bh[nt][1], bh[nt][2], bh[nt][3], addr);
                LDM4(bl[nt][0], bl[nt][1], bl[nt][2], bl[nt][3], addr + 8192);
            }
#pragma unroll
            for (int mi = 0; mi < 2; mi++)
#pragma unroll
                for (int n8 = 0; n8 < 8; n8++) {
                    const int nt = n8 >> 1, hh = (n8 & 1) * 2;
                    MMA16816(acc[mi][n8], ah[mi], bh[nt][hh], bh[nt][hh + 1]);
                }
#pragma unroll
            for (int mi = 0; mi < 2; mi++)
#pragma unroll
                for (int n8 = 0; n8 < 8; n8++) {
                    const int nt = n8 >> 1, hh = (n8 & 1) * 2;
                    MMA16816(acc[mi][n8], ah[mi], bl[nt][hh], bl[nt][hh + 1]);
                }
#pragma unroll
            for (int mi = 0; mi < 2; mi++)
#pragma unroll
                for (int n8 = 0; n8 < 8; n8++) {
                    const int nt = n8 >> 1, hh = (n8 & 1) * 2;
                    MMA16816(acc[mi][n8], al[mi], bh[nt][hh], bh[nt][hh + 1]);
                }
        }
    }

    const int r0 = rowBase + wm * 32 + (lane >> 2);
    const int c0 = colBase + wn * 64 + (lane & 3) * 2;

    if (EPI == 0) {
#pragma unroll
        for (int mi = 0; mi < 2; mi++)
#pragma unroll
            for (int n8 = 0; n8 < 8; n8++) {
                const int row = r0 + mi * 16;
                const int col = c0 + n8 * 8;
                const float2 bv = *reinterpret_cast<const float2*>(bias + col);
                float2 o0 = make_float2(acc[mi][n8][0] + bv.x, acc[mi][n8][1] + bv.y);
                float2 o1 = make_float2(acc[mi][n8][2] + bv.x, acc[mi][n8][3] + bv.y);
                *reinterpret_cast<float2*>(C + (size_t)row * N + col)       = o0;
                *reinterpret_cast<float2*>(C + (size_t)(row + 8) * N + col) = o1;
            }
    } else {
        auto wr = [&](int row, int col, float x0, float x1) {
            const int sect = col >> 10;
            const int coli = col & 1023;
            const int bb = row >> 10, t = row & 1023;
            if (sect == 2) {
                *reinterpret_cast<float2*>(C + (size_t)row * 1024 + coli) =
                    make_float2(x0, x1);
            } else {
                const int hh = coli >> 6, d = coli & 63;
                const size_t idx = ((size_t)(bb * 16 + hh) * 1024 + t) * 64 + d;
                if (sect == 0) { x0 *= 0.125f; x1 *= 0.125f; }
                __nv_bfloat16 h0, l0, h1, l1;
                split_bf16(x0, h0, l0); split_bf16(x1, h1, l1);
                if (sect == 0) {
                    *reinterpret_cast<uint32_t*>(g_qh + idx) = pack2(h0, h1);
                    *reinterpret_cast<uint32_t*>(g_ql + idx) = pack2(l0, l1);
                } else {
                    *reinterpret_cast<uint32_t*>(g_kh + idx) = pack2(h0, h1);
                    *reinterpret_cast<uint32_t*>(g_kl + idx) = pack2(l0, l1);
                }
            }
        };
#pragma unroll
        for (int mi = 0; mi < 2; mi++)
#pragma unroll
            for (int n8 = 0; n8 < 8; n8++) {
                const int row = r0 + mi * 16;
                const int col = c0 + n8 * 8;
                const float2 bv = *reinterpret_cast<const float2*>(bias + col);
                wr(row,     col, acc[mi][n8][0] + bv.x, acc[mi][n8][1] + bv.y);
                wr(row + 8, col, acc[mi][n8][2] + bv.x, acc[mi][n8][3] + bv.y);
            }
    }
}

// ---------------------------------------------------------------------------
// V prepass (unchanged)
// ---------------------------------------------------------------------------
__global__ __launch_bounds__(256)
void vprep_kernel()
{
    __shared__ float vs[64][65];
    const int bh = blockIdx.y;
    const int b  = bh >> 4;
    const int h  = bh & 15;
    const int t0 = blockIdx.x * 64;
    const int tid = threadIdx.x;

    {
        const int r  = tid >> 2;
        const int dg = (tid & 3) * 16;
        const float* vp = g_v + (size_t)(b * SEQT + t0 + r) * EMB + h * HDIM + dg;
#pragma unroll
        for (int j = 0; j < 4; j++) {
            float4 t = reinterpret_cast<const float4*>(vp)[j];
            vs[r][dg + 4 * j + 0] = t.x; vs[r][dg + 4 * j + 1] = t.y;
            vs[r][dg + 4 * j + 2] = t.z; vs[r][dg + 4 * j + 3] = t.w;
        }
    }
    __syncthreads();
    {
        const int d  = tid >> 2;
        const int tg = (tid & 3) * 16;
        uint32_t hw[8], lw[8];
#pragma unroll
        for (int j = 0; j < 8; j++) {
            float x0 = vs[tg + 2 * j][d], x1 = vs[tg + 2 * j + 1][d];
            __nv_bfloat16 h0, l0, h1, l1;
            split_bf16(x0, h0, l0); split_bf16(x1, h1, l1);
            hw[j] = pack2(h0, h1); lw[j] = pack2(l0, l1);
        }
        const size_t vo = ((size_t)bh * HDIM + d) * SEQT + t0 + tg;
        *reinterpret_cast<uint4*>(g_vth + vo)     = *reinterpret_cast<uint4*>(hw);
        *reinterpret_cast<uint4*>(g_vth + vo + 8) = *reinterpret_cast<uint4*>(hw + 4);
        *reinterpret_cast<uint4*>(g_vtl + vo)     = *reinterpret_cast<uint4*>(lw);
        *reinterpret_cast<uint4*>(g_vtl + vo + 8) = *reinterpret_cast<uint4*>(lw + 4);
    }
}

// ---------------------------------------------------------------------------
// Tensorized flash attention, key-split warp layout.
// grid (8, 64), block 512 (16 warps). Warps 0-7: q rows x keys [0,32);
// warps 8-15: same q rows x keys [32,64). Cross-warp O/l combine at end.
// ---------------------------------------------------------------------------
#define AQH   0u
#define AQL   18432u
#define ABUF0 36864u
#define ABUF1 73728u
#define AMSK  110592u
#define OSCR  36864u            // O-combine scratch (reuses ABUF0 area)
#define RSCR  (36864u + 32768u) // row-sum scratch
#define ATTN_SMEM (110592 + 4096 + 128)
#define RS 144u

__global__ __launch_bounds__(512, 1)
void attn_mma_kernel(const float* __restrict__ attn_bias,
                     const unsigned char* __restrict__ kmask)
{
    extern __shared__ char dsm[];
    char* sp = dsm + ((128 - (smem_u32(dsm) & 127)) & 127);
    const uint32_t sb = smem_u32(sp);

    const int bh = blockIdx.y;
    const int b  = bh >> 4;
    const int h  = bh & 15;
    const int qbase = blockIdx.x * 128;
    const int tid  = threadIdx.x;
    const int lane = tid & 31;
    const int w    = tid >> 5;     // 0..15
    const int wq   = w & 7;        // q-row group
    const int kh2  = (w >> 3) * 32;  // key-half offset

    for (int i = tid; i < SEQT; i += 512)
        *reinterpret_cast<float*>(sp + AMSK + i * 4) =
            kmask[b * SEQT + i] ? -3.0e38f : 0.f;

    // stage Q hi/lo: 2048 16B chunks over 512 threads
#pragma unroll
    for (int i = 0; i < 4; i++) {
        int g = tid + i * 512;
        int arr = g >> 10, rem = g & 1023;
        int row = rem >> 3, cc = rem & 7;
        const __nv_bfloat16* src = (arr ? g_ql : g_qh) +
            ((size_t)bh * SEQT + qbase + row) * HDIM + cc * 8;
        uint32_t dst = sb + (arr ? AQL : AQH) + row * RS + cc * 16;
        CPASYNC16(dst, src);
    }

    auto load_kv = [&](int kb, uint32_t bufoff) {
#pragma unroll
        for (int i = 0; i < 4; i++) {
            int g = tid + i * 512;
            int arr = g >> 9, rem = g & 511;
            int row = rem >> 3, cc = rem & 7;
            const __nv_bfloat16* src;
            if (arr == 0)      src = g_kh  + ((size_t)bh * SEQT + kb + row) * HDIM + cc * 8;
            else if (arr == 1) src = g_kl  + ((size_t)bh * SEQT + kb + row) * HDIM + cc * 8;
            else if (arr == 2) src = g_vth + ((size_t)bh * HDIM + row) * SEQT + kb + cc * 8;
            else               src = g_vtl + ((size_t)bh * HDIM + row) * SEQT + kb + cc * 8;
            uint32_t dst = sb + bufoff + (uint32_t)arr * 9216u + row * RS + cc * 16;
            CPASYNC16(dst, src);
        }
    };

    load_kv(0, ABUF0);
    CPCOMMIT();
    CPWAIT0();
    __syncthreads();

    // Q-hi fragments held; Q-lo reloaded per d-group inside the loop
    const uint32_t aRow  = (uint32_t)(wq * 16 + (lane & 15));
    const uint32_t aColH = (uint32_t)((lane >> 4) * 8);
    uint32_t qfh[4][4];
#pragma unroll
    for (int kc = 0; kc < 4; kc++) {
        uint32_t addr = sb + AQH + aRow * RS + (aColH + kc * 16) * 2;
        LDM4(qfh[kc][0], qfh[kc][1], qfh[kc][2], qfh[kc][3], addr);
    }

    float oacc[8][4];
#pragma unroll
    for (int i = 0; i < 8; i++)
#pragma unroll
        for (int j = 0; j < 4; j++) oacc[i][j] = 0.f;
    float rs0 = 0.f, rs1 = 0.f;

    const uint32_t bRowB = (uint32_t)((lane & 7) + ((lane >> 4) << 3));
    const uint32_t bHi8  = (uint32_t)(((lane >> 3) & 1) * 8);
    const float* biasp = attn_bias + (size_t)bh * SEQT * SEQT +
        (size_t)(qbase + wq * 16 + (lane >> 2)) * SEQT + kh2 + (lane & 3) * 2;

    for (int it = 0; it < 16; ++it) {
        const int kb = it * 64;
        const uint32_t buf = (it & 1) ? ABUF1 : ABUF0;
        if (it + 1 < 16) {
            load_kv((it + 1) * 64, (it & 1) ? ABUF0 : ABUF1);
            CPCOMMIT();
        }
        float2 bias0[4], bias1[4];
#pragma unroll
        for (int n8 = 0; n8 < 4; n8++) {
            bias0[n8] = *reinterpret_cast<const float2*>(biasp + kb + n8 * 8);
            bias1[n8] = *reinterpret_cast<const float2*>(biasp + 8 * SEQT + kb + n8 * 8);
        }

        // S = Q K^T over this warp's 32-key half (x3, term-major)
        float sacc[4][4];
#pragma unroll
        for (int i = 0; i < 4; i++)
#pragma unroll
            for (int j = 0; j < 4; j++) sacc[i][j] = 0.f;
#pragma unroll
        for (int kc = 0; kc < 4; kc++) {
            uint32_t kfh[2][4], kfl[2][4], qfl[4];
#pragma unroll
            for (int nt = 0; nt < 2; nt++) {
                uint32_t addr = sb + buf + (kh2 + nt * 16 + bRowB) * RS + (kc * 16 + bHi8) * 2;
                LDM4(kfh[nt][0], kfh[nt][1], kfh[nt][2], kfh[nt][3], addr);
                LDM4(kfl[nt][0], kfl[nt][1], kfl[nt][2], kfl[nt][3], addr + 9216);
            }
            {
                uint32_t addr = sb + AQL + aRow * RS + (aColH + kc * 16) * 2;
                LDM4(qfl[0], qfl[1], qfl[2], qfl[3], addr);
            }
#pragma unroll
            for (int n8 = 0; n8 < 4; n8++) {
                const int nt = n8 >> 1, hh = (n8 & 1) * 2;
                MMA16816(sacc[n8], qfh[kc], kfh[nt][hh], kfh[nt][hh + 1]);
            }
#pragma unroll
            for (int n8 = 0; n8 < 4; n8++) {
                const int nt = n8 >> 1, hh = (n8 & 1) * 2;
                MMA16816(sacc[n8], qfh[kc], kfl[nt][hh], kfl[nt][hh + 1]);
            }
#pragma unroll
            for (int n8 = 0; n8 < 4; n8++) {
                const int nt = n8 >> 1, hh = (n8 & 1) * 2;
                MMA16816(sacc[n8], qfl, kfh[nt][hh], kfh[nt][hh + 1]);
            }
        }

        // softmax numerators (no max-subtraction)
        uint32_t pph[8], ppl[8];
#pragma unroll
        for (int n8 = 0; n8 < 4; n8++) {
            float2 mk = *reinterpret_cast<const float2*>(
                sp + AMSK + (kb + kh2 + n8 * 8 + (lane & 3) * 2) * 4);
            float p0 = __expf(sacc[n8][0] + bias0[n8].x + mk.x);
            float p1 = __expf(sacc[n8][1] + bias0[n8].y + mk.y);
            float p2 = __expf(sacc[n8][2] + bias1[n8].x + mk.x);
            float p3 = __expf(sacc[n8][3] + bias1[n8].y + mk.y);
            rs0 += p0 + p1;
            rs1 += p2 + p3;
            __nv_bfloat16 h0, l0, h1, l1, h2, l2, h3, l3;
            split_bf16(p0, h0, l0); split_bf16(p1, h1, l1);
            split_bf16(p2, h2, l2); split_bf16(p3, h3, l3);
            pph[n8 * 2]     = pack2(h0, h1);
            pph[n8 * 2 + 1] = pack2(h2, h3);
            ppl[n8 * 2]     = pack2(l0, l1);
            ppl[n8 * 2 + 1] = pack2(l2, l3);
        }

        // O += P V over this warp's 32-key half (x3, term-major)
#pragma unroll
        for (int kc = 0; kc < 2; kc++) {
            uint32_t pah[4] = { pph[4 * kc], pph[4 * kc + 1], pph[4 * kc + 2], pph[4 * kc + 3] };
            uint32_t pal[4] = { ppl[4 * kc], ppl[4 * kc + 1], ppl[4 * kc + 2], ppl[4 * kc + 3] };
            uint32_t vfh[4][4], vfl[4][4];
#pragma unroll
            for (int nt = 0; nt < 4; nt++) {
                uint32_t addr = sb + buf + 18432u + (bRowB + nt * 16) * RS +
                                (kh2 + kc * 16 + bHi8) * 2;
                LDM4(vfh[nt][0], vfh[nt][1], vfh[nt][2], vfh[nt][3], addr);
                LDM4(vfl[nt][0], vfl[nt][1], vfl[nt][2], vfl[nt][3], addr + 9216);
            }
#pragma unroll
            for (int n8 = 0; n8 < 8; n8++) {
                const int nt = n8 >> 1, hh = (n8 & 1) * 2;
                MMA16816(oacc[n8], pah, vfh[nt][hh], vfh[nt][hh + 1]);
            }
#pragma unroll
            for (int n8 = 0; n8 < 8; n8++) {
                const int nt = n8 >> 1, hh = (n8 & 1) * 2;
                MMA16816(oacc[n8], pah, vfl[nt][hh], vfl[nt][hh + 1]);
            }
#pragma unroll
            for (int n8 = 0; n8 < 8; n8++) {
                const int nt = n8 >> 1, hh = (n8 & 1) * 2;
                MMA16816(oacc[n8], pal, vfh[nt][hh], vfh[nt][hh + 1]);
            }
        }

        CPWAIT0();
        __syncthreads();
    }

    // quad-reduce partial row sums
    rs0 += __shfl_xor_sync(0xffffffffu, rs0, 1);
    rs0 += __shfl_xor_sync(0xffffffffu, rs0, 2);
    rs1 += __shfl_xor_sync(0xffffffffu, rs1, 1);
    rs1 += __shfl_xor_sync(0xffffffffu, rs1, 2);

    // cross-half combine: warps 8-15 park partial O + l in smem
    if (w >= 8) {
        const uint32_t ob = sb + OSCR + (uint32_t)(w - 8) * 4096u;
#pragma unroll
        for (int n8 = 0; n8 < 8; n8++) {
            float4 t = make_float4(oacc[n8][0], oacc[n8][1], oacc[n8][2], oacc[n8][3]);
            *reinterpret_cast<float4*>(dsm + (ob - smem_u32(dsm)) + n8 * 512 + lane * 16) = t;
        }
        *reinterpret_cast<float2*>(dsm + (sb + RSCR - smem_u32(dsm)) + (w - 8) * 256 + lane * 8)
            = make_float2(rs0, rs1);
    }
    __syncthreads();
    if (w < 8) {
        const uint32_t ob = sb + OSCR + (uint32_t)w * 4096u;
        float2 prs = *reinterpret_cast<float2*>(
            dsm + (sb + RSCR - smem_u32(dsm)) + w * 256 + lane * 8);
        const float inv0 = 1.f / (rs0 + prs.x);
        const float inv1 = 1.f / (rs1 + prs.y);

        const int row0 = qbase + w * 16 + (lane >> 2);
        const int col0 = h * HDIM + (lane & 3) * 2;
#pragma unroll
        for (int n8 = 0; n8 < 8; n8++) {
            float4 t = *reinterpret_cast<float4*>(
                dsm + (ob - smem_u32(dsm)) + n8 * 512 + lane * 16);
            float x0 = (oacc[n8][0] + t.x) * inv0, x1 = (oacc[n8][1] + t.y) * inv0;
            float y0 = (oacc[n8][2] + t.z) * inv1, y1 = (oacc[n8][3] + t.w) * inv1;
            __nv_bfloat16 h0, l0, h1, l1;
            size_t i0 = (size_t)(b * SEQT + row0) * EMB + col0 + n8 * 8;
            size_t i1 = (size_t)(b * SEQT + row0 + 8) * EMB + col0 + n8 * 8;
            split_bf16(x0, h0, l0); split_bf16(x1, h1, l1);
            *reinterpret_cast<uint32_t*>(g_aoh + i0) = pack2(h0, h1);
            *reinterpret_cast<uint32_t*>(g_aol + i0) = pack2(l0, l1);
            split_bf16(y0, h0, l0); split_bf16(y1, h1, l1);
            *reinterpret_cast<uint32_t*>(g_aoh + i1) = pack2(h0, h1);
            *reinterpret_cast<uint32_t*>(g_aol + i1) = pack2(l0, l1);
        }
    }
}

// ---------------------------------------------------------------------------
// Launch
// ---------------------------------------------------------------------------
extern "C" void kernel_launch(void* const* d_in, const int* in_sizes, int n_in,
                              void* d_out, int out_size)
{
    const float*         query = (const float*)d_in[0];
    const float*         abias = (const float*)d_in[1];
    const unsigned char* kmask = (const unsigned char*)d_in[2];
    const float*         in_w  = (const float*)d_in[3];
    const float*         in_b  = (const float*)d_in[4];
    const float*         out_w = (const float*)d_in[5];
    const float*         out_b = (const float*)d_in[6];
    float*               out   = (float*)d_out;

    __nv_bfloat16 *xh, *xl, *w1h, *w1l, *w2h, *w2l, *aoh, *aol;
    float* v;
    cudaGetSymbolAddress((void**)&xh,  g_xh);
    cudaGetSymbolAddress((void**)&xl,  g_xl);
    cudaGetSymbolAddress((void**)&w1h, g_w1h);
    cudaGetSymbolAddress((void**)&w1l, g_w1l);
    cudaGetSymbolAddress((void**)&w2h, g_w2h);
    cudaGetSymbolAddress((void**)&w2l, g_w2l);
    cudaGetSymbolAddress((void**)&aoh, g_aoh);
    cudaGetSymbolAddress((void**)&aol, g_aol);
    cudaGetSymbolAddress((void**)&v,   g_v);

    cudaFuncSetAttribute(gemm_pre_kernel<0>,
                         cudaFuncAttributeMaxDynamicSharedMemorySize, GEMM_SMEM);
    cudaFuncSetAttribute(gemm_pre_kernel<1>,
                         cudaFuncAttributeMaxDynamicSharedMemorySize, GEMM_SMEM);
    cudaFuncSetAttribute(attn_mma_kernel,
                         cudaFuncAttributeMaxDynamicSharedMemorySize, ATTN_SMEM);

    // 0) pre-split operands
    split_kernel<<<(MTOK * EMB / 4 + 255) / 256, 256>>>(query, xh, xl, MTOK * EMB / 4);
    split_kernel<<<(E3 * EMB / 4 + 255) / 256, 256>>>(in_w, w1h, w1l, E3 * EMB / 4);
    split_kernel<<<(EMB * EMB / 4 + 255) / 256, 256>>>(out_w, w2h, w2l, EMB * EMB / 4);

    // 1) QKV projection + fused split/scale epilogue
    {
        dim3 grid(E3 / 128, MTOK / 128);
        gemm_pre_kernel<1><<<grid, 256, GEMM_SMEM>>>(xh, xl, w1h, w1l, in_b, v, E3, EMB);
    }
    // 2) V transpose/split
    {
        dim3 grid(SEQT / 64, BH);
        vprep_kernel<<<grid, 256>>>();
    }
    // 3) Attention (512 threads, key-split warps)
    {
        dim3 grid(SEQT / 128, BH);
        attn_mma_kernel<<<grid, 512, ATTN_SMEM>>>(abias, kmask);
    }
    // 4) Output projection
    {
        dim3 grid(EMB / 128, MTOK / 128);
        gemm_pre_kernel<0><<<grid, 256, GEMM_SMEM>>>(aoh, aol, w2h, w2l, out_b, out, EMB, EMB);
    }
}

// round 8
// speedup vs baseline: 3.3402x; 1.0351x over previous
#include <cuda_runtime.h>
#include <cuda_bf16.h>
#include <cuda_fp16.h>
#include <cstdint>
#include <math.h>

#define BATCH 4
#define SEQT 1024
#define EMB 1024
#define NHEAD 16
#define HDIM 64
#define E3 (3 * EMB)
#define MTOK (BATCH * SEQT)
#define BH (BATCH * NHEAD)

// Scratch
__device__ __nv_bfloat16 g_xh[(size_t)MTOK * EMB];
__device__ __nv_bfloat16 g_xl[(size_t)MTOK * EMB];
__device__ __nv_bfloat16 g_w1h[(size_t)E3 * EMB];
__device__ __nv_bfloat16 g_w1l[(size_t)E3 * EMB];
__device__ __nv_bfloat16 g_w2h[(size_t)EMB * EMB];
__device__ __nv_bfloat16 g_w2l[(size_t)EMB * EMB];
__device__ float         g_v  [(size_t)MTOK * EMB];
__device__ __nv_bfloat16 g_aoh[(size_t)MTOK * EMB];
__device__ __nv_bfloat16 g_aol[(size_t)MTOK * EMB];
__device__ __nv_bfloat16 g_qh[(size_t)BH * SEQT * HDIM];
__device__ __nv_bfloat16 g_ql[(size_t)BH * SEQT * HDIM];
__device__ __nv_bfloat16 g_kh[(size_t)BH * SEQT * HDIM];
__device__ __nv_bfloat16 g_kl[(size_t)BH * SEQT * HDIM];
__device__ __half        g_vth[(size_t)BH * HDIM * SEQT];  // V^T fp16 hi
__device__ __half        g_vtl[(size_t)BH * HDIM * SEQT];  // V^T fp16 lo

// ---------------------------------------------------------------------------
// helpers
// ---------------------------------------------------------------------------
__device__ __forceinline__ uint32_t smem_u32(const void* p) {
    uint32_t a;
    asm("{ .reg .u64 t; cvta.to.shared.u64 t, %1; cvt.u32.u64 %0, t; }"
        : "=r"(a) : "l"(p));
    return a;
}

#define LDM4(r0, r1, r2, r3, addr) \
    asm volatile("ldmatrix.sync.aligned.m8n8.x4.shared.b16 {%0,%1,%2,%3}, [%4];" \
                 : "=r"(r0), "=r"(r1), "=r"(r2), "=r"(r3) : "r"(addr))

#define MMA16816(d, a, b0, b1) \
    asm volatile("mma.sync.aligned.m16n8k16.row.col.f32.bf16.bf16.f32 " \
                 "{%0,%1,%2,%3},{%4,%5,%6,%7},{%8,%9},{%0,%1,%2,%3};" \
                 : "+f"((d)[0]), "+f"((d)[1]), "+f"((d)[2]), "+f"((d)[3]) \
                 : "r"((a)[0]), "r"((a)[1]), "r"((a)[2]), "r"((a)[3]), \
                   "r"(b0), "r"(b1))

#define MMAF16(d, a, b0, b1) \
    asm volatile("mma.sync.aligned.m16n8k16.row.col.f32.f16.f16.f32 " \
                 "{%0,%1,%2,%3},{%4,%5,%6,%7},{%8,%9},{%0,%1,%2,%3};" \
                 : "+f"((d)[0]), "+f"((d)[1]), "+f"((d)[2]), "+f"((d)[3]) \
                 : "r"((a)[0]), "r"((a)[1]), "r"((a)[2]), "r"((a)[3]), \
                   "r"(b0), "r"(b1))

#define CPASYNC16(sdst, gsrc) \
    asm volatile("cp.async.cg.shared.global [%0], [%1], 16;" \
                 :: "r"(sdst), "l"(gsrc) : "memory")
#define CPCOMMIT() asm volatile("cp.async.commit_group;" ::: "memory")
#define CPWAIT0()  asm volatile("cp.async.wait_group 0;" ::: "memory")
#define CPWAIT1()  asm volatile("cp.async.wait_group 1;" ::: "memory")

__device__ __forceinline__ void split_bf16(float x, __nv_bfloat16& h, __nv_bfloat16& l) {
    h = __float2bfloat16_rn(x);
    l = __float2bfloat16_rn(x - __bfloat162float(h));
}
__device__ __forceinline__ uint32_t pack2(__nv_bfloat16 a, __nv_bfloat16 b) {
    __nv_bfloat162 t(a, b);
    return *reinterpret_cast<uint32_t*>(&t);
}
__device__ __forceinline__ void split_fp16(float x, __half& h, __half& l) {
    h = __float2half_rn(x);
    l = __float2half_rn(x - __half2float(h));
}
__device__ __forceinline__ uint32_t pack2h(__half a, __half b) {
    __half2 t(a, b);
    return *reinterpret_cast<uint32_t*>(&t);
}

// ---------------------------------------------------------------------------
// Elementwise fp32 -> bf16 hi/lo split
// ---------------------------------------------------------------------------
__global__ __launch_bounds__(256)
void split_kernel(const float* __restrict__ src,
                  __nv_bfloat16* __restrict__ dh,
                  __nv_bfloat16* __restrict__ dl, int n4)
{
    int i = blockIdx.x * 256 + threadIdx.x;
    if (i >= n4) return;
    float4 v = reinterpret_cast<const float4*>(src)[i];
    __nv_bfloat16 h0, l0, h1, l1, h2, l2, h3, l3;
    split_bf16(v.x, h0, l0); split_bf16(v.y, h1, l1);
    split_bf16(v.z, h2, l2); split_bf16(v.w, h3, l3);
    reinterpret_cast<uint2*>(dh)[i] = make_uint2(pack2(h0, h1), pack2(h2, h3));
    reinterpret_cast<uint2*>(dl)[i] = make_uint2(pack2(l0, l1), pack2(l2, l3));
}

// ---------------------------------------------------------------------------
// bf16x3 GEMM (unchanged from round 6/7)
// ---------------------------------------------------------------------------
#define STG_B 32768u
#define GEMM_SMEM (3 * 32768 + 128)

template<int EPI>
__global__ __launch_bounds__(256, 2)
void gemm_pre_kernel(const __nv_bfloat16* __restrict__ Ah,
                     const __nv_bfloat16* __restrict__ Al,
                     const __nv_bfloat16* __restrict__ Bh,
                     const __nv_bfloat16* __restrict__ Bl,
                     const float* __restrict__ bias,
                     float* __restrict__ C,
                     int N, int K)
{
    extern __shared__ char dsm[];
    char* sp = dsm + ((128 - (smem_u32(dsm) & 127)) & 127);
    const uint32_t sb = smem_u32(sp);

    const int tid  = threadIdx.x;
    const int lane = tid & 31;
    const int wm   = (tid >> 5) & 3;
    const int wn   = tid >> 7;
    const int rowBase = blockIdx.y * 128;
    const int colBase = blockIdx.x * 128;

    float acc[2][8][4];
#pragma unroll
    for (int i = 0; i < 2; i++)
#pragma unroll
        for (int j = 0; j < 8; j++)
#pragma unroll
            for (int q = 0; q < 4; q++) acc[i][j][q] = 0.f;

    auto issue = [&](int it_, int stg) {
        const int kt = it_ * 32;
        const uint32_t so = sb + (uint32_t)stg * STG_B;
#pragma unroll
        for (int i = 0; i < 8; i++) {
            int g = tid + i * 256;
            int arr = g >> 9;
            int rem = g & 511;
            int row = rem >> 2, c = rem & 3;
            int cs = c ^ ((row >> 1) & 3);
            const __nv_bfloat16* src;
            if (arr == 0)      src = Ah + (size_t)(rowBase + row) * K + kt + c * 8;
            else if (arr == 1) src = Al + (size_t)(rowBase + row) * K + kt + c * 8;
            else if (arr == 2) src = Bh + (size_t)(colBase + row) * K + kt + c * 8;
            else               src = Bl + (size_t)(colBase + row) * K + kt + c * 8;
            CPASYNC16(so + (uint32_t)arr * 8192u + (uint32_t)(row * 64 + cs * 16), src);
        }
    };

    const uint32_t aRow = (uint32_t)(wm * 32 + (lane & 15));
    const uint32_t aHi  = (uint32_t)(lane >> 4);
    const uint32_t aSwz = (aRow >> 1) & 3;
    const uint32_t bRow = (uint32_t)(wn * 64 + (lane & 7) + ((lane >> 4) << 3));
    const uint32_t bHi  = (uint32_t)((lane >> 3) & 1);
    const uint32_t bSwz = (bRow >> 1) & 3;

    const int NIT = K / 32;
    issue(0, 0); CPCOMMIT();
    issue(1, 1); CPCOMMIT();

    for (int it = 0; it < NIT; ++it) {
        const int cur = it % 3;
        CPWAIT1();
        __syncthreads();
        if (it + 2 < NIT) issue(it + 2, (it + 2) % 3);
        CPCOMMIT();

        const uint32_t tb = sb + (uint32_t)cur * STG_B;
#pragma unroll
        for (int ks = 0; ks < 2; ks++) {
            uint32_t ah[2][4], al[2][4], bh[4][4], bl[4][4];
            const uint32_t caA = ((uint32_t)(ks * 2) + aHi) ^ aSwz;
            const uint32_t caB = ((uint32_t)(ks * 2) + bHi) ^ bSwz;
#pragma unroll
            for (int mi = 0; mi < 2; mi++) {
                uint32_t addr = tb + (aRow + mi * 16) * 64 + caA * 16;
                LDM4(ah[mi][0], ah[mi][1], ah[mi][2], ah[mi][3], addr);
                LDM4(al[mi][0], al[mi][1], al[mi][2], al[mi][3], addr + 8192);
            }
#pragma unroll
            for (int nt = 0; nt < 4; nt++) {
                uint32_t addr = tb + 16384u + (bRow + nt * 16) * 64 + caB * 16;
                LDM4(bh[nt][0], bh[nt][1], bh[nt][2], bh[nt][3], addr);
                LDM4(bl[nt][0], bl[nt][1], bl[nt][2], bl[nt][3], addr + 8192);
            }
#pragma unroll
            for (int mi = 0; mi < 2; mi++)
#pragma unroll
                for (int n8 = 0; n8 < 8; n8++) {
                    const int nt = n8 >> 1, hh = (n8 & 1) * 2;
                    MMA16816(acc[mi][n8], ah[mi], bh[nt][hh], bh[nt][hh + 1]);
                }
#pragma unroll
            for (int mi = 0; mi < 2; mi++)
#pragma unroll
                for (int n8 = 0; n8 < 8; n8++) {
                    const int nt = n8 >> 1, hh = (n8 & 1) * 2;
                    MMA16816(acc[mi][n8], ah[mi], bl[nt][hh], bl[nt][hh + 1]);
                }
#pragma unroll
            for (int mi = 0; mi < 2; mi++)
#pragma unroll
                for (int n8 = 0; n8 < 8; n8++) {
                    const int nt = n8 >> 1, hh = (n8 & 1) * 2;
                    MMA16816(acc[mi][n8], al[mi], bh[nt][hh], bh[nt][hh + 1]);
                }
        }
    }

    const int r0 = rowBase + wm * 32 + (lane >> 2);
    const int c0 = colBase + wn * 64 + (lane & 3) * 2;

    if (EPI == 0) {
#pragma unroll
        for (int mi = 0; mi < 2; mi++)
#pragma unroll
            for (int n8 = 0; n8 < 8; n8++) {
                const int row = r0 + mi * 16;
                const int col = c0 + n8 * 8;
                const float2 bv = *reinterpret_cast<const float2*>(bias + col);
                float2 o0 = make_float2(acc[mi][n8][0] + bv.x, acc[mi][n8][1] + bv.y);
                float2 o1 = make_float2(acc[mi][n8][2] + bv.x, acc[mi][n8][3] + bv.y);
                *reinterpret_cast<float2*>(C + (size_t)row * N + col)       = o0;
                *reinterpret_cast<float2*>(C + (size_t)(row + 8) * N + col) = o1;
            }
    } else {
        auto wr = [&](int row, int col, float x0, float x1) {
            const int sect = col >> 10;
            const int coli = col & 1023;
            const int bb = row >> 10, t = row & 1023;
            if (sect == 2) {
                *reinterpret_cast<float2*>(C + (size_t)row * 1024 + coli) =
                    make_float2(x0, x1);
            } else {
                const int hh = coli >> 6, d = coli & 63;
                const size_t idx = ((size_t)(bb * 16 + hh) * 1024 + t) * 64 + d;
                if (sect == 0) { x0 *= 0.125f; x1 *= 0.125f; }
                __nv_bfloat16 h0, l0, h1, l1;
                split_bf16(x0, h0, l0); split_bf16(x1, h1, l1);
                if (sect == 0) {
                    *reinterpret_cast<uint32_t*>(g_qh + idx) = pack2(h0, h1);
                    *reinterpret_cast<uint32_t*>(g_ql + idx) = pack2(l0, l1);
                } else {
                    *reinterpret_cast<uint32_t*>(g_kh + idx) = pack2(h0, h1);
                    *reinterpret_cast<uint32_t*>(g_kl + idx) = pack2(l0, l1);
                }
            }
        };
#pragma unroll
        for (int mi = 0; mi < 2; mi++)
#pragma unroll
            for (int n8 = 0; n8 < 8; n8++) {
                const int row = r0 + mi * 16;
                const int col = c0 + n8 * 8;
                const float2 bv = *reinterpret_cast<const float2*>(bias + col);
                wr(row,     col, acc[mi][n8][0] + bv.x, acc[mi][n8][1] + bv.y);
                wr(row + 8, col, acc[mi][n8][2] + bv.x, acc[mi][n8][3] + bv.y);
            }
    }
}

// ---------------------------------------------------------------------------
// V prepass: g_v fp32 -> transposed fp16 hi/lo [bh][d][t]
// ---------------------------------------------------------------------------
__global__ __launch_bounds__(256)
void vprep_kernel()
{
    __shared__ float vs[64][65];
    const int bh = blockIdx.y;
    const int b  = bh >> 4;
    const int h  = bh & 15;
    const int t0 = blockIdx.x * 64;
    const int tid = threadIdx.x;

    {
        const int r  = tid >> 2;
        const int dg = (tid & 3) * 16;
        const float* vp = g_v + (size_t)(b * SEQT + t0 + r) * EMB + h * HDIM + dg;
#pragma unroll
        for (int j = 0; j < 4; j++) {
            float4 t = reinterpret_cast<const float4*>(vp)[j];
            vs[r][dg + 4 * j + 0] = t.x; vs[r][dg + 4 * j + 1] = t.y;
            vs[r][dg + 4 * j + 2] = t.z; vs[r][dg + 4 * j + 3] = t.w;
        }
    }
    __syncthreads();
    {
        const int d  = tid >> 2;
        const int tg = (tid & 3) * 16;
        uint32_t hw[8], lw[8];
#pragma unroll
        for (int j = 0; j < 8; j++) {
            float x0 = vs[tg + 2 * j][d], x1 = vs[tg + 2 * j + 1][d];
            __half h0, l0, h1, l1;
            split_fp16(x0, h0, l0); split_fp16(x1, h1, l1);
            hw[j] = pack2h(h0, h1); lw[j] = pack2h(l0, l1);
        }
        const size_t vo = ((size_t)bh * HDIM + d) * SEQT + t0 + tg;
        *reinterpret_cast<uint4*>(g_vth + vo)     = *reinterpret_cast<uint4*>(hw);
        *reinterpret_cast<uint4*>(g_vth + vo + 8) = *reinterpret_cast<uint4*>(hw + 4);
        *reinterpret_cast<uint4*>(g_vtl + vo)     = *reinterpret_cast<uint4*>(lw);
        *reinterpret_cast<uint4*>(g_vtl + vo + 8) = *reinterpret_cast<uint4*>(lw + 4);
    }
}

// ---------------------------------------------------------------------------
// Tensorized flash attention, key-split warps; S = bf16 x3, PV = fp16 x2.
// exp argument shifted by -10 (global constant; cancels in O/l) to keep
// p within fp16 range. grid (8, 64), block 512.
// ---------------------------------------------------------------------------
#define AQH   0u
#define AQL   18432u
#define ABUF0 36864u
#define ABUF1 73728u
#define AMSK  110592u
#define OSCR  36864u
#define RSCR  (36864u + 32768u)
#define ATTN_SMEM (110592 + 4096 + 128)
#define RS 144u
#define EXPSHIFT 10.0f

__global__ __launch_bounds__(512, 1)
void attn_mma_kernel(const float* __restrict__ attn_bias,
                     const unsigned char* __restrict__ kmask)
{
    extern __shared__ char dsm[];
    char* sp = dsm + ((128 - (smem_u32(dsm) & 127)) & 127);
    const uint32_t sb = smem_u32(sp);

    const int bh = blockIdx.y;
    const int b  = bh >> 4;
    const int h  = bh & 15;
    const int qbase = blockIdx.x * 128;
    const int tid  = threadIdx.x;
    const int lane = tid & 31;
    const int w    = tid >> 5;
    const int wq   = w & 7;
    const int kh2  = (w >> 3) * 32;

    for (int i = tid; i < SEQT; i += 512)
        *reinterpret_cast<float*>(sp + AMSK + i * 4) =
            kmask[b * SEQT + i] ? -3.0e38f : 0.f;

#pragma unroll
    for (int i = 0; i < 4; i++) {
        int g = tid + i * 512;
        int arr = g >> 10, rem = g & 1023;
        int row = rem >> 3, cc = rem & 7;
        const __nv_bfloat16* src = (arr ? g_ql : g_qh) +
            ((size_t)bh * SEQT + qbase + row) * HDIM + cc * 8;
        uint32_t dst = sb + (arr ? AQL : AQH) + row * RS + cc * 16;
        CPASYNC16(dst, src);
    }

    auto load_kv = [&](int kb, uint32_t bufoff) {
#pragma unroll
        for (int i = 0; i < 4; i++) {
            int g = tid + i * 512;
            int arr = g >> 9, rem = g & 511;
            int row = rem >> 3, cc = rem & 7;
            const void* src;
            if (arr == 0)      src = g_kh  + ((size_t)bh * SEQT + kb + row) * HDIM + cc * 8;
            else if (arr == 1) src = g_kl  + ((size_t)bh * SEQT + kb + row) * HDIM + cc * 8;
            else if (arr == 2) src = g_vth + ((size_t)bh * HDIM + row) * SEQT + kb + cc * 8;
            else               src = g_vtl + ((size_t)bh * HDIM + row) * SEQT + kb + cc * 8;
            uint32_t dst = sb + bufoff + (uint32_t)arr * 9216u + row * RS + cc * 16;
            CPASYNC16(dst, src);
        }
    };

    load_kv(0, ABUF0);
    CPCOMMIT();
    CPWAIT0();
    __syncthreads();

    const uint32_t aRow  = (uint32_t)(wq * 16 + (lane & 15));
    const uint32_t aColH = (uint32_t)((lane >> 4) * 8);
    uint32_t qfh[4][4];
#pragma unroll
    for (int kc = 0; kc < 4; kc++) {
        uint32_t addr = sb + AQH + aRow * RS + (aColH + kc * 16) * 2;
        LDM4(qfh[kc][0], qfh[kc][1], qfh[kc][2], qfh[kc][3], addr);
    }

    float oacc[8][4];
#pragma unroll
    for (int i = 0; i < 8; i++)
#pragma unroll
        for (int j = 0; j < 4; j++) oacc[i][j] = 0.f;
    float rs0 = 0.f, rs1 = 0.f;

    const uint32_t bRowB = (uint32_t)((lane & 7) + ((lane >> 4) << 3));
    const uint32_t bHi8  = (uint32_t)(((lane >> 3) & 1) * 8);
    const float* biasp = attn_bias + (size_t)bh * SEQT * SEQT +
        (size_t)(qbase + wq * 16 + (lane >> 2)) * SEQT + kh2 + (lane & 3) * 2;

    for (int it = 0; it < 16; ++it) {
        const int kb = it * 64;
        const uint32_t buf = (it & 1) ? ABUF1 : ABUF0;
        if (it + 1 < 16) {
            load_kv((it + 1) * 64, (it & 1) ? ABUF0 : ABUF1);
            CPCOMMIT();
        }
        float2 bias0[4], bias1[4];
#pragma unroll
        for (int n8 = 0; n8 < 4; n8++) {
            bias0[n8] = *reinterpret_cast<const float2*>(biasp + kb + n8 * 8);
            bias1[n8] = *reinterpret_cast<const float2*>(biasp + 8 * SEQT + kb + n8 * 8);
        }

        // S = Q K^T over this warp's 32-key half (bf16 x3, term-major)
        float sacc[4][4];
#pragma unroll
        for (int i = 0; i < 4; i++)
#pragma unroll
            for (int j = 0; j < 4; j++) sacc[i][j] = 0.f;
#pragma unroll
        for (int kc = 0; kc < 4; kc++) {
            uint32_t kfh[2][4], kfl[2][4], qfl[4];
#pragma unroll
            for (int nt = 0; nt < 2; nt++) {
                uint32_t addr = sb + buf + (kh2 + nt * 16 + bRowB) * RS + (kc * 16 + bHi8) * 2;
                LDM4(kfh[nt][0], kfh[nt][1], kfh[nt][2], kfh[nt][3], addr);
                LDM4(kfl[nt][0], kfl[nt][1], kfl[nt][2], kfl[nt][3], addr + 9216);
            }
            {
                uint32_t addr = sb + AQL + aRow * RS + (aColH + kc * 16) * 2;
                LDM4(qfl[0], qfl[1], qfl[2], qfl[3], addr);
            }
#pragma unroll
            for (int n8 = 0; n8 < 4; n8++) {
                const int nt = n8 >> 1, hh = (n8 & 1) * 2;
                MMA16816(sacc[n8], qfh[kc], kfh[nt][hh], kfh[nt][hh + 1]);
            }
#pragma unroll
            for (int n8 = 0; n8 < 4; n8++) {
                const int nt = n8 >> 1, hh = (n8 & 1) * 2;
                MMA16816(sacc[n8], qfh[kc], kfl[nt][hh], kfl[nt][hh + 1]);
            }
#pragma unroll
            for (int n8 = 0; n8 < 4; n8++) {
                const int nt = n8 >> 1, hh = (n8 & 1) * 2;
                MMA16816(sacc[n8], qfl, kfh[nt][hh], kfh[nt][hh + 1]);
            }
        }

        // softmax numerators, shifted by -EXPSHIFT (cancels in O/l); P -> fp16
        uint32_t pph[8];
#pragma unroll
        for (int n8 = 0; n8 < 4; n8++) {
            float2 mk = *reinterpret_cast<const float2*>(
                sp + AMSK + (kb + kh2 + n8 * 8 + (lane & 3) * 2) * 4);
            float p0 = __expf(sacc[n8][0] + bias0[n8].x + mk.x - EXPSHIFT);
            float p1 = __expf(sacc[n8][1] + bias0[n8].y + mk.y - EXPSHIFT);
            float p2 = __expf(sacc[n8][2] + bias1[n8].x + mk.x - EXPSHIFT);
            float p3 = __expf(sacc[n8][3] + bias1[n8].y + mk.y - EXPSHIFT);
            rs0 += p0 + p1;
            rs1 += p2 + p3;
            __half2 a = __floats2half2_rn(p0, p1);
            __half2 bq = __floats2half2_rn(p2, p3);
            pph[n8 * 2]     = *reinterpret_cast<uint32_t*>(&a);
            pph[n8 * 2 + 1] = *reinterpret_cast<uint32_t*>(&bq);
        }

        // O += P V over this warp's 32-key half (fp16 x2: Ph*Vh + Ph*Vl)
#pragma unroll
        for (int kc = 0; kc < 2; kc++) {
            uint32_t pah[4] = { pph[4 * kc], pph[4 * kc + 1], pph[4 * kc + 2], pph[4 * kc + 3] };
            uint32_t vfh[4][4], vfl[4][4];
#pragma unroll
            for (int nt = 0; nt < 4; nt++) {
                uint32_t addr = sb + buf + 18432u + (bRowB + nt * 16) * RS +
                                (kh2 + kc * 16 + bHi8) * 2;
                LDM4(vfh[nt][0], vfh[nt][1], vfh[nt][2], vfh[nt][3], addr);
                LDM4(vfl[nt][0], vfl[nt][1], vfl[nt][2], vfl[nt][3], addr + 9216);
            }
#pragma unroll
            for (int n8 = 0; n8 < 8; n8++) {
                const int nt = n8 >> 1, hh = (n8 & 1) * 2;
                MMAF16(oacc[n8], pah, vfh[nt][hh], vfh[nt][hh + 1]);
            }
#pragma unroll
            for (int n8 = 0; n8 < 8; n8++) {
                const int nt = n8 >> 1, hh = (n8 & 1) * 2;
                MMAF16(oacc[n8], pah, vfl[nt][hh], vfl[nt][hh + 1]);
            }
        }

        CPWAIT0();
        __syncthreads();
    }

    rs0 += __shfl_xor_sync(0xffffffffu, rs0, 1);
    rs0 += __shfl_xor_sync(0xffffffffu, rs0, 2);
    rs1 += __shfl_xor_sync(0xffffffffu, rs1, 1);
    rs1 += __shfl_xor_sync(0xffffffffu, rs1, 2);

    if (w >= 8) {
        const uint32_t ob = sb + OSCR + (uint32_t)(w - 8) * 4096u;
#pragma unroll
        for (int n8 = 0; n8 < 8; n8++) {
            float4 t = make_float4(oacc[n8][0], oacc[n8][1], oacc[n8][2], oacc[n8][3]);
            *reinterpret_cast<float4*>(dsm + (ob - smem_u32(dsm)) + n8 * 512 + lane * 16) = t;
        }
        *reinterpret_cast<float2*>(dsm + (sb + RSCR - smem_u32(dsm)) + (w - 8) * 256 + lane * 8)
            = make_float2(rs0, rs1);
    }
    __syncthreads();
    if (w < 8) {
        const uint32_t ob = sb + OSCR + (uint32_t)w * 4096u;
        float2 prs = *reinterpret_cast<float2*>(
            dsm + (sb + RSCR - smem_u32(dsm)) + w * 256 + lane * 8);
        const float inv0 = 1.f / (rs0 + prs.x);
        const float inv1 = 1.f / (rs1 + prs.y);

        const int row0 = qbase + w * 16 + (lane >> 2);
        const int col0 = h * HDIM + (lane & 3) * 2;
#pragma unroll
        for (int n8 = 0; n8 < 8; n8++) {
            float4 t = *reinterpret_cast<float4*>(
                dsm + (ob - smem_u32(dsm)) + n8 * 512 + lane * 16);
            float x0 = (oacc[n8][0] + t.x) * inv0, x1 = (oacc[n8][1] + t.y) * inv0;
            float y0 = (oacc[n8][2] + t.z) * inv1, y1 = (oacc[n8][3] + t.w) * inv1;
            __nv_bfloat16 h0, l0, h1, l1;
            size_t i0 = (size_t)(b * SEQT + row0) * EMB + col0 + n8 * 8;
            size_t i1 = (size_t)(b * SEQT + row0 + 8) * EMB + col0 + n8 * 8;
            split_bf16(x0, h0, l0); split_bf16(x1, h1, l1);
            *reinterpret_cast<uint32_t*>(g_aoh + i0) = pack2(h0, h1);
            *reinterpret_cast<uint32_t*>(g_aol + i0) = pack2(l0, l1);
            split_bf16(y0, h0, l0); split_bf16(y1, h1, l1);
            *reinterpret_cast<uint32_t*>(g_aoh + i1) = pack2(h0, h1);
            *reinterpret_cast<uint32_t*>(g_aol + i1) = pack2(l0, l1);
        }
    }
}

// ---------------------------------------------------------------------------
// Launch
// ---------------------------------------------------------------------------
extern "C" void kernel_launch(void* const* d_in, const int* in_sizes, int n_in,
                              void* d_out, int out_size)
{
    const float*         query = (const float*)d_in[0];
    const float*         abias = (const float*)d_in[1];
    const unsigned char* kmask = (const unsigned char*)d_in[2];
    const float*         in_w  = (const float*)d_in[3];
    const float*         in_b  = (const float*)d_in[4];
    const float*         out_w = (const float*)d_in[5];
    const float*         out_b = (const float*)d_in[6];
    float*               out   = (float*)d_out;

    __nv_bfloat16 *xh, *xl, *w1h, *w1l, *w2h, *w2l, *aoh, *aol;
    float* v;
    cudaGetSymbolAddress((void**)&xh,  g_xh);
    cudaGetSymbolAddress((void**)&xl,  g_xl);
    cudaGetSymbolAddress((void**)&w1h, g_w1h);
    cudaGetSymbolAddress((void**)&w1l, g_w1l);
    cudaGetSymbolAddress((void**)&w2h, g_w2h);
    cudaGetSymbolAddress((void**)&w2l, g_w2l);
    cudaGetSymbolAddress((void**)&aoh, g_aoh);
    cudaGetSymbolAddress((void**)&aol, g_aol);
    cudaGetSymbolAddress((void**)&v,   g_v);

    cudaFuncSetAttribute(gemm_pre_kernel<0>,
                         cudaFuncAttributeMaxDynamicSharedMemorySize, GEMM_SMEM);
    cudaFuncSetAttribute(gemm_pre_kernel<1>,
                         cudaFuncAttributeMaxDynamicSharedMemorySize, GEMM_SMEM);
    cudaFuncSetAttribute(attn_mma_kernel,
                         cudaFuncAttributeMaxDynamicSharedMemorySize, ATTN_SMEM);

    // 0) pre-split operands
    split_kernel<<<(MTOK * EMB / 4 + 255) / 256, 256>>>(query, xh, xl, MTOK * EMB / 4);
    split_kernel<<<(E3 * EMB / 4 + 255) / 256, 256>>>(in_w, w1h, w1l, E3 * EMB / 4);
    split_kernel<<<(EMB * EMB / 4 + 255) / 256, 256>>>(out_w, w2h, w2l, EMB * EMB / 4);

    // 1) QKV projection + fused split/scale epilogue
    {
        dim3 grid(E3 / 128, MTOK / 128);
        gemm_pre_kernel<1><<<grid, 256, GEMM_SMEM>>>(xh, xl, w1h, w1l, in_b, v, E3, EMB);
    }
    // 2) V transpose/split (fp16)
    {
        dim3 grid(SEQT / 64, BH);
        vprep_kernel<<<grid, 256>>>();
    }
    // 3) Attention
    {
        dim3 grid(SEQT / 128, BH);
        attn_mma_kernel<<<grid, 512, ATTN_SMEM>>>(abias, kmask);
    }
    // 4) Output projection
    {
        dim3 grid(EMB / 128, MTOK / 128);
        gemm_pre_kernel<0><<<grid, 256, GEMM_SMEM>>>(aoh, aol, w2h, w2l, out_b, out, EMB, EMB);
    }
}

// round 9
// speedup vs baseline: 3.3450x; 1.0014x over previous
#include <cuda_runtime.h>
#include <cuda_bf16.h>
#include <cuda_fp16.h>
#include <cstdint>
#include <math.h>

#define BATCH 4
#define SEQT 1024
#define EMB 1024
#define NHEAD 16
#define HDIM 64
#define E3 (3 * EMB)
#define MTOK (BATCH * SEQT)
#define BH (BATCH * NHEAD)

// Scratch
__device__ __nv_bfloat16 g_xh[(size_t)MTOK * EMB];
__device__ __nv_bfloat16 g_xl[(size_t)MTOK * EMB];
__device__ __nv_bfloat16 g_w1h[(size_t)E3 * EMB];
__device__ __nv_bfloat16 g_w1l[(size_t)E3 * EMB];
__device__ __nv_bfloat16 g_w2h[(size_t)EMB * EMB];
__device__ __nv_bfloat16 g_w2l[(size_t)EMB * EMB];
__device__ float         g_v  [(size_t)MTOK * EMB];
__device__ __nv_bfloat16 g_aoh[(size_t)MTOK * EMB];
__device__ __nv_bfloat16 g_aol[(size_t)MTOK * EMB];
__device__ __half        g_qf [(size_t)BH * SEQT * HDIM];  // Q fp16 (scaled)
__device__ __half        g_kh [(size_t)BH * SEQT * HDIM];  // K fp16 hi
__device__ __half        g_kl [(size_t)BH * SEQT * HDIM];  // K fp16 lo
__device__ __half        g_vth[(size_t)BH * HDIM * SEQT];  // V^T fp16 hi
__device__ __half        g_vtl[(size_t)BH * HDIM * SEQT];  // V^T fp16 lo

// ---------------------------------------------------------------------------
// helpers
// ---------------------------------------------------------------------------
__device__ __forceinline__ uint32_t smem_u32(const void* p) {
    uint32_t a;
    asm("{ .reg .u64 t; cvta.to.shared.u64 t, %1; cvt.u32.u64 %0, t; }"
        : "=r"(a) : "l"(p));
    return a;
}

#define LDM4(r0, r1, r2, r3, addr) \
    asm volatile("ldmatrix.sync.aligned.m8n8.x4.shared.b16 {%0,%1,%2,%3}, [%4];" \
                 : "=r"(r0), "=r"(r1), "=r"(r2), "=r"(r3) : "r"(addr))

#define MMA16816(d, a, b0, b1) \
    asm volatile("mma.sync.aligned.m16n8k16.row.col.f32.bf16.bf16.f32 " \
                 "{%0,%1,%2,%3},{%4,%5,%6,%7},{%8,%9},{%0,%1,%2,%3};" \
                 : "+f"((d)[0]), "+f"((d)[1]), "+f"((d)[2]), "+f"((d)[3]) \
                 : "r"((a)[0]), "r"((a)[1]), "r"((a)[2]), "r"((a)[3]), \
                   "r"(b0), "r"(b1))

#define MMAF16(d, a, b0, b1) \
    asm volatile("mma.sync.aligned.m16n8k16.row.col.f32.f16.f16.f32 " \
                 "{%0,%1,%2,%3},{%4,%5,%6,%7},{%8,%9},{%0,%1,%2,%3};" \
                 : "+f"((d)[0]), "+f"((d)[1]), "+f"((d)[2]), "+f"((d)[3]) \
                 : "r"((a)[0]), "r"((a)[1]), "r"((a)[2]), "r"((a)[3]), \
                   "r"(b0), "r"(b1))

#define CPASYNC16(sdst, gsrc) \
    asm volatile("cp.async.cg.shared.global [%0], [%1], 16;" \
                 :: "r"(sdst), "l"(gsrc) : "memory")
#define CPCOMMIT() asm volatile("cp.async.commit_group;" ::: "memory")
#define CPWAIT0()  asm volatile("cp.async.wait_group 0;" ::: "memory")
#define CPWAIT1()  asm volatile("cp.async.wait_group 1;" ::: "memory")

__device__ __forceinline__ void split_bf16(float x, __nv_bfloat16& h, __nv_bfloat16& l) {
    h = __float2bfloat16_rn(x);
    l = __float2bfloat16_rn(x - __bfloat162float(h));
}
__device__ __forceinline__ uint32_t pack2(__nv_bfloat16 a, __nv_bfloat16 b) {
    __nv_bfloat162 t(a, b);
    return *reinterpret_cast<uint32_t*>(&t);
}
__device__ __forceinline__ void split_fp16(float x, __half& h, __half& l) {
    h = __float2half_rn(x);
    l = __float2half_rn(x - __half2float(h));
}
__device__ __forceinline__ uint32_t pack2h(__half a, __half b) {
    __half2 t(a, b);
    return *reinterpret_cast<uint32_t*>(&t);
}

// ---------------------------------------------------------------------------
// Elementwise fp32 -> bf16 hi/lo split
// ---------------------------------------------------------------------------
__global__ __launch_bounds__(256)
void split_kernel(const float* __restrict__ src,
                  __nv_bfloat16* __restrict__ dh,
                  __nv_bfloat16* __restrict__ dl, int n4)
{
    int i = blockIdx.x * 256 + threadIdx.x;
    if (i >= n4) return;
    float4 v = reinterpret_cast<const float4*>(src)[i];
    __nv_bfloat16 h0, l0, h1, l1, h2, l2, h3, l3;
    split_bf16(v.x, h0, l0); split_bf16(v.y, h1, l1);
    split_bf16(v.z, h2, l2); split_bf16(v.w, h3, l3);
    reinterpret_cast<uint2*>(dh)[i] = make_uint2(pack2(h0, h1), pack2(h2, h3));
    reinterpret_cast<uint2*>(dl)[i] = make_uint2(pack2(l0, l1), pack2(l2, l3));
}

// ---------------------------------------------------------------------------
// bf16x3 GEMM (unchanged structure; EPI=1 now writes fp16 q / fp16 hi-lo k)
// ---------------------------------------------------------------------------
#define STG_B 32768u
#define GEMM_SMEM (3 * 32768 + 128)

template<int EPI>
__global__ __launch_bounds__(256, 2)
void gemm_pre_kernel(const __nv_bfloat16* __restrict__ Ah,
                     const __nv_bfloat16* __restrict__ Al,
                     const __nv_bfloat16* __restrict__ Bh,
                     const __nv_bfloat16* __restrict__ Bl,
                     const float* __restrict__ bias,
                     float* __restrict__ C,
                     int N, int K)
{
    extern __shared__ char dsm[];
    char* sp = dsm + ((128 - (smem_u32(dsm) & 127)) & 127);
    const uint32_t sb = smem_u32(sp);

    const int tid  = threadIdx.x;
    const int lane = tid & 31;
    const int wm   = (tid >> 5) & 3;
    const int wn   = tid >> 7;
    const int rowBase = blockIdx.y * 128;
    const int colBase = blockIdx.x * 128;

    float acc[2][8][4];
#pragma unroll
    for (int i = 0; i < 2; i++)
#pragma unroll
        for (int j = 0; j < 8; j++)
#pragma unroll
            for (int q = 0; q < 4; q++) acc[i][j][q] = 0.f;

    auto issue = [&](int it_, int stg) {
        const int kt = it_ * 32;
        const uint32_t so = sb + (uint32_t)stg * STG_B;
#pragma unroll
        for (int i = 0; i < 8; i++) {
            int g = tid + i * 256;
            int arr = g >> 9;
            int rem = g & 511;
            int row = rem >> 2, c = rem & 3;
            int cs = c ^ ((row >> 1) & 3);
            const __nv_bfloat16* src;
            if (arr == 0)      src = Ah + (size_t)(rowBase + row) * K + kt + c * 8;
            else if (arr == 1) src = Al + (size_t)(rowBase + row) * K + kt + c * 8;
            else if (arr == 2) src = Bh + (size_t)(colBase + row) * K + kt + c * 8;
            else               src = Bl + (size_t)(colBase + row) * K + kt + c * 8;
            CPASYNC16(so + (uint32_t)arr * 8192u + (uint32_t)(row * 64 + cs * 16), src);
        }
    };

    const uint32_t aRow = (uint32_t)(wm * 32 + (lane & 15));
    const uint32_t aHi  = (uint32_t)(lane >> 4);
    const uint32_t aSwz = (aRow >> 1) & 3;
    const uint32_t bRow = (uint32_t)(wn * 64 + (lane & 7) + ((lane >> 4) << 3));
    const uint32_t bHi  = (uint32_t)((lane >> 3) & 1);
    const uint32_t bSwz = (bRow >> 1) & 3;

    const int NIT = K / 32;
    issue(0, 0); CPCOMMIT();
    issue(1, 1); CPCOMMIT();

    for (int it = 0; it < NIT; ++it) {
        const int cur = it % 3;
        CPWAIT1();
        __syncthreads();
        if (it + 2 < NIT) issue(it + 2, (it + 2) % 3);
        CPCOMMIT();

        const uint32_t tb = sb + (uint32_t)cur * STG_B;
#pragma unroll
        for (int ks = 0; ks < 2; ks++) {
            uint32_t ah[2][4], al[2][4], bh[4][4], bl[4][4];
            const uint32_t caA = ((uint32_t)(ks * 2) + aHi) ^ aSwz;
            const uint32_t caB = ((uint32_t)(ks * 2) + bHi) ^ bSwz;
#pragma unroll
            for (int mi = 0; mi < 2; mi++) {
                uint32_t addr = tb + (aRow + mi * 16) * 64 + caA * 16;
                LDM4(ah[mi][0], ah[mi][1], ah[mi][2], ah[mi][3], addr);
                LDM4(al[mi][0], al[mi][1], al[mi][2], al[mi][3], addr + 8192);
            }
#pragma unroll
            for (int nt = 0; nt < 4; nt++) {
                uint32_t addr = tb + 16384u + (bRow + nt * 16) * 64 + caB * 16;
                LDM4(bh[nt][0], bh[nt][1], bh[nt][2], bh[nt][3], addr);
                LDM4(bl[nt][0], bl[nt][1], bl[nt][2], bl[nt][3], addr + 8192);
            }
#pragma unroll
            for (int mi = 0; mi < 2; mi++)
#pragma unroll
                for (int n8 = 0; n8 < 8; n8++) {
                    const int nt = n8 >> 1, hh = (n8 & 1) * 2;
                    MMA16816(acc[mi][n8], ah[mi], bh[nt][hh], bh[nt][hh + 1]);
                }
#pragma unroll
            for (int mi = 0; mi < 2; mi++)
#pragma unroll
                for (int n8 = 0; n8 < 8; n8++) {
                    const int nt = n8 >> 1, hh = (n8 & 1) * 2;
                    MMA16816(acc[mi][n8], ah[mi], bl[nt][hh], bl[nt][hh + 1]);
                }
#pragma unroll
            for (int mi = 0; mi < 2; mi++)
#pragma unroll
                for (int n8 = 0; n8 < 8; n8++) {
                    const int nt = n8 >> 1, hh = (n8 & 1) * 2;
                    MMA16816(acc[mi][n8], al[mi], bh[nt][hh], bh[nt][hh + 1]);
                }
        }
    }

    const int r0 = rowBase + wm * 32 + (lane >> 2);
    const int c0 = colBase + wn * 64 + (lane & 3) * 2;

    if (EPI == 0) {
#pragma unroll
        for (int mi = 0; mi < 2; mi++)
#pragma unroll
            for (int n8 = 0; n8 < 8; n8++) {
                const int row = r0 + mi * 16;
                const int col = c0 + n8 * 8;
                const float2 bv = *reinterpret_cast<const float2*>(bias + col);
                float2 o0 = make_float2(acc[mi][n8][0] + bv.x, acc[mi][n8][1] + bv.y);
                float2 o1 = make_float2(acc[mi][n8][2] + bv.x, acc[mi][n8][3] + bv.y);
                *reinterpret_cast<float2*>(C + (size_t)row * N + col)       = o0;
                *reinterpret_cast<float2*>(C + (size_t)(row + 8) * N + col) = o1;
            }
    } else {
        // QKV epilogue: Q -> fp16 (scaled), K -> fp16 hi/lo, V -> fp32 g_v
        auto wr = [&](int row, int col, float x0, float x1) {
            const int sect = col >> 10;
            const int coli = col & 1023;
            const int bb = row >> 10, t = row & 1023;
            if (sect == 2) {
                *reinterpret_cast<float2*>(C + (size_t)row * 1024 + coli) =
                    make_float2(x0, x1);
            } else {
                const int hh = coli >> 6, d = coli & 63;
                const size_t idx = ((size_t)(bb * 16 + hh) * 1024 + t) * 64 + d;
                if (sect == 0) {
                    __half q0 = __float2half_rn(x0 * 0.125f);
                    __half q1 = __float2half_rn(x1 * 0.125f);
                    *reinterpret_cast<uint32_t*>(g_qf + idx) = pack2h(q0, q1);
                } else {
                    __half h0, l0, h1, l1;
                    split_fp16(x0, h0, l0); split_fp16(x1, h1, l1);
                    *reinterpret_cast<uint32_t*>(g_kh + idx) = pack2h(h0, h1);
                    *reinterpret_cast<uint32_t*>(g_kl + idx) = pack2h(l0, l1);
                }
            }
        };
#pragma unroll
        for (int mi = 0; mi < 2; mi++)
#pragma unroll
            for (int n8 = 0; n8 < 8; n8++) {
                const int row = r0 + mi * 16;
                const int col = c0 + n8 * 8;
                const float2 bv = *reinterpret_cast<const float2*>(bias + col);
                wr(row,     col, acc[mi][n8][0] + bv.x, acc[mi][n8][1] + bv.y);
                wr(row + 8, col, acc[mi][n8][2] + bv.x, acc[mi][n8][3] + bv.y);
            }
    }
}

// ---------------------------------------------------------------------------
// V prepass: g_v fp32 -> transposed fp16 hi/lo [bh][d][t]
// ---------------------------------------------------------------------------
__global__ __launch_bounds__(256)
void vprep_kernel()
{
    __shared__ float vs[64][65];
    const int bh = blockIdx.y;
    const int b  = bh >> 4;
    const int h  = bh & 15;
    const int t0 = blockIdx.x * 64;
    const int tid = threadIdx.x;

    {
        const int r  = tid >> 2;
        const int dg = (tid & 3) * 16;
        const float* vp = g_v + (size_t)(b * SEQT + t0 + r) * EMB + h * HDIM + dg;
#pragma unroll
        for (int j = 0; j < 4; j++) {
            float4 t = reinterpret_cast<const float4*>(vp)[j];
            vs[r][dg + 4 * j + 0] = t.x; vs[r][dg + 4 * j + 1] = t.y;
            vs[r][dg + 4 * j + 2] = t.z; vs[r][dg + 4 * j + 3] = t.w;
        }
    }
    __syncthreads();
    {
        const int d  = tid >> 2;
        const int tg = (tid & 3) * 16;
        uint32_t hw[8], lw[8];
#pragma unroll
        for (int j = 0; j < 8; j++) {
            float x0 = vs[tg + 2 * j][d], x1 = vs[tg + 2 * j + 1][d];
            __half h0, l0, h1, l1;
            split_fp16(x0, h0, l0); split_fp16(x1, h1, l1);
            hw[j] = pack2h(h0, h1); lw[j] = pack2h(l0, l1);
        }
        const size_t vo = ((size_t)bh * HDIM + d) * SEQT + t0 + tg;
        *reinterpret_cast<uint4*>(g_vth + vo)     = *reinterpret_cast<uint4*>(hw);
        *reinterpret_cast<uint4*>(g_vth + vo + 8) = *reinterpret_cast<uint4*>(hw + 4);
        *reinterpret_cast<uint4*>(g_vtl + vo)     = *reinterpret_cast<uint4*>(lw);
        *reinterpret_cast<uint4*>(g_vtl + vo + 8) = *reinterpret_cast<uint4*>(lw + 4);
    }
}

// ---------------------------------------------------------------------------
// Tensorized flash attention, key-split warps.
// S = Q(fp16) x K(fp16 hi/lo) x2 MMAs; PV = P(fp16) x V(fp16 hi/lo) x2 MMAs.
// exp shifted by -10 (global constant; cancels). grid (8,64), block 512.
// ---------------------------------------------------------------------------
#define AQF   0u
#define ABUF0 18432u
#define ABUF1 55296u
#define AMSK  92160u
#define OSCR  18432u
#define RSCR  (18432u + 32768u)
#define ATTN_SMEM (92160 + 4096 + 128)
#define RS 144u
#define EXPSHIFT 10.0f

__global__ __launch_bounds__(512, 1)
void attn_mma_kernel(const float* __restrict__ attn_bias,
                     const unsigned char* __restrict__ kmask)
{
    extern __shared__ char dsm[];
    char* sp = dsm + ((128 - (smem_u32(dsm) & 127)) & 127);
    const uint32_t sb = smem_u32(sp);

    const int bh = blockIdx.y;
    const int b  = bh >> 4;
    const int h  = bh & 15;
    const int qbase = blockIdx.x * 128;
    const int tid  = threadIdx.x;
    const int lane = tid & 31;
    const int w    = tid >> 5;
    const int wq   = w & 7;
    const int kh2  = (w >> 3) * 32;

    for (int i = tid; i < SEQT; i += 512)
        *reinterpret_cast<float*>(sp + AMSK + i * 4) =
            kmask[b * SEQT + i] ? -3.0e38f : 0.f;

    // stage Q fp16: 1024 16B chunks over 512 threads
#pragma unroll
    for (int i = 0; i < 2; i++) {
        int g = tid + i * 512;
        int row = g >> 3, cc = g & 7;
        const __half* src = g_qf + ((size_t)bh * SEQT + qbase + row) * HDIM + cc * 8;
        uint32_t dst = sb + AQF + row * RS + cc * 16;
        CPASYNC16(dst, src);
    }

    auto load_kv = [&](int kb, uint32_t bufoff) {
#pragma unroll
        for (int i = 0; i < 4; i++) {
            int g = tid + i * 512;
            int arr = g >> 9, rem = g & 511;
            int row = rem >> 3, cc = rem & 7;
            const void* src;
            if (arr == 0)      src = g_kh  + ((size_t)bh * SEQT + kb + row) * HDIM + cc * 8;
            else if (arr == 1) src = g_kl  + ((size_t)bh * SEQT + kb + row) * HDIM + cc * 8;
            else if (arr == 2) src = g_vth + ((size_t)bh * HDIM + row) * SEQT + kb + cc * 8;
            else               src = g_vtl + ((size_t)bh * HDIM + row) * SEQT + kb + cc * 8;
            uint32_t dst = sb + bufoff + (uint32_t)arr * 9216u + row * RS + cc * 16;
            CPASYNC16(dst, src);
        }
    };

    load_kv(0, ABUF0);
    CPCOMMIT();
    CPWAIT0();
    __syncthreads();

    // Q fragments (fp16, held in registers)
    const uint32_t aRow  = (uint32_t)(wq * 16 + (lane & 15));
    const uint32_t aColH = (uint32_t)((lane >> 4) * 8);
    uint32_t qf[4][4];
#pragma unroll
    for (int kc = 0; kc < 4; kc++) {
        uint32_t addr = sb + AQF + aRow * RS + (aColH + kc * 16) * 2;
        LDM4(qf[kc][0], qf[kc][1], qf[kc][2], qf[kc][3], addr);
    }

    float oacc[8][4];
#pragma unroll
    for (int i = 0; i < 8; i++)
#pragma unroll
        for (int j = 0; j < 4; j++) oacc[i][j] = 0.f;
    float rs0 = 0.f, rs1 = 0.f;

    const uint32_t bRowB = (uint32_t)((lane & 7) + ((lane >> 4) << 3));
    const uint32_t bHi8  = (uint32_t)(((lane >> 3) & 1) * 8);
    const float* biasp = attn_bias + (size_t)bh * SEQT * SEQT +
        (size_t)(qbase + wq * 16 + (lane >> 2)) * SEQT + kh2 + (lane & 3) * 2;

    for (int it = 0; it < 16; ++it) {
        const int kb = it * 64;
        const uint32_t buf = (it & 1) ? ABUF1 : ABUF0;
        if (it + 1 < 16) {
            load_kv((it + 1) * 64, (it & 1) ? ABUF0 : ABUF1);
            CPCOMMIT();
        }
        float2 bias0[4], bias1[4];
#pragma unroll
        for (int n8 = 0; n8 < 4; n8++) {
            bias0[n8] = *reinterpret_cast<const float2*>(biasp + kb + n8 * 8);
            bias1[n8] = *reinterpret_cast<const float2*>(biasp + 8 * SEQT + kb + n8 * 8);
        }

        // S = Q K^T over this warp's 32-key half (fp16 x2, term-major)
        float sacc[4][4];
#pragma unroll
        for (int i = 0; i < 4; i++)
#pragma unroll
            for (int j = 0; j < 4; j++) sacc[i][j] = 0.f;
#pragma unroll
        for (int kc = 0; kc < 4; kc++) {
            uint32_t kfh[2][4], kfl[2][4];
#pragma unroll
            for (int nt = 0; nt < 2; nt++) {
                uint32_t addr = sb + buf + (kh2 + nt * 16 + bRowB) * RS + (kc * 16 + bHi8) * 2;
                LDM4(kfh[nt][0], kfh[nt][1], kfh[nt][2], kfh[nt][3], addr);
                LDM4(kfl[nt][0], kfl[nt][1], kfl[nt][2], kfl[nt][3], addr + 9216);
            }
#pragma unroll
            for (int n8 = 0; n8 < 4; n8++) {
                const int nt = n8 >> 1, hh = (n8 & 1) * 2;
                MMAF16(sacc[n8], qf[kc], kfh[nt][hh], kfh[nt][hh + 1]);
            }
#pragma unroll
            for (int n8 = 0; n8 < 4; n8++) {
                const int nt = n8 >> 1, hh = (n8 & 1) * 2;
                MMAF16(sacc[n8], qf[kc], kfl[nt][hh], kfl[nt][hh + 1]);
            }
        }

        // softmax numerators, shifted; P -> fp16
        uint32_t pph[8];
#pragma unroll
        for (int n8 = 0; n8 < 4; n8++) {
            float2 mk = *reinterpret_cast<const float2*>(
                sp + AMSK + (kb + kh2 + n8 * 8 + (lane & 3) * 2) * 4);
            float p0 = __expf(sacc[n8][0] + bias0[n8].x + mk.x - EXPSHIFT);
            float p1 = __expf(sacc[n8][1] + bias0[n8].y + mk.y - EXPSHIFT);
            float p2 = __expf(sacc[n8][2] + bias1[n8].x + mk.x - EXPSHIFT);
            float p3 = __expf(sacc[n8][3] + bias1[n8].y + mk.y - EXPSHIFT);
            rs0 += p0 + p1;
            rs1 += p2 + p3;
            __half2 a = __floats2half2_rn(p0, p1);
            __half2 bq = __floats2half2_rn(p2, p3);
            pph[n8 * 2]     = *reinterpret_cast<uint32_t*>(&a);
            pph[n8 * 2 + 1] = *reinterpret_cast<uint32_t*>(&bq);
        }

        // O += P V over this warp's 32-key half (fp16 x2)
#pragma unroll
        for (int kc = 0; kc < 2; kc++) {
            uint32_t pah[4] = { pph[4 * kc], pph[4 * kc + 1], pph[4 * kc + 2], pph[4 * kc + 3] };
            uint32_t vfh[4][4], vfl[4][4];
#pragma unroll
            for (int nt = 0; nt < 4; nt++) {
                uint32_t addr = sb + buf + 18432u + (bRowB + nt * 16) * RS +
                                (kh2 + kc * 16 + bHi8) * 2;
                LDM4(vfh[nt][0], vfh[nt][1], vfh[nt][2], vfh[nt][3], addr);
                LDM4(vfl[nt][0], vfl[nt][1], vfl[nt][2], vfl[nt][3], addr + 9216);
            }
#pragma unroll
            for (int n8 = 0; n8 < 8; n8++) {
                const int nt = n8 >> 1, hh = (n8 & 1) * 2;
                MMAF16(oacc[n8], pah, vfh[nt][hh], vfh[nt][hh + 1]);
            }
#pragma unroll
            for (int n8 = 0; n8 < 8; n8++) {
                const int nt = n8 >> 1, hh = (n8 & 1) * 2;
                MMAF16(oacc[n8], pah, vfl[nt][hh], vfl[nt][hh + 1]);
            }
        }

        CPWAIT0();
        __syncthreads();
    }

    rs0 += __shfl_xor_sync(0xffffffffu, rs0, 1);
    rs0 += __shfl_xor_sync(0xffffffffu, rs0, 2);
    rs1 += __shfl_xor_sync(0xffffffffu, rs1, 1);
    rs1 += __shfl_xor_sync(0xffffffffu, rs1, 2);

    if (w >= 8) {
        const uint32_t ob = sb + OSCR + (uint32_t)(w - 8) * 4096u;
#pragma unroll
        for (int n8 = 0; n8 < 8; n8++) {
            float4 t = make_float4(oacc[n8][0], oacc[n8][1], oacc[n8][2], oacc[n8][3]);
            *reinterpret_cast<float4*>(dsm + (ob - smem_u32(dsm)) + n8 * 512 + lane * 16) = t;
        }
        *reinterpret_cast<float2*>(dsm + (sb + RSCR - smem_u32(dsm)) + (w - 8) * 256 + lane * 8)
            = make_float2(rs0, rs1);
    }
    __syncthreads();
    if (w < 8) {
        const uint32_t ob = sb + OSCR + (uint32_t)w * 4096u;
        float2 prs = *reinterpret_cast<float2*>(
            dsm + (sb + RSCR - smem_u32(dsm)) + w * 256 + lane * 8);
        const float inv0 = 1.f / (rs0 + prs.x);
        const float inv1 = 1.f / (rs1 + prs.y);

        const int row0 = qbase + w * 16 + (lane >> 2);
        const int col0 = h * HDIM + (lane & 3) * 2;
#pragma unroll
        for (int n8 = 0; n8 < 8; n8++) {
            float4 t = *reinterpret_cast<float4*>(
                dsm + (ob - smem_u32(dsm)) + n8 * 512 + lane * 16);
            float x0 = (oacc[n8][0] + t.x) * inv0, x1 = (oacc[n8][1] + t.y) * inv0;
            float y0 = (oacc[n8][2] + t.z) * inv1, y1 = (oacc[n8][3] + t.w) * inv1;
            __nv_bfloat16 h0, l0, h1, l1;
            size_t i0 = (size_t)(b * SEQT + row0) * EMB + col0 + n8 * 8;
            size_t i1 = (size_t)(b * SEQT + row0 + 8) * EMB + col0 + n8 * 8;
            split_bf16(x0, h0, l0); split_bf16(x1, h1, l1);
            *reinterpret_cast<uint32_t*>(g_aoh + i0) = pack2(h0, h1);
            *reinterpret_cast<uint32_t*>(g_aol + i0) = pack2(l0, l1);
            split_bf16(y0, h0, l0); split_bf16(y1, h1, l1);
            *reinterpret_cast<uint32_t*>(g_aoh + i1) = pack2(h0, h1);
            *reinterpret_cast<uint32_t*>(g_aol + i1) = pack2(l0, l1);
        }
    }
}

// ---------------------------------------------------------------------------
// Launch
// ---------------------------------------------------------------------------
extern "C" void kernel_launch(void* const* d_in, const int* in_sizes, int n_in,
                              void* d_out, int out_size)
{
    const float*         query = (const float*)d_in[0];
    const float*         abias = (const float*)d_in[1];
    const unsigned char* kmask = (const unsigned char*)d_in[2];
    const float*         in_w  = (const float*)d_in[3];
    const float*         in_b  = (const float*)d_in[4];
    const float*         out_w = (const float*)d_in[5];
    const float*         out_b = (const float*)d_in[6];
    float*               out   = (float*)d_out;

    __nv_bfloat16 *xh, *xl, *w1h, *w1l, *w2h, *w2l, *aoh, *aol;
    float* v;
    cudaGetSymbolAddress((void**)&xh,  g_xh);
    cudaGetSymbolAddress((void**)&xl,  g_xl);
    cudaGetSymbolAddress((void**)&w1h, g_w1h);
    cudaGetSymbolAddress((void**)&w1l, g_w1l);
    cudaGetSymbolAddress((void**)&w2h, g_w2h);
    cudaGetSymbolAddress((void**)&w2l, g_w2l);
    cudaGetSymbolAddress((void**)&aoh, g_aoh);
    cudaGetSymbolAddress((void**)&aol, g_aol);
    cudaGetSymbolAddress((void**)&v,   g_v);

    cudaFuncSetAttribute(gemm_pre_kernel<0>,
                         cudaFuncAttributeMaxDynamicSharedMemorySize, GEMM_SMEM);
    cudaFuncSetAttribute(gemm_pre_kernel<1>,
                         cudaFuncAttributeMaxDynamicSharedMemorySize, GEMM_SMEM);
    cudaFuncSetAttribute(attn_mma_kernel,
                         cudaFuncAttributeMaxDynamicSharedMemorySize, ATTN_SMEM);

    // 0) pre-split operands
    split_kernel<<<(MTOK * EMB / 4 + 255) / 256, 256>>>(query, xh, xl, MTOK * EMB / 4);
    split_kernel<<<(E3 * EMB / 4 + 255) / 256, 256>>>(in_w, w1h, w1l, E3 * EMB / 4);
    split_kernel<<<(EMB * EMB / 4 + 255) / 256, 256>>>(out_w, w2h, w2l, EMB * EMB / 4);

    // 1) QKV projection + fused fp16 q/k epilogue
    {
        dim3 grid(E3 / 128, MTOK / 128);
        gemm_pre_kernel<1><<<grid, 256, GEMM_SMEM>>>(xh, xl, w1h, w1l, in_b, v, E3, EMB);
    }
    // 2) V transpose/split (fp16)
    {
        dim3 grid(SEQT / 64, BH);
        vprep_kernel<<<grid, 256>>>();
    }
    // 3) Attention
    {
        dim3 grid(SEQT / 128, BH);
        attn_mma_kernel<<<grid, 512, ATTN_SMEM>>>(abias, kmask);
    }
    // 4) Output projection
    {
        dim3 grid(EMB / 128, MTOK / 128);
        gemm_pre_kernel<0><<<grid, 256, GEMM_SMEM>>>(aoh, aol, w2h, w2l, out_b, out, EMB, EMB);
    }
}

// round 10
// speedup vs baseline: 4.0813x; 1.2201x over previous
#include <cuda_runtime.h>
#include <cuda_bf16.h>
#include <cuda_fp16.h>
#include <cstdint>
#include <math.h>

#define BATCH 4
#define SEQT 1024
#define EMB 1024
#define NHEAD 16
#define HDIM 64
#define E3 (3 * EMB)
#define MTOK (BATCH * SEQT)
#define BH (BATCH * NHEAD)

// Scratch (fp16 operands)
__device__ __half g_xh [(size_t)MTOK * EMB];   // query fp16 hi
__device__ __half g_xl [(size_t)MTOK * EMB];   // query fp16 lo
__device__ __half g_w1 [(size_t)E3 * EMB];     // in_w fp16
__device__ __half g_w2 [(size_t)EMB * EMB];    // out_w fp16
__device__ float  g_v  [(size_t)MTOK * EMB];
__device__ __half g_aoh[(size_t)MTOK * EMB];   // attention out fp16 hi
__device__ __half g_aol[(size_t)MTOK * EMB];   // attention out fp16 lo
__device__ __half g_qf [(size_t)BH * SEQT * HDIM];
__device__ __half g_kh [(size_t)BH * SEQT * HDIM];
__device__ __half g_kl [(size_t)BH * SEQT * HDIM];
__device__ __half g_vth[(size_t)BH * HDIM * SEQT];
__device__ __half g_vtl[(size_t)BH * HDIM * SEQT];

// ---------------------------------------------------------------------------
// helpers
// ---------------------------------------------------------------------------
__device__ __forceinline__ uint32_t smem_u32(const void* p) {
    uint32_t a;
    asm("{ .reg .u64 t; cvta.to.shared.u64 t, %1; cvt.u32.u64 %0, t; }"
        : "=r"(a) : "l"(p));
    return a;
}

#define LDM4(r0, r1, r2, r3, addr) \
    asm volatile("ldmatrix.sync.aligned.m8n8.x4.shared.b16 {%0,%1,%2,%3}, [%4];" \
                 : "=r"(r0), "=r"(r1), "=r"(r2), "=r"(r3) : "r"(addr))

#define MMAF16(d, a, b0, b1) \
    asm volatile("mma.sync.aligned.m16n8k16.row.col.f32.f16.f16.f32 " \
                 "{%0,%1,%2,%3},{%4,%5,%6,%7},{%8,%9},{%0,%1,%2,%3};" \
                 : "+f"((d)[0]), "+f"((d)[1]), "+f"((d)[2]), "+f"((d)[3]) \
                 : "r"((a)[0]), "r"((a)[1]), "r"((a)[2]), "r"((a)[3]), \
                   "r"(b0), "r"(b1))

#define CPASYNC16(sdst, gsrc) \
    asm volatile("cp.async.cg.shared.global [%0], [%1], 16;" \
                 :: "r"(sdst), "l"(gsrc) : "memory")
#define CPCOMMIT() asm volatile("cp.async.commit_group;" ::: "memory")
#define CPWAIT0()  asm volatile("cp.async.wait_group 0;" ::: "memory")
#define CPWAIT1()  asm volatile("cp.async.wait_group 1;" ::: "memory")

__device__ __forceinline__ void split_fp16(float x, __half& h, __half& l) {
    h = __float2half_rn(x);
    l = __float2half_rn(x - __half2float(h));
}
__device__ __forceinline__ uint32_t pack2h(__half a, __half b) {
    __half2 t(a, b);
    return *reinterpret_cast<uint32_t*>(&t);
}

// ---------------------------------------------------------------------------
// Elementwise converters
// ---------------------------------------------------------------------------
__global__ __launch_bounds__(256)
void splitH_kernel(const float* __restrict__ src,
                   __half* __restrict__ dh,
                   __half* __restrict__ dl, int n4)
{
    int i = blockIdx.x * 256 + threadIdx.x;
    if (i >= n4) return;
    float4 v = reinterpret_cast<const float4*>(src)[i];
    __half h0, l0, h1, l1, h2, l2, h3, l3;
    split_fp16(v.x, h0, l0); split_fp16(v.y, h1, l1);
    split_fp16(v.z, h2, l2); split_fp16(v.w, h3, l3);
    reinterpret_cast<uint2*>(dh)[i] = make_uint2(pack2h(h0, h1), pack2h(h2, h3));
    reinterpret_cast<uint2*>(dl)[i] = make_uint2(pack2h(l0, l1), pack2h(l2, l3));
}

__global__ __launch_bounds__(256)
void half_kernel(const float* __restrict__ src,
                 __half* __restrict__ dst, int n4)
{
    int i = blockIdx.x * 256 + threadIdx.x;
    if (i >= n4) return;
    float4 v = reinterpret_cast<const float4*>(src)[i];
    reinterpret_cast<uint2*>(dst)[i] =
        make_uint2(pack2h(__float2half_rn(v.x), __float2half_rn(v.y)),
                   pack2h(__float2half_rn(v.z), __float2half_rn(v.w)));
}

// ---------------------------------------------------------------------------
// fp16 x2 GEMM: C[M,N] = (Ah+Al)[M,K] @ B[N,K]^T + bias[N]
// A = fp16 hi/lo, B = single fp16. 2 MMAs per tile-pair. 3-stage cp.async,
// 2 CTAs/SM. CTA 128x128, BK=32, 256 thr, warps 4(m) x 2(n), tile 32x64.
// ---------------------------------------------------------------------------
#define STG_B 24576u            // Ah 8K | Al 8K | B 8K
#define GEMM_SMEM (3 * 24576 + 128)

template<int EPI>
__global__ __launch_bounds__(256, 2)
void gemm_f16_kernel(const __half* __restrict__ Ah,
                     const __half* __restrict__ Al,
                     const __half* __restrict__ Bs,
                     const float* __restrict__ bias,
                     float* __restrict__ C,
                     int N, int K)
{
    extern __shared__ char dsm[];
    char* sp = dsm + ((128 - (smem_u32(dsm) & 127)) & 127);
    const uint32_t sb = smem_u32(sp);

    const int tid  = threadIdx.x;
    const int lane = tid & 31;
    const int wm   = (tid >> 5) & 3;
    const int wn   = tid >> 7;
    const int rowBase = blockIdx.y * 128;
    const int colBase = blockIdx.x * 128;

    float acc[2][8][4];
#pragma unroll
    for (int i = 0; i < 2; i++)
#pragma unroll
        for (int j = 0; j < 8; j++)
#pragma unroll
            for (int q = 0; q < 4; q++) acc[i][j][q] = 0.f;

    auto issue = [&](int it_, int stg) {
        const int kt = it_ * 32;
        const uint32_t so = sb + (uint32_t)stg * STG_B;
#pragma unroll
        for (int i = 0; i < 6; i++) {
            int g = tid + i * 256;            // 0..1535
            int arr = g >> 9;                 // 0=Ah 1=Al 2=B
            int rem = g & 511;
            int row = rem >> 2, c = rem & 3;
            int cs = c ^ ((row >> 1) & 3);
            const __half* src;
            if (arr == 0)      src = Ah + (size_t)(rowBase + row) * K + kt + c * 8;
            else if (arr == 1) src = Al + (size_t)(rowBase + row) * K + kt + c * 8;
            else               src = Bs + (size_t)(colBase + row) * K + kt + c * 8;
            CPASYNC16(so + (uint32_t)arr * 8192u + (uint32_t)(row * 64 + cs * 16), src);
        }
    };

    const uint32_t aRow = (uint32_t)(wm * 32 + (lane & 15));
    const uint32_t aHi  = (uint32_t)(lane >> 4);
    const uint32_t aSwz = (aRow >> 1) & 3;
    const uint32_t bRow = (uint32_t)(wn * 64 + (lane & 7) + ((lane >> 4) << 3));
    const uint32_t bHi  = (uint32_t)((lane >> 3) & 1);
    const uint32_t bSwz = (bRow >> 1) & 3;

    const int NIT = K / 32;
    issue(0, 0); CPCOMMIT();
    issue(1, 1); CPCOMMIT();

    for (int it = 0; it < NIT; ++it) {
        const int cur = it % 3;
        CPWAIT1();
        __syncthreads();
        if (it + 2 < NIT) issue(it + 2, (it + 2) % 3);
        CPCOMMIT();

        const uint32_t tb = sb + (uint32_t)cur * STG_B;
#pragma unroll
        for (int ks = 0; ks < 2; ks++) {
            uint32_t ah[2][4], al[2][4], bs[4][4];
            const uint32_t caA = ((uint32_t)(ks * 2) + aHi) ^ aSwz;
            const uint32_t caB = ((uint32_t)(ks * 2) + bHi) ^ bSwz;
#pragma unroll
            for (int mi = 0; mi < 2; mi++) {
                uint32_t addr = tb + (aRow + mi * 16) * 64 + caA * 16;
                LDM4(ah[mi][0], ah[mi][1], ah[mi][2], ah[mi][3], addr);
                LDM4(al[mi][0], al[mi][1], al[mi][2], al[mi][3], addr + 8192);
            }
#pragma unroll
            for (int nt = 0; nt < 4; nt++) {
                uint32_t addr = tb + 16384u + (bRow + nt * 16) * 64 + caB * 16;
                LDM4(bs[nt][0], bs[nt][1], bs[nt][2], bs[nt][3], addr);
            }
            // term-major: 16 independent MMAs per term
#pragma unroll
            for (int mi = 0; mi < 2; mi++)
#pragma unroll
                for (int n8 = 0; n8 < 8; n8++) {
                    const int nt = n8 >> 1, hh = (n8 & 1) * 2;
                    MMAF16(acc[mi][n8], ah[mi], bs[nt][hh], bs[nt][hh + 1]);
                }
#pragma unroll
            for (int mi = 0; mi < 2; mi++)
#pragma unroll
                for (int n8 = 0; n8 < 8; n8++) {
                    const int nt = n8 >> 1, hh = (n8 & 1) * 2;
                    MMAF16(acc[mi][n8], al[mi], bs[nt][hh], bs[nt][hh + 1]);
                }
        }
    }

    const int r0 = rowBase + wm * 32 + (lane >> 2);
    const int c0 = colBase + wn * 64 + (lane & 3) * 2;

    if (EPI == 0) {
#pragma unroll
        for (int mi = 0; mi < 2; mi++)
#pragma unroll
            for (int n8 = 0; n8 < 8; n8++) {
                const int row = r0 + mi * 16;
                const int col = c0 + n8 * 8;
                const float2 bv = *reinterpret_cast<const float2*>(bias + col);
                float2 o0 = make_float2(acc[mi][n8][0] + bv.x, acc[mi][n8][1] + bv.y);
                float2 o1 = make_float2(acc[mi][n8][2] + bv.x, acc[mi][n8][3] + bv.y);
                *reinterpret_cast<float2*>(C + (size_t)row * N + col)       = o0;
                *reinterpret_cast<float2*>(C + (size_t)(row + 8) * N + col) = o1;
            }
    } else {
        // QKV epilogue: Q -> fp16 scaled, K -> fp16 hi/lo, V -> fp32 g_v
        auto wr = [&](int row, int col, float x0, float x1) {
            const int sect = col >> 10;
            const int coli = col & 1023;
            const int bb = row >> 10, t = row & 1023;
            if (sect == 2) {
                *reinterpret_cast<float2*>(C + (size_t)row * 1024 + coli) =
                    make_float2(x0, x1);
            } else {
                const int hh = coli >> 6, d = coli & 63;
                const size_t idx = ((size_t)(bb * 16 + hh) * 1024 + t) * 64 + d;
                if (sect == 0) {
                    __half q0 = __float2half_rn(x0 * 0.125f);
                    __half q1 = __float2half_rn(x1 * 0.125f);
                    *reinterpret_cast<uint32_t*>(g_qf + idx) = pack2h(q0, q1);
                } else {
                    __half h0, l0, h1, l1;
                    split_fp16(x0, h0, l0); split_fp16(x1, h1, l1);
                    *reinterpret_cast<uint32_t*>(g_kh + idx) = pack2h(h0, h1);
                    *reinterpret_cast<uint32_t*>(g_kl + idx) = pack2h(l0, l1);
                }
            }
        };
#pragma unroll
        for (int mi = 0; mi < 2; mi++)
#pragma unroll
            for (int n8 = 0; n8 < 8; n8++) {
                const int row = r0 + mi * 16;
                const int col = c0 + n8 * 8;
                const float2 bv = *reinterpret_cast<const float2*>(bias + col);
                wr(row,     col, acc[mi][n8][0] + bv.x, acc[mi][n8][1] + bv.y);
                wr(row + 8, col, acc[mi][n8][2] + bv.x, acc[mi][n8][3] + bv.y);
            }
    }
}

// ---------------------------------------------------------------------------
// V prepass: g_v fp32 -> transposed fp16 hi/lo [bh][d][t]
// ---------------------------------------------------------------------------
__global__ __launch_bounds__(256)
void vprep_kernel()
{
    __shared__ float vs[64][65];
    const int bh = blockIdx.y;
    const int b  = bh >> 4;
    const int h  = bh & 15;
    const int t0 = blockIdx.x * 64;
    const int tid = threadIdx.x;

    {
        const int r  = tid >> 2;
        const int dg = (tid & 3) * 16;
        const float* vp = g_v + (size_t)(b * SEQT + t0 + r) * EMB + h * HDIM + dg;
#pragma unroll
        for (int j = 0; j < 4; j++) {
            float4 t = reinterpret_cast<const float4*>(vp)[j];
            vs[r][dg + 4 * j + 0] = t.x; vs[r][dg + 4 * j + 1] = t.y;
            vs[r][dg + 4 * j + 2] = t.z; vs[r][dg + 4 * j + 3] = t.w;
        }
    }
    __syncthreads();
    {
        const int d  = tid >> 2;
        const int tg = (tid & 3) * 16;
        uint32_t hw[8], lw[8];
#pragma unroll
        for (int j = 0; j < 8; j++) {
            float x0 = vs[tg + 2 * j][d], x1 = vs[tg + 2 * j + 1][d];
            __half h0, l0, h1, l1;
            split_fp16(x0, h0, l0); split_fp16(x1, h1, l1);
            hw[j] = pack2h(h0, h1); lw[j] = pack2h(l0, l1);
        }
        const size_t vo = ((size_t)bh * HDIM + d) * SEQT + t0 + tg;
        *reinterpret_cast<uint4*>(g_vth + vo)     = *reinterpret_cast<uint4*>(hw);
        *reinterpret_cast<uint4*>(g_vth + vo + 8) = *reinterpret_cast<uint4*>(hw + 4);
        *reinterpret_cast<uint4*>(g_vtl + vo)     = *reinterpret_cast<uint4*>(lw);
        *reinterpret_cast<uint4*>(g_vtl + vo + 8) = *reinterpret_cast<uint4*>(lw + 4);
    }
}

// ---------------------------------------------------------------------------
// Tensorized flash attention, key-split warps (unchanged from round 9,
// except O epilogue writes fp16 hi/lo).
// ---------------------------------------------------------------------------
#define AQF   0u
#define ABUF0 18432u
#define ABUF1 55296u
#define AMSK  92160u
#define OSCR  18432u
#define RSCR  (18432u + 32768u)
#define ATTN_SMEM (92160 + 4096 + 128)
#define RS 144u
#define EXPSHIFT 10.0f

__global__ __launch_bounds__(512, 1)
void attn_mma_kernel(const float* __restrict__ attn_bias,
                     const unsigned char* __restrict__ kmask)
{
    extern __shared__ char dsm[];
    char* sp = dsm + ((128 - (smem_u32(dsm) & 127)) & 127);
    const uint32_t sb = smem_u32(sp);

    const int bh = blockIdx.y;
    const int b  = bh >> 4;
    const int h  = bh & 15;
    const int qbase = blockIdx.x * 128;
    const int tid  = threadIdx.x;
    const int lane = tid & 31;
    const int w    = tid >> 5;
    const int wq   = w & 7;
    const int kh2  = (w >> 3) * 32;

    for (int i = tid; i < SEQT; i += 512)
        *reinterpret_cast<float*>(sp + AMSK + i * 4) =
            kmask[b * SEQT + i] ? -3.0e38f : 0.f;

#pragma unroll
    for (int i = 0; i < 2; i++) {
        int g = tid + i * 512;
        int row = g >> 3, cc = g & 7;
        const __half* src = g_qf + ((size_t)bh * SEQT + qbase + row) * HDIM + cc * 8;
        uint32_t dst = sb + AQF + row * RS + cc * 16;
        CPASYNC16(dst, src);
    }

    auto load_kv = [&](int kb, uint32_t bufoff) {
#pragma unroll
        for (int i = 0; i < 4; i++) {
            int g = tid + i * 512;
            int arr = g >> 9, rem = g & 511;
            int row = rem >> 3, cc = rem & 7;
            const void* src;
            if (arr == 0)      src = g_kh  + ((size_t)bh * SEQT + kb + row) * HDIM + cc * 8;
            else if (arr == 1) src = g_kl  + ((size_t)bh * SEQT + kb + row) * HDIM + cc * 8;
            else if (arr == 2) src = g_vth + ((size_t)bh * HDIM + row) * SEQT + kb + cc * 8;
            else               src = g_vtl + ((size_t)bh * HDIM + row) * SEQT + kb + cc * 8;
            uint32_t dst = sb + bufoff + (uint32_t)arr * 9216u + row * RS + cc * 16;
            CPASYNC16(dst, src);
        }
    };

    load_kv(0, ABUF0);
    CPCOMMIT();
    CPWAIT0();
    __syncthreads();

    const uint32_t aRow  = (uint32_t)(wq * 16 + (lane & 15));
    const uint32_t aColH = (uint32_t)((lane >> 4) * 8);
    uint32_t qf[4][4];
#pragma unroll
    for (int kc = 0; kc < 4; kc++) {
        uint32_t addr = sb + AQF + aRow * RS + (aColH + kc * 16) * 2;
        LDM4(qf[kc][0], qf[kc][1], qf[kc][2], qf[kc][3], addr);
    }

    float oacc[8][4];
#pragma unroll
    for (int i = 0; i < 8; i++)
#pragma unroll
        for (int j = 0; j < 4; j++) oacc[i][j] = 0.f;
    float rs0 = 0.f, rs1 = 0.f;

    const uint32_t bRowB = (uint32_t)((lane & 7) + ((lane >> 4) << 3));
    const uint32_t bHi8  = (uint32_t)(((lane >> 3) & 1) * 8);
    const float* biasp = attn_bias + (size_t)bh * SEQT * SEQT +
        (size_t)(qbase + wq * 16 + (lane >> 2)) * SEQT + kh2 + (lane & 3) * 2;

    for (int it = 0; it < 16; ++it) {
        const int kb = it * 64;
        const uint32_t buf = (it & 1) ? ABUF1 : ABUF0;
        if (it + 1 < 16) {
            load_kv((it + 1) * 64, (it & 1) ? ABUF0 : ABUF1);
            CPCOMMIT();
        }
        float2 bias0[4], bias1[4];
#pragma unroll
        for (int n8 = 0; n8 < 4; n8++) {
            bias0[n8] = *reinterpret_cast<const float2*>(biasp + kb + n8 * 8);
            bias1[n8] = *reinterpret_cast<const float2*>(biasp + 8 * SEQT + kb + n8 * 8);
        }

        float sacc[4][4];
#pragma unroll
        for (int i = 0; i < 4; i++)
#pragma unroll
            for (int j = 0; j < 4; j++) sacc[i][j] = 0.f;
#pragma unroll
        for (int kc = 0; kc < 4; kc++) {
            uint32_t kfh[2][4], kfl[2][4];
#pragma unroll
            for (int nt = 0; nt < 2; nt++) {
                uint32_t addr = sb + buf + (kh2 + nt * 16 + bRowB) * RS + (kc * 16 + bHi8) * 2;
                LDM4(kfh[nt][0], kfh[nt][1], kfh[nt][2], kfh[nt][3], addr);
                LDM4(kfl[nt][0], kfl[nt][1], kfl[nt][2], kfl[nt][3], addr + 9216);
            }
#pragma unroll
            for (int n8 = 0; n8 < 4; n8++) {
                const int nt = n8 >> 1, hh = (n8 & 1) * 2;
                MMAF16(sacc[n8], qf[kc], kfh[nt][hh], kfh[nt][hh + 1]);
            }
#pragma unroll
            for (int n8 = 0; n8 < 4; n8++) {
                const int nt = n8 >> 1, hh = (n8 & 1) * 2;
                MMAF16(sacc[n8], qf[kc], kfl[nt][hh], kfl[nt][hh + 1]);
            }
        }

        uint32_t pph[8];
#pragma unroll
        for (int n8 = 0; n8 < 4; n8++) {
            float2 mk = *reinterpret_cast<const float2*>(
                sp + AMSK + (kb + kh2 + n8 * 8 + (lane & 3) * 2) * 4);
            float p0 = __expf(sacc[n8][0] + bias0[n8].x + mk.x - EXPSHIFT);
            float p1 = __expf(sacc[n8][1] + bias0[n8].y + mk.y - EXPSHIFT);
            float p2 = __expf(sacc[n8][2] + bias1[n8].x + mk.x - EXPSHIFT);
            float p3 = __expf(sacc[n8][3] + bias1[n8].y + mk.y - EXPSHIFT);
            rs0 += p0 + p1;
            rs1 += p2 + p3;
            __half2 a = __floats2half2_rn(p0, p1);
            __half2 bq = __floats2half2_rn(p2, p3);
            pph[n8 * 2]     = *reinterpret_cast<uint32_t*>(&a);
            pph[n8 * 2 + 1] = *reinterpret_cast<uint32_t*>(&bq);
        }

#pragma unroll
        for (int kc = 0; kc < 2; kc++) {
            uint32_t pah[4] = { pph[4 * kc], pph[4 * kc + 1], pph[4 * kc + 2], pph[4 * kc + 3] };
            uint32_t vfh[4][4], vfl[4][4];
#pragma unroll
            for (int nt = 0; nt < 4; nt++) {
                uint32_t addr = sb + buf + 18432u + (bRowB + nt * 16) * RS +
                                (kh2 + kc * 16 + bHi8) * 2;
                LDM4(vfh[nt][0], vfh[nt][1], vfh[nt][2], vfh[nt][3], addr);
                LDM4(vfl[nt][0], vfl[nt][1], vfl[nt][2], vfl[nt][3], addr + 9216);
            }
#pragma unroll
            for (int n8 = 0; n8 < 8; n8++) {
                const int nt = n8 >> 1, hh = (n8 & 1) * 2;
                MMAF16(oacc[n8], pah, vfh[nt][hh], vfh[nt][hh + 1]);
            }
#pragma unroll
            for (int n8 = 0; n8 < 8; n8++) {
                const int nt = n8 >> 1, hh = (n8 & 1) * 2;
                MMAF16(oacc[n8], pah, vfl[nt][hh], vfl[nt][hh + 1]);
            }
        }

        CPWAIT0();
        __syncthreads();
    }

    rs0 += __shfl_xor_sync(0xffffffffu, rs0, 1);
    rs0 += __shfl_xor_sync(0xffffffffu, rs0, 2);
    rs1 += __shfl_xor_sync(0xffffffffu, rs1, 1);
    rs1 += __shfl_xor_sync(0xffffffffu, rs1, 2);

    if (w >= 8) {
        const uint32_t ob = sb + OSCR + (uint32_t)(w - 8) * 4096u;
#pragma unroll
        for (int n8 = 0; n8 < 8; n8++) {
            float4 t = make_float4(oacc[n8][0], oacc[n8][1], oacc[n8][2], oacc[n8][3]);
            *reinterpret_cast<float4*>(dsm + (ob - smem_u32(dsm)) + n8 * 512 + lane * 16) = t;
        }
        *reinterpret_cast<float2*>(dsm + (sb + RSCR - smem_u32(dsm)) + (w - 8) * 256 + lane * 8)
            = make_float2(rs0, rs1);
    }
    __syncthreads();
    if (w < 8) {
        const uint32_t ob = sb + OSCR + (uint32_t)w * 4096u;
        float2 prs = *reinterpret_cast<float2*>(
            dsm + (sb + RSCR - smem_u32(dsm)) + w * 256 + lane * 8);
        const float inv0 = 1.f / (rs0 + prs.x);
        const float inv1 = 1.f / (rs1 + prs.y);

        const int row0 = qbase + w * 16 + (lane >> 2);
        const int col0 = h * HDIM + (lane & 3) * 2;
#pragma unroll
        for (int n8 = 0; n8 < 8; n8++) {
            float4 t = *reinterpret_cast<float4*>(
                dsm + (ob - smem_u32(dsm)) + n8 * 512 + lane * 16);
            float x0 = (oacc[n8][0] + t.x) * inv0, x1 = (oacc[n8][1] + t.y) * inv0;
            float y0 = (oacc[n8][2] + t.z) * inv1, y1 = (oacc[n8][3] + t.w) * inv1;
            __half h0, l0, h1, l1;
            size_t i0 = (size_t)(b * SEQT + row0) * EMB + col0 + n8 * 8;
            size_t i1 = (size_t)(b * SEQT + row0 + 8) * EMB + col0 + n8 * 8;
            split_fp16(x0, h0, l0); split_fp16(x1, h1, l1);
            *reinterpret_cast<uint32_t*>(g_aoh + i0) = pack2h(h0, h1);
            *reinterpret_cast<uint32_t*>(g_aol + i0) = pack2h(l0, l1);
            split_fp16(y0, h0, l0); split_fp16(y1, h1, l1);
            *reinterpret_cast<uint32_t*>(g_aoh + i1) = pack2h(h0, h1);
            *reinterpret_cast<uint32_t*>(g_aol + i1) = pack2h(l0, l1);
        }
    }
}

// ---------------------------------------------------------------------------
// Launch
// ---------------------------------------------------------------------------
extern "C" void kernel_launch(void* const* d_in, const int* in_sizes, int n_in,
                              void* d_out, int out_size)
{
    const float*         query = (const float*)d_in[0];
    const float*         abias = (const float*)d_in[1];
    const unsigned char* kmask = (const unsigned char*)d_in[2];
    const float*         in_w  = (const float*)d_in[3];
    const float*         in_b  = (const float*)d_in[4];
    const float*         out_w = (const float*)d_in[5];
    const float*         out_b = (const float*)d_in[6];
    float*               out   = (float*)d_out;

    __half *xh, *xl, *w1, *w2, *aoh, *aol;
    float* v;
    cudaGetSymbolAddress((void**)&xh,  g_xh);
    cudaGetSymbolAddress((void**)&xl,  g_xl);
    cudaGetSymbolAddress((void**)&w1,  g_w1);
    cudaGetSymbolAddress((void**)&w2,  g_w2);
    cudaGetSymbolAddress((void**)&aoh, g_aoh);
    cudaGetSymbolAddress((void**)&aol, g_aol);
    cudaGetSymbolAddress((void**)&v,   g_v);

    cudaFuncSetAttribute(gemm_f16_kernel<0>,
                         cudaFuncAttributeMaxDynamicSharedMemorySize, GEMM_SMEM);
    cudaFuncSetAttribute(gemm_f16_kernel<1>,
                         cudaFuncAttributeMaxDynamicSharedMemorySize, GEMM_SMEM);
    cudaFuncSetAttribute(attn_mma_kernel,
                         cudaFuncAttributeMaxDynamicSharedMemorySize, ATTN_SMEM);

    // 0) operand conversion: query -> fp16 hi/lo; weights -> fp16
    splitH_kernel<<<(MTOK * EMB / 4 + 255) / 256, 256>>>(query, xh, xl, MTOK * EMB / 4);
    half_kernel<<<(E3 * EMB / 4 + 255) / 256, 256>>>(in_w, w1, E3 * EMB / 4);
    half_kernel<<<(EMB * EMB / 4 + 255) / 256, 256>>>(out_w, w2, EMB * EMB / 4);

    // 1) QKV projection (fp16 x2) + fused fp16 q/k epilogue
    {
        dim3 grid(E3 / 128, MTOK / 128);
        gemm_f16_kernel<1><<<grid, 256, GEMM_SMEM>>>(xh, xl, w1, in_b, v, E3, EMB);
    }
    // 2) V transpose/split (fp16)
    {
        dim3 grid(SEQT / 64, BH);
        vprep_kernel<<<grid, 256>>>();
    }
    // 3) Attention
    {
        dim3 grid(SEQT / 128, BH);
        attn_mma_kernel<<<grid, 512, ATTN_SMEM>>>(abias, kmask);
    }
    // 4) Output projection (fp16 x2)
    {
        dim3 grid(EMB / 128, MTOK / 128);
        gemm_f16_kernel<0><<<grid, 256, GEMM_SMEM>>>(aoh, aol, w2, out_b, out, EMB, EMB);
    }
}

// round 11
// speedup vs baseline: 4.5803x; 1.1223x over previous
#include <cuda_runtime.h>
#include <cuda_bf16.h>
#include <cuda_fp16.h>
#include <cstdint>
#include <math.h>

#define BATCH 4
#define SEQT 1024
#define EMB 1024
#define NHEAD 16
#define HDIM 64
#define E3 (3 * EMB)
#define MTOK (BATCH * SEQT)
#define BH (BATCH * NHEAD)

// Scratch (fp16 operands)
__device__ __half g_xh [(size_t)MTOK * EMB];   // query fp16 hi
__device__ __half g_xl [(size_t)MTOK * EMB];   // query fp16 lo
__device__ __half g_w1 [(size_t)E3 * EMB];     // in_w fp16
__device__ __half g_w2 [(size_t)EMB * EMB];    // out_w fp16
__device__ float  g_v  [(size_t)MTOK * EMB];
__device__ __half g_aoh[(size_t)MTOK * EMB];   // attention out fp16 hi
__device__ __half g_aol[(size_t)MTOK * EMB];   // attention out fp16 lo
__device__ __half g_qf [(size_t)BH * SEQT * HDIM];
__device__ __half g_kh [(size_t)BH * SEQT * HDIM];
__device__ __half g_kl [(size_t)BH * SEQT * HDIM];
__device__ __half g_vth[(size_t)BH * HDIM * SEQT];  // V^T fp16 (single)

// ---------------------------------------------------------------------------
// helpers
// ---------------------------------------------------------------------------
__device__ __forceinline__ uint32_t smem_u32(const void* p) {
    uint32_t a;
    asm("{ .reg .u64 t; cvta.to.shared.u64 t, %1; cvt.u32.u64 %0, t; }"
        : "=r"(a) : "l"(p));
    return a;
}

#define LDM4(r0, r1, r2, r3, addr) \
    asm volatile("ldmatrix.sync.aligned.m8n8.x4.shared.b16 {%0,%1,%2,%3}, [%4];" \
                 : "=r"(r0), "=r"(r1), "=r"(r2), "=r"(r3) : "r"(addr))

#define MMAF16(d, a, b0, b1) \
    asm volatile("mma.sync.aligned.m16n8k16.row.col.f32.f16.f16.f32 " \
                 "{%0,%1,%2,%3},{%4,%5,%6,%7},{%8,%9},{%0,%1,%2,%3};" \
                 : "+f"((d)[0]), "+f"((d)[1]), "+f"((d)[2]), "+f"((d)[3]) \
                 : "r"((a)[0]), "r"((a)[1]), "r"((a)[2]), "r"((a)[3]), \
                   "r"(b0), "r"(b1))

#define CPASYNC16(sdst, gsrc) \
    asm volatile("cp.async.cg.shared.global [%0], [%1], 16;" \
                 :: "r"(sdst), "l"(gsrc) : "memory")
#define CPCOMMIT() asm volatile("cp.async.commit_group;" ::: "memory")
#define CPWAIT0()  asm volatile("cp.async.wait_group 0;" ::: "memory")
#define CPWAIT1()  asm volatile("cp.async.wait_group 1;" ::: "memory")

__device__ __forceinline__ void split_fp16(float x, __half& h, __half& l) {
    h = __float2half_rn(x);
    l = __float2half_rn(x - __half2float(h));
}
__device__ __forceinline__ uint32_t pack2h(__half a, __half b) {
    __half2 t(a, b);
    return *reinterpret_cast<uint32_t*>(&t);
}

// ---------------------------------------------------------------------------
// Elementwise converters
// ---------------------------------------------------------------------------
__global__ __launch_bounds__(256)
void splitH_kernel(const float* __restrict__ src,
                   __half* __restrict__ dh,
                   __half* __restrict__ dl, int n4)
{
    int i = blockIdx.x * 256 + threadIdx.x;
    if (i >= n4) return;
    float4 v = reinterpret_cast<const float4*>(src)[i];
    __half h0, l0, h1, l1, h2, l2, h3, l3;
    split_fp16(v.x, h0, l0); split_fp16(v.y, h1, l1);
    split_fp16(v.z, h2, l2); split_fp16(v.w, h3, l3);
    reinterpret_cast<uint2*>(dh)[i] = make_uint2(pack2h(h0, h1), pack2h(h2, h3));
    reinterpret_cast<uint2*>(dl)[i] = make_uint2(pack2h(l0, l1), pack2h(l2, l3));
}

__global__ __launch_bounds__(256)
void half_kernel(const float* __restrict__ src,
                 __half* __restrict__ dst, int n4)
{
    int i = blockIdx.x * 256 + threadIdx.x;
    if (i >= n4) return;
    float4 v = reinterpret_cast<const float4*>(src)[i];
    reinterpret_cast<uint2*>(dst)[i] =
        make_uint2(pack2h(__float2half_rn(v.x), __float2half_rn(v.y)),
                   pack2h(__float2half_rn(v.z), __float2half_rn(v.w)));
}

// ---------------------------------------------------------------------------
// fp16 x2 GEMM (unchanged from round 10)
// ---------------------------------------------------------------------------
#define STG_B 24576u
#define GEMM_SMEM (3 * 24576 + 128)

template<int EPI>
__global__ __launch_bounds__(256, 2)
void gemm_f16_kernel(const __half* __restrict__ Ah,
                     const __half* __restrict__ Al,
                     const __half* __restrict__ Bs,
                     const float* __restrict__ bias,
                     float* __restrict__ C,
                     int N, int K)
{
    extern __shared__ char dsm[];
    char* sp = dsm + ((128 - (smem_u32(dsm) & 127)) & 127);
    const uint32_t sb = smem_u32(sp);

    const int tid  = threadIdx.x;
    const int lane = tid & 31;
    const int wm   = (tid >> 5) & 3;
    const int wn   = tid >> 7;
    const int rowBase = blockIdx.y * 128;
    const int colBase = blockIdx.x * 128;

    float acc[2][8][4];
#pragma unroll
    for (int i = 0; i < 2; i++)
#pragma unroll
        for (int j = 0; j < 8; j++)
#pragma unroll
            for (int q = 0; q < 4; q++) acc[i][j][q] = 0.f;

    auto issue = [&](int it_, int stg) {
        const int kt = it_ * 32;
        const uint32_t so = sb + (uint32_t)stg * STG_B;
#pragma unroll
        for (int i = 0; i < 6; i++) {
            int g = tid + i * 256;
            int arr = g >> 9;
            int rem = g & 511;
            int row = rem >> 2, c = rem & 3;
            int cs = c ^ ((row >> 1) & 3);
            const __half* src;
            if (arr == 0)      src = Ah + (size_t)(rowBase + row) * K + kt + c * 8;
            else if (arr == 1) src = Al + (size_t)(rowBase + row) * K + kt + c * 8;
            else               src = Bs + (size_t)(colBase + row) * K + kt + c * 8;
            CPASYNC16(so + (uint32_t)arr * 8192u + (uint32_t)(row * 64 + cs * 16), src);
        }
    };

    const uint32_t aRow = (uint32_t)(wm * 32 + (lane & 15));
    const uint32_t aHi  = (uint32_t)(lane >> 4);
    const uint32_t aSwz = (aRow >> 1) & 3;
    const uint32_t bRow = (uint32_t)(wn * 64 + (lane & 7) + ((lane >> 4) << 3));
    const uint32_t bHi  = (uint32_t)((lane >> 3) & 1);
    const uint32_t bSwz = (bRow >> 1) & 3;

    const int NIT = K / 32;
    issue(0, 0); CPCOMMIT();
    issue(1, 1); CPCOMMIT();

    for (int it = 0; it < NIT; ++it) {
        const int cur = it % 3;
        CPWAIT1();
        __syncthreads();
        if (it + 2 < NIT) issue(it + 2, (it + 2) % 3);
        CPCOMMIT();

        const uint32_t tb = sb + (uint32_t)cur * STG_B;
#pragma unroll
        for (int ks = 0; ks < 2; ks++) {
            uint32_t ah[2][4], al[2][4], bs[4][4];
            const uint32_t caA = ((uint32_t)(ks * 2) + aHi) ^ aSwz;
            const uint32_t caB = ((uint32_t)(ks * 2) + bHi) ^ bSwz;
#pragma unroll
            for (int mi = 0; mi < 2; mi++) {
                uint32_t addr = tb + (aRow + mi * 16) * 64 + caA * 16;
                LDM4(ah[mi][0], ah[mi][1], ah[mi][2], ah[mi][3], addr);
                LDM4(al[mi][0], al[mi][1], al[mi][2], al[mi][3], addr + 8192);
            }
#pragma unroll
            for (int nt = 0; nt < 4; nt++) {
                uint32_t addr = tb + 16384u + (bRow + nt * 16) * 64 + caB * 16;
                LDM4(bs[nt][0], bs[nt][1], bs[nt][2], bs[nt][3], addr);
            }
#pragma unroll
            for (int mi = 0; mi < 2; mi++)
#pragma unroll
                for (int n8 = 0; n8 < 8; n8++) {
                    const int nt = n8 >> 1, hh = (n8 & 1) * 2;
                    MMAF16(acc[mi][n8], ah[mi], bs[nt][hh], bs[nt][hh + 1]);
                }
#pragma unroll
            for (int mi = 0; mi < 2; mi++)
#pragma unroll
                for (int n8 = 0; n8 < 8; n8++) {
                    const int nt = n8 >> 1, hh = (n8 & 1) * 2;
                    MMAF16(acc[mi][n8], al[mi], bs[nt][hh], bs[nt][hh + 1]);
                }
        }
    }

    const int r0 = rowBase + wm * 32 + (lane >> 2);
    const int c0 = colBase + wn * 64 + (lane & 3) * 2;

    if (EPI == 0) {
#pragma unroll
        for (int mi = 0; mi < 2; mi++)
#pragma unroll
            for (int n8 = 0; n8 < 8; n8++) {
                const int row = r0 + mi * 16;
                const int col = c0 + n8 * 8;
                const float2 bv = *reinterpret_cast<const float2*>(bias + col);
                float2 o0 = make_float2(acc[mi][n8][0] + bv.x, acc[mi][n8][1] + bv.y);
                float2 o1 = make_float2(acc[mi][n8][2] + bv.x, acc[mi][n8][3] + bv.y);
                *reinterpret_cast<float2*>(C + (size_t)row * N + col)       = o0;
                *reinterpret_cast<float2*>(C + (size_t)(row + 8) * N + col) = o1;
            }
    } else {
        auto wr = [&](int row, int col, float x0, float x1) {
            const int sect = col >> 10;
            const int coli = col & 1023;
            const int bb = row >> 10, t = row & 1023;
            if (sect == 2) {
                *reinterpret_cast<float2*>(C + (size_t)row * 1024 + coli) =
                    make_float2(x0, x1);
            } else {
                const int hh = coli >> 6, d = coli & 63;
                const size_t idx = ((size_t)(bb * 16 + hh) * 1024 + t) * 64 + d;
                if (sect == 0) {
                    __half q0 = __float2half_rn(x0 * 0.125f);
                    __half q1 = __float2half_rn(x1 * 0.125f);
                    *reinterpret_cast<uint32_t*>(g_qf + idx) = pack2h(q0, q1);
                } else {
                    __half h0, l0, h1, l1;
                    split_fp16(x0, h0, l0); split_fp16(x1, h1, l1);
                    *reinterpret_cast<uint32_t*>(g_kh + idx) = pack2h(h0, h1);
                    *reinterpret_cast<uint32_t*>(g_kl + idx) = pack2h(l0, l1);
                }
            }
        };
#pragma unroll
        for (int mi = 0; mi < 2; mi++)
#pragma unroll
            for (int n8 = 0; n8 < 8; n8++) {
                const int row = r0 + mi * 16;
                const int col = c0 + n8 * 8;
                const float2 bv = *reinterpret_cast<const float2*>(bias + col);
                wr(row,     col, acc[mi][n8][0] + bv.x, acc[mi][n8][1] + bv.y);
                wr(row + 8, col, acc[mi][n8][2] + bv.x, acc[mi][n8][3] + bv.y);
            }
    }
}

// ---------------------------------------------------------------------------
// V prepass: g_v fp32 -> transposed single fp16 [bh][d][t]
// ---------------------------------------------------------------------------
__global__ __launch_bounds__(256)
void vprep_kernel()
{
    __shared__ float vs[64][65];
    const int bh = blockIdx.y;
    const int b  = bh >> 4;
    const int h  = bh & 15;
    const int t0 = blockIdx.x * 64;
    const int tid = threadIdx.x;

    {
        const int r  = tid >> 2;
        const int dg = (tid & 3) * 16;
        const float* vp = g_v + (size_t)(b * SEQT + t0 + r) * EMB + h * HDIM + dg;
#pragma unroll
        for (int j = 0; j < 4; j++) {
            float4 t = reinterpret_cast<const float4*>(vp)[j];
            vs[r][dg + 4 * j + 0] = t.x; vs[r][dg + 4 * j + 1] = t.y;
            vs[r][dg + 4 * j + 2] = t.z; vs[r][dg + 4 * j + 3] = t.w;
        }
    }
    __syncthreads();
    {
        const int d  = tid >> 2;
        const int tg = (tid & 3) * 16;
        uint32_t hw[8];
#pragma unroll
        for (int j = 0; j < 8; j++) {
            hw[j] = pack2h(__float2half_rn(vs[tg + 2 * j][d]),
                           __float2half_rn(vs[tg + 2 * j + 1][d]));
        }
        const size_t vo = ((size_t)bh * HDIM + d) * SEQT + t0 + tg;
        *reinterpret_cast<uint4*>(g_vth + vo)     = *reinterpret_cast<uint4*>(hw);
        *reinterpret_cast<uint4*>(g_vth + vo + 8) = *reinterpret_cast<uint4*>(hw + 4);
    }
}

// ---------------------------------------------------------------------------
// Flash attention v2: 256 q-rows/CTA, 32 q-rows per warp, key-split halves.
// S = Q(fp16) x K(fp16 hi/lo) x2; PV = P(fp16) x V(fp16 single) x1.
// grid (4, 64), block 512. Tensor-bound by design (LDSM per MMA halved).
// ---------------------------------------------------------------------------
#define AQF   0u
#define ABUF0 36864u
#define ABUF1 64512u
#define AMSK  92160u
#define OSCR  0u
#define RSCR  65536u
#define ATTN_SMEM (92160 + 4096 + 128)
#define RS 144u
#define EXPSHIFT 10.0f

__global__ __launch_bounds__(512, 1)
void attn_mma_kernel(const float* __restrict__ attn_bias,
                     const unsigned char* __restrict__ kmask)
{
    extern __shared__ char dsm[];
    char* sp = dsm + ((128 - (smem_u32(dsm) & 127)) & 127);
    const uint32_t sb = smem_u32(sp);

    const int bh = blockIdx.y;
    const int b  = bh >> 4;
    const int h  = bh & 15;
    const int qbase = blockIdx.x * 256;
    const int tid  = threadIdx.x;
    const int lane = tid & 31;
    const int w    = tid >> 5;
    const int wq   = w & 7;          // q-group of 32 rows
    const int kh2  = (w >> 3) * 32;  // key-half offset

    for (int i = tid; i < SEQT; i += 512)
        *reinterpret_cast<float*>(sp + AMSK + i * 4) =
            kmask[b * SEQT + i] ? -3.0e38f : 0.f;

    // stage Q fp16: 256 rows x 8 chunks = 2048
#pragma unroll
    for (int i = 0; i < 4; i++) {
        int g = tid + i * 512;
        int row = g >> 3, cc = g & 7;
        CPASYNC16(sb + AQF + row * RS + cc * 16,
                  g_qf + ((size_t)bh * SEQT + qbase + row) * HDIM + cc * 8);
    }

    auto load_kv = [&](int kb, uint32_t bufoff) {
#pragma unroll
        for (int i = 0; i < 3; i++) {
            int g = tid + i * 512;            // 0..1535
            int arr = g >> 9;                 // 0=Kh 1=Kl 2=V^T
            int rem = g & 511;
            int row = rem >> 3, cc = rem & 7;
            const void* src;
            if (arr == 0)      src = g_kh  + ((size_t)bh * SEQT + kb + row) * HDIM + cc * 8;
            else if (arr == 1) src = g_kl  + ((size_t)bh * SEQT + kb + row) * HDIM + cc * 8;
            else               src = g_vth + ((size_t)bh * HDIM + row) * SEQT + kb + cc * 8;
            CPASYNC16(sb + bufoff + (uint32_t)arr * 9216u + row * RS + cc * 16, src);
        }
    };

    load_kv(0, ABUF0);
    CPCOMMIT();
    CPWAIT0();
    __syncthreads();

    float oacc[2][8][4];
#pragma unroll
    for (int mi = 0; mi < 2; mi++)
#pragma unroll
        for (int i = 0; i < 8; i++)
#pragma unroll
            for (int j = 0; j < 4; j++) oacc[mi][i][j] = 0.f;
    float rsum[2][2] = {{0.f, 0.f}, {0.f, 0.f}};

    const uint32_t aColH = (uint32_t)((lane >> 4) * 8);
    const uint32_t aRowL = (uint32_t)(lane & 15);
    const uint32_t bRowB = (uint32_t)((lane & 7) + ((lane >> 4) << 3));
    const uint32_t bHi8  = (uint32_t)(((lane >> 3) & 1) * 8);
    const float* biasp = attn_bias + (size_t)bh * SEQT * SEQT +
        (size_t)(qbase + wq * 32 + (lane >> 2)) * SEQT + kh2 + (lane & 3) * 2;

    for (int it = 0; it < 16; ++it) {
        const int kb = it * 64;
        const uint32_t buf = (it & 1) ? ABUF1 : ABUF0;
        if (it + 1 < 16) {
            load_kv((it + 1) * 64, (it & 1) ? ABUF0 : ABUF1);
            CPCOMMIT();
        }

        // ---- S = Q K^T over 32-key half, 32 q-rows (fp16 x2) ----
        float sacc[2][4][4];
#pragma unroll
        for (int mi = 0; mi < 2; mi++)
#pragma unroll
            for (int i = 0; i < 4; i++)
#pragma unroll
                for (int j = 0; j < 4; j++) sacc[mi][i][j] = 0.f;

#pragma unroll
        for (int kc = 0; kc < 4; kc++) {
            uint32_t kfh[2][4], kfl[2][4];
#pragma unroll
            for (int nt = 0; nt < 2; nt++) {
                uint32_t addr = sb + buf + (kh2 + nt * 16 + bRowB) * RS + (kc * 16 + bHi8) * 2;
                LDM4(kfh[nt][0], kfh[nt][1], kfh[nt][2], kfh[nt][3], addr);
                LDM4(kfl[nt][0], kfl[nt][1], kfl[nt][2], kfl[nt][3], addr + 9216);
            }
#pragma unroll
            for (int mi = 0; mi < 2; mi++) {
                uint32_t qf[4];
                uint32_t qaddr = sb + AQF + (wq * 32 + mi * 16 + aRowL) * RS +
                                 (aColH + kc * 16) * 2;
                LDM4(qf[0], qf[1], qf[2], qf[3], qaddr);
#pragma unroll
                for (int n8 = 0; n8 < 4; n8++) {
                    const int nt = n8 >> 1, hh = (n8 & 1) * 2;
                    MMAF16(sacc[mi][n8], qf, kfh[nt][hh], kfh[nt][hh + 1]);
                }
#pragma unroll
                for (int n8 = 0; n8 < 4; n8++) {
                    const int nt = n8 >> 1, hh = (n8 & 1) * 2;
                    MMAF16(sacc[mi][n8], qf, kfl[nt][hh], kfl[nt][hh + 1]);
                }
            }
        }

        // ---- softmax numerators (shifted), P -> fp16 ----
        uint32_t pph[2][8];
#pragma unroll
        for (int mi = 0; mi < 2; mi++)
#pragma unroll
            for (int n8 = 0; n8 < 4; n8++) {
                float2 bias0 = *reinterpret_cast<const float2*>(
                    biasp + (size_t)mi * 16 * SEQT + kb + n8 * 8);
                float2 bias1 = *reinterpret_cast<const float2*>(
                    biasp + (size_t)(mi * 16 + 8) * SEQT + kb + n8 * 8);
                float2 mk = *reinterpret_cast<const float2*>(
                    sp + AMSK + (kb + kh2 + n8 * 8 + (lane & 3) * 2) * 4);
                float p0 = __expf(sacc[mi][n8][0] + bias0.x + mk.x - EXPSHIFT);
                float p1 = __expf(sacc[mi][n8][1] + bias0.y + mk.y - EXPSHIFT);
                float p2 = __expf(sacc[mi][n8][2] + bias1.x + mk.x - EXPSHIFT);
                float p3 = __expf(sacc[mi][n8][3] + bias1.y + mk.y - EXPSHIFT);
                rsum[mi][0] += p0 + p1;
                rsum[mi][1] += p2 + p3;
                __half2 a = __floats2half2_rn(p0, p1);
                __half2 bq = __floats2half2_rn(p2, p3);
                pph[mi][n8 * 2]     = *reinterpret_cast<uint32_t*>(&a);
                pph[mi][n8 * 2 + 1] = *reinterpret_cast<uint32_t*>(&bq);
            }

        // ---- O += P V over 32-key half (single V) ----
#pragma unroll
        for (int kc2 = 0; kc2 < 2; kc2++) {
            uint32_t vfh[4][4];
#pragma unroll
            for (int nt = 0; nt < 4; nt++) {
                uint32_t addr = sb + buf + 18432u + (bRowB + nt * 16) * RS +
                                (kh2 + kc2 * 16 + bHi8) * 2;
                LDM4(vfh[nt][0], vfh[nt][1], vfh[nt][2], vfh[nt][3], addr);
            }
#pragma unroll
            for (int mi = 0; mi < 2; mi++) {
                uint32_t pah[4] = { pph[mi][4 * kc2],     pph[mi][4 * kc2 + 1],
                                    pph[mi][4 * kc2 + 2], pph[mi][4 * kc2 + 3] };
#pragma unroll
                for (int n8 = 0; n8 < 8; n8++) {
                    const int nt = n8 >> 1, hh = (n8 & 1) * 2;
                    MMAF16(oacc[mi][n8], pah, vfh[nt][hh], vfh[nt][hh + 1]);
                }
            }
        }

        CPWAIT0();
        __syncthreads();
    }

    // quad-reduce partial row sums
#pragma unroll
    for (int mi = 0; mi < 2; mi++)
#pragma unroll
        for (int j = 0; j < 2; j++) {
            rsum[mi][j] += __shfl_xor_sync(0xffffffffu, rsum[mi][j], 1);
            rsum[mi][j] += __shfl_xor_sync(0xffffffffu, rsum[mi][j], 2);
        }

    // cross-half combine: warps 8-15 park O + l in smem (KV/Q areas dead)
    if (w >= 8) {
        const uint32_t ob = sb + OSCR + (uint32_t)(w - 8) * 8192u;
#pragma unroll
        for (int mi = 0; mi < 2; mi++)
#pragma unroll
            for (int n8 = 0; n8 < 8; n8++) {
                float4 t = make_float4(oacc[mi][n8][0], oacc[mi][n8][1],
                                       oacc[mi][n8][2], oacc[mi][n8][3]);
                *reinterpret_cast<float4*>(
                    dsm + (ob - smem_u32(dsm)) + mi * 4096 + n8 * 512 + lane * 16) = t;
            }
        *reinterpret_cast<float4*>(
            dsm + (sb + RSCR - smem_u32(dsm)) + (w - 8) * 512 + lane * 16) =
            make_float4(rsum[0][0], rsum[0][1], rsum[1][0], rsum[1][1]);
    }
    __syncthreads();
    if (w < 8) {
        const uint32_t ob = sb + OSCR + (uint32_t)w * 8192u;
        float4 prs = *reinterpret_cast<float4*>(
            dsm + (sb + RSCR - smem_u32(dsm)) + w * 512 + lane * 16);
        float inv[2][2];
        inv[0][0] = 1.f / (rsum[0][0] + prs.x);
        inv[0][1] = 1.f / (rsum[0][1] + prs.y);
        inv[1][0] = 1.f / (rsum[1][0] + prs.z);
        inv[1][1] = 1.f / (rsum[1][1] + prs.w);

        const int col0 = h * HDIM + (lane & 3) * 2;
#pragma unroll
        for (int mi = 0; mi < 2; mi++) {
            const int row0 = qbase + wq * 32 + mi * 16 + (lane >> 2);
#pragma unroll
            for (int n8 = 0; n8 < 8; n8++) {
                float4 t = *reinterpret_cast<float4*>(
                    dsm + (ob - smem_u32(dsm)) + mi * 4096 + n8 * 512 + lane * 16);
                float x0 = (oacc[mi][n8][0] + t.x) * inv[mi][0];
                float x1 = (oacc[mi][n8][1] + t.y) * inv[mi][0];
                float y0 = (oacc[mi][n8][2] + t.z) * inv[mi][1];
                float y1 = (oacc[mi][n8][3] + t.w) * inv[mi][1];
                __half h0, l0, h1, l1;
                size_t i0 = (size_t)(b * SEQT + row0) * EMB + col0 + n8 * 8;
                size_t i1 = (size_t)(b * SEQT + row0 + 8) * EMB + col0 + n8 * 8;
                split_fp16(x0, h0, l0); split_fp16(x1, h1, l1);
                *reinterpret_cast<uint32_t*>(g_aoh + i0) = pack2h(h0, h1);
                *reinterpret_cast<uint32_t*>(g_aol + i0) = pack2h(l0, l1);
                split_fp16(y0, h0, l0); split_fp16(y1, h1, l1);
                *reinterpret_cast<uint32_t*>(g_aoh + i1) = pack2h(h0, h1);
                *reinterpret_cast<uint32_t*>(g_aol + i1) = pack2h(l0, l1);
            }
        }
    }
}

// ---------------------------------------------------------------------------
// Launch
// ---------------------------------------------------------------------------
extern "C" void kernel_launch(void* const* d_in, const int* in_sizes, int n_in,
                              void* d_out, int out_size)
{
    const float*         query = (const float*)d_in[0];
    const float*         abias = (const float*)d_in[1];
    const unsigned char* kmask = (const unsigned char*)d_in[2];
    const float*         in_w  = (const float*)d_in[3];
    const float*         in_b  = (const float*)d_in[4];
    const float*         out_w = (const float*)d_in[5];
    const float*         out_b = (const float*)d_in[6];
    float*               out   = (float*)d_out;

    __half *xh, *xl, *w1, *w2, *aoh, *aol;
    float* v;
    cudaGetSymbolAddress((void**)&xh,  g_xh);
    cudaGetSymbolAddress((void**)&xl,  g_xl);
    cudaGetSymbolAddress((void**)&w1,  g_w1);
    cudaGetSymbolAddress((void**)&w2,  g_w2);
    cudaGetSymbolAddress((void**)&aoh, g_aoh);
    cudaGetSymbolAddress((void**)&aol, g_aol);
    cudaGetSymbolAddress((void**)&v,   g_v);

    cudaFuncSetAttribute(gemm_f16_kernel<0>,
                         cudaFuncAttributeMaxDynamicSharedMemorySize, GEMM_SMEM);
    cudaFuncSetAttribute(gemm_f16_kernel<1>,
                         cudaFuncAttributeMaxDynamicSharedMemorySize, GEMM_SMEM);
    cudaFuncSetAttribute(attn_mma_kernel,
                         cudaFuncAttributeMaxDynamicSharedMemorySize, ATTN_SMEM);

    // 0) operand conversion
    splitH_kernel<<<(MTOK * EMB / 4 + 255) / 256, 256>>>(query, xh, xl, MTOK * EMB / 4);
    half_kernel<<<(E3 * EMB / 4 + 255) / 256, 256>>>(in_w, w1, E3 * EMB / 4);
    half_kernel<<<(EMB * EMB / 4 + 255) / 256, 256>>>(out_w, w2, EMB * EMB / 4);

    // 1) QKV projection (fp16 x2) + fused fp16 q/k epilogue
    {
        dim3 grid(E3 / 128, MTOK / 128);
        gemm_f16_kernel<1><<<grid, 256, GEMM_SMEM>>>(xh, xl, w1, in_b, v, E3, EMB);
    }
    // 2) V transpose (single fp16)
    {
        dim3 grid(SEQT / 64, BH);
        vprep_kernel<<<grid, 256>>>();
    }
    // 3) Attention (256 q-rows/CTA)
    {
        dim3 grid(SEQT / 256, BH);
        attn_mma_kernel<<<grid, 512, ATTN_SMEM>>>(abias, kmask);
    }
    // 4) Output projection (fp16 x2)
    {
        dim3 grid(EMB / 128, MTOK / 128);
        gemm_f16_kernel<0><<<grid, 256, GEMM_SMEM>>>(aoh, aol, w2, out_b, out, EMB, EMB);
    }
}

// round 12
// speedup vs baseline: 5.3898x; 1.1767x over previous
#include <cuda_runtime.h>
#include <cuda_bf16.h>
#include <cuda_fp16.h>
#include <cstdint>
#include <math.h>

#define BATCH 4
#define SEQT 1024
#define EMB 1024
#define NHEAD 16
#define HDIM 64
#define E3 (3 * EMB)
#define MTOK (BATCH * SEQT)
#define BH (BATCH * NHEAD)

// Scratch (fp16 operands)
__device__ __half g_xh [(size_t)MTOK * EMB];   // query fp16 hi
__device__ __half g_xl [(size_t)MTOK * EMB];   // query fp16 lo
__device__ __half g_w1 [(size_t)E3 * EMB];     // in_w fp16
__device__ __half g_w2 [(size_t)EMB * EMB];    // out_w fp16
__device__ float  g_v  [(size_t)MTOK * EMB];
__device__ __half g_ao [(size_t)MTOK * EMB];   // attention out fp16 (single)
__device__ __half g_qf [(size_t)BH * SEQT * HDIM];
__device__ __half g_kh [(size_t)BH * SEQT * HDIM];
__device__ __half g_kl [(size_t)BH * SEQT * HDIM];
__device__ __half g_vth[(size_t)BH * HDIM * SEQT];  // V^T fp16 (single)

// ---------------------------------------------------------------------------
// helpers
// ---------------------------------------------------------------------------
__device__ __forceinline__ uint32_t smem_u32(const void* p) {
    uint32_t a;
    asm("{ .reg .u64 t; cvta.to.shared.u64 t, %1; cvt.u32.u64 %0, t; }"
        : "=r"(a) : "l"(p));
    return a;
}

#define LDM4(r0, r1, r2, r3, addr) \
    asm volatile("ldmatrix.sync.aligned.m8n8.x4.shared.b16 {%0,%1,%2,%3}, [%4];" \
                 : "=r"(r0), "=r"(r1), "=r"(r2), "=r"(r3) : "r"(addr))

#define MMAF16(d, a, b0, b1) \
    asm volatile("mma.sync.aligned.m16n8k16.row.col.f32.f16.f16.f32 " \
                 "{%0,%1,%2,%3},{%4,%5,%6,%7},{%8,%9},{%0,%1,%2,%3};" \
                 : "+f"((d)[0]), "+f"((d)[1]), "+f"((d)[2]), "+f"((d)[3]) \
                 : "r"((a)[0]), "r"((a)[1]), "r"((a)[2]), "r"((a)[3]), \
                   "r"(b0), "r"(b1))

#define CPASYNC16(sdst, gsrc) \
    asm volatile("cp.async.cg.shared.global [%0], [%1], 16;" \
                 :: "r"(sdst), "l"(gsrc) : "memory")
#define CPCOMMIT() asm volatile("cp.async.commit_group;" ::: "memory")
#define CPWAIT0()  asm volatile("cp.async.wait_group 0;" ::: "memory")
#define CPWAIT1()  asm volatile("cp.async.wait_group 1;" ::: "memory")

__device__ __forceinline__ void split_fp16(float x, __half& h, __half& l) {
    h = __float2half_rn(x);
    l = __float2half_rn(x - __half2float(h));
}
__device__ __forceinline__ uint32_t pack2h(__half a, __half b) {
    __half2 t(a, b);
    return *reinterpret_cast<uint32_t*>(&t);
}

// ---------------------------------------------------------------------------
// Elementwise converters
// ---------------------------------------------------------------------------
__global__ __launch_bounds__(256)
void splitH_kernel(const float* __restrict__ src,
                   __half* __restrict__ dh,
                   __half* __restrict__ dl, int n4)
{
    int i = blockIdx.x * 256 + threadIdx.x;
    if (i >= n4) return;
    float4 v = reinterpret_cast<const float4*>(src)[i];
    __half h0, l0, h1, l1, h2, l2, h3, l3;
    split_fp16(v.x, h0, l0); split_fp16(v.y, h1, l1);
    split_fp16(v.z, h2, l2); split_fp16(v.w, h3, l3);
    reinterpret_cast<uint2*>(dh)[i] = make_uint2(pack2h(h0, h1), pack2h(h2, h3));
    reinterpret_cast<uint2*>(dl)[i] = make_uint2(pack2h(l0, l1), pack2h(l2, l3));
}

__global__ __launch_bounds__(256)
void half_kernel(const float* __restrict__ src,
                 __half* __restrict__ dst, int n4)
{
    int i = blockIdx.x * 256 + threadIdx.x;
    if (i >= n4) return;
    float4 v = reinterpret_cast<const float4*>(src)[i];
    reinterpret_cast<uint2*>(dst)[i] =
        make_uint2(pack2h(__float2half_rn(v.x), __float2half_rn(v.y)),
                   pack2h(__float2half_rn(v.z), __float2half_rn(v.w)));
}

// ---------------------------------------------------------------------------
// fp16 GEMM with per-tile term count.
// EPI=1 (QKV): K-section tiles (colBase in [1024,2048)) use 2 terms (Ah+Al),
//              Q/V sections use 1 term (outputs are fp16-quantized anyway).
// EPI=0 (out-proj): 1 term always.
// ---------------------------------------------------------------------------
#define STG_B 24576u
#define GEMM_SMEM (3 * 24576 + 128)

template<int EPI>
__global__ __launch_bounds__(256, 2)
void gemm_f16_kernel(const __half* __restrict__ Ah,
                     const __half* __restrict__ Al,
                     const __half* __restrict__ Bs,
                     const float* __restrict__ bias,
                     float* __restrict__ C,
                     int N, int K)
{
    extern __shared__ char dsm[];
    char* sp = dsm + ((128 - (smem_u32(dsm) & 127)) & 127);
    const uint32_t sb = smem_u32(sp);

    const int tid  = threadIdx.x;
    const int lane = tid & 31;
    const int wm   = (tid >> 5) & 3;
    const int wn   = tid >> 7;
    const int rowBase = blockIdx.y * 128;
    const int colBase = blockIdx.x * 128;
    const bool two_terms = (EPI == 1) && ((colBase >> 10) == 1);

    float acc[2][8][4];
#pragma unroll
    for (int i = 0; i < 2; i++)
#pragma unroll
        for (int j = 0; j < 8; j++)
#pragma unroll
            for (int q = 0; q < 4; q++) acc[i][j][q] = 0.f;

    auto issue = [&](int it_, int stg) {
        const int kt = it_ * 32;
        const uint32_t so = sb + (uint32_t)stg * STG_B;
#pragma unroll
        for (int i = 0; i < 6; i++) {
            int g = tid + i * 256;
            int arr = g >> 9;
            int rem = g & 511;
            int row = rem >> 2, c = rem & 3;
            int cs = c ^ ((row >> 1) & 3);
            const __half* src;
            if (arr == 0)      src = Ah + (size_t)(rowBase + row) * K + kt + c * 8;
            else if (arr == 1) {
                if (!two_terms) continue;
                src = Al + (size_t)(rowBase + row) * K + kt + c * 8;
            }
            else               src = Bs + (size_t)(colBase + row) * K + kt + c * 8;
            CPASYNC16(so + (uint32_t)arr * 8192u + (uint32_t)(row * 64 + cs * 16), src);
        }
    };

    const uint32_t aRow = (uint32_t)(wm * 32 + (lane & 15));
    const uint32_t aHi  = (uint32_t)(lane >> 4);
    const uint32_t aSwz = (aRow >> 1) & 3;
    const uint32_t bRow = (uint32_t)(wn * 64 + (lane & 7) + ((lane >> 4) << 3));
    const uint32_t bHi  = (uint32_t)((lane >> 3) & 1);
    const uint32_t bSwz = (bRow >> 1) & 3;

    const int NIT = K / 32;
    issue(0, 0); CPCOMMIT();
    issue(1, 1); CPCOMMIT();

    for (int it = 0; it < NIT; ++it) {
        const int cur = it % 3;
        CPWAIT1();
        __syncthreads();
        if (it + 2 < NIT) issue(it + 2, (it + 2) % 3);
        CPCOMMIT();

        const uint32_t tb = sb + (uint32_t)cur * STG_B;
#pragma unroll
        for (int ks = 0; ks < 2; ks++) {
            uint32_t ah[2][4], al[2][4], bs[4][4];
            const uint32_t caA = ((uint32_t)(ks * 2) + aHi) ^ aSwz;
            const uint32_t caB = ((uint32_t)(ks * 2) + bHi) ^ bSwz;
#pragma unroll
            for (int mi = 0; mi < 2; mi++) {
                uint32_t addr = tb + (aRow + mi * 16) * 64 + caA * 16;
                LDM4(ah[mi][0], ah[mi][1], ah[mi][2], ah[mi][3], addr);
            }
            if (two_terms) {
#pragma unroll
                for (int mi = 0; mi < 2; mi++) {
                    uint32_t addr = tb + (aRow + mi * 16) * 64 + caA * 16;
                    LDM4(al[mi][0], al[mi][1], al[mi][2], al[mi][3], addr + 8192);
                }
            }
#pragma unroll
            for (int nt = 0; nt < 4; nt++) {
                uint32_t addr = tb + 16384u + (bRow + nt * 16) * 64 + caB * 16;
                LDM4(bs[nt][0], bs[nt][1], bs[nt][2], bs[nt][3], addr);
            }
#pragma unroll
            for (int mi = 0; mi < 2; mi++)
#pragma unroll
                for (int n8 = 0; n8 < 8; n8++) {
                    const int nt = n8 >> 1, hh = (n8 & 1) * 2;
                    MMAF16(acc[mi][n8], ah[mi], bs[nt][hh], bs[nt][hh + 1]);
                }
            if (two_terms) {
#pragma unroll
                for (int mi = 0; mi < 2; mi++)
#pragma unroll
                    for (int n8 = 0; n8 < 8; n8++) {
                        const int nt = n8 >> 1, hh = (n8 & 1) * 2;
                        MMAF16(acc[mi][n8], al[mi], bs[nt][hh], bs[nt][hh + 1]);
                    }
            }
        }
    }

    const int r0 = rowBase + wm * 32 + (lane >> 2);
    const int c0 = colBase + wn * 64 + (lane & 3) * 2;

    if (EPI == 0) {
#pragma unroll
        for (int mi = 0; mi < 2; mi++)
#pragma unroll
            for (int n8 = 0; n8 < 8; n8++) {
                const int row = r0 + mi * 16;
                const int col = c0 + n8 * 8;
                const float2 bv = *reinterpret_cast<const float2*>(bias + col);
                float2 o0 = make_float2(acc[mi][n8][0] + bv.x, acc[mi][n8][1] + bv.y);
                float2 o1 = make_float2(acc[mi][n8][2] + bv.x, acc[mi][n8][3] + bv.y);
                *reinterpret_cast<float2*>(C + (size_t)row * N + col)       = o0;
                *reinterpret_cast<float2*>(C + (size_t)(row + 8) * N + col) = o1;
            }
    } else {
        auto wr = [&](int row, int col, float x0, float x1) {
            const int sect = col >> 10;
            const int coli = col & 1023;
            const int bb = row >> 10, t = row & 1023;
            if (sect == 2) {
                *reinterpret_cast<float2*>(C + (size_t)row * 1024 + coli) =
                    make_float2(x0, x1);
            } else {
                const int hh = coli >> 6, d = coli & 63;
                const size_t idx = ((size_t)(bb * 16 + hh) * 1024 + t) * 64 + d;
                if (sect == 0) {
                    __half q0 = __float2half_rn(x0 * 0.125f);
                    __half q1 = __float2half_rn(x1 * 0.125f);
                    *reinterpret_cast<uint32_t*>(g_qf + idx) = pack2h(q0, q1);
                } else {
                    __half h0, l0, h1, l1;
                    split_fp16(x0, h0, l0); split_fp16(x1, h1, l1);
                    *reinterpret_cast<uint32_t*>(g_kh + idx) = pack2h(h0, h1);
                    *reinterpret_cast<uint32_t*>(g_kl + idx) = pack2h(l0, l1);
                }
            }
        };
#pragma unroll
        for (int mi = 0; mi < 2; mi++)
#pragma unroll
            for (int n8 = 0; n8 < 8; n8++) {
                const int row = r0 + mi * 16;
                const int col = c0 + n8 * 8;
                const float2 bv = *reinterpret_cast<const float2*>(bias + col);
                wr(row,     col, acc[mi][n8][0] + bv.x, acc[mi][n8][1] + bv.y);
                wr(row + 8, col, acc[mi][n8][2] + bv.x, acc[mi][n8][3] + bv.y);
            }
    }
}

// ---------------------------------------------------------------------------
// V prepass: g_v fp32 -> transposed single fp16 [bh][d][t]
// ---------------------------------------------------------------------------
__global__ __launch_bounds__(256)
void vprep_kernel()
{
    __shared__ float vs[64][65];
    const int bh = blockIdx.y;
    const int b  = bh >> 4;
    const int h  = bh & 15;
    const int t0 = blockIdx.x * 64;
    const int tid = threadIdx.x;

    {
        const int r  = tid >> 2;
        const int dg = (tid & 3) * 16;
        const float* vp = g_v + (size_t)(b * SEQT + t0 + r) * EMB + h * HDIM + dg;
#pragma unroll
        for (int j = 0; j < 4; j++) {
            float4 t = reinterpret_cast<const float4*>(vp)[j];
            vs[r][dg + 4 * j + 0] = t.x; vs[r][dg + 4 * j + 1] = t.y;
            vs[r][dg + 4 * j + 2] = t.z; vs[r][dg + 4 * j + 3] = t.w;
        }
    }
    __syncthreads();
    {
        const int d  = tid >> 2;
        const int tg = (tid & 3) * 16;
        uint32_t hw[8];
#pragma unroll
        for (int j = 0; j < 8; j++) {
            hw[j] = pack2h(__float2half_rn(vs[tg + 2 * j][d]),
                           __float2half_rn(vs[tg + 2 * j + 1][d]));
        }
        const size_t vo = ((size_t)bh * HDIM + d) * SEQT + t0 + tg;
        *reinterpret_cast<uint4*>(g_vth + vo)     = *reinterpret_cast<uint4*>(hw);
        *reinterpret_cast<uint4*>(g_vth + vo + 8) = *reinterpret_cast<uint4*>(hw + 4);
    }
}

// ---------------------------------------------------------------------------
// Flash attention (round-11 structure): 256 q-rows/CTA, 32 q-rows/warp,
// key-split halves. O epilogue writes single fp16.
// ---------------------------------------------------------------------------
#define AQF   0u
#define ABUF0 36864u
#define ABUF1 64512u
#define AMSK  92160u
#define OSCR  0u
#define RSCR  65536u
#define ATTN_SMEM (92160 + 4096 + 128)
#define RS 144u
#define EXPSHIFT 10.0f

__global__ __launch_bounds__(512, 1)
void attn_mma_kernel(const float* __restrict__ attn_bias,
                     const unsigned char* __restrict__ kmask)
{
    extern __shared__ char dsm[];
    char* sp = dsm + ((128 - (smem_u32(dsm) & 127)) & 127);
    const uint32_t sb = smem_u32(sp);

    const int bh = blockIdx.y;
    const int b  = bh >> 4;
    const int h  = bh & 15;
    const int qbase = blockIdx.x * 256;
    const int tid  = threadIdx.x;
    const int lane = tid & 31;
    const int w    = tid >> 5;
    const int wq   = w & 7;
    const int kh2  = (w >> 3) * 32;

    for (int i = tid; i < SEQT; i += 512)
        *reinterpret_cast<float*>(sp + AMSK + i * 4) =
            kmask[b * SEQT + i] ? -3.0e38f : 0.f;

#pragma unroll
    for (int i = 0; i < 4; i++) {
        int g = tid + i * 512;
        int row = g >> 3, cc = g & 7;
        CPASYNC16(sb + AQF + row * RS + cc * 16,
                  g_qf + ((size_t)bh * SEQT + qbase + row) * HDIM + cc * 8);
    }

    auto load_kv = [&](int kb, uint32_t bufoff) {
#pragma unroll
        for (int i = 0; i < 3; i++) {
            int g = tid + i * 512;
            int arr = g >> 9;
            int rem = g & 511;
            int row = rem >> 3, cc = rem & 7;
            const void* src;
            if (arr == 0)      src = g_kh  + ((size_t)bh * SEQT + kb + row) * HDIM + cc * 8;
            else if (arr == 1) src = g_kl  + ((size_t)bh * SEQT + kb + row) * HDIM + cc * 8;
            else               src = g_vth + ((size_t)bh * HDIM + row) * SEQT + kb + cc * 8;
            CPASYNC16(sb + bufoff + (uint32_t)arr * 9216u + row * RS + cc * 16, src);
        }
    };

    load_kv(0, ABUF0);
    CPCOMMIT();
    CPWAIT0();
    __syncthreads();

    float oacc[2][8][4];
#pragma unroll
    for (int mi = 0; mi < 2; mi++)
#pragma unroll
        for (int i = 0; i < 8; i++)
#pragma unroll
            for (int j = 0; j < 4; j++) oacc[mi][i][j] = 0.f;
    float rsum[2][2] = {{0.f, 0.f}, {0.f, 0.f}};

    const uint32_t aColH = (uint32_t)((lane >> 4) * 8);
    const uint32_t aRowL = (uint32_t)(lane & 15);
    const uint32_t bRowB = (uint32_t)((lane & 7) + ((lane >> 4) << 3));
    const uint32_t bHi8  = (uint32_t)(((lane >> 3) & 1) * 8);
    const float* biasp = attn_bias + (size_t)bh * SEQT * SEQT +
        (size_t)(qbase + wq * 32 + (lane >> 2)) * SEQT + kh2 + (lane & 3) * 2;

    for (int it = 0; it < 16; ++it) {
        const int kb = it * 64;
        const uint32_t buf = (it & 1) ? ABUF1 : ABUF0;
        if (it + 1 < 16) {
            load_kv((it + 1) * 64, (it & 1) ? ABUF0 : ABUF1);
            CPCOMMIT();
        }

        float sacc[2][4][4];
#pragma unroll
        for (int mi = 0; mi < 2; mi++)
#pragma unroll
            for (int i = 0; i < 4; i++)
#pragma unroll
                for (int j = 0; j < 4; j++) sacc[mi][i][j] = 0.f;

#pragma unroll
        for (int kc = 0; kc < 4; kc++) {
            uint32_t kfh[2][4], kfl[2][4];
#pragma unroll
            for (int nt = 0; nt < 2; nt++) {
                uint32_t addr = sb + buf + (kh2 + nt * 16 + bRowB) * RS + (kc * 16 + bHi8) * 2;
                LDM4(kfh[nt][0], kfh[nt][1], kfh[nt][2], kfh[nt][3], addr);
                LDM4(kfl[nt][0], kfl[nt][1], kfl[nt][2], kfl[nt][3], addr + 9216);
            }
#pragma unroll
            for (int mi = 0; mi < 2; mi++) {
                uint32_t qf[4];
                uint32_t qaddr = sb + AQF + (wq * 32 + mi * 16 + aRowL) * RS +
                                 (aColH + kc * 16) * 2;
                LDM4(qf[0], qf[1], qf[2], qf[3], qaddr);
#pragma unroll
                for (int n8 = 0; n8 < 4; n8++) {
                    const int nt = n8 >> 1, hh = (n8 & 1) * 2;
                    MMAF16(sacc[mi][n8], qf, kfh[nt][hh], kfh[nt][hh + 1]);
                }
#pragma unroll
                for (int n8 = 0; n8 < 4; n8++) {
                    const int nt = n8 >> 1, hh = (n8 & 1) * 2;
                    MMAF16(sacc[mi][n8], qf, kfl[nt][hh], kfl[nt][hh + 1]);
                }
            }
        }

        uint32_t pph[2][8];
#pragma unroll
        for (int mi = 0; mi < 2; mi++)
#pragma unroll
            for (int n8 = 0; n8 < 4; n8++) {
                float2 bias0 = *reinterpret_cast<const float2*>(
                    biasp + (size_t)mi * 16 * SEQT + kb + n8 * 8);
                float2 bias1 = *reinterpret_cast<const float2*>(
                    biasp + (size_t)(mi * 16 + 8) * SEQT + kb + n8 * 8);
                float2 mk = *reinterpret_cast<const float2*>(
                    sp + AMSK + (kb + kh2 + n8 * 8 + (lane & 3) * 2) * 4);
                float p0 = __expf(sacc[mi][n8][0] + bias0.x + mk.x - EXPSHIFT);
                float p1 = __expf(sacc[mi][n8][1] + bias0.y + mk.y - EXPSHIFT);
                float p2 = __expf(sacc[mi][n8][2] + bias1.x + mk.x - EXPSHIFT);
                float p3 = __expf(sacc[mi][n8][3] + bias1.y + mk.y - EXPSHIFT);
                rsum[mi][0] += p0 + p1;
                rsum[mi][1] += p2 + p3;
                __half2 a = __floats2half2_rn(p0, p1);
                __half2 bq = __floats2half2_rn(p2, p3);
                pph[mi][n8 * 2]     = *reinterpret_cast<uint32_t*>(&a);
                pph[mi][n8 * 2 + 1] = *reinterpret_cast<uint32_t*>(&bq);
            }

#pragma unroll
        for (int kc2 = 0; kc2 < 2; kc2++) {
            uint32_t vfh[4][4];
#pragma unroll
            for (int nt = 0; nt < 4; nt++) {
                uint32_t addr = sb + buf + 18432u + (bRowB + nt * 16) * RS +
                                (kh2 + kc2 * 16 + bHi8) * 2;
                LDM4(vfh[nt][0], vfh[nt][1], vfh[nt][2], vfh[nt][3], addr);
            }
#pragma unroll
            for (int mi = 0; mi < 2; mi++) {
                uint32_t pah[4] = { pph[mi][4 * kc2],     pph[mi][4 * kc2 + 1],
                                    pph[mi][4 * kc2 + 2], pph[mi][4 * kc2 + 3] };
#pragma unroll
                for (int n8 = 0; n8 < 8; n8++) {
                    const int nt = n8 >> 1, hh = (n8 & 1) * 2;
                    MMAF16(oacc[mi][n8], pah, vfh[nt][hh], vfh[nt][hh + 1]);
                }
            }
        }

        CPWAIT0();
        __syncthreads();
    }

#pragma unroll
    for (int mi = 0; mi < 2; mi++)
#pragma unroll
        for (int j = 0; j < 2; j++) {
            rsum[mi][j] += __shfl_xor_sync(0xffffffffu, rsum[mi][j], 1);
            rsum[mi][j] += __shfl_xor_sync(0xffffffffu, rsum[mi][j], 2);
        }

    if (w >= 8) {
        const uint32_t ob = sb + OSCR + (uint32_t)(w - 8) * 8192u;
#pragma unroll
        for (int mi = 0; mi < 2; mi++)
#pragma unroll
            for (int n8 = 0; n8 < 8; n8++) {
                float4 t = make_float4(oacc[mi][n8][0], oacc[mi][n8][1],
                                       oacc[mi][n8][2], oacc[mi][n8][3]);
                *reinterpret_cast<float4*>(
                    dsm + (ob - smem_u32(dsm)) + mi * 4096 + n8 * 512 + lane * 16) = t;
            }
        *reinterpret_cast<float4*>(
            dsm + (sb + RSCR - smem_u32(dsm)) + (w - 8) * 512 + lane * 16) =
            make_float4(rsum[0][0], rsum[0][1], rsum[1][0], rsum[1][1]);
    }
    __syncthreads();
    if (w < 8) {
        const uint32_t ob = sb + OSCR + (uint32_t)w * 8192u;
        float4 prs = *reinterpret_cast<float4*>(
            dsm + (sb + RSCR - smem_u32(dsm)) + w * 512 + lane * 16);
        float inv[2][2];
        inv[0][0] = 1.f / (rsum[0][0] + prs.x);
        inv[0][1] = 1.f / (rsum[0][1] + prs.y);
        inv[1][0] = 1.f / (rsum[1][0] + prs.z);
        inv[1][1] = 1.f / (rsum[1][1] + prs.w);

        const int col0 = h * HDIM + (lane & 3) * 2;
#pragma unroll
        for (int mi = 0; mi < 2; mi++) {
            const int row0 = qbase + wq * 32 + mi * 16 + (lane >> 2);
#pragma unroll
            for (int n8 = 0; n8 < 8; n8++) {
                float4 t = *reinterpret_cast<float4*>(
                    dsm + (ob - smem_u32(dsm)) + mi * 4096 + n8 * 512 + lane * 16);
                float x0 = (oacc[mi][n8][0] + t.x) * inv[mi][0];
                float x1 = (oacc[mi][n8][1] + t.y) * inv[mi][0];
                float y0 = (oacc[mi][n8][2] + t.z) * inv[mi][1];
                float y1 = (oacc[mi][n8][3] + t.w) * inv[mi][1];
                size_t i0 = (size_t)(b * SEQT + row0) * EMB + col0 + n8 * 8;
                size_t i1 = (size_t)(b * SEQT + row0 + 8) * EMB + col0 + n8 * 8;
                *reinterpret_cast<uint32_t*>(g_ao + i0) =
                    pack2h(__float2half_rn(x0), __float2half_rn(x1));
                *reinterpret_cast<uint32_t*>(g_ao + i1) =
                    pack2h(__float2half_rn(y0), __float2half_rn(y1));
            }
        }
    }
}

// ---------------------------------------------------------------------------
// Launch
// ---------------------------------------------------------------------------
extern "C" void kernel_launch(void* const* d_in, const int* in_sizes, int n_in,
                              void* d_out, int out_size)
{
    const float*         query = (const float*)d_in[0];
    const float*         abias = (const float*)d_in[1];
    const unsigned char* kmask = (const unsigned char*)d_in[2];
    const float*         in_w  = (const float*)d_in[3];
    const float*         in_b  = (const float*)d_in[4];
    const float*         out_w = (const float*)d_in[5];
    const float*         out_b = (const float*)d_in[6];
    float*               out   = (float*)d_out;

    __half *xh, *xl, *w1, *w2, *ao;
    float* v;
    cudaGetSymbolAddress((void**)&xh, g_xh);
    cudaGetSymbolAddress((void**)&xl, g_xl);
    cudaGetSymbolAddress((void**)&w1, g_w1);
    cudaGetSymbolAddress((void**)&w2, g_w2);
    cudaGetSymbolAddress((void**)&ao, g_ao);
    cudaGetSymbolAddress((void**)&v,  g_v);

    cudaFuncSetAttribute(gemm_f16_kernel<0>,
                         cudaFuncAttributeMaxDynamicSharedMemorySize, GEMM_SMEM);
    cudaFuncSetAttribute(gemm_f16_kernel<1>,
                         cudaFuncAttributeMaxDynamicSharedMemorySize, GEMM_SMEM);
    cudaFuncSetAttribute(attn_mma_kernel,
                         cudaFuncAttributeMaxDynamicSharedMemorySize, ATTN_SMEM);

    // 0) operand conversion
    splitH_kernel<<<(MTOK * EMB / 4 + 255) / 256, 256>>>(query, xh, xl, MTOK * EMB / 4);
    half_kernel<<<(E3 * EMB / 4 + 255) / 256, 256>>>(in_w, w1, E3 * EMB / 4);
    half_kernel<<<(EMB * EMB / 4 + 255) / 256, 256>>>(out_w, w2, EMB * EMB / 4);

    // 1) QKV projection (x2 for K section, x1 for Q/V) + fused epilogue
    {
        dim3 grid(E3 / 128, MTOK / 128);
        gemm_f16_kernel<1><<<grid, 256, GEMM_SMEM>>>(xh, xl, w1, in_b, v, E3, EMB);
    }
    // 2) V transpose (single fp16)
    {
        dim3 grid(SEQT / 64, BH);
        vprep_kernel<<<grid, 256>>>();
    }
    // 3) Attention
    {
        dim3 grid(SEQT / 256, BH);
        attn_mma_kernel<<<grid, 512, ATTN_SMEM>>>(abias, kmask);
    }
    // 4) Output projection (x1)
    {
        dim3 grid(EMB / 128, MTOK / 128);
        gemm_f16_kernel<0><<<grid, 256, GEMM_SMEM>>>(ao, ao, w2, out_b, out, EMB, EMB);
    }
}

// round 13
// speedup vs baseline: 6.0973x; 1.1313x over previous
#include <cuda_runtime.h>
#include <cuda_bf16.h>
#include <cuda_fp16.h>
#include <cstdint>
#include <math.h>

#define BATCH 4
#define SEQT 1024
#define EMB 1024
#define NHEAD 16
#define HDIM 64
#define E3 (3 * EMB)
#define MTOK (BATCH * SEQT)
#define BH (BATCH * NHEAD)

// Scratch (fp16 operands)
__device__ __half g_xh [(size_t)MTOK * EMB];   // query fp16 hi
__device__ __half g_xl [(size_t)MTOK * EMB];   // query fp16 lo
__device__ __half g_w1 [(size_t)E3 * EMB];     // in_w fp16
__device__ __half g_w2 [(size_t)EMB * EMB];    // out_w fp16
__device__ __half g_ao [(size_t)MTOK * EMB];   // attention out fp16
__device__ __half g_qf [(size_t)BH * SEQT * HDIM];
__device__ __half g_kh [(size_t)BH * SEQT * HDIM];
__device__ __half g_kl [(size_t)BH * SEQT * HDIM];
__device__ __half g_vth[(size_t)BH * HDIM * SEQT];  // V^T fp16

// ---------------------------------------------------------------------------
// helpers
// ---------------------------------------------------------------------------
__device__ __forceinline__ uint32_t smem_u32(const void* p) {
    uint32_t a;
    asm("{ .reg .u64 t; cvta.to.shared.u64 t, %1; cvt.u32.u64 %0, t; }"
        : "=r"(a) : "l"(p));
    return a;
}

#define LDM4(r0, r1, r2, r3, addr) \
    asm volatile("ldmatrix.sync.aligned.m8n8.x4.shared.b16 {%0,%1,%2,%3}, [%4];" \
                 : "=r"(r0), "=r"(r1), "=r"(r2), "=r"(r3) : "r"(addr))

#define MMAF16(d, a, b0, b1) \
    asm volatile("mma.sync.aligned.m16n8k16.row.col.f32.f16.f16.f32 " \
                 "{%0,%1,%2,%3},{%4,%5,%6,%7},{%8,%9},{%0,%1,%2,%3};" \
                 : "+f"((d)[0]), "+f"((d)[1]), "+f"((d)[2]), "+f"((d)[3]) \
                 : "r"((a)[0]), "r"((a)[1]), "r"((a)[2]), "r"((a)[3]), \
                   "r"(b0), "r"(b1))

#define CPASYNC16(sdst, gsrc) \
    asm volatile("cp.async.cg.shared.global [%0], [%1], 16;" \
                 :: "r"(sdst), "l"(gsrc) : "memory")
#define CPCOMMIT() asm volatile("cp.async.commit_group;" ::: "memory")
#define CPWAIT0()  asm volatile("cp.async.wait_group 0;" ::: "memory")
#define CPWAIT1()  asm volatile("cp.async.wait_group 1;" ::: "memory")

__device__ __forceinline__ void split_fp16(float x, __half& h, __half& l) {
    h = __float2half_rn(x);
    l = __float2half_rn(x - __half2float(h));
}
__device__ __forceinline__ uint32_t pack2h(__half a, __half b) {
    __half2 t(a, b);
    return *reinterpret_cast<uint32_t*>(&t);
}

// ---------------------------------------------------------------------------
// Elementwise converters
// ---------------------------------------------------------------------------
__global__ __launch_bounds__(256)
void splitH_kernel(const float* __restrict__ src,
                   __half* __restrict__ dh,
                   __half* __restrict__ dl, int n4)
{
    int i = blockIdx.x * 256 + threadIdx.x;
    if (i >= n4) return;
    float4 v = reinterpret_cast<const float4*>(src)[i];
    __half h0, l0, h1, l1, h2, l2, h3, l3;
    split_fp16(v.x, h0, l0); split_fp16(v.y, h1, l1);
    split_fp16(v.z, h2, l2); split_fp16(v.w, h3, l3);
    reinterpret_cast<uint2*>(dh)[i] = make_uint2(pack2h(h0, h1), pack2h(h2, h3));
    reinterpret_cast<uint2*>(dl)[i] = make_uint2(pack2h(l0, l1), pack2h(l2, l3));
}

__global__ __launch_bounds__(256)
void half_kernel(const float* __restrict__ src,
                 __half* __restrict__ dst, int n4)
{
    int i = blockIdx.x * 256 + threadIdx.x;
    if (i >= n4) return;
    float4 v = reinterpret_cast<const float4*>(src)[i];
    reinterpret_cast<uint2*>(dst)[i] =
        make_uint2(pack2h(__float2half_rn(v.x), __float2half_rn(v.y)),
                   pack2h(__float2half_rn(v.z), __float2half_rn(v.w)));
}

// ---------------------------------------------------------------------------
// fp16 GEMM with per-tile term count (round-12 structure).
// EPI=1 (QKV): K-section tiles 2 terms; Q/V sections 1 term.
//   Epilogue: Q -> fp16 scaled; K -> fp16 hi/lo; V -> DIRECT transposed fp16.
// EPI=0 (out-proj): 1 term.
// ---------------------------------------------------------------------------
#define STG_B 24576u
#define GEMM_SMEM (3 * 24576 + 128)

template<int EPI>
__global__ __launch_bounds__(256, 2)
void gemm_f16_kernel(const __half* __restrict__ Ah,
                     const __half* __restrict__ Al,
                     const __half* __restrict__ Bs,
                     const float* __restrict__ bias,
                     float* __restrict__ C,
                     int N, int K)
{
    extern __shared__ char dsm[];
    char* sp = dsm + ((128 - (smem_u32(dsm) & 127)) & 127);
    const uint32_t sb = smem_u32(sp);

    const int tid  = threadIdx.x;
    const int lane = tid & 31;
    const int wm   = (tid >> 5) & 3;
    const int wn   = tid >> 7;
    const int rowBase = blockIdx.y * 128;
    const int colBase = blockIdx.x * 128;
    const bool two_terms = (EPI == 1) && ((colBase >> 10) == 1);

    float acc[2][8][4];
#pragma unroll
    for (int i = 0; i < 2; i++)
#pragma unroll
        for (int j = 0; j < 8; j++)
#pragma unroll
            for (int q = 0; q < 4; q++) acc[i][j][q] = 0.f;

    auto issue = [&](int it_, int stg) {
        const int kt = it_ * 32;
        const uint32_t so = sb + (uint32_t)stg * STG_B;
#pragma unroll
        for (int i = 0; i < 6; i++) {
            int g = tid + i * 256;
            int arr = g >> 9;
            int rem = g & 511;
            int row = rem >> 2, c = rem & 3;
            int cs = c ^ ((row >> 1) & 3);
            const __half* src;
            if (arr == 0)      src = Ah + (size_t)(rowBase + row) * K + kt + c * 8;
            else if (arr == 1) {
                if (!two_terms) continue;
                src = Al + (size_t)(rowBase + row) * K + kt + c * 8;
            }
            else               src = Bs + (size_t)(colBase + row) * K + kt + c * 8;
            CPASYNC16(so + (uint32_t)arr * 8192u + (uint32_t)(row * 64 + cs * 16), src);
        }
    };

    const uint32_t aRow = (uint32_t)(wm * 32 + (lane & 15));
    const uint32_t aHi  = (uint32_t)(lane >> 4);
    const uint32_t aSwz = (aRow >> 1) & 3;
    const uint32_t bRow = (uint32_t)(wn * 64 + (lane & 7) + ((lane >> 4) << 3));
    const uint32_t bHi  = (uint32_t)((lane >> 3) & 1);
    const uint32_t bSwz = (bRow >> 1) & 3;

    const int NIT = K / 32;
    issue(0, 0); CPCOMMIT();
    issue(1, 1); CPCOMMIT();

    for (int it = 0; it < NIT; ++it) {
        const int cur = it % 3;
        CPWAIT1();
        __syncthreads();
        if (it + 2 < NIT) issue(it + 2, (it + 2) % 3);
        CPCOMMIT();

        const uint32_t tb = sb + (uint32_t)cur * STG_B;
#pragma unroll
        for (int ks = 0; ks < 2; ks++) {
            uint32_t ah[2][4], al[2][4], bs[4][4];
            const uint32_t caA = ((uint32_t)(ks * 2) + aHi) ^ aSwz;
            const uint32_t caB = ((uint32_t)(ks * 2) + bHi) ^ bSwz;
#pragma unroll
            for (int mi = 0; mi < 2; mi++) {
                uint32_t addr = tb + (aRow + mi * 16) * 64 + caA * 16;
                LDM4(ah[mi][0], ah[mi][1], ah[mi][2], ah[mi][3], addr);
            }
            if (two_terms) {
#pragma unroll
                for (int mi = 0; mi < 2; mi++) {
                    uint32_t addr = tb + (aRow + mi * 16) * 64 + caA * 16;
                    LDM4(al[mi][0], al[mi][1], al[mi][2], al[mi][3], addr + 8192);
                }
            }
#pragma unroll
            for (int nt = 0; nt < 4; nt++) {
                uint32_t addr = tb + 16384u + (bRow + nt * 16) * 64 + caB * 16;
                LDM4(bs[nt][0], bs[nt][1], bs[nt][2], bs[nt][3], addr);
            }
#pragma unroll
            for (int mi = 0; mi < 2; mi++)
#pragma unroll
                for (int n8 = 0; n8 < 8; n8++) {
                    const int nt = n8 >> 1, hh = (n8 & 1) * 2;
                    MMAF16(acc[mi][n8], ah[mi], bs[nt][hh], bs[nt][hh + 1]);
                }
            if (two_terms) {
#pragma unroll
                for (int mi = 0; mi < 2; mi++)
#pragma unroll
                    for (int n8 = 0; n8 < 8; n8++) {
                        const int nt = n8 >> 1, hh = (n8 & 1) * 2;
                        MMAF16(acc[mi][n8], al[mi], bs[nt][hh], bs[nt][hh + 1]);
                    }
            }
        }
    }

    const int r0 = rowBase + wm * 32 + (lane >> 2);
    const int c0 = colBase + wn * 64 + (lane & 3) * 2;

    if (EPI == 0) {
#pragma unroll
        for (int mi = 0; mi < 2; mi++)
#pragma unroll
            for (int n8 = 0; n8 < 8; n8++) {
                const int row = r0 + mi * 16;
                const int col = c0 + n8 * 8;
                const float2 bv = *reinterpret_cast<const float2*>(bias + col);
                float2 o0 = make_float2(acc[mi][n8][0] + bv.x, acc[mi][n8][1] + bv.y);
                float2 o1 = make_float2(acc[mi][n8][2] + bv.x, acc[mi][n8][3] + bv.y);
                *reinterpret_cast<float2*>(C + (size_t)row * N + col)       = o0;
                *reinterpret_cast<float2*>(C + (size_t)(row + 8) * N + col) = o1;
            }
    } else {
        auto wr = [&](int row, int col, float x0, float x1) {
            const int sect = col >> 10;
            const int coli = col & 1023;
            const int bb = row >> 10, t = row & 1023;
            const int hh = coli >> 6, d = coli & 63;
            if (sect == 2) {
                // V: direct transposed fp16 write [bh][d][t]
                const size_t base = (size_t)(bb * 16 + hh) * HDIM;
                g_vth[(base + d)     * SEQT + t] = __float2half_rn(x0);
                g_vth[(base + d + 1) * SEQT + t] = __float2half_rn(x1);
            } else {
                const size_t idx = ((size_t)(bb * 16 + hh) * 1024 + t) * 64 + d;
                if (sect == 0) {
                    __half q0 = __float2half_rn(x0 * 0.125f);
                    __half q1 = __float2half_rn(x1 * 0.125f);
                    *reinterpret_cast<uint32_t*>(g_qf + idx) = pack2h(q0, q1);
                } else {
                    __half h0, l0, h1, l1;
                    split_fp16(x0, h0, l0); split_fp16(x1, h1, l1);
                    *reinterpret_cast<uint32_t*>(g_kh + idx) = pack2h(h0, h1);
                    *reinterpret_cast<uint32_t*>(g_kl + idx) = pack2h(l0, l1);
                }
            }
        };
#pragma unroll
        for (int mi = 0; mi < 2; mi++)
#pragma unroll
            for (int n8 = 0; n8 < 8; n8++) {
                const int row = r0 + mi * 16;
                const int col = c0 + n8 * 8;
                const float2 bv = *reinterpret_cast<const float2*>(bias + col);
                wr(row,     col, acc[mi][n8][0] + bv.x, acc[mi][n8][1] + bv.y);
                wr(row + 8, col, acc[mi][n8][2] + bv.x, acc[mi][n8][3] + bv.y);
            }
    }
}

// ---------------------------------------------------------------------------
// Flash attention: 256 q-rows/CTA, 32 q-rows/warp, key-split halves.
// Bias staged through smem (cp.async, double-buffered, 16B-chunk swizzle).
// Mask table pre-folds the -EXPSHIFT constant.
// ---------------------------------------------------------------------------
#define AQF   0u
#define ABUF0 36864u
#define ABUF1 64512u
#define AMSK  92160u
#define BIAS0 96256u
#define BIAS1 161792u
#define OSCR  0u
#define RSCR  65536u
#define ATTN_SMEM (227328 + 128)
#define RS 144u
#define EXPSHIFT 10.0f

__global__ __launch_bounds__(512, 1)
void attn_mma_kernel(const float* __restrict__ attn_bias,
                     const unsigned char* __restrict__ kmask)
{
    extern __shared__ char dsm[];
    char* sp = dsm + ((128 - (smem_u32(dsm) & 127)) & 127);
    const uint32_t sb = smem_u32(sp);

    const int bh = blockIdx.y;
    const int b  = bh >> 4;
    const int h  = bh & 15;
    const int qbase = blockIdx.x * 256;
    const int tid  = threadIdx.x;
    const int lane = tid & 31;
    const int w    = tid >> 5;
    const int wq   = w & 7;
    const int kh2  = (w >> 3) * 32;

    // mask table with EXPSHIFT folded in
    for (int i = tid; i < SEQT; i += 512)
        *reinterpret_cast<float*>(sp + AMSK + i * 4) =
            kmask[b * SEQT + i] ? -3.0e38f : -EXPSHIFT;

    // stage Q fp16
#pragma unroll
    for (int i = 0; i < 4; i++) {
        int g = tid + i * 512;
        int row = g >> 3, cc = g & 7;
        CPASYNC16(sb + AQF + row * RS + cc * 16,
                  g_qf + ((size_t)bh * SEQT + qbase + row) * HDIM + cc * 8);
    }

    const float* biasg = attn_bias + (size_t)bh * SEQT * SEQT;

    auto load_kv = [&](int kb, uint32_t bufoff) {
#pragma unroll
        for (int i = 0; i < 3; i++) {
            int g = tid + i * 512;
            int arr = g >> 9;
            int rem = g & 511;
            int row = rem >> 3, cc = rem & 7;
            const void* src;
            if (arr == 0)      src = g_kh  + ((size_t)bh * SEQT + kb + row) * HDIM + cc * 8;
            else if (arr == 1) src = g_kl  + ((size_t)bh * SEQT + kb + row) * HDIM + cc * 8;
            else               src = g_vth + ((size_t)bh * HDIM + row) * SEQT + kb + cc * 8;
            CPASYNC16(sb + bufoff + (uint32_t)arr * 9216u + row * RS + cc * 16, src);
        }
    };
    auto load_bias = [&](int kb, uint32_t bufoff) {
        // 256 rows x 64 cols fp32 = 4096 16B chunks; swizzle ch ^= row&15
#pragma unroll
        for (int i = 0; i < 8; i++) {
            int g = tid + i * 512;
            int row = g >> 4, ch = g & 15;
            CPASYNC16(sb + bufoff + (uint32_t)(row * 256) +
                          ((uint32_t)(ch ^ (row & 15)) << 4),
                      biasg + (size_t)(qbase + row) * SEQT + kb + ch * 4);
        }
    };

    load_kv(0, ABUF0);
    load_bias(0, BIAS0);
    CPCOMMIT();
    CPWAIT0();
    __syncthreads();

    float oacc[2][8][4];
#pragma unroll
    for (int mi = 0; mi < 2; mi++)
#pragma unroll
        for (int i = 0; i < 8; i++)
#pragma unroll
            for (int j = 0; j < 4; j++) oacc[mi][i][j] = 0.f;
    float rsum[2][2] = {{0.f, 0.f}, {0.f, 0.f}};

    const uint32_t aColH = (uint32_t)((lane >> 4) * 8);
    const uint32_t aRowL = (uint32_t)(lane & 15);
    const uint32_t bRowB = (uint32_t)((lane & 7) + ((lane >> 4) << 3));
    const uint32_t bHi8  = (uint32_t)(((lane >> 3) & 1) * 8);

    auto bias_rd = [&](uint32_t bbuf, int rloc, int col) -> float2 {
        uint32_t addr = bbuf + (uint32_t)(rloc * 256) +
            ((uint32_t)((col >> 2) ^ (rloc & 15)) << 4) + (uint32_t)((col & 3) << 2);
        return *reinterpret_cast<float2*>(sp + addr);
    };

    for (int it = 0; it < 16; ++it) {
        const int kb = it * 64;
        const uint32_t buf  = (it & 1) ? ABUF1 : ABUF0;
        const uint32_t bbuf = (it & 1) ? BIAS1 : BIAS0;
        if (it + 1 < 16) {
            load_kv((it + 1) * 64, (it & 1) ? ABUF0 : ABUF1);
            load_bias((it + 1) * 64, (it & 1) ? BIAS0 : BIAS1);
            CPCOMMIT();
        }

        float sacc[2][4][4];
#pragma unroll
        for (int mi = 0; mi < 2; mi++)
#pragma unroll
            for (int i = 0; i < 4; i++)
#pragma unroll
                for (int j = 0; j < 4; j++) sacc[mi][i][j] = 0.f;

#pragma unroll
        for (int kc = 0; kc < 4; kc++) {
            uint32_t kfh[2][4], kfl[2][4];
#pragma unroll
            for (int nt = 0; nt < 2; nt++) {
                uint32_t addr = sb + buf + (kh2 + nt * 16 + bRowB) * RS + (kc * 16 + bHi8) * 2;
                LDM4(kfh[nt][0], kfh[nt][1], kfh[nt][2], kfh[nt][3], addr);
                LDM4(kfl[nt][0], kfl[nt][1], kfl[nt][2], kfl[nt][3], addr + 9216);
            }
#pragma unroll
            for (int mi = 0; mi < 2; mi++) {
                uint32_t qf[4];
                uint32_t qaddr = sb + AQF + (wq * 32 + mi * 16 + aRowL) * RS +
                                 (aColH + kc * 16) * 2;
                LDM4(qf[0], qf[1], qf[2], qf[3], qaddr);
#pragma unroll
                for (int n8 = 0; n8 < 4; n8++) {
                    const int nt = n8 >> 1, hh = (n8 & 1) * 2;
                    MMAF16(sacc[mi][n8], qf, kfh[nt][hh], kfh[nt][hh + 1]);
                }
#pragma unroll
                for (int n8 = 0; n8 < 4; n8++) {
                    const int nt = n8 >> 1, hh = (n8 & 1) * 2;
                    MMAF16(sacc[mi][n8], qf, kfl[nt][hh], kfl[nt][hh + 1]);
                }
            }
        }

        // softmax numerators: bias from smem, mask (w/ -EXPSHIFT) from smem
        uint32_t pph[2][8];
#pragma unroll
        for (int mi = 0; mi < 2; mi++)
#pragma unroll
            for (int n8 = 0; n8 < 4; n8++) {
                const int col  = kh2 + n8 * 8 + (lane & 3) * 2;
                const int rloc = wq * 32 + mi * 16 + (lane >> 2);
                float2 b0 = bias_rd(bbuf, rloc,     col);
                float2 b1 = bias_rd(bbuf, rloc + 8, col);
                float2 mk = *reinterpret_cast<const float2*>(
                    sp + AMSK + (kb + col) * 4);
                float p0 = __expf(sacc[mi][n8][0] + b0.x + mk.x);
                float p1 = __expf(sacc[mi][n8][1] + b0.y + mk.y);
                float p2 = __expf(sacc[mi][n8][2] + b1.x + mk.x);
                float p3 = __expf(sacc[mi][n8][3] + b1.y + mk.y);
                rsum[mi][0] += p0 + p1;
                rsum[mi][1] += p2 + p3;
                __half2 a = __floats2half2_rn(p0, p1);
                __half2 bq = __floats2half2_rn(p2, p3);
                pph[mi][n8 * 2]     = *reinterpret_cast<uint32_t*>(&a);
                pph[mi][n8 * 2 + 1] = *reinterpret_cast<uint32_t*>(&bq);
            }

#pragma unroll
        for (int kc2 = 0; kc2 < 2; kc2++) {
            uint32_t vfh[4][4];
#pragma unroll
            for (int nt = 0; nt < 4; nt++) {
                uint32_t addr = sb + buf + 18432u + (bRowB + nt * 16) * RS +
                                (kh2 + kc2 * 16 + bHi8) * 2;
                LDM4(vfh[nt][0], vfh[nt][1], vfh[nt][2], vfh[nt][3], addr);
            }
#pragma unroll
            for (int mi = 0; mi < 2; mi++) {
                uint32_t pah[4] = { pph[mi][4 * kc2],     pph[mi][4 * kc2 + 1],
                                    pph[mi][4 * kc2 + 2], pph[mi][4 * kc2 + 3] };
#pragma unroll
                for (int n8 = 0; n8 < 8; n8++) {
                    const int nt = n8 >> 1, hh = (n8 & 1) * 2;
                    MMAF16(oacc[mi][n8], pah, vfh[nt][hh], vfh[nt][hh + 1]);
                }
            }
        }

        CPWAIT0();
        __syncthreads();
    }

#pragma unroll
    for (int mi = 0; mi < 2; mi++)
#pragma unroll
        for (int j = 0; j < 2; j++) {
            rsum[mi][j] += __shfl_xor_sync(0xffffffffu, rsum[mi][j], 1);
            rsum[mi][j] += __shfl_xor_sync(0xffffffffu, rsum[mi][j], 2);
        }

    if (w >= 8) {
        const uint32_t ob = OSCR + (uint32_t)(w - 8) * 8192u;
#pragma unroll
        for (int mi = 0; mi < 2; mi++)
#pragma unroll
            for (int n8 = 0; n8 < 8; n8++) {
                float4 t = make_float4(oacc[mi][n8][0], oacc[mi][n8][1],
                                       oacc[mi][n8][2], oacc[mi][n8][3]);
                *reinterpret_cast<float4*>(sp + ob + mi * 4096 + n8 * 512 + lane * 16) = t;
            }
        *reinterpret_cast<float4*>(sp + RSCR + (w - 8) * 512 + lane * 16) =
            make_float4(rsum[0][0], rsum[0][1], rsum[1][0], rsum[1][1]);
    }
    __syncthreads();
    if (w < 8) {
        const uint32_t ob = OSCR + (uint32_t)w * 8192u;
        float4 prs = *reinterpret_cast<float4*>(sp + RSCR + w * 512 + lane * 16);
        float inv[2][2];
        inv[0][0] = 1.f / (rsum[0][0] + prs.x);
        inv[0][1] = 1.f / (rsum[0][1] + prs.y);
        inv[1][0] = 1.f / (rsum[1][0] + prs.z);
        inv[1][1] = 1.f / (rsum[1][1] + prs.w);

        const int col0 = h * HDIM + (lane & 3) * 2;
#pragma unroll
        for (int mi = 0; mi < 2; mi++) {
            const int row0 = qbase + wq * 32 + mi * 16 + (lane >> 2);
#pragma unroll
            for (int n8 = 0; n8 < 8; n8++) {
                float4 t = *reinterpret_cast<float4*>(
                    sp + ob + mi * 4096 + n8 * 512 + lane * 16);
                float x0 = (oacc[mi][n8][0] + t.x) * inv[mi][0];
                float x1 = (oacc[mi][n8][1] + t.y) * inv[mi][0];
                float y0 = (oacc[mi][n8][2] + t.z) * inv[mi][1];
                float y1 = (oacc[mi][n8][3] + t.w) * inv[mi][1];
                size_t i0 = (size_t)(b * SEQT + row0) * EMB + col0 + n8 * 8;
                size_t i1 = (size_t)(b * SEQT + row0 + 8) * EMB + col0 + n8 * 8;
                *reinterpret_cast<uint32_t*>(g_ao + i0) =
                    pack2h(__float2half_rn(x0), __float2half_rn(x1));
                *reinterpret_cast<uint32_t*>(g_ao + i1) =
                    pack2h(__float2half_rn(y0), __float2half_rn(y1));
            }
        }
    }
}

// ---------------------------------------------------------------------------
// Launch
// ---------------------------------------------------------------------------
extern "C" void kernel_launch(void* const* d_in, const int* in_sizes, int n_in,
                              void* d_out, int out_size)
{
    const float*         query = (const float*)d_in[0];
    const float*         abias = (const float*)d_in[1];
    const unsigned char* kmask = (const unsigned char*)d_in[2];
    const float*         in_w  = (const float*)d_in[3];
    const float*         in_b  = (const float*)d_in[4];
    const float*         out_w = (const float*)d_in[5];
    const float*         out_b = (const float*)d_in[6];
    float*               out   = (float*)d_out;

    __half *xh, *xl, *w1, *w2, *ao;
    cudaGetSymbolAddress((void**)&xh, g_xh);
    cudaGetSymbolAddress((void**)&xl, g_xl);
    cudaGetSymbolAddress((void**)&w1, g_w1);
    cudaGetSymbolAddress((void**)&w2, g_w2);
    cudaGetSymbolAddress((void**)&ao, g_ao);

    cudaFuncSetAttribute(gemm_f16_kernel<0>,
                         cudaFuncAttributeMaxDynamicSharedMemorySize, GEMM_SMEM);
    cudaFuncSetAttribute(gemm_f16_kernel<1>,
                         cudaFuncAttributeMaxDynamicSharedMemorySize, GEMM_SMEM);
    cudaFuncSetAttribute(attn_mma_kernel,
                         cudaFuncAttributeMaxDynamicSharedMemorySize, ATTN_SMEM);

    // 0) operand conversion
    splitH_kernel<<<(MTOK * EMB / 4 + 255) / 256, 256>>>(query, xh, xl, MTOK * EMB / 4);
    half_kernel<<<(E3 * EMB / 4 + 255) / 256, 256>>>(in_w, w1, E3 * EMB / 4);
    half_kernel<<<(EMB * EMB / 4 + 255) / 256, 256>>>(out_w, w2, EMB * EMB / 4);

    // 1) QKV projection + fused epilogue (V written transposed directly)
    {
        dim3 grid(E3 / 128, MTOK / 128);
        gemm_f16_kernel<1><<<grid, 256, GEMM_SMEM>>>(xh, xl, w1, in_b, nullptr, E3, EMB);
    }
    // 2) Attention (bias staged through smem)
    {
        dim3 grid(SEQT / 256, BH);
        attn_mma_kernel<<<grid, 512, ATTN_SMEM>>>(abias, kmask);
    }
    // 3) Output projection (x1)
    {
        dim3 grid(EMB / 128, MTOK / 128);
        gemm_f16_kernel<0><<<grid, 256, GEMM_SMEM>>>(ao, ao, w2, out_b, out, EMB, EMB);
    }
}

// round 14
// speedup vs baseline: 6.2260x; 1.0211x over previous
#include <cuda_runtime.h>
#include <cuda_bf16.h>
#include <cuda_fp16.h>
#include <cstdint>
#include <math.h>

#define BATCH 4
#define SEQT 1024
#define EMB 1024
#define NHEAD 16
#define HDIM 64
#define E3 (3 * EMB)
#define MTOK (BATCH * SEQT)
#define BH (BATCH * NHEAD)

// Scratch (fp16 operands)
__device__ __half g_xh [(size_t)MTOK * EMB];
__device__ __half g_xl [(size_t)MTOK * EMB];
__device__ __half g_w1 [(size_t)E3 * EMB];
__device__ __half g_w2 [(size_t)EMB * EMB];
__device__ __half g_ao [(size_t)MTOK * EMB];
__device__ __half g_qf [(size_t)BH * SEQT * HDIM];
__device__ __half g_kh [(size_t)BH * SEQT * HDIM];
__device__ __half g_kl [(size_t)BH * SEQT * HDIM];
__device__ __half g_vth[(size_t)BH * HDIM * SEQT];

// ---------------------------------------------------------------------------
// helpers
// ---------------------------------------------------------------------------
__device__ __forceinline__ uint32_t smem_u32(const void* p) {
    uint32_t a;
    asm("{ .reg .u64 t; cvta.to.shared.u64 t, %1; cvt.u32.u64 %0, t; }"
        : "=r"(a) : "l"(p));
    return a;
}

#define LDM4(r0, r1, r2, r3, addr) \
    asm volatile("ldmatrix.sync.aligned.m8n8.x4.shared.b16 {%0,%1,%2,%3}, [%4];" \
                 : "=r"(r0), "=r"(r1), "=r"(r2), "=r"(r3) : "r"(addr))

#define MMAF16(d, a, b0, b1) \
    asm volatile("mma.sync.aligned.m16n8k16.row.col.f32.f16.f16.f32 " \
                 "{%0,%1,%2,%3},{%4,%5,%6,%7},{%8,%9},{%0,%1,%2,%3};" \
                 : "+f"((d)[0]), "+f"((d)[1]), "+f"((d)[2]), "+f"((d)[3]) \
                 : "r"((a)[0]), "r"((a)[1]), "r"((a)[2]), "r"((a)[3]), \
                   "r"(b0), "r"(b1))

#define CPASYNC16(sdst, gsrc) \
    asm volatile("cp.async.cg.shared.global [%0], [%1], 16;" \
                 :: "r"(sdst), "l"(gsrc) : "memory")
#define CPCOMMIT() asm volatile("cp.async.commit_group;" ::: "memory")
#define CPWAIT0()  asm volatile("cp.async.wait_group 0;" ::: "memory")
#define CPWAIT1()  asm volatile("cp.async.wait_group 1;" ::: "memory")

__device__ __forceinline__ void split_fp16(float x, __half& h, __half& l) {
    h = __float2half_rn(x);
    l = __float2half_rn(x - __half2float(h));
}
__device__ __forceinline__ uint32_t pack2h(__half a, __half b) {
    __half2 t(a, b);
    return *reinterpret_cast<uint32_t*>(&t);
}

// ---------------------------------------------------------------------------
// Elementwise converters
// ---------------------------------------------------------------------------
__global__ __launch_bounds__(256)
void splitH_kernel(const float* __restrict__ src,
                   __half* __restrict__ dh,
                   __half* __restrict__ dl, int n4)
{
    int i = blockIdx.x * 256 + threadIdx.x;
    if (i >= n4) return;
    float4 v = reinterpret_cast<const float4*>(src)[i];
    __half h0, l0, h1, l1, h2, l2, h3, l3;
    split_fp16(v.x, h0, l0); split_fp16(v.y, h1, l1);
    split_fp16(v.z, h2, l2); split_fp16(v.w, h3, l3);
    reinterpret_cast<uint2*>(dh)[i] = make_uint2(pack2h(h0, h1), pack2h(h2, h3));
    reinterpret_cast<uint2*>(dl)[i] = make_uint2(pack2h(l0, l1), pack2h(l2, l3));
}

__global__ __launch_bounds__(256)
void half_kernel(const float* __restrict__ src,
                 __half* __restrict__ dst, int n4)
{
    int i = blockIdx.x * 256 + threadIdx.x;
    if (i >= n4) return;
    float4 v = reinterpret_cast<const float4*>(src)[i];
    reinterpret_cast<uint2*>(dst)[i] =
        make_uint2(pack2h(__float2half_rn(v.x), __float2half_rn(v.y)),
                   pack2h(__float2half_rn(v.z), __float2half_rn(v.w)));
}

// ---------------------------------------------------------------------------
// fp16 GEMM, dual mainloop:
//   1-term tiles: BK=64 per stage (A 16K | B 16K), 3-stage, 16 iters.
//   2-term tiles (QKV K-section): BK=32 (Ah|Al|B 8K each), 3-stage, 32 iters.
// EPI=1 (QKV) epilogue: Q fp16 scaled / K fp16 hi-lo / V transposed fp16.
// EPI=0 (out-proj): fp32 C + bias.
// ---------------------------------------------------------------------------
#define STG32 24576u
#define STG64 32768u
#define GEMM_SMEM (3 * 32768 + 128)

template<int EPI>
__global__ __launch_bounds__(256, 2)
void gemm_f16_kernel(const __half* __restrict__ Ah,
                     const __half* __restrict__ Al,
                     const __half* __restrict__ Bs,
                     const float* __restrict__ bias,
                     float* __restrict__ C,
                     int N, int K)
{
    extern __shared__ char dsm[];
    char* sp = dsm + ((128 - (smem_u32(dsm) & 127)) & 127);
    const uint32_t sb = smem_u32(sp);

    const int tid  = threadIdx.x;
    const int lane = tid & 31;
    const int wm   = (tid >> 5) & 3;
    const int wn   = tid >> 7;
    const int rowBase = blockIdx.y * 128;
    const int colBase = blockIdx.x * 128;
    const bool two_terms = (EPI == 1) && ((colBase >> 10) == 1);

    float acc[2][8][4];
#pragma unroll
    for (int i = 0; i < 2; i++)
#pragma unroll
        for (int j = 0; j < 8; j++)
#pragma unroll
            for (int q = 0; q < 4; q++) acc[i][j][q] = 0.f;

    const uint32_t aRow = (uint32_t)(wm * 32 + (lane & 15));
    const uint32_t aHi  = (uint32_t)(lane >> 4);
    const uint32_t bRow = (uint32_t)(wn * 64 + (lane & 7) + ((lane >> 4) << 3));
    const uint32_t bHi  = (uint32_t)((lane >> 3) & 1);

    if (two_terms) {
        // ----- BK=32, 3 terms of smem (Ah|Al|B), 2 MMAs per A-row pair -----
        const uint32_t aSwz = (aRow >> 1) & 3;
        const uint32_t bSwz = (bRow >> 1) & 3;
        auto issue = [&](int it_, int stg) {
            const int kt = it_ * 32;
            const uint32_t so = sb + (uint32_t)stg * STG32;
#pragma unroll
            for (int i = 0; i < 6; i++) {
                int g = tid + i * 256;
                int arr = g >> 9;
                int rem = g & 511;
                int row = rem >> 2, c = rem & 3;
                int cs = c ^ ((row >> 1) & 3);
                const __half* src;
                if (arr == 0)      src = Ah + (size_t)(rowBase + row) * K + kt + c * 8;
                else if (arr == 1) src = Al + (size_t)(rowBase + row) * K + kt + c * 8;
                else               src = Bs + (size_t)(colBase + row) * K + kt + c * 8;
                CPASYNC16(so + (uint32_t)arr * 8192u + (uint32_t)(row * 64 + cs * 16), src);
            }
        };

        const int NIT = K / 32;
        issue(0, 0); CPCOMMIT();
        issue(1, 1); CPCOMMIT();

        for (int it = 0; it < NIT; ++it) {
            const int cur = it % 3;
            CPWAIT1();
            __syncthreads();
            if (it + 2 < NIT) issue(it + 2, (it + 2) % 3);
            CPCOMMIT();

            const uint32_t tb = sb + (uint32_t)cur * STG32;
#pragma unroll
            for (int ks = 0; ks < 2; ks++) {
                uint32_t ah[2][4], al[2][4], bs[4][4];
                const uint32_t caA = ((uint32_t)(ks * 2) + aHi) ^ aSwz;
                const uint32_t caB = ((uint32_t)(ks * 2) + bHi) ^ bSwz;
#pragma unroll
                for (int mi = 0; mi < 2; mi++) {
                    uint32_t addr = tb + (aRow + mi * 16) * 64 + caA * 16;
                    LDM4(ah[mi][0], ah[mi][1], ah[mi][2], ah[mi][3], addr);
                    LDM4(al[mi][0], al[mi][1], al[mi][2], al[mi][3], addr + 8192);
                }
#pragma unroll
                for (int nt = 0; nt < 4; nt++) {
                    uint32_t addr = tb + 16384u + (bRow + nt * 16) * 64 + caB * 16;
                    LDM4(bs[nt][0], bs[nt][1], bs[nt][2], bs[nt][3], addr);
                }
#pragma unroll
                for (int mi = 0; mi < 2; mi++)
#pragma unroll
                    for (int n8 = 0; n8 < 8; n8++) {
                        const int nt = n8 >> 1, hh = (n8 & 1) * 2;
                        MMAF16(acc[mi][n8], ah[mi], bs[nt][hh], bs[nt][hh + 1]);
                    }
#pragma unroll
                for (int mi = 0; mi < 2; mi++)
#pragma unroll
                    for (int n8 = 0; n8 < 8; n8++) {
                        const int nt = n8 >> 1, hh = (n8 & 1) * 2;
                        MMAF16(acc[mi][n8], al[mi], bs[nt][hh], bs[nt][hh + 1]);
                    }
            }
        }
    } else {
        // ----- BK=64, 1-term (A|B, 16K each), 128B rows, cs = cc ^ (row&7) --
        const uint32_t aSwz = aRow & 7;
        const uint32_t bSwz = bRow & 7;
        auto issue = [&](int it_, int stg) {
            const int kt = it_ * 64;
            const uint32_t so = sb + (uint32_t)stg * STG64;
#pragma unroll
            for (int i = 0; i < 8; i++) {
                int g = tid + i * 256;           // 0..2047
                int arr = g >> 10;               // 0=A 1=B
                int rem = g & 1023;
                int row = rem >> 3, cc = rem & 7;
                int cs = cc ^ (row & 7);
                const __half* src = arr
                    ? Bs + (size_t)(colBase + row) * K + kt + cc * 8
                    : Ah + (size_t)(rowBase + row) * K + kt + cc * 8;
                CPASYNC16(so + (uint32_t)arr * 16384u + (uint32_t)(row * 128 + cs * 16), src);
            }
        };

        const int NIT = K / 64;
        issue(0, 0); CPCOMMIT();
        issue(1, 1); CPCOMMIT();

        for (int it = 0; it < NIT; ++it) {
            const int cur = it % 3;
            CPWAIT1();
            __syncthreads();
            if (it + 2 < NIT) issue(it + 2, (it + 2) % 3);
            CPCOMMIT();

            const uint32_t tb = sb + (uint32_t)cur * STG64;
#pragma unroll
            for (int ks = 0; ks < 4; ks++) {
                uint32_t ah[2][4], bs[4][4];
                const uint32_t caA = ((uint32_t)(ks * 2) + aHi) ^ aSwz;
                const uint32_t caB = ((uint32_t)(ks * 2) + bHi) ^ bSwz;
#pragma unroll
                for (int mi = 0; mi < 2; mi++) {
                    uint32_t addr = tb + (aRow + mi * 16) * 128 + caA * 16;
                    LDM4(ah[mi][0], ah[mi][1], ah[mi][2], ah[mi][3], addr);
                }
#pragma unroll
                for (int nt = 0; nt < 4; nt++) {
                    uint32_t addr = tb + 16384u + (bRow + nt * 16) * 128 + caB * 16;
                    LDM4(bs[nt][0], bs[nt][1], bs[nt][2], bs[nt][3], addr);
                }
#pragma unroll
                for (int mi = 0; mi < 2; mi++)
#pragma unroll
                    for (int n8 = 0; n8 < 8; n8++) {
                        const int nt = n8 >> 1, hh = (n8 & 1) * 2;
                        MMAF16(acc[mi][n8], ah[mi], bs[nt][hh], bs[nt][hh + 1]);
                    }
            }
        }
    }

    const int r0 = rowBase + wm * 32 + (lane >> 2);
    const int c0 = colBase + wn * 64 + (lane & 3) * 2;

    if (EPI == 0) {
#pragma unroll
        for (int mi = 0; mi < 2; mi++)
#pragma unroll
            for (int n8 = 0; n8 < 8; n8++) {
                const int row = r0 + mi * 16;
                const int col = c0 + n8 * 8;
                const float2 bv = *reinterpret_cast<const float2*>(bias + col);
                float2 o0 = make_float2(acc[mi][n8][0] + bv.x, acc[mi][n8][1] + bv.y);
                float2 o1 = make_float2(acc[mi][n8][2] + bv.x, acc[mi][n8][3] + bv.y);
                *reinterpret_cast<float2*>(C + (size_t)row * N + col)       = o0;
                *reinterpret_cast<float2*>(C + (size_t)(row + 8) * N + col) = o1;
            }
    } else {
        auto wr = [&](int row, int col, float x0, float x1) {
            const int sect = col >> 10;
            const int coli = col & 1023;
            const int bb = row >> 10, t = row & 1023;
            const int hh = coli >> 6, d = coli & 63;
            if (sect == 2) {
                const size_t base = (size_t)(bb * 16 + hh) * HDIM;
                g_vth[(base + d)     * SEQT + t] = __float2half_rn(x0);
                g_vth[(base + d + 1) * SEQT + t] = __float2half_rn(x1);
            } else {
                const size_t idx = ((size_t)(bb * 16 + hh) * 1024 + t) * 64 + d;
                if (sect == 0) {
                    __half q0 = __float2half_rn(x0 * 0.125f);
                    __half q1 = __float2half_rn(x1 * 0.125f);
                    *reinterpret_cast<uint32_t*>(g_qf + idx) = pack2h(q0, q1);
                } else {
                    __half h0, l0, h1, l1;
                    split_fp16(x0, h0, l0); split_fp16(x1, h1, l1);
                    *reinterpret_cast<uint32_t*>(g_kh + idx) = pack2h(h0, h1);
                    *reinterpret_cast<uint32_t*>(g_kl + idx) = pack2h(l0, l1);
                }
            }
        };
#pragma unroll
        for (int mi = 0; mi < 2; mi++)
#pragma unroll
            for (int n8 = 0; n8 < 8; n8++) {
                const int row = r0 + mi * 16;
                const int col = c0 + n8 * 8;
                const float2 bv = *reinterpret_cast<const float2*>(bias + col);
                wr(row,     col, acc[mi][n8][0] + bv.x, acc[mi][n8][1] + bv.y);
                wr(row + 8, col, acc[mi][n8][2] + bv.x, acc[mi][n8][3] + bv.y);
            }
    }
}

// ---------------------------------------------------------------------------
// Flash attention (unchanged from round 13)
// ---------------------------------------------------------------------------
#define AQF   0u
#define ABUF0 36864u
#define ABUF1 64512u
#define AMSK  92160u
#define BIAS0 96256u
#define BIAS1 161792u
#define OSCR  0u
#define RSCR  65536u
#define ATTN_SMEM (227328 + 128)
#define RS 144u
#define EXPSHIFT 10.0f

__global__ __launch_bounds__(512, 1)
void attn_mma_kernel(const float* __restrict__ attn_bias,
                     const unsigned char* __restrict__ kmask)
{
    extern __shared__ char dsm[];
    char* sp = dsm + ((128 - (smem_u32(dsm) & 127)) & 127);
    const uint32_t sb = smem_u32(sp);

    const int bh = blockIdx.y;
    const int b  = bh >> 4;
    const int h  = bh & 15;
    const int qbase = blockIdx.x * 256;
    const int tid  = threadIdx.x;
    const int lane = tid & 31;
    const int w    = tid >> 5;
    const int wq   = w & 7;
    const int kh2  = (w >> 3) * 32;

    for (int i = tid; i < SEQT; i += 512)
        *reinterpret_cast<float*>(sp + AMSK + i * 4) =
            kmask[b * SEQT + i] ? -3.0e38f : -EXPSHIFT;

#pragma unroll
    for (int i = 0; i < 4; i++) {
        int g = tid + i * 512;
        int row = g >> 3, cc = g & 7;
        CPASYNC16(sb + AQF + row * RS + cc * 16,
                  g_qf + ((size_t)bh * SEQT + qbase + row) * HDIM + cc * 8);
    }

    const float* biasg = attn_bias + (size_t)bh * SEQT * SEQT;

    auto load_kv = [&](int kb, uint32_t bufoff) {
#pragma unroll
        for (int i = 0; i < 3; i++) {
            int g = tid + i * 512;
            int arr = g >> 9;
            int rem = g & 511;
            int row = rem >> 3, cc = rem & 7;
            const void* src;
            if (arr == 0)      src = g_kh  + ((size_t)bh * SEQT + kb + row) * HDIM + cc * 8;
            else if (arr == 1) src = g_kl  + ((size_t)bh * SEQT + kb + row) * HDIM + cc * 8;
            else               src = g_vth + ((size_t)bh * HDIM + row) * SEQT + kb + cc * 8;
            CPASYNC16(sb + bufoff + (uint32_t)arr * 9216u + row * RS + cc * 16, src);
        }
    };
    auto load_bias = [&](int kb, uint32_t bufoff) {
#pragma unroll
        for (int i = 0; i < 8; i++) {
            int g = tid + i * 512;
            int row = g >> 4, ch = g & 15;
            CPASYNC16(sb + bufoff + (uint32_t)(row * 256) +
                          ((uint32_t)(ch ^ (row & 15)) << 4),
                      biasg + (size_t)(qbase + row) * SEQT + kb + ch * 4);
        }
    };

    load_kv(0, ABUF0);
    load_bias(0, BIAS0);
    CPCOMMIT();
    CPWAIT0();
    __syncthreads();

    float oacc[2][8][4];
#pragma unroll
    for (int mi = 0; mi < 2; mi++)
#pragma unroll
        for (int i = 0; i < 8; i++)
#pragma unroll
            for (int j = 0; j < 4; j++) oacc[mi][i][j] = 0.f;
    float rsum[2][2] = {{0.f, 0.f}, {0.f, 0.f}};

    const uint32_t aColH = (uint32_t)((lane >> 4) * 8);
    const uint32_t aRowL = (uint32_t)(lane & 15);
    const uint32_t bRowB = (uint32_t)((lane & 7) + ((lane >> 4) << 3));
    const uint32_t bHi8  = (uint32_t)(((lane >> 3) & 1) * 8);

    auto bias_rd = [&](uint32_t bbuf, int rloc, int col) -> float2 {
        uint32_t addr = bbuf + (uint32_t)(rloc * 256) +
            ((uint32_t)((col >> 2) ^ (rloc & 15)) << 4) + (uint32_t)((col & 3) << 2);
        return *reinterpret_cast<float2*>(sp + addr);
    };

    for (int it = 0; it < 16; ++it) {
        const int kb = it * 64;
        const uint32_t buf  = (it & 1) ? ABUF1 : ABUF0;
        const uint32_t bbuf = (it & 1) ? BIAS1 : BIAS0;
        if (it + 1 < 16) {
            load_kv((it + 1) * 64, (it & 1) ? ABUF0 : ABUF1);
            load_bias((it + 1) * 64, (it & 1) ? BIAS0 : BIAS1);
            CPCOMMIT();
        }

        float sacc[2][4][4];
#pragma unroll
        for (int mi = 0; mi < 2; mi++)
#pragma unroll
            for (int i = 0; i < 4; i++)
#pragma unroll
                for (int j = 0; j < 4; j++) sacc[mi][i][j] = 0.f;

#pragma unroll
        for (int kc = 0; kc < 4; kc++) {
            uint32_t kfh[2][4], kfl[2][4];
#pragma unroll
            for (int nt = 0; nt < 2; nt++) {
                uint32_t addr = sb + buf + (kh2 + nt * 16 + bRowB) * RS + (kc * 16 + bHi8) * 2;
                LDM4(kfh[nt][0], kfh[nt][1], kfh[nt][2], kfh[nt][3], addr);
                LDM4(kfl[nt][0], kfl[nt][1], kfl[nt][2], kfl[nt][3], addr + 9216);
            }
#pragma unroll
            for (int mi = 0; mi < 2; mi++) {
                uint32_t qf[4];
                uint32_t qaddr = sb + AQF + (wq * 32 + mi * 16 + aRowL) * RS +
                                 (aColH + kc * 16) * 2;
                LDM4(qf[0], qf[1], qf[2], qf[3], qaddr);
#pragma unroll
                for (int n8 = 0; n8 < 4; n8++) {
                    const int nt = n8 >> 1, hh = (n8 & 1) * 2;
                    MMAF16(sacc[mi][n8], qf, kfh[nt][hh], kfh[nt][hh + 1]);
                }
#pragma unroll
                for (int n8 = 0; n8 < 4; n8++) {
                    const int nt = n8 >> 1, hh = (n8 & 1) * 2;
                    MMAF16(sacc[mi][n8], qf, kfl[nt][hh], kfl[nt][hh + 1]);
                }
            }
        }

        uint32_t pph[2][8];
#pragma unroll
        for (int mi = 0; mi < 2; mi++)
#pragma unroll
            for (int n8 = 0; n8 < 4; n8++) {
                const int col  = kh2 + n8 * 8 + (lane & 3) * 2;
                const int rloc = wq * 32 + mi * 16 + (lane >> 2);
                float2 b0 = bias_rd(bbuf, rloc,     col);
                float2 b1 = bias_rd(bbuf, rloc + 8, col);
                float2 mk = *reinterpret_cast<const float2*>(
                    sp + AMSK + (kb + col) * 4);
                float p0 = __expf(sacc[mi][n8][0] + b0.x + mk.x);
                float p1 = __expf(sacc[mi][n8][1] + b0.y + mk.y);
                float p2 = __expf(sacc[mi][n8][2] + b1.x + mk.x);
                float p3 = __expf(sacc[mi][n8][3] + b1.y + mk.y);
                rsum[mi][0] += p0 + p1;
                rsum[mi][1] += p2 + p3;
                __half2 a = __floats2half2_rn(p0, p1);
                __half2 bq = __floats2half2_rn(p2, p3);
                pph[mi][n8 * 2]     = *reinterpret_cast<uint32_t*>(&a);
                pph[mi][n8 * 2 + 1] = *reinterpret_cast<uint32_t*>(&bq);
            }

#pragma unroll
        for (int kc2 = 0; kc2 < 2; kc2++) {
            uint32_t vfh[4][4];
#pragma unroll
            for (int nt = 0; nt < 4; nt++) {
                uint32_t addr = sb + buf + 18432u + (bRowB + nt * 16) * RS +
                                (kh2 + kc2 * 16 + bHi8) * 2;
                LDM4(vfh[nt][0], vfh[nt][1], vfh[nt][2], vfh[nt][3], addr);
            }
#pragma unroll
            for (int mi = 0; mi < 2; mi++) {
                uint32_t pah[4] = { pph[mi][4 * kc2],     pph[mi][4 * kc2 + 1],
                                    pph[mi][4 * kc2 + 2], pph[mi][4 * kc2 + 3] };
#pragma unroll
                for (int n8 = 0; n8 < 8; n8++) {
                    const int nt = n8 >> 1, hh = (n8 & 1) * 2;
                    MMAF16(oacc[mi][n8], pah, vfh[nt][hh], vfh[nt][hh + 1]);
                }
            }
        }

        CPWAIT0();
        __syncthreads();
    }

#pragma unroll
    for (int mi = 0; mi < 2; mi++)
#pragma unroll
        for (int j = 0; j < 2; j++) {
            rsum[mi][j] += __shfl_xor_sync(0xffffffffu, rsum[mi][j], 1);
            rsum[mi][j] += __shfl_xor_sync(0xffffffffu, rsum[mi][j], 2);
        }

    if (w >= 8) {
        const uint32_t ob = OSCR + (uint32_t)(w - 8) * 8192u;
#pragma unroll
        for (int mi = 0; mi < 2; mi++)
#pragma unroll
            for (int n8 = 0; n8 < 8; n8++) {
                float4 t = make_float4(oacc[mi][n8][0], oacc[mi][n8][1],
                                       oacc[mi][n8][2], oacc[mi][n8][3]);
                *reinterpret_cast<float4*>(sp + ob + mi * 4096 + n8 * 512 + lane * 16) = t;
            }
        *reinterpret_cast<float4*>(sp + RSCR + (w - 8) * 512 + lane * 16) =
            make_float4(rsum[0][0], rsum[0][1], rsum[1][0], rsum[1][1]);
    }
    __syncthreads();
    if (w < 8) {
        const uint32_t ob = OSCR + (uint32_t)w * 8192u;
        float4 prs = *reinterpret_cast<float4*>(sp + RSCR + w * 512 + lane * 16);
        float inv[2][2];
        inv[0][0] = 1.f / (rsum[0][0] + prs.x);
        inv[0][1] = 1.f / (rsum[0][1] + prs.y);
        inv[1][0] = 1.f / (rsum[1][0] + prs.z);
        inv[1][1] = 1.f / (rsum[1][1] + prs.w);

        const int col0 = h * HDIM + (lane & 3) * 2;
#pragma unroll
        for (int mi = 0; mi < 2; mi++) {
            const int row0 = qbase + wq * 32 + mi * 16 + (lane >> 2);
#pragma unroll
            for (int n8 = 0; n8 < 8; n8++) {
                float4 t = *reinterpret_cast<float4*>(
                    sp + ob + mi * 4096 + n8 * 512 + lane * 16);
                float x0 = (oacc[mi][n8][0] + t.x) * inv[mi][0];
                float x1 = (oacc[mi][n8][1] + t.y) * inv[mi][0];
                float y0 = (oacc[mi][n8][2] + t.z) * inv[mi][1];
                float y1 = (oacc[mi][n8][3] + t.w) * inv[mi][1];
                size_t i0 = (size_t)(b * SEQT + row0) * EMB + col0 + n8 * 8;
                size_t i1 = (size_t)(b * SEQT + row0 + 8) * EMB + col0 + n8 * 8;
                *reinterpret_cast<uint32_t*>(g_ao + i0) =
                    pack2h(__float2half_rn(x0), __float2half_rn(x1));
                *reinterpret_cast<uint32_t*>(g_ao + i1) =
                    pack2h(__float2half_rn(y0), __float2half_rn(y1));
            }
        }
    }
}

// ---------------------------------------------------------------------------
// Launch
// ---------------------------------------------------------------------------
extern "C" void kernel_launch(void* const* d_in, const int* in_sizes, int n_in,
                              void* d_out, int out_size)
{
    const float*         query = (const float*)d_in[0];
    const float*         abias = (const float*)d_in[1];
    const unsigned char* kmask = (const unsigned char*)d_in[2];
    const float*         in_w  = (const float*)d_in[3];
    const float*         in_b  = (const float*)d_in[4];
    const float*         out_w = (const float*)d_in[5];
    const float*         out_b = (const float*)d_in[6];
    float*               out   = (float*)d_out;

    __half *xh, *xl, *w1, *w2, *ao;
    cudaGetSymbolAddress((void**)&xh, g_xh);
    cudaGetSymbolAddress((void**)&xl, g_xl);
    cudaGetSymbolAddress((void**)&w1, g_w1);
    cudaGetSymbolAddress((void**)&w2, g_w2);
    cudaGetSymbolAddress((void**)&ao, g_ao);

    cudaFuncSetAttribute(gemm_f16_kernel<0>,
                         cudaFuncAttributeMaxDynamicSharedMemorySize, GEMM_SMEM);
    cudaFuncSetAttribute(gemm_f16_kernel<1>,
                         cudaFuncAttributeMaxDynamicSharedMemorySize, GEMM_SMEM);
    cudaFuncSetAttribute(attn_mma_kernel,
                         cudaFuncAttributeMaxDynamicSharedMemorySize, ATTN_SMEM);

    // 0) operand conversion
    splitH_kernel<<<(MTOK * EMB / 4 + 255) / 256, 256>>>(query, xh, xl, MTOK * EMB / 4);
    half_kernel<<<(E3 * EMB / 4 + 255) / 256, 256>>>(in_w, w1, E3 * EMB / 4);
    half_kernel<<<(EMB * EMB / 4 + 255) / 256, 256>>>(out_w, w2, EMB * EMB / 4);

    // 1) QKV projection + fused epilogue
    {
        dim3 grid(E3 / 128, MTOK / 128);
        gemm_f16_kernel<1><<<grid, 256, GEMM_SMEM>>>(xh, xl, w1, in_b, nullptr, E3, EMB);
    }
    // 2) Attention
    {
        dim3 grid(SEQT / 256, BH);
        attn_mma_kernel<<<grid, 512, ATTN_SMEM>>>(abias, kmask);
    }
    // 3) Output projection
    {
        dim3 grid(EMB / 128, MTOK / 128);
        gemm_f16_kernel<0><<<grid, 256, GEMM_SMEM>>>(ao, ao, w2, out_b, out, EMB, EMB);
    }
}

// round 15
// speedup vs baseline: 7.4201x; 1.1918x over previous
#include <cuda_runtime.h>
#include <cuda_bf16.h>
#include <cuda_fp16.h>
#include <cstdint>
#include <math.h>

#define BATCH 4
#define SEQT 1024
#define EMB 1024
#define NHEAD 16
#define HDIM 64
#define E3 (3 * EMB)
#define MTOK (BATCH * SEQT)
#define BH (BATCH * NHEAD)

// Scratch (fp16 operands)
__device__ __half g_xf [(size_t)MTOK * EMB];   // query fp16
__device__ __half g_w1 [(size_t)E3 * EMB];     // in_w fp16
__device__ __half g_w2 [(size_t)EMB * EMB];    // out_w fp16
__device__ __half g_ao [(size_t)MTOK * EMB];   // attention out fp16
__device__ __half g_qf [(size_t)BH * SEQT * HDIM];  // Q fp16 (scaled)
__device__ __half g_kf [(size_t)BH * SEQT * HDIM];  // K fp16
__device__ __half g_vth[(size_t)BH * HDIM * SEQT];  // V^T fp16

// ---------------------------------------------------------------------------
// helpers
// ---------------------------------------------------------------------------
__device__ __forceinline__ uint32_t smem_u32(const void* p) {
    uint32_t a;
    asm("{ .reg .u64 t; cvta.to.shared.u64 t, %1; cvt.u32.u64 %0, t; }"
        : "=r"(a) : "l"(p));
    return a;
}

#define LDM4(r0, r1, r2, r3, addr) \
    asm volatile("ldmatrix.sync.aligned.m8n8.x4.shared.b16 {%0,%1,%2,%3}, [%4];" \
                 : "=r"(r0), "=r"(r1), "=r"(r2), "=r"(r3) : "r"(addr))

#define MMAF16(d, a, b0, b1) \
    asm volatile("mma.sync.aligned.m16n8k16.row.col.f32.f16.f16.f32 " \
                 "{%0,%1,%2,%3},{%4,%5,%6,%7},{%8,%9},{%0,%1,%2,%3};" \
                 : "+f"((d)[0]), "+f"((d)[1]), "+f"((d)[2]), "+f"((d)[3]) \
                 : "r"((a)[0]), "r"((a)[1]), "r"((a)[2]), "r"((a)[3]), \
                   "r"(b0), "r"(b1))

#define CPASYNC16(sdst, gsrc) \
    asm volatile("cp.async.cg.shared.global [%0], [%1], 16;" \
                 :: "r"(sdst), "l"(gsrc) : "memory")
#define CPCOMMIT() asm volatile("cp.async.commit_group;" ::: "memory")
#define CPWAIT0()  asm volatile("cp.async.wait_group 0;" ::: "memory")
#define CPWAIT1()  asm volatile("cp.async.wait_group 1;" ::: "memory")

__device__ __forceinline__ uint32_t pack2h(__half a, __half b) {
    __half2 t(a, b);
    return *reinterpret_cast<uint32_t*>(&t);
}

// ---------------------------------------------------------------------------
// fp32 -> fp16 converter
// ---------------------------------------------------------------------------
__global__ __launch_bounds__(256)
void half_kernel(const float* __restrict__ src,
                 __half* __restrict__ dst, int n4)
{
    int i = blockIdx.x * 256 + threadIdx.x;
    if (i >= n4) return;
    float4 v = reinterpret_cast<const float4*>(src)[i];
    reinterpret_cast<uint2*>(dst)[i] =
        make_uint2(pack2h(__float2half_rn(v.x), __float2half_rn(v.y)),
                   pack2h(__float2half_rn(v.z), __float2half_rn(v.w)));
}

// ---------------------------------------------------------------------------
// fp16 1-term GEMM, BK=64 per stage (A 16K | B 16K), 3-stage, 2 CTAs/SM.
// CTA 128x128, 256 thr, warps 4(m) x 2(n), warp tile 32x64.
// EPI=1 (QKV): Q fp16 scaled / K fp16 / V transposed fp16.
// EPI=0 (out-proj): fp32 C + bias.
// ---------------------------------------------------------------------------
#define STG64 32768u
#define GEMM_SMEM (3 * 32768 + 128)

template<int EPI>
__global__ __launch_bounds__(256, 2)
void gemm_f16_kernel(const __half* __restrict__ As,
                     const __half* __restrict__ Bs,
                     const float* __restrict__ bias,
                     float* __restrict__ C,
                     int N, int K)
{
    extern __shared__ char dsm[];
    char* sp = dsm + ((128 - (smem_u32(dsm) & 127)) & 127);
    const uint32_t sb = smem_u32(sp);

    const int tid  = threadIdx.x;
    const int lane = tid & 31;
    const int wm   = (tid >> 5) & 3;
    const int wn   = tid >> 7;
    const int rowBase = blockIdx.y * 128;
    const int colBase = blockIdx.x * 128;

    float acc[2][8][4];
#pragma unroll
    for (int i = 0; i < 2; i++)
#pragma unroll
        for (int j = 0; j < 8; j++)
#pragma unroll
            for (int q = 0; q < 4; q++) acc[i][j][q] = 0.f;

    const uint32_t aRow = (uint32_t)(wm * 32 + (lane & 15));
    const uint32_t aHi  = (uint32_t)(lane >> 4);
    const uint32_t bRow = (uint32_t)(wn * 64 + (lane & 7) + ((lane >> 4) << 3));
    const uint32_t bHi  = (uint32_t)((lane >> 3) & 1);
    const uint32_t aSwz = aRow & 7;
    const uint32_t bSwz = bRow & 7;

    auto issue = [&](int it_, int stg) {
        const int kt = it_ * 64;
        const uint32_t so = sb + (uint32_t)stg * STG64;
#pragma unroll
        for (int i = 0; i < 8; i++) {
            int g = tid + i * 256;           // 0..2047
            int arr = g >> 10;               // 0=A 1=B
            int rem = g & 1023;
            int row = rem >> 3, cc = rem & 7;
            int cs = cc ^ (row & 7);
            const __half* src = arr
                ? Bs + (size_t)(colBase + row) * K + kt + cc * 8
                : As + (size_t)(rowBase + row) * K + kt + cc * 8;
            CPASYNC16(so + (uint32_t)arr * 16384u + (uint32_t)(row * 128 + cs * 16), src);
        }
    };

    const int NIT = K / 64;
    issue(0, 0); CPCOMMIT();
    issue(1, 1); CPCOMMIT();

    for (int it = 0; it < NIT; ++it) {
        const int cur = it % 3;
        CPWAIT1();
        __syncthreads();
        if (it + 2 < NIT) issue(it + 2, (it + 2) % 3);
        CPCOMMIT();

        const uint32_t tb = sb + (uint32_t)cur * STG64;
#pragma unroll
        for (int ks = 0; ks < 4; ks++) {
            uint32_t ah[2][4], bs[4][4];
            const uint32_t caA = ((uint32_t)(ks * 2) + aHi) ^ aSwz;
            const uint32_t caB = ((uint32_t)(ks * 2) + bHi) ^ bSwz;
#pragma unroll
            for (int mi = 0; mi < 2; mi++) {
                uint32_t addr = tb + (aRow + mi * 16) * 128 + caA * 16;
                LDM4(ah[mi][0], ah[mi][1], ah[mi][2], ah[mi][3], addr);
            }
#pragma unroll
            for (int nt = 0; nt < 4; nt++) {
                uint32_t addr = tb + 16384u + (bRow + nt * 16) * 128 + caB * 16;
                LDM4(bs[nt][0], bs[nt][1], bs[nt][2], bs[nt][3], addr);
            }
#pragma unroll
            for (int mi = 0; mi < 2; mi++)
#pragma unroll
                for (int n8 = 0; n8 < 8; n8++) {
                    const int nt = n8 >> 1, hh = (n8 & 1) * 2;
                    MMAF16(acc[mi][n8], ah[mi], bs[nt][hh], bs[nt][hh + 1]);
                }
        }
    }

    const int r0 = rowBase + wm * 32 + (lane >> 2);
    const int c0 = colBase + wn * 64 + (lane & 3) * 2;

    if (EPI == 0) {
#pragma unroll
        for (int mi = 0; mi < 2; mi++)
#pragma unroll
            for (int n8 = 0; n8 < 8; n8++) {
                const int row = r0 + mi * 16;
                const int col = c0 + n8 * 8;
                const float2 bv = *reinterpret_cast<const float2*>(bias + col);
                float2 o0 = make_float2(acc[mi][n8][0] + bv.x, acc[mi][n8][1] + bv.y);
                float2 o1 = make_float2(acc[mi][n8][2] + bv.x, acc[mi][n8][3] + bv.y);
                *reinterpret_cast<float2*>(C + (size_t)row * N + col)       = o0;
                *reinterpret_cast<float2*>(C + (size_t)(row + 8) * N + col) = o1;
            }
    } else {
        auto wr = [&](int row, int col, float x0, float x1) {
            const int sect = col >> 10;
            const int coli = col & 1023;
            const int bb = row >> 10, t = row & 1023;
            const int hh = coli >> 6, d = coli & 63;
            if (sect == 2) {
                const size_t base = (size_t)(bb * 16 + hh) * HDIM;
                g_vth[(base + d)     * SEQT + t] = __float2half_rn(x0);
                g_vth[(base + d + 1) * SEQT + t] = __float2half_rn(x1);
            } else {
                const size_t idx = ((size_t)(bb * 16 + hh) * 1024 + t) * 64 + d;
                if (sect == 0) {
                    *reinterpret_cast<uint32_t*>(g_qf + idx) =
                        pack2h(__float2half_rn(x0 * 0.125f),
                               __float2half_rn(x1 * 0.125f));
                } else {
                    *reinterpret_cast<uint32_t*>(g_kf + idx) =
                        pack2h(__float2half_rn(x0), __float2half_rn(x1));
                }
            }
        };
#pragma unroll
        for (int mi = 0; mi < 2; mi++)
#pragma unroll
            for (int n8 = 0; n8 < 8; n8++) {
                const int row = r0 + mi * 16;
                const int col = c0 + n8 * 8;
                const float2 bv = *reinterpret_cast<const float2*>(bias + col);
                wr(row,     col, acc[mi][n8][0] + bv.x, acc[mi][n8][1] + bv.y);
                wr(row + 8, col, acc[mi][n8][2] + bv.x, acc[mi][n8][3] + bv.y);
            }
    }
}

// ---------------------------------------------------------------------------
// Flash attention: 256 q-rows/CTA, 32 q-rows/warp, key-split halves.
// S = Q(fp16) x K(fp16) x1; PV = P(fp16) x V(fp16) x1.
// Bias staged through smem; mask table folds -EXPSHIFT.
// ---------------------------------------------------------------------------
#define AQF   0u
#define ABUF0 36864u
#define ABUF1 55296u
#define AMSK  73728u
#define BIAS0 77824u
#define BIAS1 143360u
#define OSCR  0u
#define RSCR  65536u
#define ATTN_SMEM (208896 + 128)
#define RS 144u
#define EXPSHIFT 10.0f

__global__ __launch_bounds__(512, 1)
void attn_mma_kernel(const float* __restrict__ attn_bias,
                     const unsigned char* __restrict__ kmask)
{
    extern __shared__ char dsm[];
    char* sp = dsm + ((128 - (smem_u32(dsm) & 127)) & 127);
    const uint32_t sb = smem_u32(sp);

    const int bh = blockIdx.y;
    const int b  = bh >> 4;
    const int h  = bh & 15;
    const int qbase = blockIdx.x * 256;
    const int tid  = threadIdx.x;
    const int lane = tid & 31;
    const int w    = tid >> 5;
    const int wq   = w & 7;
    const int kh2  = (w >> 3) * 32;

    for (int i = tid; i < SEQT; i += 512)
        *reinterpret_cast<float*>(sp + AMSK + i * 4) =
            kmask[b * SEQT + i] ? -3.0e38f : -EXPSHIFT;

#pragma unroll
    for (int i = 0; i < 4; i++) {
        int g = tid + i * 512;
        int row = g >> 3, cc = g & 7;
        CPASYNC16(sb + AQF + row * RS + cc * 16,
                  g_qf + ((size_t)bh * SEQT + qbase + row) * HDIM + cc * 8);
    }

    const float* biasg = attn_bias + (size_t)bh * SEQT * SEQT;

    auto load_kv = [&](int kb, uint32_t bufoff) {
#pragma unroll
        for (int i = 0; i < 2; i++) {
            int g = tid + i * 512;            // 0..1023
            int arr = g >> 9;                 // 0=K 1=V^T
            int rem = g & 511;
            int row = rem >> 3, cc = rem & 7;
            const void* src = arr
                ? (const void*)(g_vth + ((size_t)bh * HDIM + row) * SEQT + kb + cc * 8)
                : (const void*)(g_kf  + ((size_t)bh * SEQT + kb + row) * HDIM + cc * 8);
            CPASYNC16(sb + bufoff + (uint32_t)arr * 9216u + row * RS + cc * 16, src);
        }
    };
    auto load_bias = [&](int kb, uint32_t bufoff) {
#pragma unroll
        for (int i = 0; i < 8; i++) {
            int g = tid + i * 512;
            int row = g >> 4, ch = g & 15;
            CPASYNC16(sb + bufoff + (uint32_t)(row * 256) +
                          ((uint32_t)(ch ^ (row & 15)) << 4),
                      biasg + (size_t)(qbase + row) * SEQT + kb + ch * 4);
        }
    };

    load_kv(0, ABUF0);
    load_bias(0, BIAS0);
    CPCOMMIT();
    CPWAIT0();
    __syncthreads();

    float oacc[2][8][4];
#pragma unroll
    for (int mi = 0; mi < 2; mi++)
#pragma unroll
        for (int i = 0; i < 8; i++)
#pragma unroll
            for (int j = 0; j < 4; j++) oacc[mi][i][j] = 0.f;
    float rsum[2][2] = {{0.f, 0.f}, {0.f, 0.f}};

    const uint32_t aColH = (uint32_t)((lane >> 4) * 8);
    const uint32_t aRowL = (uint32_t)(lane & 15);
    const uint32_t bRowB = (uint32_t)((lane & 7) + ((lane >> 4) << 3));
    const uint32_t bHi8  = (uint32_t)(((lane >> 3) & 1) * 8);

    auto bias_rd = [&](uint32_t bbuf, int rloc, int col) -> float2 {
        uint32_t addr = bbuf + (uint32_t)(rloc * 256) +
            ((uint32_t)((col >> 2) ^ (rloc & 15)) << 4) + (uint32_t)((col & 3) << 2);
        return *reinterpret_cast<float2*>(sp + addr);
    };

    for (int it = 0; it < 16; ++it) {
        const int kb = it * 64;
        const uint32_t buf  = (it & 1) ? ABUF1 : ABUF0;
        const uint32_t bbuf = (it & 1) ? BIAS1 : BIAS0;
        if (it + 1 < 16) {
            load_kv((it + 1) * 64, (it & 1) ? ABUF0 : ABUF1);
            load_bias((it + 1) * 64, (it & 1) ? BIAS0 : BIAS1);
            CPCOMMIT();
        }

        // ---- S = Q K^T over 32-key half, 32 q-rows (single term) ----
        float sacc[2][4][4];
#pragma unroll
        for (int mi = 0; mi < 2; mi++)
#pragma unroll
            for (int i = 0; i < 4; i++)
#pragma unroll
                for (int j = 0; j < 4; j++) sacc[mi][i][j] = 0.f;

#pragma unroll
        for (int kc = 0; kc < 4; kc++) {
            uint32_t kf[2][4];
#pragma unroll
            for (int nt = 0; nt < 2; nt++) {
                uint32_t addr = sb + buf + (kh2 + nt * 16 + bRowB) * RS + (kc * 16 + bHi8) * 2;
                LDM4(kf[nt][0], kf[nt][1], kf[nt][2], kf[nt][3], addr);
            }
#pragma unroll
            for (int mi = 0; mi < 2; mi++) {
                uint32_t qf[4];
                uint32_t qaddr = sb + AQF + (wq * 32 + mi * 16 + aRowL) * RS +
                                 (aColH + kc * 16) * 2;
                LDM4(qf[0], qf[1], qf[2], qf[3], qaddr);
#pragma unroll
                for (int n8 = 0; n8 < 4; n8++) {
                    const int nt = n8 >> 1, hh = (n8 & 1) * 2;
                    MMAF16(sacc[mi][n8], qf, kf[nt][hh], kf[nt][hh + 1]);
                }
            }
        }

        // ---- softmax numerators (bias + mask from smem), P -> fp16 ----
        uint32_t pph[2][8];
#pragma unroll
        for (int mi = 0; mi < 2; mi++)
#pragma unroll
            for (int n8 = 0; n8 < 4; n8++) {
                const int col  = kh2 + n8 * 8 + (lane & 3) * 2;
                const int rloc = wq * 32 + mi * 16 + (lane >> 2);
                float2 b0 = bias_rd(bbuf, rloc,     col);
                float2 b1 = bias_rd(bbuf, rloc + 8, col);
                float2 mk = *reinterpret_cast<const float2*>(
                    sp + AMSK + (kb + col) * 4);
                float p0 = __expf(sacc[mi][n8][0] + b0.x + mk.x);
                float p1 = __expf(sacc[mi][n8][1] + b0.y + mk.y);
                float p2 = __expf(sacc[mi][n8][2] + b1.x + mk.x);
                float p3 = __expf(sacc[mi][n8][3] + b1.y + mk.y);
                rsum[mi][0] += p0 + p1;
                rsum[mi][1] += p2 + p3;
                __half2 a = __floats2half2_rn(p0, p1);
                __half2 bq = __floats2half2_rn(p2, p3);
                pph[mi][n8 * 2]     = *reinterpret_cast<uint32_t*>(&a);
                pph[mi][n8 * 2 + 1] = *reinterpret_cast<uint32_t*>(&bq);
            }

        // ---- O += P V over 32-key half ----
#pragma unroll
        for (int kc2 = 0; kc2 < 2; kc2++) {
            uint32_t vfh[4][4];
#pragma unroll
            for (int nt = 0; nt < 4; nt++) {
                uint32_t addr = sb + buf + 9216u + (bRowB + nt * 16) * RS +
                                (kh2 + kc2 * 16 + bHi8) * 2;
                LDM4(vfh[nt][0], vfh[nt][1], vfh[nt][2], vfh[nt][3], addr);
            }
#pragma unroll
            for (int mi = 0; mi < 2; mi++) {
                uint32_t pah[4] = { pph[mi][4 * kc2],     pph[mi][4 * kc2 + 1],
                                    pph[mi][4 * kc2 + 2], pph[mi][4 * kc2 + 3] };
#pragma unroll
                for (int n8 = 0; n8 < 8; n8++) {
                    const int nt = n8 >> 1, hh = (n8 & 1) * 2;
                    MMAF16(oacc[mi][n8], pah, vfh[nt][hh], vfh[nt][hh + 1]);
                }
            }
        }

        CPWAIT0();
        __syncthreads();
    }

#pragma unroll
    for (int mi = 0; mi < 2; mi++)
#pragma unroll
        for (int j = 0; j < 2; j++) {
            rsum[mi][j] += __shfl_xor_sync(0xffffffffu, rsum[mi][j], 1);
            rsum[mi][j] += __shfl_xor_sync(0xffffffffu, rsum[mi][j], 2);
        }

    if (w >= 8) {
        const uint32_t ob = OSCR + (uint32_t)(w - 8) * 8192u;
#pragma unroll
        for (int mi = 0; mi < 2; mi++)
#pragma unroll
            for (int n8 = 0; n8 < 8; n8++) {
                float4 t = make_float4(oacc[mi][n8][0], oacc[mi][n8][1],
                                       oacc[mi][n8][2], oacc[mi][n8][3]);
                *reinterpret_cast<float4*>(sp + ob + mi * 4096 + n8 * 512 + lane * 16) = t;
            }
        *reinterpret_cast<float4*>(sp + RSCR + (w - 8) * 512 + lane * 16) =
            make_float4(rsum[0][0], rsum[0][1], rsum[1][0], rsum[1][1]);
    }
    __syncthreads();
    if (w < 8) {
        const uint32_t ob = OSCR + (uint32_t)w * 8192u;
        float4 prs = *reinterpret_cast<float4*>(sp + RSCR + w * 512 + lane * 16);
        float inv[2][2];
        inv[0][0] = 1.f / (rsum[0][0] + prs.x);
        inv[0][1] = 1.f / (rsum[0][1] + prs.y);
        inv[1][0] = 1.f / (rsum[1][0] + prs.z);
        inv[1][1] = 1.f / (rsum[1][1] + prs.w);

        const int col0 = h * HDIM + (lane & 3) * 2;
#pragma unroll
        for (int mi = 0; mi < 2; mi++) {
            const int row0 = qbase + wq * 32 + mi * 16 + (lane >> 2);
#pragma unroll
            for (int n8 = 0; n8 < 8; n8++) {
                float4 t = *reinterpret_cast<float4*>(
                    sp + ob + mi * 4096 + n8 * 512 + lane * 16);
                float x0 = (oacc[mi][n8][0] + t.x) * inv[mi][0];
                float x1 = (oacc[mi][n8][1] + t.y) * inv[mi][0];
                float y0 = (oacc[mi][n8][2] + t.z) * inv[mi][1];
                float y1 = (oacc[mi][n8][3] + t.w) * inv[mi][1];
                size_t i0 = (size_t)(b * SEQT + row0) * EMB + col0 + n8 * 8;
                size_t i1 = (size_t)(b * SEQT + row0 + 8) * EMB + col0 + n8 * 8;
                *reinterpret_cast<uint32_t*>(g_ao + i0) =
                    pack2h(__float2half_rn(x0), __float2half_rn(x1));
                *reinterpret_cast<uint32_t*>(g_ao + i1) =
                    pack2h(__float2half_rn(y0), __float2half_rn(y1));
            }
        }
    }
}

// ---------------------------------------------------------------------------
// Launch
// ---------------------------------------------------------------------------
extern "C" void kernel_launch(void* const* d_in, const int* in_sizes, int n_in,
                              void* d_out, int out_size)
{
    const float*         query = (const float*)d_in[0];
    const float*         abias = (const float*)d_in[1];
    const unsigned char* kmask = (const unsigned char*)d_in[2];
    const float*         in_w  = (const float*)d_in[3];
    const float*         in_b  = (const float*)d_in[4];
    const float*         out_w = (const float*)d_in[5];
    const float*         out_b = (const float*)d_in[6];
    float*               out   = (float*)d_out;

    __half *xf, *w1, *w2, *ao;
    cudaGetSymbolAddress((void**)&xf, g_xf);
    cudaGetSymbolAddress((void**)&w1, g_w1);
    cudaGetSymbolAddress((void**)&w2, g_w2);
    cudaGetSymbolAddress((void**)&ao, g_ao);

    cudaFuncSetAttribute(gemm_f16_kernel<0>,
                         cudaFuncAttributeMaxDynamicSharedMemorySize, GEMM_SMEM);
    cudaFuncSetAttribute(gemm_f16_kernel<1>,
                         cudaFuncAttributeMaxDynamicSharedMemorySize, GEMM_SMEM);
    cudaFuncSetAttribute(attn_mma_kernel,
                         cudaFuncAttributeMaxDynamicSharedMemorySize, ATTN_SMEM);

    // 0) operand conversion (all single fp16 now)
    half_kernel<<<(MTOK * EMB / 4 + 255) / 256, 256>>>(query, xf, MTOK * EMB / 4);
    half_kernel<<<(E3 * EMB / 4 + 255) / 256, 256>>>(in_w, w1, E3 * EMB / 4);
    half_kernel<<<(EMB * EMB / 4 + 255) / 256, 256>>>(out_w, w2, EMB * EMB / 4);

    // 1) QKV projection (uniform 1-term BK=64) + fused epilogue
    {
        dim3 grid(E3 / 128, MTOK / 128);
        gemm_f16_kernel<1><<<grid, 256, GEMM_SMEM>>>(xf, w1, in_b, nullptr, E3, EMB);
    }
    // 2) Attention
    {
        dim3 grid(SEQT / 256, BH);
        attn_mma_kernel<<<grid, 512, ATTN_SMEM>>>(abias, kmask);
    }
    // 3) Output projection
    {
        dim3 grid(EMB / 128, MTOK / 128);
        gemm_f16_kernel<0><<<grid, 256, GEMM_SMEM>>>(ao, w2, out_b, out, EMB, EMB);
    }
}

// round 16
// speedup vs baseline: 7.7691x; 1.0470x over previous
#include <cuda_runtime.h>
#include <cuda_bf16.h>
#include <cuda_fp16.h>
#include <cstdint>
#include <math.h>

#define BATCH 4
#define SEQT 1024
#define EMB 1024
#define NHEAD 16
#define HDIM 64
#define E3 (3 * EMB)
#define MTOK (BATCH * SEQT)
#define BH (BATCH * NHEAD)

// Scratch (fp16 operands)
__device__ __half g_xf [(size_t)MTOK * EMB];
__device__ __half g_w1 [(size_t)E3 * EMB];
__device__ __half g_w2 [(size_t)EMB * EMB];
__device__ __half g_ao [(size_t)MTOK * EMB];
__device__ __half g_qf [(size_t)BH * SEQT * HDIM];
__device__ __half g_kf [(size_t)BH * SEQT * HDIM];
__device__ __half g_vth[(size_t)BH * HDIM * SEQT];

// ---------------------------------------------------------------------------
// helpers
// ---------------------------------------------------------------------------
__device__ __forceinline__ uint32_t smem_u32(const void* p) {
    uint32_t a;
    asm("{ .reg .u64 t; cvta.to.shared.u64 t, %1; cvt.u32.u64 %0, t; }"
        : "=r"(a) : "l"(p));
    return a;
}

#define LDM4(r0, r1, r2, r3, addr) \
    asm volatile("ldmatrix.sync.aligned.m8n8.x4.shared.b16 {%0,%1,%2,%3}, [%4];" \
                 : "=r"(r0), "=r"(r1), "=r"(r2), "=r"(r3) : "r"(addr))

#define MMAF16(d, a, b0, b1) \
    asm volatile("mma.sync.aligned.m16n8k16.row.col.f32.f16.f16.f32 " \
                 "{%0,%1,%2,%3},{%4,%5,%6,%7},{%8,%9},{%0,%1,%2,%3};" \
                 : "+f"((d)[0]), "+f"((d)[1]), "+f"((d)[2]), "+f"((d)[3]) \
                 : "r"((a)[0]), "r"((a)[1]), "r"((a)[2]), "r"((a)[3]), \
                   "r"(b0), "r"(b1))

#define CPASYNC16(sdst, gsrc) \
    asm volatile("cp.async.cg.shared.global [%0], [%1], 16;" \
                 :: "r"(sdst), "l"(gsrc) : "memory")
#define CPCOMMIT() asm volatile("cp.async.commit_group;" ::: "memory")
#define CPWAIT0()  asm volatile("cp.async.wait_group 0;" ::: "memory")
#define CPWAIT1()  asm volatile("cp.async.wait_group 1;" ::: "memory")

__device__ __forceinline__ uint32_t pack2h(__half a, __half b) {
    __half2 t(a, b);
    return *reinterpret_cast<uint32_t*>(&t);
}

// ---------------------------------------------------------------------------
// Fused fp32 -> fp16 converter for all three operands (one launch)
// ---------------------------------------------------------------------------
#define CQ4 (MTOK * EMB / 4)          // 1048576
#define CW14 (E3 * EMB / 4)           // 786432
#define CW24 (EMB * EMB / 4)          // 262144
#define CTOT (CQ4 + CW14 + CW24)

__global__ __launch_bounds__(256)
void convert_all_kernel(const float* __restrict__ q,
                        const float* __restrict__ w1s,
                        const float* __restrict__ w2s)
{
    int i = blockIdx.x * 256 + threadIdx.x;
    if (i >= CTOT) return;
    const float* src;
    __half* dst;
    int j;
    if (i < CQ4)             { src = q;   dst = g_xf; j = i; }
    else if (i < CQ4 + CW14) { src = w1s; dst = g_w1; j = i - CQ4; }
    else                     { src = w2s; dst = g_w2; j = i - CQ4 - CW14; }
    float4 v = reinterpret_cast<const float4*>(src)[j];
    reinterpret_cast<uint2*>(dst)[j] =
        make_uint2(pack2h(__float2half_rn(v.x), __float2half_rn(v.y)),
                   pack2h(__float2half_rn(v.z), __float2half_rn(v.w)));
}

// ---------------------------------------------------------------------------
// fp16 1-term GEMM, BK=64, 3-stage, 2 CTAs/SM, strength-reduced loader.
// CTA 128x128, 256 thr, warps 4(m) x 2(n), warp tile 32x64.
// ---------------------------------------------------------------------------
#define STG64 32768u
#define GEMM_SMEM (3 * 32768 + 128)

template<int EPI>
__global__ __launch_bounds__(256, 2)
void gemm_f16_kernel(const __half* __restrict__ As,
                     const __half* __restrict__ Bs,
                     const float* __restrict__ bias,
                     float* __restrict__ C,
                     int N, int K)
{
    extern __shared__ char dsm[];
    char* sp = dsm + ((128 - (smem_u32(dsm) & 127)) & 127);
    const uint32_t sb = smem_u32(sp);

    const int tid  = threadIdx.x;
    const int lane = tid & 31;
    const int wm   = (tid >> 5) & 3;
    const int wn   = tid >> 7;
    const int rowBase = blockIdx.y * 128;
    const int colBase = blockIdx.x * 128;

    float acc[2][8][4];
#pragma unroll
    for (int i = 0; i < 2; i++)
#pragma unroll
        for (int j = 0; j < 8; j++)
#pragma unroll
            for (int q = 0; q < 4; q++) acc[i][j][q] = 0.f;

    // --- strength-reduced loader state ---
    const int lrow = tid >> 3;            // 0..31
    const int lcc  = tid & 7;
    const int lcs  = lcc ^ (lrow & 7);    // per-thread constant swizzle
    const uint32_t d0 = (uint32_t)(lrow * 128 + lcs * 16);
    const __half* pa = As + (size_t)(rowBase + lrow) * K + lcc * 8;
    const __half* pb = Bs + (size_t)(colBase + lrow) * K + lcc * 8;
    const size_t rstep = (size_t)32 * K;

    auto issue = [&](int kt, uint32_t so) {
#pragma unroll
        for (int i = 0; i < 4; i++)
            CPASYNC16(so + d0 + 4096u * i, pa + kt + rstep * i);
#pragma unroll
        for (int i = 0; i < 4; i++)
            CPASYNC16(so + 16384u + d0 + 4096u * i, pb + kt + rstep * i);
    };

    const uint32_t aRow = (uint32_t)(wm * 32 + (lane & 15));
    const uint32_t aHi  = (uint32_t)(lane >> 4);
    const uint32_t bRow = (uint32_t)(wn * 64 + (lane & 7) + ((lane >> 4) << 3));
    const uint32_t bHi  = (uint32_t)((lane >> 3) & 1);
    const uint32_t aSwz = aRow & 7;
    const uint32_t bSwz = bRow & 7;

    const int NIT = K / 64;
    uint32_t tbc = sb;                 // current stage
    uint32_t tbn = sb + STG64;         // next
    uint32_t tbi = sb + 2 * STG64;     // issue target

    issue(0, tbc);  CPCOMMIT();
    issue(64, tbn); CPCOMMIT();

    for (int it = 0; it < NIT; ++it) {
        CPWAIT1();
        __syncthreads();
        if (it + 2 < NIT) issue((it + 2) * 64, tbi);
        CPCOMMIT();

        const uint32_t tb = tbc;
#pragma unroll
        for (int ks = 0; ks < 4; ks++) {
            uint32_t ah[2][4], bs[4][4];
            const uint32_t caA = ((uint32_t)(ks * 2) + aHi) ^ aSwz;
            const uint32_t caB = ((uint32_t)(ks * 2) + bHi) ^ bSwz;
#pragma unroll
            for (int mi = 0; mi < 2; mi++) {
                uint32_t addr = tb + (aRow + mi * 16) * 128 + caA * 16;
                LDM4(ah[mi][0], ah[mi][1], ah[mi][2], ah[mi][3], addr);
            }
#pragma unroll
            for (int nt = 0; nt < 4; nt++) {
                uint32_t addr = tb + 16384u + (bRow + nt * 16) * 128 + caB * 16;
                LDM4(bs[nt][0], bs[nt][1], bs[nt][2], bs[nt][3], addr);
            }
#pragma unroll
            for (int mi = 0; mi < 2; mi++)
#pragma unroll
                for (int n8 = 0; n8 < 8; n8++) {
                    const int nt = n8 >> 1, hh = (n8 & 1) * 2;
                    MMAF16(acc[mi][n8], ah[mi], bs[nt][hh], bs[nt][hh + 1]);
                }
        }
        // rotate ring
        uint32_t t = tbc; tbc = tbn; tbn = tbi; tbi = t;
    }

    const int r0 = rowBase + wm * 32 + (lane >> 2);
    const int c0 = colBase + wn * 64 + (lane & 3) * 2;

    if (EPI == 0) {
#pragma unroll
        for (int mi = 0; mi < 2; mi++)
#pragma unroll
            for (int n8 = 0; n8 < 8; n8++) {
                const int row = r0 + mi * 16;
                const int col = c0 + n8 * 8;
                const float2 bv = *reinterpret_cast<const float2*>(bias + col);
                float2 o0 = make_float2(acc[mi][n8][0] + bv.x, acc[mi][n8][1] + bv.y);
                float2 o1 = make_float2(acc[mi][n8][2] + bv.x, acc[mi][n8][3] + bv.y);
                *reinterpret_cast<float2*>(C + (size_t)row * N + col)       = o0;
                *reinterpret_cast<float2*>(C + (size_t)(row + 8) * N + col) = o1;
            }
    } else {
        auto wr = [&](int row, int col, float x0, float x1) {
            const int sect = col >> 10;
            const int coli = col & 1023;
            const int bb = row >> 10, t = row & 1023;
            const int hh = coli >> 6, d = coli & 63;
            if (sect == 2) {
                const size_t base = (size_t)(bb * 16 + hh) * HDIM;
                g_vth[(base + d)     * SEQT + t] = __float2half_rn(x0);
                g_vth[(base + d + 1) * SEQT + t] = __float2half_rn(x1);
            } else {
                const size_t idx = ((size_t)(bb * 16 + hh) * 1024 + t) * 64 + d;
                if (sect == 0) {
                    *reinterpret_cast<uint32_t*>(g_qf + idx) =
                        pack2h(__float2half_rn(x0 * 0.125f),
                               __float2half_rn(x1 * 0.125f));
                } else {
                    *reinterpret_cast<uint32_t*>(g_kf + idx) =
                        pack2h(__float2half_rn(x0), __float2half_rn(x1));
                }
            }
        };
#pragma unroll
        for (int mi = 0; mi < 2; mi++)
#pragma unroll
            for (int n8 = 0; n8 < 8; n8++) {
                const int row = r0 + mi * 16;
                const int col = c0 + n8 * 8;
                const float2 bv = *reinterpret_cast<const float2*>(bias + col);
                wr(row,     col, acc[mi][n8][0] + bv.x, acc[mi][n8][1] + bv.y);
                wr(row + 8, col, acc[mi][n8][2] + bv.x, acc[mi][n8][3] + bv.y);
            }
    }
}

// ---------------------------------------------------------------------------
// Flash attention: 256 q-rows/CTA, 32 q-rows/warp, key-split halves.
// Strength-reduced KV/bias loaders. Bias via smem; mask folds -EXPSHIFT.
// ---------------------------------------------------------------------------
#define AQF   0u
#define ABUF0 36864u
#define ABUF1 55296u
#define AMSK  73728u
#define BIAS0 77824u
#define BIAS1 143360u
#define OSCR  0u
#define RSCR  65536u
#define ATTN_SMEM (208896 + 128)
#define RS 144u
#define EXPSHIFT 10.0f

__global__ __launch_bounds__(512, 1)
void attn_mma_kernel(const float* __restrict__ attn_bias,
                     const unsigned char* __restrict__ kmask)
{
    extern __shared__ char dsm[];
    char* sp = dsm + ((128 - (smem_u32(dsm) & 127)) & 127);
    const uint32_t sb = smem_u32(sp);

    const int bh = blockIdx.y;
    const int b  = bh >> 4;
    const int h  = bh & 15;
    const int qbase = blockIdx.x * 256;
    const int tid  = threadIdx.x;
    const int lane = tid & 31;
    const int w    = tid >> 5;
    const int wq   = w & 7;
    const int kh2  = (w >> 3) * 32;

    for (int i = tid; i < SEQT; i += 512)
        *reinterpret_cast<float*>(sp + AMSK + i * 4) =
            kmask[b * SEQT + i] ? -3.0e38f : -EXPSHIFT;

#pragma unroll
    for (int i = 0; i < 4; i++) {
        int g = tid + i * 512;
        int row = g >> 3, cc = g & 7;
        CPASYNC16(sb + AQF + row * RS + cc * 16,
                  g_qf + ((size_t)bh * SEQT + qbase + row) * HDIM + cc * 8);
    }

    // --- strength-reduced KV loader state ---
    const int krow = tid >> 3, kcc = tid & 7;      // krow 0..63
    const uint32_t kvd = (uint32_t)(krow * RS + kcc * 16);
    const __half* pk = g_kf  + ((size_t)bh * SEQT + krow) * HDIM + kcc * 8;
    const __half* pv = g_vth + ((size_t)bh * HDIM + krow) * SEQT + kcc * 8;

    auto load_kv = [&](int kb, uint32_t bufoff) {
        CPASYNC16(sb + bufoff + kvd,         pk + (size_t)kb * HDIM);
        CPASYNC16(sb + bufoff + 9216u + kvd, pv + kb);
    };

    // --- strength-reduced bias loader state ---
    const int brow = tid >> 4, bch = tid & 15;     // brow 0..31
    const int bswz = bch ^ (brow & 15);
    const uint32_t bd0 = (uint32_t)(brow * 256 + bswz * 16);
    const float* pbias = attn_bias + (size_t)bh * SEQT * SEQT +
                         (size_t)(qbase + brow) * SEQT + bch * 4;

    auto load_bias = [&](int kb, uint32_t bufoff) {
#pragma unroll
        for (int i = 0; i < 8; i++)
            CPASYNC16(sb + bufoff + bd0 + 8192u * i,
                      pbias + (size_t)(32 * i) * SEQT + kb);
    };

    load_kv(0, ABUF0);
    load_bias(0, BIAS0);
    CPCOMMIT();
    CPWAIT0();
    __syncthreads();

    float oacc[2][8][4];
#pragma unroll
    for (int mi = 0; mi < 2; mi++)
#pragma unroll
        for (int i = 0; i < 8; i++)
#pragma unroll
            for (int j = 0; j < 4; j++) oacc[mi][i][j] = 0.f;
    float rsum[2][2] = {{0.f, 0.f}, {0.f, 0.f}};

    const uint32_t aColH = (uint32_t)((lane >> 4) * 8);
    const uint32_t aRowL = (uint32_t)(lane & 15);
    const uint32_t bRowB = (uint32_t)((lane & 7) + ((lane >> 4) << 3));
    const uint32_t bHi8  = (uint32_t)(((lane >> 3) & 1) * 8);

    auto bias_rd = [&](uint32_t bbuf, int rloc, int col) -> float2 {
        uint32_t addr = bbuf + (uint32_t)(rloc * 256) +
            ((uint32_t)((col >> 2) ^ (rloc & 15)) << 4) + (uint32_t)((col & 3) << 2);
        return *reinterpret_cast<float2*>(sp + addr);
    };

    for (int it = 0; it < 16; ++it) {
        const int kb = it * 64;
        const uint32_t buf  = (it & 1) ? ABUF1 : ABUF0;
        const uint32_t bbuf = (it & 1) ? BIAS1 : BIAS0;
        if (it + 1 < 16) {
            load_kv((it + 1) * 64, (it & 1) ? ABUF0 : ABUF1);
            load_bias((it + 1) * 64, (it & 1) ? BIAS0 : BIAS1);
            CPCOMMIT();
        }

        // ---- S = Q K^T over 32-key half, 32 q-rows ----
        float sacc[2][4][4];
#pragma unroll
        for (int mi = 0; mi < 2; mi++)
#pragma unroll
            for (int i = 0; i < 4; i++)
#pragma unroll
                for (int j = 0; j < 4; j++) sacc[mi][i][j] = 0.f;

#pragma unroll
        for (int kc = 0; kc < 4; kc++) {
            uint32_t kf[2][4];
#pragma unroll
            for (int nt = 0; nt < 2; nt++) {
                uint32_t addr = sb + buf + (kh2 + nt * 16 + bRowB) * RS + (kc * 16 + bHi8) * 2;
                LDM4(kf[nt][0], kf[nt][1], kf[nt][2], kf[nt][3], addr);
            }
#pragma unroll
            for (int mi = 0; mi < 2; mi++) {
                uint32_t qf[4];
                uint32_t qaddr = sb + AQF + (wq * 32 + mi * 16 + aRowL) * RS +
                                 (aColH + kc * 16) * 2;
                LDM4(qf[0], qf[1], qf[2], qf[3], qaddr);
#pragma unroll
                for (int n8 = 0; n8 < 4; n8++) {
                    const int nt = n8 >> 1, hh = (n8 & 1) * 2;
                    MMAF16(sacc[mi][n8], qf, kf[nt][hh], kf[nt][hh + 1]);
                }
            }
        }

        // ---- softmax numerators, P -> fp16 ----
        uint32_t pph[2][8];
#pragma unroll
        for (int mi = 0; mi < 2; mi++)
#pragma unroll
            for (int n8 = 0; n8 < 4; n8++) {
                const int col  = kh2 + n8 * 8 + (lane & 3) * 2;
                const int rloc = wq * 32 + mi * 16 + (lane >> 2);
                float2 b0 = bias_rd(bbuf, rloc,     col);
                float2 b1 = bias_rd(bbuf, rloc + 8, col);
                float2 mk = *reinterpret_cast<const float2*>(
                    sp + AMSK + (kb + col) * 4);
                float p0 = __expf(sacc[mi][n8][0] + b0.x + mk.x);
                float p1 = __expf(sacc[mi][n8][1] + b0.y + mk.y);
                float p2 = __expf(sacc[mi][n8][2] + b1.x + mk.x);
                float p3 = __expf(sacc[mi][n8][3] + b1.y + mk.y);
                rsum[mi][0] += p0 + p1;
                rsum[mi][1] += p2 + p3;
                __half2 a = __floats2half2_rn(p0, p1);
                __half2 bq = __floats2half2_rn(p2, p3);
                pph[mi][n8 * 2]     = *reinterpret_cast<uint32_t*>(&a);
                pph[mi][n8 * 2 + 1] = *reinterpret_cast<uint32_t*>(&bq);
            }

        // ---- O += P V over 32-key half ----
#pragma unroll
        for (int kc2 = 0; kc2 < 2; kc2++) {
            uint32_t vfh[4][4];
#pragma unroll
            for (int nt = 0; nt < 4; nt++) {
                uint32_t addr = sb + buf + 9216u + (bRowB + nt * 16) * RS +
                                (kh2 + kc2 * 16 + bHi8) * 2;
                LDM4(vfh[nt][0], vfh[nt][1], vfh[nt][2], vfh[nt][3], addr);
            }
#pragma unroll
            for (int mi = 0; mi < 2; mi++) {
                uint32_t pah[4] = { pph[mi][4 * kc2],     pph[mi][4 * kc2 + 1],
                                    pph[mi][4 * kc2 + 2], pph[mi][4 * kc2 + 3] };
#pragma unroll
                for (int n8 = 0; n8 < 8; n8++) {
                    const int nt = n8 >> 1, hh = (n8 & 1) * 2;
                    MMAF16(oacc[mi][n8], pah, vfh[nt][hh], vfh[nt][hh + 1]);
                }
            }
        }

        CPWAIT0();
        __syncthreads();
    }

#pragma unroll
    for (int mi = 0; mi < 2; mi++)
#pragma unroll
        for (int j = 0; j < 2; j++) {
            rsum[mi][j] += __shfl_xor_sync(0xffffffffu, rsum[mi][j], 1);
            rsum[mi][j] += __shfl_xor_sync(0xffffffffu, rsum[mi][j], 2);
        }

    if (w >= 8) {
        const uint32_t ob = OSCR + (uint32_t)(w - 8) * 8192u;
#pragma unroll
        for (int mi = 0; mi < 2; mi++)
#pragma unroll
            for (int n8 = 0; n8 < 8; n8++) {
                float4 t = make_float4(oacc[mi][n8][0], oacc[mi][n8][1],
                                       oacc[mi][n8][2], oacc[mi][n8][3]);
                *reinterpret_cast<float4*>(sp + ob + mi * 4096 + n8 * 512 + lane * 16) = t;
            }
        *reinterpret_cast<float4*>(sp + RSCR + (w - 8) * 512 + lane * 16) =
            make_float4(rsum[0][0], rsum[0][1], rsum[1][0], rsum[1][1]);
    }
    __syncthreads();
    if (w < 8) {
        const uint32_t ob = OSCR + (uint32_t)w * 8192u;
        float4 prs = *reinterpret_cast<float4*>(sp + RSCR + w * 512 + lane * 16);
        float inv[2][2];
        inv[0][0] = 1.f / (rsum[0][0] + prs.x);
        inv[0][1] = 1.f / (rsum[0][1] + prs.y);
        inv[1][0] = 1.f / (rsum[1][0] + prs.z);
        inv[1][1] = 1.f / (rsum[1][1] + prs.w);

        const int col0 = h * HDIM + (lane & 3) * 2;
#pragma unroll
        for (int mi = 0; mi < 2; mi++) {
            const int row0 = qbase + wq * 32 + mi * 16 + (lane >> 2);
#pragma unroll
            for (int n8 = 0; n8 < 8; n8++) {
                float4 t = *reinterpret_cast<float4*>(
                    sp + ob + mi * 4096 + n8 * 512 + lane * 16);
                float x0 = (oacc[mi][n8][0] + t.x) * inv[mi][0];
                float x1 = (oacc[mi][n8][1] + t.y) * inv[mi][0];
                float y0 = (oacc[mi][n8][2] + t.z) * inv[mi][1];
                float y1 = (oacc[mi][n8][3] + t.w) * inv[mi][1];
                size_t i0 = (size_t)(b * SEQT + row0) * EMB + col0 + n8 * 8;
                size_t i1 = (size_t)(b * SEQT + row0 + 8) * EMB + col0 + n8 * 8;
                *reinterpret_cast<uint32_t*>(g_ao + i0) =
                    pack2h(__float2half_rn(x0), __float2half_rn(x1));
                *reinterpret_cast<uint32_t*>(g_ao + i1) =
                    pack2h(__float2half_rn(y0), __float2half_rn(y1));
            }
        }
    }
}

// ---------------------------------------------------------------------------
// Launch
// ---------------------------------------------------------------------------
extern "C" void kernel_launch(void* const* d_in, const int* in_sizes, int n_in,
                              void* d_out, int out_size)
{
    const float*         query = (const float*)d_in[0];
    const float*         abias = (const float*)d_in[1];
    const unsigned char* kmask = (const unsigned char*)d_in[2];
    const float*         in_w  = (const float*)d_in[3];
    const float*         in_b  = (const float*)d_in[4];
    const float*         out_w = (const float*)d_in[5];
    const float*         out_b = (const float*)d_in[6];
    float*               out   = (float*)d_out;

    __half *xf, *w1, *w2, *ao;
    cudaGetSymbolAddress((void**)&xf, g_xf);
    cudaGetSymbolAddress((void**)&w1, g_w1);
    cudaGetSymbolAddress((void**)&w2, g_w2);
    cudaGetSymbolAddress((void**)&ao, g_ao);

    cudaFuncSetAttribute(gemm_f16_kernel<0>,
                         cudaFuncAttributeMaxDynamicSharedMemorySize, GEMM_SMEM);
    cudaFuncSetAttribute(gemm_f16_kernel<1>,
                         cudaFuncAttributeMaxDynamicSharedMemorySize, GEMM_SMEM);
    cudaFuncSetAttribute(attn_mma_kernel,
                         cudaFuncAttributeMaxDynamicSharedMemorySize, ATTN_SMEM);

    // 0) fused operand conversion (single launch)
    convert_all_kernel<<<(CTOT + 255) / 256, 256>>>(query, in_w, out_w);

    // 1) QKV projection + fused epilogue
    {
        dim3 grid(E3 / 128, MTOK / 128);
        gemm_f16_kernel<1><<<grid, 256, GEMM_SMEM>>>(xf, w1, in_b, nullptr, E3, EMB);
    }
    // 2) Attention
    {
        dim3 grid(SEQT / 256, BH);
        attn_mma_kernel<<<grid, 512, ATTN_SMEM>>>(abias, kmask);
    }
    // 3) Output projection
    {
        dim3 grid(EMB / 128, MTOK / 128);
        gemm_f16_kernel<0><<<grid, 256, GEMM_SMEM>>>(ao, w2, out_b, out, EMB, EMB);
    }
}

// round 17
// speedup vs baseline: 7.8280x; 1.0076x over previous
#include <cuda_runtime.h>
#include <cuda_bf16.h>
#include <cuda_fp16.h>
#include <cstdint>
#include <math.h>

#define BATCH 4
#define SEQT 1024
#define EMB 1024
#define NHEAD 16
#define HDIM 64
#define E3 (3 * EMB)
#define MTOK (BATCH * SEQT)
#define BH (BATCH * NHEAD)

// Scratch (fp16 operands)
__device__ __half g_xf [(size_t)MTOK * EMB];
__device__ __half g_w1 [(size_t)E3 * EMB];
__device__ __half g_w2 [(size_t)EMB * EMB];
__device__ __half g_ao [(size_t)MTOK * EMB];
__device__ __half g_qf [(size_t)BH * SEQT * HDIM];
__device__ __half g_kf [(size_t)BH * SEQT * HDIM];
__device__ __half g_vth[(size_t)BH * HDIM * SEQT];

// ---------------------------------------------------------------------------
// helpers
// ---------------------------------------------------------------------------
__device__ __forceinline__ uint32_t smem_u32(const void* p) {
    uint32_t a;
    asm("{ .reg .u64 t; cvta.to.shared.u64 t, %1; cvt.u32.u64 %0, t; }"
        : "=r"(a) : "l"(p));
    return a;
}

#define LDM4(r0, r1, r2, r3, addr) \
    asm volatile("ldmatrix.sync.aligned.m8n8.x4.shared.b16 {%0,%1,%2,%3}, [%4];" \
                 : "=r"(r0), "=r"(r1), "=r"(r2), "=r"(r3) : "r"(addr))

#define MMAF16(d, a, b0, b1) \
    asm volatile("mma.sync.aligned.m16n8k16.row.col.f32.f16.f16.f32 " \
                 "{%0,%1,%2,%3},{%4,%5,%6,%7},{%8,%9},{%0,%1,%2,%3};" \
                 : "+f"((d)[0]), "+f"((d)[1]), "+f"((d)[2]), "+f"((d)[3]) \
                 : "r"((a)[0]), "r"((a)[1]), "r"((a)[2]), "r"((a)[3]), \
                   "r"(b0), "r"(b1))

#define CPASYNC16(sdst, gsrc) \
    asm volatile("cp.async.cg.shared.global [%0], [%1], 16;" \
                 :: "r"(sdst), "l"(gsrc) : "memory")
#define CPCOMMIT() asm volatile("cp.async.commit_group;" ::: "memory")
#define CPWAIT0()  asm volatile("cp.async.wait_group 0;" ::: "memory")
#define CPWAIT1()  asm volatile("cp.async.wait_group 1;" ::: "memory")

__device__ __forceinline__ uint32_t pack2h(__half a, __half b) {
    __half2 t(a, b);
    return *reinterpret_cast<uint32_t*>(&t);
}

// ---------------------------------------------------------------------------
// Fused fp32 -> fp16 converter (one launch)
// ---------------------------------------------------------------------------
#define CQ4 (MTOK * EMB / 4)
#define CW14 (E3 * EMB / 4)
#define CW24 (EMB * EMB / 4)
#define CTOT (CQ4 + CW14 + CW24)

__global__ __launch_bounds__(256)
void convert_all_kernel(const float* __restrict__ q,
                        const float* __restrict__ w1s,
                        const float* __restrict__ w2s)
{
    int i = blockIdx.x * 256 + threadIdx.x;
    if (i >= CTOT) return;
    const float* src;
    __half* dst;
    int j;
    if (i < CQ4)             { src = q;   dst = g_xf; j = i; }
    else if (i < CQ4 + CW14) { src = w1s; dst = g_w1; j = i - CQ4; }
    else                     { src = w2s; dst = g_w2; j = i - CQ4 - CW14; }
    float4 v = reinterpret_cast<const float4*>(src)[j];
    reinterpret_cast<uint2*>(dst)[j] =
        make_uint2(pack2h(__float2half_rn(v.x), __float2half_rn(v.y)),
                   pack2h(__float2half_rn(v.z), __float2half_rn(v.w)));
}

// ---------------------------------------------------------------------------
// fp16 1-term GEMM, BK=64, 3-stage, 2 CTAs/SM.
// Mainloop: explicit fragment double-buffering across ks (LDSM of ks+1
// overlaps MMAs of ks).
// ---------------------------------------------------------------------------
#define STG64 32768u
#define GEMM_SMEM (3 * 32768 + 128)

template<int EPI>
__global__ __launch_bounds__(256, 2)
void gemm_f16_kernel(const __half* __restrict__ As,
                     const __half* __restrict__ Bs,
                     const float* __restrict__ bias,
                     float* __restrict__ C,
                     int N, int K)
{
    extern __shared__ char dsm[];
    char* sp = dsm + ((128 - (smem_u32(dsm) & 127)) & 127);
    const uint32_t sb = smem_u32(sp);

    const int tid  = threadIdx.x;
    const int lane = tid & 31;
    const int wm   = (tid >> 5) & 3;
    const int wn   = tid >> 7;
    const int rowBase = blockIdx.y * 128;
    const int colBase = blockIdx.x * 128;

    float acc[2][8][4];
#pragma unroll
    for (int i = 0; i < 2; i++)
#pragma unroll
        for (int j = 0; j < 8; j++)
#pragma unroll
            for (int q = 0; q < 4; q++) acc[i][j][q] = 0.f;

    // --- loader: running pointers, constant swizzle ---
    const int lrow = tid >> 3;
    const int lcc  = tid & 7;
    const int lcs  = lcc ^ (lrow & 7);
    const uint32_t d0 = (uint32_t)(lrow * 128 + lcs * 16);
    const __half* pa = As + (size_t)(rowBase + lrow) * K + lcc * 8;
    const __half* pb = Bs + (size_t)(colBase + lrow) * K + lcc * 8;
    const size_t rstep = (size_t)32 * K;

    auto issue = [&](uint32_t so) {
#pragma unroll
        for (int i = 0; i < 4; i++)
            CPASYNC16(so + d0 + 4096u * i, pa + rstep * i);
#pragma unroll
        for (int i = 0; i < 4; i++)
            CPASYNC16(so + 16384u + d0 + 4096u * i, pb + rstep * i);
        pa += 64; pb += 64;
    };

    const uint32_t aRow = (uint32_t)(wm * 32 + (lane & 15));
    const uint32_t aHi  = (uint32_t)(lane >> 4);
    const uint32_t bRow = (uint32_t)(wn * 64 + (lane & 7) + ((lane >> 4) << 3));
    const uint32_t bHi  = (uint32_t)((lane >> 3) & 1);
    const uint32_t aSwz = aRow & 7;
    const uint32_t bSwz = bRow & 7;
    // base addresses within a stage (add tb at use)
    const uint32_t aAddr0 = aRow * 128;
    const uint32_t aAddr1 = (aRow + 16) * 128;
    const uint32_t bAddr0 = 16384u + bRow * 128;

    const int NIT = K / 64;
    uint32_t tbc = sb;
    uint32_t tbn = sb + STG64;
    uint32_t tbi = sb + 2 * STG64;

    issue(tbc); CPCOMMIT();
    issue(tbn); CPCOMMIT();

    for (int it = 0; it < NIT; ++it) {
        CPWAIT1();
        __syncthreads();
        if (it + 2 < NIT) issue(tbi);
        CPCOMMIT();

        const uint32_t tb = tbc;
        uint32_t ah[2][2][4], bsf[2][4][4];

        // preload ks=0 fragments
        {
            const uint32_t caA = aHi ^ aSwz;
            const uint32_t caB = bHi ^ bSwz;
            LDM4(ah[0][0][0], ah[0][0][1], ah[0][0][2], ah[0][0][3],
                 tb + aAddr0 + caA * 16);
            LDM4(ah[0][1][0], ah[0][1][1], ah[0][1][2], ah[0][1][3],
                 tb + aAddr1 + caA * 16);
#pragma unroll
            for (int nt = 0; nt < 4; nt++)
                LDM4(bsf[0][nt][0], bsf[0][nt][1], bsf[0][nt][2], bsf[0][nt][3],
                     tb + bAddr0 + nt * 2048 + caB * 16);
        }

#pragma unroll
        for (int ks = 0; ks < 4; ks++) {
            const int cur = ks & 1, nxt = cur ^ 1;
            if (ks < 3) {
                const uint32_t caA = ((uint32_t)((ks + 1) * 2) + aHi) ^ aSwz;
                const uint32_t caB = ((uint32_t)((ks + 1) * 2) + bHi) ^ bSwz;
                LDM4(ah[nxt][0][0], ah[nxt][0][1], ah[nxt][0][2], ah[nxt][0][3],
                     tb + aAddr0 + caA * 16);
                LDM4(ah[nxt][1][0], ah[nxt][1][1], ah[nxt][1][2], ah[nxt][1][3],
                     tb + aAddr1 + caA * 16);
#pragma unroll
                for (int nt = 0; nt < 4; nt++)
                    LDM4(bsf[nxt][nt][0], bsf[nxt][nt][1],
                         bsf[nxt][nt][2], bsf[nxt][nt][3],
                         tb + bAddr0 + nt * 2048 + caB * 16);
            }
#pragma unroll
            for (int mi = 0; mi < 2; mi++)
#pragma unroll
                for (int n8 = 0; n8 < 8; n8++) {
                    const int nt = n8 >> 1, hh = (n8 & 1) * 2;
                    MMAF16(acc[mi][n8], ah[cur][mi],
                           bsf[cur][nt][hh], bsf[cur][nt][hh + 1]);
                }
        }
        uint32_t t = tbc; tbc = tbn; tbn = tbi; tbi = t;
    }

    const int r0 = rowBase + wm * 32 + (lane >> 2);
    const int c0 = colBase + wn * 64 + (lane & 3) * 2;

    if (EPI == 0) {
#pragma unroll
        for (int mi = 0; mi < 2; mi++)
#pragma unroll
            for (int n8 = 0; n8 < 8; n8++) {
                const int row = r0 + mi * 16;
                const int col = c0 + n8 * 8;
                const float2 bv = *reinterpret_cast<const float2*>(bias + col);
                float2 o0 = make_float2(acc[mi][n8][0] + bv.x, acc[mi][n8][1] + bv.y);
                float2 o1 = make_float2(acc[mi][n8][2] + bv.x, acc[mi][n8][3] + bv.y);
                *reinterpret_cast<float2*>(C + (size_t)row * N + col)       = o0;
                *reinterpret_cast<float2*>(C + (size_t)(row + 8) * N + col) = o1;
            }
    } else {
        auto wr = [&](int row, int col, float x0, float x1) {
            const int sect = col >> 10;
            const int coli = col & 1023;
            const int bb = row >> 10, t = row & 1023;
            const int hh = coli >> 6, d = coli & 63;
            if (sect == 2) {
                const size_t base = (size_t)(bb * 16 + hh) * HDIM;
                g_vth[(base + d)     * SEQT + t] = __float2half_rn(x0);
                g_vth[(base + d + 1) * SEQT + t] = __float2half_rn(x1);
            } else {
                const size_t idx = ((size_t)(bb * 16 + hh) * 1024 + t) * 64 + d;
                if (sect == 0) {
                    *reinterpret_cast<uint32_t*>(g_qf + idx) =
                        pack2h(__float2half_rn(x0 * 0.125f),
                               __float2half_rn(x1 * 0.125f));
                } else {
                    *reinterpret_cast<uint32_t*>(g_kf + idx) =
                        pack2h(__float2half_rn(x0), __float2half_rn(x1));
                }
            }
        };
#pragma unroll
        for (int mi = 0; mi < 2; mi++)
#pragma unroll
            for (int n8 = 0; n8 < 8; n8++) {
                const int row = r0 + mi * 16;
                const int col = c0 + n8 * 8;
                const float2 bv = *reinterpret_cast<const float2*>(bias + col);
                wr(row,     col, acc[mi][n8][0] + bv.x, acc[mi][n8][1] + bv.y);
                wr(row + 8, col, acc[mi][n8][2] + bv.x, acc[mi][n8][3] + bv.y);
            }
    }
}

// ---------------------------------------------------------------------------
// Flash attention (unchanged from round 16)
// ---------------------------------------------------------------------------
#define AQF   0u
#define ABUF0 36864u
#define ABUF1 55296u
#define AMSK  73728u
#define BIAS0 77824u
#define BIAS1 143360u
#define OSCR  0u
#define RSCR  65536u
#define ATTN_SMEM (208896 + 128)
#define RS 144u
#define EXPSHIFT 10.0f

__global__ __launch_bounds__(512, 1)
void attn_mma_kernel(const float* __restrict__ attn_bias,
                     const unsigned char* __restrict__ kmask)
{
    extern __shared__ char dsm[];
    char* sp = dsm + ((128 - (smem_u32(dsm) & 127)) & 127);
    const uint32_t sb = smem_u32(sp);

    const int bh = blockIdx.y;
    const int b  = bh >> 4;
    const int h  = bh & 15;
    const int qbase = blockIdx.x * 256;
    const int tid  = threadIdx.x;
    const int lane = tid & 31;
    const int w    = tid >> 5;
    const int wq   = w & 7;
    const int kh2  = (w >> 3) * 32;

    for (int i = tid; i < SEQT; i += 512)
        *reinterpret_cast<float*>(sp + AMSK + i * 4) =
            kmask[b * SEQT + i] ? -3.0e38f : -EXPSHIFT;

#pragma unroll
    for (int i = 0; i < 4; i++) {
        int g = tid + i * 512;
        int row = g >> 3, cc = g & 7;
        CPASYNC16(sb + AQF + row * RS + cc * 16,
                  g_qf + ((size_t)bh * SEQT + qbase + row) * HDIM + cc * 8);
    }

    const int krow = tid >> 3, kcc = tid & 7;
    const uint32_t kvd = (uint32_t)(krow * RS + kcc * 16);
    const __half* pk = g_kf  + ((size_t)bh * SEQT + krow) * HDIM + kcc * 8;
    const __half* pv = g_vth + ((size_t)bh * HDIM + krow) * SEQT + kcc * 8;

    auto load_kv = [&](int kb, uint32_t bufoff) {
        CPASYNC16(sb + bufoff + kvd,         pk + (size_t)kb * HDIM);
        CPASYNC16(sb + bufoff + 9216u + kvd, pv + kb);
    };

    const int brow = tid >> 4, bch = tid & 15;
    const int bswz = bch ^ (brow & 15);
    const uint32_t bd0 = (uint32_t)(brow * 256 + bswz * 16);
    const float* pbias = attn_bias + (size_t)bh * SEQT * SEQT +
                         (size_t)(qbase + brow) * SEQT + bch * 4;

    auto load_bias = [&](int kb, uint32_t bufoff) {
#pragma unroll
        for (int i = 0; i < 8; i++)
            CPASYNC16(sb + bufoff + bd0 + 8192u * i,
                      pbias + (size_t)(32 * i) * SEQT + kb);
    };

    load_kv(0, ABUF0);
    load_bias(0, BIAS0);
    CPCOMMIT();
    CPWAIT0();
    __syncthreads();

    float oacc[2][8][4];
#pragma unroll
    for (int mi = 0; mi < 2; mi++)
#pragma unroll
        for (int i = 0; i < 8; i++)
#pragma unroll
            for (int j = 0; j < 4; j++) oacc[mi][i][j] = 0.f;
    float rsum[2][2] = {{0.f, 0.f}, {0.f, 0.f}};

    const uint32_t aColH = (uint32_t)((lane >> 4) * 8);
    const uint32_t aRowL = (uint32_t)(lane & 15);
    const uint32_t bRowB = (uint32_t)((lane & 7) + ((lane >> 4) << 3));
    const uint32_t bHi8  = (uint32_t)(((lane >> 3) & 1) * 8);

    auto bias_rd = [&](uint32_t bbuf, int rloc, int col) -> float2 {
        uint32_t addr = bbuf + (uint32_t)(rloc * 256) +
            ((uint32_t)((col >> 2) ^ (rloc & 15)) << 4) + (uint32_t)((col & 3) << 2);
        return *reinterpret_cast<float2*>(sp + addr);
    };

    for (int it = 0; it < 16; ++it) {
        const int kb = it * 64;
        const uint32_t buf  = (it & 1) ? ABUF1 : ABUF0;
        const uint32_t bbuf = (it & 1) ? BIAS1 : BIAS0;
        if (it + 1 < 16) {
            load_kv((it + 1) * 64, (it & 1) ? ABUF0 : ABUF1);
            load_bias((it + 1) * 64, (it & 1) ? BIAS0 : BIAS1);
            CPCOMMIT();
        }

        float sacc[2][4][4];
#pragma unroll
        for (int mi = 0; mi < 2; mi++)
#pragma unroll
            for (int i = 0; i < 4; i++)
#pragma unroll
                for (int j = 0; j < 4; j++) sacc[mi][i][j] = 0.f;

#pragma unroll
        for (int kc = 0; kc < 4; kc++) {
            uint32_t kf[2][4];
#pragma unroll
            for (int nt = 0; nt < 2; nt++) {
                uint32_t addr = sb + buf + (kh2 + nt * 16 + bRowB) * RS + (kc * 16 + bHi8) * 2;
                LDM4(kf[nt][0], kf[nt][1], kf[nt][2], kf[nt][3], addr);
            }
#pragma unroll
            for (int mi = 0; mi < 2; mi++) {
                uint32_t qf[4];
                uint32_t qaddr = sb + AQF + (wq * 32 + mi * 16 + aRowL) * RS +
                                 (aColH + kc * 16) * 2;
                LDM4(qf[0], qf[1], qf[2], qf[3], qaddr);
#pragma unroll
                for (int n8 = 0; n8 < 4; n8++) {
                    const int nt = n8 >> 1, hh = (n8 & 1) * 2;
                    MMAF16(sacc[mi][n8], qf, kf[nt][hh], kf[nt][hh + 1]);
                }
            }
        }

        uint32_t pph[2][8];
#pragma unroll
        for (int mi = 0; mi < 2; mi++)
#pragma unroll
            for (int n8 = 0; n8 < 4; n8++) {
                const int col  = kh2 + n8 * 8 + (lane & 3) * 2;
                const int rloc = wq * 32 + mi * 16 + (lane >> 2);
                float2 b0 = bias_rd(bbuf, rloc,     col);
                float2 b1 = bias_rd(bbuf, rloc + 8, col);
                float2 mk = *reinterpret_cast<const float2*>(
                    sp + AMSK + (kb + col) * 4);
                float p0 = __expf(sacc[mi][n8][0] + b0.x + mk.x);
                float p1 = __expf(sacc[mi][n8][1] + b0.y + mk.y);
                float p2 = __expf(sacc[mi][n8][2] + b1.x + mk.x);
                float p3 = __expf(sacc[mi][n8][3] + b1.y + mk.y);
                rsum[mi][0] += p0 + p1;
                rsum[mi][1] += p2 + p3;
                __half2 a = __floats2half2_rn(p0, p1);
                __half2 bq = __floats2half2_rn(p2, p3);
                pph[mi][n8 * 2]     = *reinterpret_cast<uint32_t*>(&a);
                pph[mi][n8 * 2 + 1] = *reinterpret_cast<uint32_t*>(&bq);
            }

#pragma unroll
        for (int kc2 = 0; kc2 < 2; kc2++) {
            uint32_t vfh[4][4];
#pragma unroll
            for (int nt = 0; nt < 4; nt++) {
                uint32_t addr = sb + buf + 9216u + (bRowB + nt * 16) * RS +
                                (kh2 + kc2 * 16 + bHi8) * 2;
                LDM4(vfh[nt][0], vfh[nt][1], vfh[nt][2], vfh[nt][3], addr);
            }
#pragma unroll
            for (int mi = 0; mi < 2; mi++) {
                uint32_t pah[4] = { pph[mi][4 * kc2],     pph[mi][4 * kc2 + 1],
                                    pph[mi][4 * kc2 + 2], pph[mi][4 * kc2 + 3] };
#pragma unroll
                for (int n8 = 0; n8 < 8; n8++) {
                    const int nt = n8 >> 1, hh = (n8 & 1) * 2;
                    MMAF16(oacc[mi][n8], pah, vfh[nt][hh], vfh[nt][hh + 1]);
                }
            }
        }

        CPWAIT0();
        __syncthreads();
    }

#pragma unroll
    for (int mi = 0; mi < 2; mi++)
#pragma unroll
        for (int j = 0; j < 2; j++) {
            rsum[mi][j] += __shfl_xor_sync(0xffffffffu, rsum[mi][j], 1);
            rsum[mi][j] += __shfl_xor_sync(0xffffffffu, rsum[mi][j], 2);
        }

    if (w >= 8) {
        const uint32_t ob = OSCR + (uint32_t)(w - 8) * 8192u;
#pragma unroll
        for (int mi = 0; mi < 2; mi++)
#pragma unroll
            for (int n8 = 0; n8 < 8; n8++) {
                float4 t = make_float4(oacc[mi][n8][0], oacc[mi][n8][1],
                                       oacc[mi][n8][2], oacc[mi][n8][3]);
                *reinterpret_cast<float4*>(sp + ob + mi * 4096 + n8 * 512 + lane * 16) = t;
            }
        *reinterpret_cast<float4*>(sp + RSCR + (w - 8) * 512 + lane * 16) =
            make_float4(rsum[0][0], rsum[0][1], rsum[1][0], rsum[1][1]);
    }
    __syncthreads();
    if (w < 8) {
        const uint32_t ob = OSCR + (uint32_t)w * 8192u;
        float4 prs = *reinterpret_cast<float4*>(sp + RSCR + w * 512 + lane * 16);
        float inv[2][2];
        inv[0][0] = 1.f / (rsum[0][0] + prs.x);
        inv[0][1] = 1.f / (rsum[0][1] + prs.y);
        inv[1][0] = 1.f / (rsum[1][0] + prs.z);
        inv[1][1] = 1.f / (rsum[1][1] + prs.w);

        const int col0 = h * HDIM + (lane & 3) * 2;
#pragma unroll
        for (int mi = 0; mi < 2; mi++) {
            const int row0 = qbase + wq * 32 + mi * 16 + (lane >> 2);
#pragma unroll
            for (int n8 = 0; n8 < 8; n8++) {
                float4 t = *reinterpret_cast<float4*>(
                    sp + ob + mi * 4096 + n8 * 512 + lane * 16);
                float x0 = (oacc[mi][n8][0] + t.x) * inv[mi][0];
                float x1 = (oacc[mi][n8][1] + t.y) * inv[mi][0];
                float y0 = (oacc[mi][n8][2] + t.z) * inv[mi][1];
                float y1 = (oacc[mi][n8][3] + t.w) * inv[mi][1];
                size_t i0 = (size_t)(b * SEQT + row0) * EMB + col0 + n8 * 8;
                size_t i1 = (size_t)(b * SEQT + row0 + 8) * EMB + col0 + n8 * 8;
                *reinterpret_cast<uint32_t*>(g_ao + i0) =
                    pack2h(__float2half_rn(x0), __float2half_rn(x1));
                *reinterpret_cast<uint32_t*>(g_ao + i1) =
                    pack2h(__float2half_rn(y0), __float2half_rn(y1));
            }
        }
    }
}

// ---------------------------------------------------------------------------
// Launch
// ---------------------------------------------------------------------------
extern "C" void kernel_launch(void* const* d_in, const int* in_sizes, int n_in,
                              void* d_out, int out_size)
{
    const float*         query = (const float*)d_in[0];
    const float*         abias = (const float*)d_in[1];
    const unsigned char* kmask = (const unsigned char*)d_in[2];
    const float*         in_w  = (const float*)d_in[3];
    const float*         in_b  = (const float*)d_in[4];
    const float*         out_w = (const float*)d_in[5];
    const float*         out_b = (const float*)d_in[6];
    float*               out   = (float*)d_out;

    __half *xf, *w1, *w2, *ao;
    cudaGetSymbolAddress((void**)&xf, g_xf);
    cudaGetSymbolAddress((void**)&w1, g_w1);
    cudaGetSymbolAddress((void**)&w2, g_w2);
    cudaGetSymbolAddress((void**)&ao, g_ao);

    cudaFuncSetAttribute(gemm_f16_kernel<0>,
                         cudaFuncAttributeMaxDynamicSharedMemorySize, GEMM_SMEM);
    cudaFuncSetAttribute(gemm_f16_kernel<1>,
                         cudaFuncAttributeMaxDynamicSharedMemorySize, GEMM_SMEM);
    cudaFuncSetAttribute(attn_mma_kernel,
                         cudaFuncAttributeMaxDynamicSharedMemorySize, ATTN_SMEM);

    // 0) fused operand conversion
    convert_all_kernel<<<(CTOT + 255) / 256, 256>>>(query, in_w, out_w);

    // 1) QKV projection + fused epilogue
    {
        dim3 grid(E3 / 128, MTOK / 128);
        gemm_f16_kernel<1><<<grid, 256, GEMM_SMEM>>>(xf, w1, in_b, nullptr, E3, EMB);
    }
    // 2) Attention
    {
        dim3 grid(SEQT / 256, BH);
        attn_mma_kernel<<<grid, 512, ATTN_SMEM>>>(abias, kmask);
    }
    // 3) Output projection
    {
        dim3 grid(EMB / 128, MTOK / 128);
        gemm_f16_kernel<0><<<grid, 256, GEMM_SMEM>>>(ao, w2, out_b, out, EMB, EMB);
    }
}